// round 2
// baseline (speedup 1.0000x reference)
#include <cuda_runtime.h>
#include <math.h>

#define BB   4
#define CDD  5
#define HIS  50
#define LL   20
#define TT   41     // 2*LL+1
#define EE   300
#define HH   16
#define VV   16
#define RR   256
#define QQ   200
#define NSC  (BB*CDD)        // 20 candidate sequences
#define NSH  (BB*HIS)        // 200 history sequences
#define NS   (NSC+NSH)       // 220
#define NBCI (BB*CDD*HIS)    // 1000

#define INV_SCALE 0.057735026918962584f   // 1/sqrt(300)

// ---------------- device scratch (static globals; no runtime allocs) ----------------
__device__ float g_X[NS*LL*EE];          // gathered embeddings     [220,20,300]
__device__ float g_Rep[NS*LL*RR];        // stage-1 outputs         [220,20,256]
__device__ float g_Q[NS*HH*LL*RR];       // itrs Q projections      [220,16,20,256]
__device__ float g_V[NS*LL*RR];          // itrs V projections      [220,20,256] (heads concat)
__device__ float g_q1[HH*RR];            // ones-row query per head
__device__ float g_v1[RR];               // ones-row value (heads concat)
__device__ float g_rep[NBCI*RR];         // pooled reps             [1000,256]
__device__ float g_score[NSC];           // pre-logsoftmax scores

// ---------------- K1: gather embeddings ----------------
__global__ void k_gather(const int* __restrict__ cand, const int* __restrict__ clk,
                         const float* __restrict__ emb) {
    int s = blockIdx.x;  // 0..219
    const int* tok = (s < NSC) ? (cand + s*LL) : (clk + (s-NSC)*LL);
    for (int idx = threadIdx.x; idx < LL*EE; idx += blockDim.x) {
        int t = idx / EE, d = idx - t*EE;
        g_X[(s*LL + t)*EE + d] = emb[(size_t)tok[t]*EE + d];
    }
}

// ---------------- K2: stage-1 word MHSA, one block per (seq, head) ----------------
// dyn smem: sX[20*300], sQ[20*300], sS[20*20], sXV[20*16]  = 12720 floats
#define K2_SMEM_FLOATS (LL*EE + LL*EE + LL*LL + LL*VV)
__global__ void __launch_bounds__(320, 4)
k_words(const float* __restrict__ Wq, const float* __restrict__ Wv) {
    extern __shared__ float sm[];
    float* sX  = sm;
    float* sQ  = sm + LL*EE;
    float* sS  = sm + 2*LL*EE;
    float* sXV = sm + 2*LL*EE + LL*LL;

    int s = blockIdx.x, h = blockIdx.y;
    int tid = threadIdx.x;

    for (int i = tid; i < LL*EE; i += 320) sX[i] = g_X[s*LL*EE + i];
    __syncthreads();

    // Q[t][j] = sum_d X[t][d] * Wq[h][d][j]
    if (tid < EE) {
        int j = tid;
        float acc[LL];
        #pragma unroll
        for (int t = 0; t < LL; t++) acc[t] = 0.f;
        const float* w = Wq + (size_t)h*EE*EE + j;
        for (int d = 0; d < EE; d++) {
            float wv = w[(size_t)d*EE];
            #pragma unroll
            for (int t = 0; t < LL; t++) acc[t] = fmaf(sX[t*EE + d], wv, acc[t]);
        }
        #pragma unroll
        for (int t = 0; t < LL; t++) sQ[t*EE + j] = acc[t];
    }
    __syncthreads();

    // S[t][u] = dot(Q[t], X[u]) / SCALE  — warp per dot
    int warp = tid >> 5, lane = tid & 31;
    for (int p = warp; p < LL*LL; p += 10) {
        int t = p / LL, u = p - t*LL;
        float partial = 0.f;
        for (int d = lane; d < EE; d += 32)
            partial = fmaf(sQ[t*EE + d], sX[u*EE + d], partial);
        #pragma unroll
        for (int o = 16; o; o >>= 1) partial += __shfl_xor_sync(0xffffffffu, partial, o);
        if (lane == 0) sS[t*LL + u] = partial * INV_SCALE;
    }
    __syncthreads();

    // softmax rows (thread per row)
    if (tid < LL) {
        float* row = sS + tid*LL;
        float m = row[0];
        #pragma unroll
        for (int u = 1; u < LL; u++) m = fmaxf(m, row[u]);
        float ssum = 0.f;
        #pragma unroll
        for (int u = 0; u < LL; u++) { float e = __expf(row[u] - m); row[u] = e; ssum += e; }
        float inv = 1.0f / ssum;
        #pragma unroll
        for (int u = 0; u < LL; u++) row[u] *= inv;
    }
    // XV[u][v] = sum_d X[u][d] * Wv[h][d][v]  (320 threads exactly)
    {
        int u = tid / VV, v = tid - (tid / VV)*VV;
        float acc = 0.f;
        const float* wv = Wv + (size_t)h*EE*VV + v;
        for (int d = 0; d < EE; d++) acc = fmaf(sX[u*EE + d], wv[d*VV], acc);
        sXV[u*VV + v] = acc;
    }
    __syncthreads();

    // out[t][v] = sum_u A[t][u] * XV[u][v]
    {
        int t = tid / VV, v = tid - (tid / VV)*VV;
        float acc = 0.f;
        #pragma unroll
        for (int u = 0; u < LL; u++) acc = fmaf(sS[t*LL + u], sXV[u*VV + v], acc);
        g_Rep[(s*LL + t)*RR + h*VV + v] = acc;
    }
}

// ---------------- K3: itrs projections, one block per (seq, head) ----------------
__global__ void __launch_bounds__(256, 4)
k_proj(const float* __restrict__ Wq, const float* __restrict__ Wv) {
    __shared__ float sRep[LL*RR];
    int s = blockIdx.x, h = blockIdx.y, tid = threadIdx.x;

    for (int i = tid; i < LL*RR; i += 256) sRep[i] = g_Rep[s*LL*RR + i];
    __syncthreads();

    // Q[t][j]
    {
        int j = tid;
        float acc[LL];
        #pragma unroll
        for (int t = 0; t < LL; t++) acc[t] = 0.f;
        const float* w = Wq + (size_t)h*RR*RR + j;
        for (int r = 0; r < RR; r++) {
            float wv = w[r*RR];
            #pragma unroll
            for (int t = 0; t < LL; t++) acc[t] = fmaf(sRep[t*RR + r], wv, acc[t]);
        }
        int base = ((s*HH + h)*LL)*RR + j;
        #pragma unroll
        for (int t = 0; t < LL; t++) g_Q[base + t*RR] = acc[t];
    }
    // V[t][v]
    for (int p = tid; p < LL*VV; p += 256) {
        int t = p / VV, v = p - (p / VV)*VV;
        float acc = 0.f;
        const float* wv = Wv + (size_t)h*RR*VV + v;
        for (int r = 0; r < RR; r++) acc = fmaf(sRep[t*RR + r], wv[r*VV], acc);
        g_V[(s*LL + t)*RR + h*VV + v] = acc;
    }
}

// ---------------- K3b: ones-row projections (column sums) ----------------
__global__ void k_ones(const float* __restrict__ Wq, const float* __restrict__ Wv) {
    int h = blockIdx.x, j = threadIdx.x;  // 16 blocks, 256 threads
    float acc = 0.f;
    const float* w = Wq + (size_t)h*RR*RR + j;
    for (int r = 0; r < RR; r++) acc += w[r*RR];
    g_q1[h*RR + j] = acc;
    if (j < VV) {
        float a2 = 0.f;
        const float* wv = Wv + (size_t)h*RR*VV + j;
        for (int r = 0; r < RR; r++) a2 += wv[r*VV];
        g_v1[h*VV + j] = a2;
    }
}

// ---------------- K4: fused attention + pooling, one block per (b,c,i) ----------------
// smem layout (floats):
#define SC_C    0
#define SC_H    (SC_C + LL*RR)          // 5120
#define SC_VC   (SC_H + LL*RR)          // 10240
#define SC_VH   (SC_VC + LL*RR)         // 15360
#define SC_V1   (SC_VH + LL*RR)         // 20480
#define SC_VAL  (SC_V1 + RR)            // 20736
#define SCR     (SC_VAL + TT*RR)        // 31232
#define SC_QC   SCR
#define SC_QH   (SCR + LL*RR)
#define SC_Q1   (SCR + 2*LL*RR)         // 41472
#define SC_S    (SC_Q1 + RR)            // 41728  (TT*TT = 1681 -> ends 43409)
#define SC_KW   SCR                     // 64*QQ = 12800 -> ends 44032
#define SC_POOL 44032
#define SC_W    (SC_POOL + 48)
#define K4_SMEM_FLOATS (SC_W + 48)      // 44128

__global__ void __launch_bounds__(256, 1)
k_fuse(const float* __restrict__ keyW, const float* __restrict__ keyb,
       const float* __restrict__ query) {
    extern __shared__ float sm[];
    float* sC   = sm + SC_C;
    float* sH   = sm + SC_H;
    float* sVc  = sm + SC_VC;
    float* sVh  = sm + SC_VH;
    float* sV1  = sm + SC_V1;
    float* sVal = sm + SC_VAL;
    float* sQc  = sm + SC_QC;
    float* sQh  = sm + SC_QH;
    float* sQ1  = sm + SC_Q1;
    float* sS   = sm + SC_S;
    float* sKW  = sm + SC_KW;
    float* sPool= sm + SC_POOL;
    float* sW   = sm + SC_W;

    int bci = blockIdx.x;
    int i   = bci % HIS;
    int bc  = bci / HIS;
    int b   = bc / CDD;
    int sc  = bc;
    int sh  = NSC + b*HIS + i;

    int tid = threadIdx.x;
    int warp = tid >> 5, lane = tid & 31;

    // persistent loads (float4)
    {
        const float4* gc  = (const float4*)(g_Rep + sc*LL*RR);
        const float4* gh  = (const float4*)(g_Rep + sh*LL*RR);
        const float4* gvc = (const float4*)(g_V   + sc*LL*RR);
        const float4* gvh = (const float4*)(g_V   + sh*LL*RR);
        float4* dC  = (float4*)sC;  float4* dH  = (float4*)sH;
        float4* dVc = (float4*)sVc; float4* dVh = (float4*)sVh;
        for (int idx = tid; idx < LL*RR/4; idx += 256) {
            dC[idx] = gc[idx]; dH[idx] = gh[idx];
            dVc[idx] = gvc[idx]; dVh[idx] = gvh[idx];
        }
        if (tid < RR) sV1[tid] = g_v1[tid];
    }

    for (int h = 0; h < HH; h++) {
        __syncthreads();   // previous head's reads of sQc/sQh/sS done; first iter: persistent loads done
        {
            const float4* gq  = (const float4*)(g_Q + (size_t)(sc*HH + h)*LL*RR);
            const float4* gq2 = (const float4*)(g_Q + (size_t)(sh*HH + h)*LL*RR);
            float4* dQc = (float4*)sQc; float4* dQh = (float4*)sQh;
            for (int idx = tid; idx < LL*RR/4; idx += 256) { dQc[idx] = gq[idx]; dQh[idx] = gq2[idx]; }
            if (tid < RR) sQ1[tid] = g_q1[h*RR + tid];
        }
        __syncthreads();

        // scores: warp per (q,k) dot over 256
        for (int p = warp; p < TT*TT; p += 8) {
            int q = p / TT, k = p - (p / TT)*TT;
            const float* qp = (q < LL) ? (sQc + q*RR) : ((q == LL) ? sQ1 : (sQh + (q-LL-1)*RR));
            const float4* q4 = (const float4*)qp;
            float partial;
            float4 a = q4[lane], a2 = q4[lane + 32];
            if (k == LL) {
                partial = a.x + a.y + a.z + a.w + a2.x + a2.y + a2.z + a2.w;
            } else {
                const float* kp = (k < LL) ? (sC + k*RR) : (sH + (k-LL-1)*RR);
                const float4* k4 = (const float4*)kp;
                float4 bb = k4[lane], b2 = k4[lane + 32];
                partial  = a.x*bb.x + a.y*bb.y + a.z*bb.z + a.w*bb.w;
                partial += a2.x*b2.x + a2.y*b2.y + a2.z*b2.z + a2.w*b2.w;
            }
            #pragma unroll
            for (int o = 16; o; o >>= 1) partial += __shfl_xor_sync(0xffffffffu, partial, o);
            if (lane == 0) sS[q*TT + k] = partial * INV_SCALE;
        }
        __syncthreads();

        // softmax rows
        if (tid < TT) {
            float* row = sS + tid*TT;
            float m = row[0];
            #pragma unroll
            for (int k = 1; k < TT; k++) m = fmaxf(m, row[k]);
            float ssum = 0.f;
            #pragma unroll
            for (int k = 0; k < TT; k++) { float e = __expf(row[k] - m); row[k] = e; ssum += e; }
            float inv = 1.0f / ssum;
            #pragma unroll
            for (int k = 0; k < TT; k++) row[k] *= inv;
        }
        __syncthreads();

        // O[q][v] = A[q] @ fusedV  -> sVal[q][h*16+v]
        for (int p = tid; p < TT*VV; p += 256) {
            int q = p / VV, v = p - (p / VV)*VV;
            int col = h*VV + v;
            const float* arow = sS + q*TT;
            float acc = arow[LL] * sV1[col];
            #pragma unroll
            for (int k = 0; k < LL; k++) acc = fmaf(arow[k], sVc[k*RR + col], acc);
            #pragma unroll
            for (int k = 0; k < LL; k++) acc = fmaf(arow[LL+1+k], sVh[k*RR + col], acc);
            sVal[q*RR + col] = acc;
        }
    }
    __syncthreads();  // sVal complete; scratch region free

    // additive pooling: kmat[t][j] = tanh(val[t] . keyW[:,j] + keyb[j])
    if (tid < TT) sPool[tid] = 0.f;

    float acc[TT];
    #pragma unroll
    for (int t = 0; t < TT; t++) acc[t] = 0.f;
    int j = tid;
    bool jact = (j < QQ);

    for (int rc = 0; rc < RR/64; rc++) {
        __syncthreads();
        for (int idx = tid; idx < 64*QQ; idx += 256) sKW[idx] = keyW[rc*64*QQ + idx];
        __syncthreads();
        if (jact) {
            for (int r = 0; r < 64; r++) {
                float w = sKW[r*QQ + j];
                int rg = rc*64 + r;
                #pragma unroll
                for (int t = 0; t < TT; t++) acc[t] = fmaf(sVal[t*RR + rg], w, acc[t]);
            }
        }
    }
    {
        float qj = jact ? query[j] : 0.f;
        float kb = jact ? keyb[j]  : 0.f;
        #pragma unroll
        for (int t = 0; t < TT; t++) {
            float v = jact ? qj * tanhf(acc[t] + kb) : 0.f;
            #pragma unroll
            for (int o = 16; o; o >>= 1) v += __shfl_xor_sync(0xffffffffu, v, o);
            if (lane == 0 && warp < 7) atomicAdd(&sPool[t], v);
        }
    }
    __syncthreads();

    if (tid == 0) {
        float m = sPool[0] * INV_SCALE;
        #pragma unroll
        for (int t = 1; t < TT; t++) m = fmaxf(m, sPool[t] * INV_SCALE);
        float ssum = 0.f;
        #pragma unroll
        for (int t = 0; t < TT; t++) { float e = __expf(sPool[t]*INV_SCALE - m); sW[t] = e; ssum += e; }
        float inv = 1.0f / ssum;
        #pragma unroll
        for (int t = 0; t < TT; t++) sW[t] *= inv;
    }
    __syncthreads();

    {
        int r = tid;  // 256
        float a2 = 0.f;
        #pragma unroll
        for (int t = 0; t < TT; t++) a2 = fmaf(sW[t], sVal[t*RR + r], a2);
        g_rep[(size_t)bci*RR + r] = a2;
    }
}

// ---------------- K5a: mean over HIS + ltr ----------------
__global__ void k_fv(const float* __restrict__ ltr_w, const float* __restrict__ ltr_b) {
    __shared__ float red[256];
    int bc = blockIdx.x;       // 20
    int r = threadIdx.x;       // 256
    float ssum = 0.f;
    for (int i = 0; i < HIS; i++) ssum += g_rep[(size_t)(bc*HIS + i)*RR + r];
    red[r] = (ssum * (1.0f/HIS)) * ltr_w[r];
    __syncthreads();
    for (int off = 128; off; off >>= 1) {
        if (r < off) red[r] += red[r + off];
        __syncthreads();
    }
    if (r == 0) g_score[bc] = red[0] + ltr_b[0];
}

// ---------------- K5b: log_softmax over CDD ----------------
__global__ void k_out(float* __restrict__ out) {
    int b = threadIdx.x;
    if (b < BB) {
        float s[CDD];
        float m = -1e30f;
        #pragma unroll
        for (int c = 0; c < CDD; c++) { s[c] = g_score[b*CDD + c]; m = fmaxf(m, s[c]); }
        float ssum = 0.f;
        #pragma unroll
        for (int c = 0; c < CDD; c++) ssum += expf(s[c] - m);
        float lse = logf(ssum);
        #pragma unroll
        for (int c = 0; c < CDD; c++) out[b*CDD + c] = s[c] - m - lse;
    }
}

// ---------------- launch ----------------
extern "C" void kernel_launch(void* const* d_in, const int* in_sizes, int n_in,
                              void* d_out, int out_size) {
    const int*   cand  = (const int*)  d_in[0];
    const int*   clk   = (const int*)  d_in[1];
    const float* emb   = (const float*)d_in[2];
    const float* Wq_w  = (const float*)d_in[3];
    const float* Wv_w  = (const float*)d_in[4];
    const float* Wq_i  = (const float*)d_in[5];
    const float* Wv_i  = (const float*)d_in[6];
    const float* keyW  = (const float*)d_in[7];
    const float* keyb  = (const float*)d_in[8];
    const float* query = (const float*)d_in[9];
    const float* ltr_w = (const float*)d_in[10];
    const float* ltr_b = (const float*)d_in[11];
    float* out = (float*)d_out;

    cudaFuncSetAttribute(k_words, cudaFuncAttributeMaxDynamicSharedMemorySize,
                         K2_SMEM_FLOATS * sizeof(float));
    cudaFuncSetAttribute(k_fuse, cudaFuncAttributeMaxDynamicSharedMemorySize,
                         K4_SMEM_FLOATS * sizeof(float));

    k_gather<<<NS, 256>>>(cand, clk, emb);
    k_words<<<dim3(NS, HH), 320, K2_SMEM_FLOATS * sizeof(float)>>>(Wq_w, Wv_w);
    k_proj<<<dim3(NS, HH), 256>>>(Wq_i, Wv_i);
    k_ones<<<HH, 256>>>(Wq_i, Wv_i);
    k_fuse<<<NBCI, 256, K4_SMEM_FLOATS * sizeof(float)>>>(keyW, keyb, query);
    k_fv<<<NSC, 256>>>(ltr_w, ltr_b);
    k_out<<<1, 32>>>(out);
}

// round 3
// speedup vs baseline: 3.3403x; 3.3403x over previous
#include <cuda_runtime.h>
#include <math.h>

#define BB   4
#define CDD  5
#define HIS  50
#define LL   20
#define TT   41     // 2*LL+1
#define EE   300
#define HH   16
#define VV   16
#define RR   256
#define QQ   200
#define NSC  (BB*CDD)        // 20 candidate sequences
#define NSH  (BB*HIS)        // 200 history sequences
#define NS   (NSC+NSH)       // 220
#define NBCI (BB*CDD*HIS)    // 1000

#define INV_SCALE 0.057735026918962584f   // 1/sqrt(300)

// ---------------- device scratch ----------------
__device__ float g_X[NS*LL*EE];          // gathered embeddings     [220,20,300]
__device__ float g_Rep[NS*LL*RR];        // stage-1 outputs (= fusion keys) [220,20,256]
__device__ float g_Q[NS*HH*LL*RR];       // itrs Q projections      [220,16,20,256]
__device__ float g_V[NS*LL*RR];          // itrs V projections      [220,20,256]
__device__ float g_q1[HH*RR];            // ones-row query per head
__device__ float g_v1[RR];               // ones-row value
__device__ float g_Scc[NSC*HH*21*21];    // cand-cand score blocks (raw dots)
__device__ float g_Shh[NSH*HH*21*21];    // his-his score blocks (raw dots)
__device__ float g_Sx1[(size_t)BB*HH*100*1000]; // Qc . H  [b][h][c*20+t][i*20+u]
__device__ float g_Sx2[(size_t)BB*HH*1000*100]; // Qh . C  [b][h][i*20+t][c*20+u]
__device__ float g_rep[NBCI*RR];         // pooled reps             [1000,256]
__device__ float g_score[NSC];           // pre-logsoftmax scores

// ---------------- K1: gather embeddings ----------------
__global__ void k_gather(const int* __restrict__ cand, const int* __restrict__ clk,
                         const float* __restrict__ emb) {
    int s = blockIdx.x;
    const int* tok = (s < NSC) ? (cand + s*LL) : (clk + (s-NSC)*LL);
    for (int idx = threadIdx.x; idx < LL*EE; idx += blockDim.x) {
        int t = idx / EE, d = idx - t*EE;
        g_X[(s*LL + t)*EE + d] = emb[(size_t)tok[t]*EE + d];
    }
}

// ---------------- K2: stage-1 word MHSA ----------------
#define K2_SMEM_FLOATS (LL*EE + LL*EE + LL*LL + LL*VV)
__global__ void __launch_bounds__(320, 4)
k_words(const float* __restrict__ Wq, const float* __restrict__ Wv) {
    extern __shared__ float sm[];
    float* sX  = sm;
    float* sQ  = sm + LL*EE;
    float* sS  = sm + 2*LL*EE;
    float* sXV = sm + 2*LL*EE + LL*LL;

    int s = blockIdx.x, h = blockIdx.y;
    int tid = threadIdx.x;

    for (int i = tid; i < LL*EE; i += 320) sX[i] = g_X[s*LL*EE + i];
    __syncthreads();

    if (tid < EE) {
        int j = tid;
        float acc[LL];
        #pragma unroll
        for (int t = 0; t < LL; t++) acc[t] = 0.f;
        const float* w = Wq + (size_t)h*EE*EE + j;
        for (int d = 0; d < EE; d++) {
            float wv = w[(size_t)d*EE];
            #pragma unroll
            for (int t = 0; t < LL; t++) acc[t] = fmaf(sX[t*EE + d], wv, acc[t]);
        }
        #pragma unroll
        for (int t = 0; t < LL; t++) sQ[t*EE + j] = acc[t];
    }
    __syncthreads();

    int warp = tid >> 5, lane = tid & 31;
    for (int p = warp; p < LL*LL; p += 10) {
        int t = p / LL, u = p - t*LL;
        float partial = 0.f;
        for (int d = lane; d < EE; d += 32)
            partial = fmaf(sQ[t*EE + d], sX[u*EE + d], partial);
        #pragma unroll
        for (int o = 16; o; o >>= 1) partial += __shfl_xor_sync(0xffffffffu, partial, o);
        if (lane == 0) sS[t*LL + u] = partial * INV_SCALE;
    }
    __syncthreads();

    if (tid < LL) {
        float* row = sS + tid*LL;
        float m = row[0];
        #pragma unroll
        for (int u = 1; u < LL; u++) m = fmaxf(m, row[u]);
        float ssum = 0.f;
        #pragma unroll
        for (int u = 0; u < LL; u++) { float e = __expf(row[u] - m); row[u] = e; ssum += e; }
        float inv = 1.0f / ssum;
        #pragma unroll
        for (int u = 0; u < LL; u++) row[u] *= inv;
    }
    {
        int u = tid / VV, v = tid - (tid / VV)*VV;
        float acc = 0.f;
        const float* wv = Wv + (size_t)h*EE*VV + v;
        for (int d = 0; d < EE; d++) acc = fmaf(sX[u*EE + d], wv[d*VV], acc);
        sXV[u*VV + v] = acc;
    }
    __syncthreads();

    {
        int t = tid / VV, v = tid - (tid / VV)*VV;
        float acc = 0.f;
        #pragma unroll
        for (int u = 0; u < LL; u++) acc = fmaf(sS[t*LL + u], sXV[u*VV + v], acc);
        g_Rep[(s*LL + t)*RR + h*VV + v] = acc;
    }
}

// ---------------- K3: itrs projections ----------------
__global__ void __launch_bounds__(256, 4)
k_proj(const float* __restrict__ Wq, const float* __restrict__ Wv) {
    __shared__ float sRep[LL*RR];
    int s = blockIdx.x, h = blockIdx.y, tid = threadIdx.x;

    for (int i = tid; i < LL*RR; i += 256) sRep[i] = g_Rep[s*LL*RR + i];
    __syncthreads();

    {
        int j = tid;
        float acc[LL];
        #pragma unroll
        for (int t = 0; t < LL; t++) acc[t] = 0.f;
        const float* w = Wq + (size_t)h*RR*RR + j;
        for (int r = 0; r < RR; r++) {
            float wv = w[r*RR];
            #pragma unroll
            for (int t = 0; t < LL; t++) acc[t] = fmaf(sRep[t*RR + r], wv, acc[t]);
        }
        int base = ((s*HH + h)*LL)*RR + j;
        #pragma unroll
        for (int t = 0; t < LL; t++) g_Q[base + t*RR] = acc[t];
    }
    for (int p = tid; p < LL*VV; p += 256) {
        int t = p / VV, v = p - (p / VV)*VV;
        float acc = 0.f;
        const float* wv = Wv + (size_t)h*RR*VV + v;
        for (int r = 0; r < RR; r++) acc = fmaf(sRep[t*RR + r], wv[r*VV], acc);
        g_V[(s*LL + t)*RR + h*VV + v] = acc;
    }
}

// ---------------- K3b: ones-row projections ----------------
__global__ void k_ones(const float* __restrict__ Wq, const float* __restrict__ Wv) {
    int h = blockIdx.x, j = threadIdx.x;
    float acc = 0.f;
    const float* w = Wq + (size_t)h*RR*RR + j;
    for (int r = 0; r < RR; r++) acc += w[r*RR];
    g_q1[h*RR + j] = acc;
    if (j < VV) {
        float a2 = 0.f;
        const float* wv = Wv + (size_t)h*RR*VV + j;
        for (int r = 0; r < RR; r++) a2 += wv[r*VV];
        g_v1[h*VV + j] = a2;
    }
}

// ---------------- K4a: diagonal score blocks (cc / hh) + ones row/col ----------------
// grid (220, 16), 256 threads. Output 21x21 raw-dot block.
__global__ void __launch_bounds__(256, 4)
k_diag() {
    __shared__ float sQ[21*RR];
    __shared__ float sK[LL*RR];
    int s = blockIdx.x, h = blockIdx.y, tid = threadIdx.x;

    {
        const float4* gq = (const float4*)(g_Q + (size_t)(s*HH + h)*LL*RR);
        const float4* gk = (const float4*)(g_Rep + (size_t)s*LL*RR);
        float4* dQ = (float4*)sQ; float4* dK = (float4*)sK;
        for (int idx = tid; idx < LL*RR/4; idx += 256) { dQ[idx] = gq[idx]; dK[idx] = gk[idx]; }
        if (tid < RR) sQ[LL*RR + tid] = g_q1[h*RR + tid];   // row 20 = q1
    }
    __syncthreads();

    float* out = (s < NSC) ? (g_Scc + ((size_t)s*HH + h)*441)
                           : (g_Shh + ((size_t)(s-NSC)*HH + h)*441);
    int warp = tid >> 5, lane = tid & 31;
    for (int p = warp; p < 21*21; p += 8) {
        int q = p / 21, k = p - q*21;
        const float4* q4 = (const float4*)(sQ + q*RR);
        float4 a = q4[lane], a2 = q4[lane + 32];
        float partial;
        if (k == 20) {
            partial = a.x + a.y + a.z + a.w + a2.x + a2.y + a2.z + a2.w;
        } else {
            const float4* k4 = (const float4*)(sK + k*RR);
            float4 bb = k4[lane], b2 = k4[lane + 32];
            partial  = a.x*bb.x + a.y*bb.y + a.z*bb.z + a.w*bb.w;
            partial += a2.x*b2.x + a2.y*b2.y + a2.z*b2.z + a2.w*b2.w;
        }
        #pragma unroll
        for (int o = 16; o; o >>= 1) partial += __shfl_xor_sync(0xffffffffu, partial, o);
        if (lane == 0) out[p] = partial;
    }
}

// ---------------- K4b: cross-score SGEMM ----------------
// flag 0: Sx1 = Qc(100x256) x H(1000x256)^T  per (b,h)   M=100,  N=1000
// flag 1: Sx2 = Qh(1000x256) x C(100x256)^T  per (b,h)   M=1000, N=100
// BM=BN=64, KC=32, 256 threads (16x16), 4x4 per thread.
#define APITCH 68
__global__ void __launch_bounds__(256, 4)
k_cross(int flag) {
    __shared__ float As[32*APITCH];
    __shared__ float Bs[32*APITCH];

    int bh = blockIdx.z;             // 0..63
    int b = bh >> 4, h = bh & 15;
    int nBase = blockIdx.x * 64;
    int mBase = blockIdx.y * 64;
    int M = flag ? 1000 : 100;
    int N = flag ? 100  : 1000;

    int tid = threadIdx.x;
    int tx = tid & 15, ty = tid >> 4;

    // per-thread load assignment: row = tid>>2 (0..63), k-group = (tid&3)*8
    int lrow = tid >> 2;
    int kgrp = (tid & 3) * 8;

    int am = mBase + lrow;
    int bn = nBase + lrow;
    bool av = am < M, bv = bn < N;
    int amc = av ? am : 0, bnc = bv ? bn : 0;

    const float *Aptr, *Bptr;
    if (!flag) {
        int c = amc / 20, t = amc % 20;
        Aptr = g_Q + (((size_t)(b*CDD + c)*HH + h)*LL + t)*RR;
        int i = bnc / 20, u = bnc % 20;
        Bptr = g_Rep + ((size_t)(NSC + b*HIS + i)*LL + u)*RR;
    } else {
        int i = amc / 20, u = amc % 20;
        Aptr = g_Q + (((size_t)(NSC + b*HIS + i)*HH + h)*LL + u)*RR;
        int c = bnc / 20, t = bnc % 20;
        Bptr = g_Rep + ((size_t)(b*CDD + c)*LL + t)*RR;
    }

    float acc[4][4];
    #pragma unroll
    for (int r = 0; r < 4; r++)
        #pragma unroll
        for (int j = 0; j < 4; j++) acc[r][j] = 0.f;

    for (int kc = 0; kc < RR; kc += 32) {
        float4 a0 = make_float4(0,0,0,0), a1 = a0, b0 = a0, b1 = a0;
        if (av) { a0 = *(const float4*)(Aptr + kc + kgrp); a1 = *(const float4*)(Aptr + kc + kgrp + 4); }
        if (bv) { b0 = *(const float4*)(Bptr + kc + kgrp); b1 = *(const float4*)(Bptr + kc + kgrp + 4); }
        __syncthreads();
        As[(kgrp+0)*APITCH + lrow] = a0.x; As[(kgrp+1)*APITCH + lrow] = a0.y;
        As[(kgrp+2)*APITCH + lrow] = a0.z; As[(kgrp+3)*APITCH + lrow] = a0.w;
        As[(kgrp+4)*APITCH + lrow] = a1.x; As[(kgrp+5)*APITCH + lrow] = a1.y;
        As[(kgrp+6)*APITCH + lrow] = a1.z; As[(kgrp+7)*APITCH + lrow] = a1.w;
        Bs[(kgrp+0)*APITCH + lrow] = b0.x; Bs[(kgrp+1)*APITCH + lrow] = b0.y;
        Bs[(kgrp+2)*APITCH + lrow] = b0.z; Bs[(kgrp+3)*APITCH + lrow] = b0.w;
        Bs[(kgrp+4)*APITCH + lrow] = b1.x; Bs[(kgrp+5)*APITCH + lrow] = b1.y;
        Bs[(kgrp+6)*APITCH + lrow] = b1.z; Bs[(kgrp+7)*APITCH + lrow] = b1.w;
        __syncthreads();

        #pragma unroll
        for (int k = 0; k < 32; k++) {
            float4 a = *(const float4*)(As + k*APITCH + ty*4);
            float4 bvv = *(const float4*)(Bs + k*APITCH + tx*4);
            float ar[4] = {a.x, a.y, a.z, a.w};
            float br[4] = {bvv.x, bvv.y, bvv.z, bvv.w};
            #pragma unroll
            for (int r = 0; r < 4; r++)
                #pragma unroll
                for (int j = 0; j < 4; j++) acc[r][j] = fmaf(ar[r], br[j], acc[r][j]);
        }
    }

    float* out = (flag ? g_Sx2 : g_Sx1) + (size_t)bh * 100 * 1000;
    #pragma unroll
    for (int r = 0; r < 4; r++) {
        int row = mBase + ty*4 + r;
        if (row < M) {
            #pragma unroll
            for (int j = 0; j < 4; j++) {
                int col = nBase + tx*4 + j;
                if (col < N) out[(size_t)row*N + col] = acc[r][j];
            }
        }
    }
}

// ---------------- K5: fused softmax + AV + pooling (scores precomputed) ----------------
#define SC_VC   0
#define SC_VH   (SC_VC + LL*RR)          // 5120
#define SC_V1   (SC_VH + LL*RR)          // 10240
#define SC_VAL  (SC_V1 + RR)             // 10496
#define SCR     (SC_VAL + TT*RR)         // 20992 (sS: 1681 / sKW chunk: 32*QQ=6400)
#define SC_POOL (SCR + 6400)             // 27392
#define SC_W    (SC_POOL + 48)           // 27440
#define K5_SMEM_FLOATS (SC_W + 48)       // 27488 floats = 109952 B

__global__ void __launch_bounds__(256, 2)
k_fuse(const float* __restrict__ keyW, const float* __restrict__ keyb,
       const float* __restrict__ query) {
    extern __shared__ float sm[];
    float* sVc  = sm + SC_VC;
    float* sVh  = sm + SC_VH;
    float* sV1  = sm + SC_V1;
    float* sVal = sm + SC_VAL;
    float* sS   = sm + SCR;
    float* sKW  = sm + SCR;
    float* sPool= sm + SC_POOL;
    float* sW   = sm + SC_W;

    int bci = blockIdx.x;
    int i   = bci % HIS;
    int bc  = bci / HIS;
    int b   = bc / CDD;
    int c   = bc - b*CDD;
    int sc  = bc;
    int sh  = NSC + b*HIS + i;

    int tid = threadIdx.x;
    int warp = tid >> 5, lane = tid & 31;

    {
        const float4* gvc = (const float4*)(g_V + (size_t)sc*LL*RR);
        const float4* gvh = (const float4*)(g_V + (size_t)sh*LL*RR);
        float4* dVc = (float4*)sVc; float4* dVh = (float4*)sVh;
        for (int idx = tid; idx < LL*RR/4; idx += 256) { dVc[idx] = gvc[idx]; dVh[idx] = gvh[idx]; }
        if (tid < RR) sV1[tid] = g_v1[tid];
    }

    for (int h = 0; h < HH; h++) {
        const float* scc = g_Scc + ((size_t)bc*HH + h)*441;
        const float* shh = g_Shh + ((size_t)(b*HIS + i)*HH + h)*441;
        const float* sx1 = g_Sx1 + ((size_t)(b*HH + h))*100*1000;
        const float* sx2 = g_Sx2 + ((size_t)(b*HH + h))*1000*100;

        __syncthreads();   // previous head's sS reads done (first iter: V loads done)
        for (int p = tid; p < TT*TT; p += 256) {
            int q = p / TT, k = p - q*TT;
            float v;
            if (q < LL) {
                if (k < LL)       v = __ldg(&scc[q*21 + k]);
                else if (k == LL) v = __ldg(&scc[q*21 + 20]);
                else              v = __ldg(&sx1[(size_t)(c*20 + q)*1000 + i*20 + (k-LL-1)]);
            } else if (q == LL) {
                if (k < LL)       v = __ldg(&scc[20*21 + k]);
                else if (k == LL) v = __ldg(&scc[20*21 + 20]);
                else              v = __ldg(&shh[20*21 + (k-LL-1)]);
            } else {
                int t = q - LL - 1;
                if (k < LL)       v = __ldg(&sx2[(size_t)(i*20 + t)*100 + c*20 + k]);
                else if (k == LL) v = __ldg(&shh[t*21 + 20]);
                else              v = __ldg(&shh[t*21 + (k-LL-1)]);
            }
            sS[p] = v * INV_SCALE;
        }
        __syncthreads();

        if (tid < TT) {
            float* row = sS + tid*TT;
            float m = row[0];
            #pragma unroll
            for (int k = 1; k < TT; k++) m = fmaxf(m, row[k]);
            float ssum = 0.f;
            #pragma unroll
            for (int k = 0; k < TT; k++) { float e = __expf(row[k] - m); row[k] = e; ssum += e; }
            float inv = 1.0f / ssum;
            #pragma unroll
            for (int k = 0; k < TT; k++) row[k] *= inv;
        }
        __syncthreads();

        for (int p = tid; p < TT*VV; p += 256) {
            int q = p / VV, v = p - (p / VV)*VV;
            int col = h*VV + v;
            const float* arow = sS + q*TT;
            float acc = arow[LL] * sV1[col];
            #pragma unroll
            for (int k = 0; k < LL; k++) acc = fmaf(arow[k], sVc[k*RR + col], acc);
            #pragma unroll
            for (int k = 0; k < LL; k++) acc = fmaf(arow[LL+1+k], sVh[k*RR + col], acc);
            sVal[q*RR + col] = acc;
        }
    }
    __syncthreads();  // sVal complete; sS region free for sKW

    if (tid < TT) sPool[tid] = 0.f;

    float acc[TT];
    #pragma unroll
    for (int t = 0; t < TT; t++) acc[t] = 0.f;
    int j = tid;
    bool jact = (j < QQ);

    for (int rc = 0; rc < RR/32; rc++) {
        __syncthreads();
        for (int idx = tid; idx < 32*QQ; idx += 256) sKW[idx] = keyW[rc*32*QQ + idx];
        __syncthreads();
        if (jact) {
            for (int r = 0; r < 32; r++) {
                float w = sKW[r*QQ + j];
                int rg = rc*32 + r;
                #pragma unroll
                for (int t = 0; t < TT; t++) acc[t] = fmaf(sVal[t*RR + rg], w, acc[t]);
            }
        }
    }
    {
        float qj = jact ? query[j] : 0.f;
        float kb = jact ? keyb[j]  : 0.f;
        #pragma unroll
        for (int t = 0; t < TT; t++) {
            float v = jact ? qj * tanhf(acc[t] + kb) : 0.f;
            #pragma unroll
            for (int o = 16; o; o >>= 1) v += __shfl_xor_sync(0xffffffffu, v, o);
            if (lane == 0 && warp < 7) atomicAdd(&sPool[t], v);
        }
    }
    __syncthreads();

    if (tid == 0) {
        float m = sPool[0] * INV_SCALE;
        #pragma unroll
        for (int t = 1; t < TT; t++) m = fmaxf(m, sPool[t] * INV_SCALE);
        float ssum = 0.f;
        #pragma unroll
        for (int t = 0; t < TT; t++) { float e = __expf(sPool[t]*INV_SCALE - m); sW[t] = e; ssum += e; }
        float inv = 1.0f / ssum;
        #pragma unroll
        for (int t = 0; t < TT; t++) sW[t] *= inv;
    }
    __syncthreads();

    {
        int r = tid;
        float a2 = 0.f;
        #pragma unroll
        for (int t = 0; t < TT; t++) a2 = fmaf(sW[t], sVal[t*RR + r], a2);
        g_rep[(size_t)bci*RR + r] = a2;
    }
}

// ---------------- K6a: mean over HIS + ltr ----------------
__global__ void k_fv(const float* __restrict__ ltr_w, const float* __restrict__ ltr_b) {
    __shared__ float red[256];
    int bc = blockIdx.x;
    int r = threadIdx.x;
    float ssum = 0.f;
    for (int i = 0; i < HIS; i++) ssum += g_rep[(size_t)(bc*HIS + i)*RR + r];
    red[r] = (ssum * (1.0f/HIS)) * ltr_w[r];
    __syncthreads();
    for (int off = 128; off; off >>= 1) {
        if (r < off) red[r] += red[r + off];
        __syncthreads();
    }
    if (r == 0) g_score[bc] = red[0] + ltr_b[0];
}

// ---------------- K6b: log_softmax over CDD ----------------
__global__ void k_out(float* __restrict__ out) {
    int b = threadIdx.x;
    if (b < BB) {
        float s[CDD];
        float m = -1e30f;
        #pragma unroll
        for (int c = 0; c < CDD; c++) { s[c] = g_score[b*CDD + c]; m = fmaxf(m, s[c]); }
        float ssum = 0.f;
        #pragma unroll
        for (int c = 0; c < CDD; c++) ssum += expf(s[c] - m);
        float lse = logf(ssum);
        #pragma unroll
        for (int c = 0; c < CDD; c++) out[b*CDD + c] = s[c] - m - lse;
    }
}

// ---------------- launch ----------------
extern "C" void kernel_launch(void* const* d_in, const int* in_sizes, int n_in,
                              void* d_out, int out_size) {
    const int*   cand  = (const int*)  d_in[0];
    const int*   clk   = (const int*)  d_in[1];
    const float* emb   = (const float*)d_in[2];
    const float* Wq_w  = (const float*)d_in[3];
    const float* Wv_w  = (const float*)d_in[4];
    const float* Wq_i  = (const float*)d_in[5];
    const float* Wv_i  = (const float*)d_in[6];
    const float* keyW  = (const float*)d_in[7];
    const float* keyb  = (const float*)d_in[8];
    const float* query = (const float*)d_in[9];
    const float* ltr_w = (const float*)d_in[10];
    const float* ltr_b = (const float*)d_in[11];
    float* out = (float*)d_out;

    cudaFuncSetAttribute(k_words, cudaFuncAttributeMaxDynamicSharedMemorySize,
                         K2_SMEM_FLOATS * sizeof(float));
    cudaFuncSetAttribute(k_fuse, cudaFuncAttributeMaxDynamicSharedMemorySize,
                         K5_SMEM_FLOATS * sizeof(float));

    k_gather<<<NS, 256>>>(cand, clk, emb);
    k_words<<<dim3(NS, HH), 320, K2_SMEM_FLOATS * sizeof(float)>>>(Wq_w, Wv_w);
    k_proj<<<dim3(NS, HH), 256>>>(Wq_i, Wv_i);
    k_ones<<<HH, 256>>>(Wq_i, Wv_i);
    k_diag<<<dim3(NS, HH), 256>>>();
    k_cross<<<dim3(16, 2, BB*HH), 256>>>(0);   // Sx1: M=100,  N=1000
    k_cross<<<dim3(2, 16, BB*HH), 256>>>(1);   // Sx2: M=1000, N=100
    k_fuse<<<NBCI, 256, K5_SMEM_FLOATS * sizeof(float)>>>(keyW, keyb, query);
    k_fv<<<NSC, 256>>>(ltr_w, ltr_b);
    k_out<<<1, 32>>>(out);
}

// round 4
// speedup vs baseline: 3.5820x; 1.0724x over previous
#include <cuda_runtime.h>
#include <math.h>

#define BB   4
#define CDD  5
#define HIS  50
#define LL   20
#define TT   41     // 2*LL+1
#define EE   300
#define EEP  320    // padded K for words GEMM
#define HH   16
#define VV   16
#define RR   256
#define QQ   200
#define NSC  (BB*CDD)        // 20 candidate sequences
#define NSH  (BB*HIS)        // 200 history sequences
#define NS   (NSC+NSH)       // 220
#define NTOK (NS*LL)         // 4400 token rows
#define NBCI (BB*CDD*HIS)    // 1000

#define INV_SCALE 0.057735026918962584f   // 1/sqrt(300)

// ---------------- device scratch ----------------
__device__ float g_Xp[NTOK*EEP];         // gathered embeddings, K-padded [4400,320]
__device__ float g_Wqp[HH*EEP*EE];       // padded words Wq [16][320][300]
__device__ float g_Qw[(size_t)NS*HH*LL*EE];  // words Q proj [s][h][t][300]
__device__ float g_Rep[NS*LL*RR];        // stage-1 outputs [220,20,256]
__device__ float g_Q[(size_t)NS*HH*LL*RR];   // itrs Q proj [s][h][t][256]
__device__ float g_V[NS*LL*RR];          // itrs V proj [220,20,256]
__device__ float g_q1[HH*RR];            // ones-row query per head
__device__ float g_v1[RR];               // ones-row value
__device__ float g_Scc[NSC*HH*21*21];
__device__ float g_Shh[NSH*HH*21*21];
__device__ float g_Sx1[(size_t)BB*HH*100*1000];
__device__ float g_Sx2[(size_t)BB*HH*1000*100];
__device__ float g_rep[NBCI*RR];
__device__ float g_score[NSC];

// ---------------- K1: gather embeddings (padded) ----------------
__global__ void k_gather(const int* __restrict__ cand, const int* __restrict__ clk,
                         const float* __restrict__ emb) {
    int s = blockIdx.x;
    const int* tok = (s < NSC) ? (cand + s*LL) : (clk + (s-NSC)*LL);
    for (int idx = threadIdx.x; idx < LL*EEP; idx += blockDim.x) {
        int t = idx / EEP, d = idx - t*EEP;
        g_Xp[(s*LL + t)*EEP + d] = (d < EE) ? emb[(size_t)tok[t]*EE + d] : 0.f;
    }
}

// ---------------- K1b: pad words Wq into [16][320][300] ----------------
__global__ void k_padW(const float* __restrict__ Wq) {
    int h = blockIdx.x;
    for (int idx = threadIdx.x; idx < EEP*EE; idx += blockDim.x) {
        int k = idx / EE, j = idx - k*EE;
        g_Wqp[(size_t)h*EEP*EE + idx] = (k < EE) ? Wq[(size_t)h*EE*EE + k*EE + j] : 0.f;
    }
}

// ---------------- GEMM helper macro pieces (64x64 tile, KC=32, 256 thr, 4x4/thr) ---
#define APITCH 68

// ---------------- K2a: words Q GEMM: g_Qw[h] = Xp @ Wqp[h] -------------
// M=4400, N=300, K=320. grid (5, 69, 16)
__global__ void __launch_bounds__(256, 4)
k_gemm_wq() {
    __shared__ float As[32*APITCH];
    __shared__ float Bs[32*APITCH];
    int h = blockIdx.z;
    int nBase = blockIdx.x * 64;
    int mBase = blockIdx.y * 64;
    int tid = threadIdx.x;
    int tx = tid & 15, ty = tid >> 4;

    int lrow = tid >> 2;
    int kgrp = (tid & 3) * 8;
    int am = mBase + lrow;
    bool av = am < NTOK;
    const float* Aptr = g_Xp + (size_t)(av ? am : 0)*EEP;

    // B load mapping: 2 float4 per thread
    int bk = tid >> 4;            // 0..15 (and +16)
    int bnb = (tid & 15) * 4;     // 0..60
    const float* Bbase = g_Wqp + (size_t)h*EEP*EE;
    bool bval = (nBase + bnb) < EE;  // float4 never straddles 300

    float acc[4][4];
    #pragma unroll
    for (int r = 0; r < 4; r++)
        #pragma unroll
        for (int j = 0; j < 4; j++) acc[r][j] = 0.f;

    for (int kc = 0; kc < EEP; kc += 32) {
        float4 a0 = make_float4(0,0,0,0), a1 = a0;
        if (av) { a0 = *(const float4*)(Aptr + kc + kgrp); a1 = *(const float4*)(Aptr + kc + kgrp + 4); }
        float4 b0 = make_float4(0,0,0,0), b1 = b0;
        if (bval) {
            b0 = *(const float4*)(Bbase + (size_t)(kc + bk)*EE + nBase + bnb);
            b1 = *(const float4*)(Bbase + (size_t)(kc + bk + 16)*EE + nBase + bnb);
        }
        __syncthreads();
        As[(kgrp+0)*APITCH + lrow] = a0.x; As[(kgrp+1)*APITCH + lrow] = a0.y;
        As[(kgrp+2)*APITCH + lrow] = a0.z; As[(kgrp+3)*APITCH + lrow] = a0.w;
        As[(kgrp+4)*APITCH + lrow] = a1.x; As[(kgrp+5)*APITCH + lrow] = a1.y;
        As[(kgrp+6)*APITCH + lrow] = a1.z; As[(kgrp+7)*APITCH + lrow] = a1.w;
        *(float4*)(Bs + bk*APITCH + bnb) = b0;
        *(float4*)(Bs + (bk+16)*APITCH + bnb) = b1;
        __syncthreads();

        #pragma unroll
        for (int k = 0; k < 32; k++) {
            float4 a = *(const float4*)(As + k*APITCH + ty*4);
            float4 b = *(const float4*)(Bs + k*APITCH + tx*4);
            float ar[4] = {a.x, a.y, a.z, a.w};
            float br[4] = {b.x, b.y, b.z, b.w};
            #pragma unroll
            for (int r = 0; r < 4; r++)
                #pragma unroll
                for (int j = 0; j < 4; j++) acc[r][j] = fmaf(ar[r], br[j], acc[r][j]);
        }
    }

    #pragma unroll
    for (int r = 0; r < 4; r++) {
        int row = mBase + ty*4 + r;
        if (row < NTOK) {
            int s = row / LL, t = row - (row/LL)*LL;
            float* out = g_Qw + (((size_t)s*HH + h)*LL + t)*EE;
            #pragma unroll
            for (int j = 0; j < 4; j++) {
                int col = nBase + tx*4 + j;
                if (col < EE) out[col] = acc[r][j];
            }
        }
    }
}

// ---------------- K2b: words attention (Q precomputed) ----------------
#define K2_SMEM_FLOATS (LL*EE + LL*EE + LL*LL + LL*VV)
__global__ void __launch_bounds__(320, 4)
k_words_attn(const float* __restrict__ Wv) {
    extern __shared__ float sm[];
    float* sX  = sm;
    float* sQ  = sm + LL*EE;
    float* sS  = sm + 2*LL*EE;
    float* sXV = sm + 2*LL*EE + LL*LL;

    int s = blockIdx.x, h = blockIdx.y;
    int tid = threadIdx.x;

    for (int idx = tid; idx < LL*EE; idx += 320) {
        int t = idx / EE, d = idx - t*EE;
        sX[idx] = g_Xp[(s*LL + t)*EEP + d];
        sQ[idx] = g_Qw[(((size_t)s*HH + h)*LL + t)*EE + d];
    }
    __syncthreads();

    int warp = tid >> 5, lane = tid & 31;
    for (int p = warp; p < LL*LL; p += 10) {
        int t = p / LL, u = p - t*LL;
        float partial = 0.f;
        for (int d = lane; d < EE; d += 32)
            partial = fmaf(sQ[t*EE + d], sX[u*EE + d], partial);
        #pragma unroll
        for (int o = 16; o; o >>= 1) partial += __shfl_xor_sync(0xffffffffu, partial, o);
        if (lane == 0) sS[t*LL + u] = partial * INV_SCALE;
    }
    __syncthreads();

    if (tid < LL) {
        float* row = sS + tid*LL;
        float m = row[0];
        #pragma unroll
        for (int u = 1; u < LL; u++) m = fmaxf(m, row[u]);
        float ssum = 0.f;
        #pragma unroll
        for (int u = 0; u < LL; u++) { float e = __expf(row[u] - m); row[u] = e; ssum += e; }
        float inv = 1.0f / ssum;
        #pragma unroll
        for (int u = 0; u < LL; u++) row[u] *= inv;
    }
    {
        int u = tid / VV, v = tid - (tid / VV)*VV;
        float acc = 0.f;
        const float* wv = Wv + (size_t)h*EE*VV + v;
        for (int d = 0; d < EE; d++) acc = fmaf(sX[u*EE + d], wv[d*VV], acc);
        sXV[u*VV + v] = acc;
    }
    __syncthreads();

    {
        int t = tid / VV, v = tid - (tid / VV)*VV;
        float acc = 0.f;
        #pragma unroll
        for (int u = 0; u < LL; u++) acc = fmaf(sS[t*LL + u], sXV[u*VV + v], acc);
        g_Rep[(s*LL + t)*RR + h*VV + v] = acc;
    }
}

// ---------------- K3a: itrs Q GEMM: g_Q[h] = Rep @ Wq_i[h] ------------
// M=4400, N=256, K=256. grid (4, 69, 16)
__global__ void __launch_bounds__(256, 4)
k_gemm_iq(const float* __restrict__ Wq) {
    __shared__ float As[32*APITCH];
    __shared__ float Bs[32*APITCH];
    int h = blockIdx.z;
    int nBase = blockIdx.x * 64;
    int mBase = blockIdx.y * 64;
    int tid = threadIdx.x;
    int tx = tid & 15, ty = tid >> 4;

    int lrow = tid >> 2;
    int kgrp = (tid & 3) * 8;
    int am = mBase + lrow;
    bool av = am < NTOK;
    const float* Aptr = g_Rep + (size_t)(av ? am : 0)*RR;

    int bk = tid >> 4;
    int bnb = (tid & 15) * 4;
    const float* Bbase = Wq + (size_t)h*RR*RR;

    float acc[4][4];
    #pragma unroll
    for (int r = 0; r < 4; r++)
        #pragma unroll
        for (int j = 0; j < 4; j++) acc[r][j] = 0.f;

    for (int kc = 0; kc < RR; kc += 32) {
        float4 a0 = make_float4(0,0,0,0), a1 = a0;
        if (av) { a0 = *(const float4*)(Aptr + kc + kgrp); a1 = *(const float4*)(Aptr + kc + kgrp + 4); }
        float4 b0 = *(const float4*)(Bbase + (size_t)(kc + bk)*RR + nBase + bnb);
        float4 b1 = *(const float4*)(Bbase + (size_t)(kc + bk + 16)*RR + nBase + bnb);
        __syncthreads();
        As[(kgrp+0)*APITCH + lrow] = a0.x; As[(kgrp+1)*APITCH + lrow] = a0.y;
        As[(kgrp+2)*APITCH + lrow] = a0.z; As[(kgrp+3)*APITCH + lrow] = a0.w;
        As[(kgrp+4)*APITCH + lrow] = a1.x; As[(kgrp+5)*APITCH + lrow] = a1.y;
        As[(kgrp+6)*APITCH + lrow] = a1.z; As[(kgrp+7)*APITCH + lrow] = a1.w;
        *(float4*)(Bs + bk*APITCH + bnb) = b0;
        *(float4*)(Bs + (bk+16)*APITCH + bnb) = b1;
        __syncthreads();

        #pragma unroll
        for (int k = 0; k < 32; k++) {
            float4 a = *(const float4*)(As + k*APITCH + ty*4);
            float4 b = *(const float4*)(Bs + k*APITCH + tx*4);
            float ar[4] = {a.x, a.y, a.z, a.w};
            float br[4] = {b.x, b.y, b.z, b.w};
            #pragma unroll
            for (int r = 0; r < 4; r++)
                #pragma unroll
                for (int j = 0; j < 4; j++) acc[r][j] = fmaf(ar[r], br[j], acc[r][j]);
        }
    }

    #pragma unroll
    for (int r = 0; r < 4; r++) {
        int row = mBase + ty*4 + r;
        if (row < NTOK) {
            int s = row / LL, t = row - (row/LL)*LL;
            float* out = g_Q + (((size_t)s*HH + h)*LL + t)*RR;
            #pragma unroll
            for (int j = 0; j < 4; j++) out[nBase + tx*4 + j] = acc[r][j];
        }
    }
}

// ---------------- K3b: itrs V projection, one block per seq ----------------
__global__ void __launch_bounds__(256, 4)
k_vproj(const float* __restrict__ Wv) {
    __shared__ float sRep[LL*RR];
    int s = blockIdx.x, tid = threadIdx.x;
    for (int i = tid; i < LL*RR; i += 256) sRep[i] = g_Rep[s*LL*RR + i];
    __syncthreads();

    int h = tid >> 4, v = tid & 15;
    float acc[LL];
    #pragma unroll
    for (int t = 0; t < LL; t++) acc[t] = 0.f;
    const float* wv = Wv + (size_t)h*RR*VV + v;
    for (int r = 0; r < RR; r++) {
        float w = wv[r*VV];
        #pragma unroll
        for (int t = 0; t < LL; t++) acc[t] = fmaf(sRep[t*RR + r], w, acc[t]);
    }
    #pragma unroll
    for (int t = 0; t < LL; t++) g_V[(s*LL + t)*RR + tid] = acc[t];
}

// ---------------- K3c: ones-row projections ----------------
__global__ void k_ones(const float* __restrict__ Wq, const float* __restrict__ Wv) {
    int h = blockIdx.x, j = threadIdx.x;
    float acc = 0.f;
    const float* w = Wq + (size_t)h*RR*RR + j;
    for (int r = 0; r < RR; r++) acc += w[r*RR];
    g_q1[h*RR + j] = acc;
    if (j < VV) {
        float a2 = 0.f;
        const float* wv = Wv + (size_t)h*RR*VV + j;
        for (int r = 0; r < RR; r++) a2 += wv[r*VV];
        g_v1[h*VV + j] = a2;
    }
}

// ---------------- K4a: diagonal score blocks ----------------
__global__ void __launch_bounds__(256, 4)
k_diag() {
    __shared__ float sQd[21*RR];
    __shared__ float sK[LL*RR];
    int s = blockIdx.x, h = blockIdx.y, tid = threadIdx.x;

    {
        const float4* gq = (const float4*)(g_Q + (size_t)(s*HH + h)*LL*RR);
        const float4* gk = (const float4*)(g_Rep + (size_t)s*LL*RR);
        float4* dQ = (float4*)sQd; float4* dK = (float4*)sK;
        for (int idx = tid; idx < LL*RR/4; idx += 256) { dQ[idx] = gq[idx]; dK[idx] = gk[idx]; }
        if (tid < RR) sQd[LL*RR + tid] = g_q1[h*RR + tid];
    }
    __syncthreads();

    float* out = (s < NSC) ? (g_Scc + ((size_t)s*HH + h)*441)
                           : (g_Shh + ((size_t)(s-NSC)*HH + h)*441);
    int warp = tid >> 5, lane = tid & 31;
    for (int p = warp; p < 21*21; p += 8) {
        int q = p / 21, k = p - q*21;
        const float4* q4 = (const float4*)(sQd + q*RR);
        float4 a = q4[lane], a2 = q4[lane + 32];
        float partial;
        if (k == 20) {
            partial = a.x + a.y + a.z + a.w + a2.x + a2.y + a2.z + a2.w;
        } else {
            const float4* k4 = (const float4*)(sK + k*RR);
            float4 bb = k4[lane], b2 = k4[lane + 32];
            partial  = a.x*bb.x + a.y*bb.y + a.z*bb.z + a.w*bb.w;
            partial += a2.x*b2.x + a2.y*b2.y + a2.z*b2.z + a2.w*b2.w;
        }
        #pragma unroll
        for (int o = 16; o; o >>= 1) partial += __shfl_xor_sync(0xffffffffu, partial, o);
        if (lane == 0) out[p] = partial;
    }
}

// ---------------- K4b: cross-score SGEMM (A.B^T, both K-major) ----------------
__global__ void __launch_bounds__(256, 4)
k_cross(int flag) {
    __shared__ float As[32*APITCH];
    __shared__ float Bs[32*APITCH];

    int bh = blockIdx.z;
    int b = bh >> 4, h = bh & 15;
    int nBase = blockIdx.x * 64;
    int mBase = blockIdx.y * 64;
    int M = flag ? 1000 : 100;
    int N = flag ? 100  : 1000;

    int tid = threadIdx.x;
    int tx = tid & 15, ty = tid >> 4;
    int lrow = tid >> 2;
    int kgrp = (tid & 3) * 8;

    int am = mBase + lrow;
    int bn = nBase + lrow;
    bool av = am < M, bv = bn < N;
    int amc = av ? am : 0, bnc = bv ? bn : 0;

    const float *Aptr, *Bptr;
    if (!flag) {
        int c = amc / 20, t = amc % 20;
        Aptr = g_Q + (((size_t)(b*CDD + c)*HH + h)*LL + t)*RR;
        int i = bnc / 20, u = bnc % 20;
        Bptr = g_Rep + ((size_t)(NSC + b*HIS + i)*LL + u)*RR;
    } else {
        int i = amc / 20, u = amc % 20;
        Aptr = g_Q + (((size_t)(NSC + b*HIS + i)*HH + h)*LL + u)*RR;
        int c = bnc / 20, t = bnc % 20;
        Bptr = g_Rep + ((size_t)(b*CDD + c)*LL + t)*RR;
    }

    float acc[4][4];
    #pragma unroll
    for (int r = 0; r < 4; r++)
        #pragma unroll
        for (int j = 0; j < 4; j++) acc[r][j] = 0.f;

    for (int kc = 0; kc < RR; kc += 32) {
        float4 a0 = make_float4(0,0,0,0), a1 = a0, b0 = a0, b1 = a0;
        if (av) { a0 = *(const float4*)(Aptr + kc + kgrp); a1 = *(const float4*)(Aptr + kc + kgrp + 4); }
        if (bv) { b0 = *(const float4*)(Bptr + kc + kgrp); b1 = *(const float4*)(Bptr + kc + kgrp + 4); }
        __syncthreads();
        As[(kgrp+0)*APITCH + lrow] = a0.x; As[(kgrp+1)*APITCH + lrow] = a0.y;
        As[(kgrp+2)*APITCH + lrow] = a0.z; As[(kgrp+3)*APITCH + lrow] = a0.w;
        As[(kgrp+4)*APITCH + lrow] = a1.x; As[(kgrp+5)*APITCH + lrow] = a1.y;
        As[(kgrp+6)*APITCH + lrow] = a1.z; As[(kgrp+7)*APITCH + lrow] = a1.w;
        Bs[(kgrp+0)*APITCH + lrow] = b0.x; Bs[(kgrp+1)*APITCH + lrow] = b0.y;
        Bs[(kgrp+2)*APITCH + lrow] = b0.z; Bs[(kgrp+3)*APITCH + lrow] = b0.w;
        Bs[(kgrp+4)*APITCH + lrow] = b1.x; Bs[(kgrp+5)*APITCH + lrow] = b1.y;
        Bs[(kgrp+6)*APITCH + lrow] = b1.z; Bs[(kgrp+7)*APITCH + lrow] = b1.w;
        __syncthreads();

        #pragma unroll
        for (int k = 0; k < 32; k++) {
            float4 a = *(const float4*)(As + k*APITCH + ty*4);
            float4 bvv = *(const float4*)(Bs + k*APITCH + tx*4);
            float ar[4] = {a.x, a.y, a.z, a.w};
            float br[4] = {bvv.x, bvv.y, bvv.z, bvv.w};
            #pragma unroll
            for (int r = 0; r < 4; r++)
                #pragma unroll
                for (int j = 0; j < 4; j++) acc[r][j] = fmaf(ar[r], br[j], acc[r][j]);
        }
    }

    float* out = (flag ? g_Sx2 : g_Sx1) + (size_t)bh * 100 * 1000;
    #pragma unroll
    for (int r = 0; r < 4; r++) {
        int row = mBase + ty*4 + r;
        if (row < M) {
            #pragma unroll
            for (int j = 0; j < 4; j++) {
                int col = nBase + tx*4 + j;
                if (col < N) out[(size_t)row*N + col] = acc[r][j];
            }
        }
    }
}

// ---------------- K5: fused softmax + AV + pooling ----------------
#define KWP 36                              // transposed keyW chunk pitch
#define SC_VC   0
#define SC_VH   (SC_VC + LL*RR)             // 5120
#define SC_V1   (SC_VH + LL*RR)             // 10240
#define SC_VAL  (SC_V1 + RR)                // 10496
#define SCR     (SC_VAL + TT*RR)            // 20992 (sS: 1681 / sKWT: 200*36=7200)
#define SC_POOL (SCR + QQ*KWP)              // 28192
#define SC_W    (SC_POOL + 48)
#define K5_SMEM_FLOATS (SC_W + 48)          // 28288 floats = 113152 B

__global__ void __launch_bounds__(256, 2)
k_fuse(const float* __restrict__ keyW, const float* __restrict__ keyb,
       const float* __restrict__ query) {
    extern __shared__ float sm[];
    float* sVc  = sm + SC_VC;
    float* sVh  = sm + SC_VH;
    float* sV1  = sm + SC_V1;
    float* sVal = sm + SC_VAL;
    float* sS   = sm + SCR;
    float* sKWT = sm + SCR;
    float* sPool= sm + SC_POOL;
    float* sW   = sm + SC_W;

    int bci = blockIdx.x;
    int i   = bci % HIS;
    int bc  = bci / HIS;
    int b   = bc / CDD;
    int c   = bc - b*CDD;
    int sc  = bc;
    int sh  = NSC + b*HIS + i;

    int tid = threadIdx.x;
    int warp = tid >> 5, lane = tid & 31;

    {
        const float4* gvc = (const float4*)(g_V + (size_t)sc*LL*RR);
        const float4* gvh = (const float4*)(g_V + (size_t)sh*LL*RR);
        float4* dVc = (float4*)sVc; float4* dVh = (float4*)sVh;
        for (int idx = tid; idx < LL*RR/4; idx += 256) { dVc[idx] = gvc[idx]; dVh[idx] = gvh[idx]; }
        if (tid < RR) sV1[tid] = g_v1[tid];
    }

    for (int h = 0; h < HH; h++) {
        const float* scc = g_Scc + ((size_t)bc*HH + h)*441;
        const float* shh = g_Shh + ((size_t)(b*HIS + i)*HH + h)*441;
        const float* sx1 = g_Sx1 + ((size_t)(b*HH + h))*100*1000;
        const float* sx2 = g_Sx2 + ((size_t)(b*HH + h))*1000*100;

        __syncthreads();
        for (int p = tid; p < TT*TT; p += 256) {
            int q = p / TT, k = p - q*TT;
            float v;
            if (q < LL) {
                if (k < LL)       v = __ldg(&scc[q*21 + k]);
                else if (k == LL) v = __ldg(&scc[q*21 + 20]);
                else              v = __ldg(&sx1[(size_t)(c*20 + q)*1000 + i*20 + (k-LL-1)]);
            } else if (q == LL) {
                if (k < LL)       v = __ldg(&scc[20*21 + k]);
                else if (k == LL) v = __ldg(&scc[20*21 + 20]);
                else              v = __ldg(&shh[20*21 + (k-LL-1)]);
            } else {
                int t = q - LL - 1;
                if (k < LL)       v = __ldg(&sx2[(size_t)(i*20 + t)*100 + c*20 + k]);
                else if (k == LL) v = __ldg(&shh[t*21 + 20]);
                else              v = __ldg(&shh[t*21 + (k-LL-1)]);
            }
            sS[p] = v * INV_SCALE;
        }
        __syncthreads();

        if (tid < TT) {
            float* row = sS + tid*TT;
            float m = row[0];
            #pragma unroll
            for (int k = 1; k < TT; k++) m = fmaxf(m, row[k]);
            float ssum = 0.f;
            #pragma unroll
            for (int k = 0; k < TT; k++) { float e = __expf(row[k] - m); row[k] = e; ssum += e; }
            float inv = 1.0f / ssum;
            #pragma unroll
            for (int k = 0; k < TT; k++) row[k] *= inv;
        }
        __syncthreads();

        for (int p = tid; p < TT*VV; p += 256) {
            int q = p / VV, v = p - (p / VV)*VV;
            int col = h*VV + v;
            const float* arow = sS + q*TT;
            float acc = arow[LL] * sV1[col];
            #pragma unroll
            for (int k = 0; k < LL; k++) acc = fmaf(arow[k], sVc[k*RR + col], acc);
            #pragma unroll
            for (int k = 0; k < LL; k++) acc = fmaf(arow[LL+1+k], sVh[k*RR + col], acc);
            sVal[q*RR + col] = acc;
        }
    }
    __syncthreads();  // sVal complete; sS region free for sKWT

    if (tid < TT) sPool[tid] = 0.f;

    float acc[TT];
    #pragma unroll
    for (int t = 0; t < TT; t++) acc[t] = 0.f;
    int j = tid;
    bool jact = (j < QQ);

    for (int rc = 0; rc < RR/32; rc++) {
        __syncthreads();
        // load + transpose keyW chunk: sKWT[j][r] = keyW[rc*32+r][j]
        for (int idx = tid; idx < 32*QQ; idx += 256) {
            int r = idx / QQ, jj = idx - r*QQ;
            sKWT[jj*KWP + r] = keyW[(rc*32 + r)*QQ + jj];
        }
        __syncthreads();
        if (jact) {
            #pragma unroll
            for (int r4 = 0; r4 < 8; r4++) {
                float4 w = *(const float4*)(sKWT + j*KWP + r4*4);
                int rg = rc*32 + r4*4;
                #pragma unroll
                for (int t = 0; t < TT; t++) {
                    float4 sv = *(const float4*)(sVal + t*RR + rg);
                    acc[t] = fmaf(w.x, sv.x, acc[t]);
                    acc[t] = fmaf(w.y, sv.y, acc[t]);
                    acc[t] = fmaf(w.z, sv.z, acc[t]);
                    acc[t] = fmaf(w.w, sv.w, acc[t]);
                }
            }
        }
    }
    {
        float qj = jact ? query[j] : 0.f;
        float kb = jact ? keyb[j]  : 0.f;
        #pragma unroll
        for (int t = 0; t < TT; t++) {
            float v = jact ? qj * tanhf(acc[t] + kb) : 0.f;
            #pragma unroll
            for (int o = 16; o; o >>= 1) v += __shfl_xor_sync(0xffffffffu, v, o);
            if (lane == 0 && warp < 7) atomicAdd(&sPool[t], v);
        }
    }
    __syncthreads();

    if (tid == 0) {
        float m = sPool[0] * INV_SCALE;
        #pragma unroll
        for (int t = 1; t < TT; t++) m = fmaxf(m, sPool[t] * INV_SCALE);
        float ssum = 0.f;
        #pragma unroll
        for (int t = 0; t < TT; t++) { float e = __expf(sPool[t]*INV_SCALE - m); sW[t] = e; ssum += e; }
        float inv = 1.0f / ssum;
        #pragma unroll
        for (int t = 0; t < TT; t++) sW[t] *= inv;
    }
    __syncthreads();

    {
        int r = tid;
        float a2 = 0.f;
        #pragma unroll
        for (int t = 0; t < TT; t++) a2 = fmaf(sW[t], sVal[t*RR + r], a2);
        g_rep[(size_t)bci*RR + r] = a2;
    }
}

// ---------------- K6a: mean over HIS + ltr ----------------
__global__ void k_fv(const float* __restrict__ ltr_w, const float* __restrict__ ltr_b) {
    __shared__ float red[256];
    int bc = blockIdx.x;
    int r = threadIdx.x;
    float ssum = 0.f;
    for (int i = 0; i < HIS; i++) ssum += g_rep[(size_t)(bc*HIS + i)*RR + r];
    red[r] = (ssum * (1.0f/HIS)) * ltr_w[r];
    __syncthreads();
    for (int off = 128; off; off >>= 1) {
        if (r < off) red[r] += red[r + off];
        __syncthreads();
    }
    if (r == 0) g_score[bc] = red[0] + ltr_b[0];
}

// ---------------- K6b: log_softmax over CDD ----------------
__global__ void k_out(float* __restrict__ out) {
    int b = threadIdx.x;
    if (b < BB) {
        float s[CDD];
        float m = -1e30f;
        #pragma unroll
        for (int c = 0; c < CDD; c++) { s[c] = g_score[b*CDD + c]; m = fmaxf(m, s[c]); }
        float ssum = 0.f;
        #pragma unroll
        for (int c = 0; c < CDD; c++) ssum += expf(s[c] - m);
        float lse = logf(ssum);
        #pragma unroll
        for (int c = 0; c < CDD; c++) out[b*CDD + c] = s[c] - m - lse;
    }
}

// ---------------- launch ----------------
extern "C" void kernel_launch(void* const* d_in, const int* in_sizes, int n_in,
                              void* d_out, int out_size) {
    const int*   cand  = (const int*)  d_in[0];
    const int*   clk   = (const int*)  d_in[1];
    const float* emb   = (const float*)d_in[2];
    const float* Wq_w  = (const float*)d_in[3];
    const float* Wv_w  = (const float*)d_in[4];
    const float* Wq_i  = (const float*)d_in[5];
    const float* Wv_i  = (const float*)d_in[6];
    const float* keyW  = (const float*)d_in[7];
    const float* keyb  = (const float*)d_in[8];
    const float* query = (const float*)d_in[9];
    const float* ltr_w = (const float*)d_in[10];
    const float* ltr_b = (const float*)d_in[11];
    float* out = (float*)d_out;

    cudaFuncSetAttribute(k_words_attn, cudaFuncAttributeMaxDynamicSharedMemorySize,
                         K2_SMEM_FLOATS * sizeof(float));
    cudaFuncSetAttribute(k_fuse, cudaFuncAttributeMaxDynamicSharedMemorySize,
                         K5_SMEM_FLOATS * sizeof(float));

    k_gather<<<NS, 256>>>(cand, clk, emb);
    k_padW<<<HH, 256>>>(Wq_w);
    k_gemm_wq<<<dim3(5, 69, HH), 256>>>();
    k_words_attn<<<dim3(NS, HH), 320, K2_SMEM_FLOATS * sizeof(float)>>>(Wv_w);
    k_gemm_iq<<<dim3(4, 69, HH), 256>>>(Wq_i);
    k_vproj<<<NS, 256>>>(Wv_i);
    k_ones<<<HH, 256>>>(Wq_i, Wv_i);
    k_diag<<<dim3(NS, HH), 256>>>();
    k_cross<<<dim3(16, 2, BB*HH), 256>>>(0);
    k_cross<<<dim3(2, 16, BB*HH), 256>>>(1);
    k_fuse<<<NBCI, 256, K5_SMEM_FLOATS * sizeof(float)>>>(keyW, keyb, query);
    k_fv<<<NSC, 256>>>(ltr_w, ltr_b);
    k_out<<<1, 32>>>(out);
}

// round 5
// speedup vs baseline: 4.1035x; 1.1456x over previous
#include <cuda_runtime.h>
#include <math.h>

#define BB   4
#define CDD  5
#define HIS  50
#define LL   20
#define TT   41
#define EE   300
#define EEP  320
#define HH   16
#define VV   16
#define RR   256
#define QQ   200
#define NSC  (BB*CDD)        // 20
#define NSH  (BB*HIS)        // 200
#define NS   (NSC+NSH)       // 220
#define NTOK (NS*LL)         // 4400
#define NBCI (BB*CDD*HIS)    // 1000

#define INV_SCALE 0.057735026918962584f   // 1/sqrt(300)

// ---------------- device scratch ----------------
__device__ float g_Xp[NTOK*EEP];             // [4400,320] padded embeddings
__device__ float g_Wqp[HH*EEP*EE];           // [16][320][300] padded words Wq
__device__ float g_Wvp[EEP*RR];              // [320][256] words Wv merged heads
__device__ float g_Wvp2[RR*RR];              // [256][256] itrs Wv merged heads
__device__ float g_Qw[(size_t)NS*HH*LL*EE];  // words Q proj [s][h][t][300]
__device__ float g_XV[NTOK*RR];              // words XV [4400][256]
__device__ float g_Rep[NS*LL*RR];            // stage-1 out [220,20,256]
__device__ float g_Q[(size_t)NS*HH*LL*RR];   // itrs Q proj [s][h][t][256]
__device__ float g_V[NS*LL*RR];              // itrs V proj [220,20,256]
__device__ float g_q1[HH*RR];
__device__ float g_v1[RR];
__device__ float g_Scc[NSC*HH*21*21];
__device__ float g_Shh[NSH*HH*21*21];
__device__ float g_Sx1[(size_t)BB*HH*100*1000];
__device__ float g_Sx2[(size_t)BB*HH*1000*100];
__device__ float g_rep[NBCI*RR];
__device__ float g_score[NSC];

// ---------------- K1: gather embeddings (padded) ----------------
__global__ void k_gather(const int* __restrict__ cand, const int* __restrict__ clk,
                         const float* __restrict__ emb) {
    int s = blockIdx.x;
    const int* tok = (s < NSC) ? (cand + s*LL) : (clk + (s-NSC)*LL);
    for (int idx = threadIdx.x; idx < LL*EEP; idx += blockDim.x) {
        int t = idx / EEP, d = idx - t*EEP;
        g_Xp[(s*LL + t)*EEP + d] = (d < EE) ? emb[(size_t)tok[t]*EE + d] : 0.f;
    }
}

// ---------------- pad kernels ----------------
__global__ void k_padW(const float* __restrict__ Wq) {
    int h = blockIdx.x;
    for (int idx = threadIdx.x; idx < EEP*EE; idx += blockDim.x) {
        int k = idx / EE, j = idx - k*EE;
        g_Wqp[(size_t)h*EEP*EE + idx] = (k < EE) ? Wq[(size_t)h*EE*EE + k*EE + j] : 0.f;
    }
}
__global__ void k_padWv(const float* __restrict__ Wv) {   // words: [h][d][v] -> [320][256]
    int idx = blockIdx.x*256 + threadIdx.x;               // 320*256 total
    int k = idx >> 8, col = idx & 255;
    int h = col >> 4, v = col & 15;
    g_Wvp[idx] = (k < EE) ? Wv[((size_t)h*EE + k)*VV + v] : 0.f;
}
__global__ void k_padWvi(const float* __restrict__ Wv) {  // itrs: [h][r][v] -> [256][256]
    int idx = blockIdx.x*256 + threadIdx.x;               // 256*256 total
    int r = idx >> 8, col = idx & 255;
    int h = col >> 4, v = col & 15;
    g_Wvp2[idx] = Wv[((size_t)h*RR + r)*VV + v];
}

// ---------------- generic 128x128x16 SGEMM, 8x8 per thread, double-buffered ----
// MODE 0: Qw  = Xp  @ Wqp[h]   M=4400 N=300  K=320   grid(3,35,16)
// MODE 1: Q   = Rep @ Wq_i[h]  M=4400 N=256  K=256   grid(2,35,16)
// MODE 2: XV  = Xp  @ Wvp      M=4400 N=256  K=320   grid(2,35,1)
// MODE 3: V   = Rep @ Wvp2     M=4400 N=256  K=256   grid(2,35,1)
// MODE 4: Sx1 = Qc  @ RepH^T   M=100  N=1000 K=256   grid(8,1,64)
// MODE 5: Sx2 = Qh  @ RepC^T   M=1000 N=100  K=256   grid(1,8,64)
#define BM 128
#define BN 128
#define BK 16
#define SP 132

template<int MODE>
__global__ void __launch_bounds__(256, 2)
k_g128(const float* __restrict__ Bglob) {
    constexpr int K   = (MODE==0 || MODE==2) ? EEP : RR;
    constexpr int M   = (MODE==4) ? 100 : (MODE==5 ? 1000 : NTOK);
    constexpr int N   = (MODE==0) ? 300 : (MODE==4 ? 1000 : (MODE==5 ? 100 : RR));
    constexpr bool BT = (MODE>=4);
    constexpr int LDB = (MODE==0) ? 300 : RR;
    constexpr int NCH = K / BK;

    __shared__ float As[2][BK*SP];
    __shared__ float Bs[2][BK*SP];

    const int tid = threadIdx.x;
    const int bz = blockIdx.z;
    const int nBase = blockIdx.x * BN;
    const int mBase = blockIdx.y * BM;
    int b = 0, h = 0;
    if (MODE==0 || MODE==1) h = bz;
    if (MODE>=4) { b = bz >> 4; h = bz & 15; }

    // A loader (transposed store): row = tid>>1, kq group = (tid&1)*2
    const int ar  = tid >> 1;
    const int akq = (tid & 1) * 2;
    const float* Arow = nullptr;
    {
        int am = mBase + ar;
        if (am < M) {
            if (MODE==0 || MODE==2) Arow = g_Xp + (size_t)am*EEP;
            else if (MODE==1 || MODE==3) Arow = g_Rep + (size_t)am*RR;
            else if (MODE==4) { int c = am/20, t = am - 20*c;
                Arow = g_Q + (size_t)(((b*CDD + c)*HH + h)*LL + t)*RR; }
            else { int i = am/20, u = am - 20*i;
                Arow = g_Q + (size_t)(((NSC + b*HIS + i)*HH + h)*LL + u)*RR; }
        }
    }
    // B loader
    const float* Brow = nullptr;   // BT modes (transposed store, same ar/akq)
    const float* Bb = nullptr;     // direct modes
    int bkr = 0, bn1 = 0; bool bok1 = false, bok2 = false;
    if (BT) {
        int bn = nBase + ar;
        if (bn < N) {
            if (MODE==4) Brow = g_Rep + ((size_t)(NSC + b*HIS)*LL + bn)*RR;
            else         Brow = g_Rep + ((size_t)(b*CDD)*LL + bn)*RR;
        }
    } else {
        if (MODE==0) Bb = g_Wqp + (size_t)h*EEP*300;
        else if (MODE==1) Bb = Bglob + (size_t)h*RR*RR;
        else if (MODE==2) Bb = g_Wvp;
        else Bb = g_Wvp2;
        bkr = tid >> 4; bn1 = (tid & 15) * 4;
        bok1 = (nBase + bn1) < N;
        bok2 = (nBase + bn1 + 64) < N;
    }

    float4 pa0, pa1, pb0, pb1;
    const float4 fz = make_float4(0.f, 0.f, 0.f, 0.f);

    auto loadChunk = [&](int kc) {
        pa0 = fz; pa1 = fz; pb0 = fz; pb1 = fz;
        if (Arow) {
            pa0 = *(const float4*)(Arow + kc + 4*akq);
            pa1 = *(const float4*)(Arow + kc + 4*akq + 4);
        }
        if (BT) {
            if (Brow) {
                pb0 = *(const float4*)(Brow + kc + 4*akq);
                pb1 = *(const float4*)(Brow + kc + 4*akq + 4);
            }
        } else {
            if (bok1) pb0 = *(const float4*)(Bb + (size_t)(kc + bkr)*LDB + nBase + bn1);
            if (bok2) pb1 = *(const float4*)(Bb + (size_t)(kc + bkr)*LDB + nBase + bn1 + 64);
        }
    };
    auto storeChunk = [&](int buf) {
        float* dA = As[buf]; float* dB = Bs[buf];
        dA[(4*akq+0)*SP + ar] = pa0.x; dA[(4*akq+1)*SP + ar] = pa0.y;
        dA[(4*akq+2)*SP + ar] = pa0.z; dA[(4*akq+3)*SP + ar] = pa0.w;
        dA[(4*akq+4)*SP + ar] = pa1.x; dA[(4*akq+5)*SP + ar] = pa1.y;
        dA[(4*akq+6)*SP + ar] = pa1.z; dA[(4*akq+7)*SP + ar] = pa1.w;
        if (BT) {
            dB[(4*akq+0)*SP + ar] = pb0.x; dB[(4*akq+1)*SP + ar] = pb0.y;
            dB[(4*akq+2)*SP + ar] = pb0.z; dB[(4*akq+3)*SP + ar] = pb0.w;
            dB[(4*akq+4)*SP + ar] = pb1.x; dB[(4*akq+5)*SP + ar] = pb1.y;
            dB[(4*akq+6)*SP + ar] = pb1.z; dB[(4*akq+7)*SP + ar] = pb1.w;
        } else {
            *(float4*)(dB + bkr*SP + bn1) = pb0;
            *(float4*)(dB + bkr*SP + bn1 + 64) = pb1;
        }
    };

    float acc[8][8];
    #pragma unroll
    for (int r = 0; r < 8; r++)
        #pragma unroll
        for (int j = 0; j < 8; j++) acc[r][j] = 0.f;

    loadChunk(0); storeChunk(0); __syncthreads();

    const int tx = tid & 15, ty = tid >> 4;
    for (int ch = 0; ch < NCH; ch++) {
        int cur = ch & 1;
        if (ch + 1 < NCH) loadChunk((ch + 1) * BK);
        const float* pAs = As[cur];
        const float* pBs = Bs[cur];
        #pragma unroll
        for (int k = 0; k < BK; k++) {
            float4 a0 = *(const float4*)(pAs + k*SP + ty*8);
            float4 a1 = *(const float4*)(pAs + k*SP + ty*8 + 4);
            float4 b0 = *(const float4*)(pBs + k*SP + tx*8);
            float4 b1 = *(const float4*)(pBs + k*SP + tx*8 + 4);
            float av[8] = {a0.x,a0.y,a0.z,a0.w,a1.x,a1.y,a1.z,a1.w};
            float bv[8] = {b0.x,b0.y,b0.z,b0.w,b1.x,b1.y,b1.z,b1.w};
            #pragma unroll
            for (int r = 0; r < 8; r++)
                #pragma unroll
                for (int j = 0; j < 8; j++) acc[r][j] = fmaf(av[r], bv[j], acc[r][j]);
        }
        if (ch + 1 < NCH) { storeChunk(cur ^ 1); __syncthreads(); }
    }

    #pragma unroll
    for (int r = 0; r < 8; r++) {
        int row = mBase + ty*8 + r;
        if (row >= M) continue;
        float* orow;
        if (MODE==0) { int s = row/20, t = row - 20*s;
            orow = g_Qw + ((size_t)(s*HH + h)*LL + t)*300; }
        else if (MODE==1) { int s = row/20, t = row - 20*s;
            orow = g_Q + ((size_t)(s*HH + h)*LL + t)*RR; }
        else if (MODE==2) orow = g_XV + (size_t)row*RR;
        else if (MODE==3) orow = g_V + (size_t)row*RR;
        else if (MODE==4) orow = g_Sx1 + (size_t)bz*100000 + (size_t)row*1000;
        else              orow = g_Sx2 + (size_t)bz*100000 + (size_t)row*100;
        int col = nBase + tx*8;
        if (col < N)
            *(float4*)(orow + col) = make_float4(acc[r][0],acc[r][1],acc[r][2],acc[r][3]);
        if (col + 4 < N)
            *(float4*)(orow + col + 4) = make_float4(acc[r][4],acc[r][5],acc[r][6],acc[r][7]);
    }
}

// ---------------- K2: words attention (Q,XV precomputed), per (s,h) ----------
#define WT_XT  0
#define WT_QT  (300*22)          // 6600
#define WT_S   (2*300*22)        // 13200, pitch 22
#define WT_XV  (WT_S + 20*22)    // 13640
#define WA_SMEM_FLOATS (WT_XV + 20*16)   // 13960 floats = 55840 B

__global__ void __launch_bounds__(128, 4)
k_wattn() {
    extern __shared__ float sm[];
    float* XT = sm + WT_XT;
    float* QT = sm + WT_QT;
    float* S  = sm + WT_S;
    float* XV = sm + WT_XV;

    int s = blockIdx.x, h = blockIdx.y, tid = threadIdx.x;

    for (int d = tid; d < EE; d += 128) {
        const float* xr = g_Xp + (size_t)s*LL*EEP + d;
        const float* qr = g_Qw + ((size_t)(s*HH + h)*LL)*300 + d;
        #pragma unroll
        for (int t = 0; t < LL; t++) {
            XT[d*22 + t] = xr[(size_t)t*EEP];
            QT[d*22 + t] = qr[(size_t)t*300];
        }
    }
    for (int p = tid; p < LL*VV; p += 128) {
        int u = p >> 4, v = p & 15;
        XV[p] = g_XV[(size_t)(s*LL + u)*RR + h*VV + v];
    }
    __syncthreads();

    if (tid < 100) {
        int ti = (tid / 10) * 2, ui = (tid % 10) * 2;
        float a00 = 0.f, a01 = 0.f, a10 = 0.f, a11 = 0.f;
        #pragma unroll 4
        for (int k = 0; k < EE; k++) {
            float2 q = *(const float2*)(QT + k*22 + ti);
            float2 x = *(const float2*)(XT + k*22 + ui);
            a00 = fmaf(q.x, x.x, a00); a01 = fmaf(q.x, x.y, a01);
            a10 = fmaf(q.y, x.x, a10); a11 = fmaf(q.y, x.y, a11);
        }
        S[ ti   *22 + ui  ] = a00 * INV_SCALE;
        S[ ti   *22 + ui+1] = a01 * INV_SCALE;
        S[(ti+1)*22 + ui  ] = a10 * INV_SCALE;
        S[(ti+1)*22 + ui+1] = a11 * INV_SCALE;
    }
    __syncthreads();

    if (tid < LL) {
        float* row = S + tid*22;
        float m = row[0];
        #pragma unroll
        for (int u = 1; u < LL; u++) m = fmaxf(m, row[u]);
        float ssum = 0.f;
        #pragma unroll
        for (int u = 0; u < LL; u++) { float e = __expf(row[u] - m); row[u] = e; ssum += e; }
        float inv = 1.0f / ssum;
        #pragma unroll
        for (int u = 0; u < LL; u++) row[u] *= inv;
    }
    __syncthreads();

    for (int p = tid; p < LL*VV; p += 128) {
        int t = p >> 4, v = p & 15;
        float acc = 0.f;
        #pragma unroll
        for (int u = 0; u < LL; u++) acc = fmaf(S[t*22 + u], XV[u*VV + v], acc);
        g_Rep[(size_t)(s*LL + t)*RR + h*VV + v] = acc;
    }
}

// ---------------- ones-row projections ----------------
__global__ void k_ones(const float* __restrict__ Wq, const float* __restrict__ Wv) {
    int h = blockIdx.x, j = threadIdx.x;
    float acc = 0.f;
    const float* w = Wq + (size_t)h*RR*RR + j;
    for (int r = 0; r < RR; r++) acc += w[r*RR];
    g_q1[h*RR + j] = acc;
    if (j < VV) {
        float a2 = 0.f;
        const float* wv = Wv + (size_t)h*RR*VV + j;
        for (int r = 0; r < RR; r++) a2 += wv[r*VV];
        g_v1[h*VV + j] = a2;
    }
}

// ---------------- diagonal score blocks ----------------
__global__ void __launch_bounds__(256, 4)
k_diag() {
    __shared__ float sQd[21*RR];
    __shared__ float sK[LL*RR];
    int s = blockIdx.x, h = blockIdx.y, tid = threadIdx.x;

    {
        const float4* gq = (const float4*)(g_Q + (size_t)(s*HH + h)*LL*RR);
        const float4* gk = (const float4*)(g_Rep + (size_t)s*LL*RR);
        float4* dQ = (float4*)sQd; float4* dK = (float4*)sK;
        for (int idx = tid; idx < LL*RR/4; idx += 256) { dQ[idx] = gq[idx]; dK[idx] = gk[idx]; }
        if (tid < RR) sQd[LL*RR + tid] = g_q1[h*RR + tid];
    }
    __syncthreads();

    float* out = (s < NSC) ? (g_Scc + ((size_t)s*HH + h)*441)
                           : (g_Shh + ((size_t)(s-NSC)*HH + h)*441);
    int warp = tid >> 5, lane = tid & 31;
    for (int p = warp; p < 21*21; p += 8) {
        int q = p / 21, k = p - q*21;
        const float4* q4 = (const float4*)(sQd + q*RR);
        float4 a = q4[lane], a2 = q4[lane + 32];
        float partial;
        if (k == 20) {
            partial = a.x + a.y + a.z + a.w + a2.x + a2.y + a2.z + a2.w;
        } else {
            const float4* k4 = (const float4*)(sK + k*RR);
            float4 bb = k4[lane], b2 = k4[lane + 32];
            partial  = a.x*bb.x + a.y*bb.y + a.z*bb.z + a.w*bb.w;
            partial += a2.x*b2.x + a2.y*b2.y + a2.z*b2.z + a2.w*b2.w;
        }
        #pragma unroll
        for (int o = 16; o; o >>= 1) partial += __shfl_xor_sync(0xffffffffu, partial, o);
        if (lane == 0) out[p] = partial;
    }
}

// ---------------- K5: fused softmax + AV + pooling ----------------
#define KWP 36
#define SC_VC   0
#define SC_VH   (SC_VC + LL*RR)
#define SC_V1   (SC_VH + LL*RR)
#define SC_VAL  (SC_V1 + RR)
#define SCR     (SC_VAL + TT*RR)
#define SC_POOL (SCR + QQ*KWP)
#define SC_W    (SC_POOL + 48)
#define K5_SMEM_FLOATS (SC_W + 48)

__global__ void __launch_bounds__(256, 2)
k_fuse(const float* __restrict__ keyW, const float* __restrict__ keyb,
       const float* __restrict__ query) {
    extern __shared__ float sm[];
    float* sVc  = sm + SC_VC;
    float* sVh  = sm + SC_VH;
    float* sV1  = sm + SC_V1;
    float* sVal = sm + SC_VAL;
    float* sS   = sm + SCR;
    float* sKWT = sm + SCR;
    float* sPool= sm + SC_POOL;
    float* sW   = sm + SC_W;

    int bci = blockIdx.x;
    int i   = bci % HIS;
    int bc  = bci / HIS;
    int b   = bc / CDD;
    int c   = bc - b*CDD;
    int sc  = bc;
    int sh  = NSC + b*HIS + i;

    int tid = threadIdx.x;
    int warp = tid >> 5, lane = tid & 31;

    {
        const float4* gvc = (const float4*)(g_V + (size_t)sc*LL*RR);
        const float4* gvh = (const float4*)(g_V + (size_t)sh*LL*RR);
        float4* dVc = (float4*)sVc; float4* dVh = (float4*)sVh;
        for (int idx = tid; idx < LL*RR/4; idx += 256) { dVc[idx] = gvc[idx]; dVh[idx] = gvh[idx]; }
        if (tid < RR) sV1[tid] = g_v1[tid];
    }

    for (int h = 0; h < HH; h++) {
        const float* scc = g_Scc + ((size_t)bc*HH + h)*441;
        const float* shh = g_Shh + ((size_t)(b*HIS + i)*HH + h)*441;
        const float* sx1 = g_Sx1 + ((size_t)(b*HH + h))*100*1000;
        const float* sx2 = g_Sx2 + ((size_t)(b*HH + h))*1000*100;

        __syncthreads();
        for (int p = tid; p < TT*TT; p += 256) {
            int q = p / TT, k = p - q*TT;
            float v;
            if (q < LL) {
                if (k < LL)       v = __ldg(&scc[q*21 + k]);
                else if (k == LL) v = __ldg(&scc[q*21 + 20]);
                else              v = __ldg(&sx1[(size_t)(c*20 + q)*1000 + i*20 + (k-LL-1)]);
            } else if (q == LL) {
                if (k < LL)       v = __ldg(&scc[20*21 + k]);
                else if (k == LL) v = __ldg(&scc[20*21 + 20]);
                else              v = __ldg(&shh[20*21 + (k-LL-1)]);
            } else {
                int t = q - LL - 1;
                if (k < LL)       v = __ldg(&sx2[(size_t)(i*20 + t)*100 + c*20 + k]);
                else if (k == LL) v = __ldg(&shh[t*21 + 20]);
                else              v = __ldg(&shh[t*21 + (k-LL-1)]);
            }
            sS[p] = v * INV_SCALE;
        }
        __syncthreads();

        if (tid < TT) {
            float* row = sS + tid*TT;
            float m = row[0];
            #pragma unroll
            for (int k = 1; k < TT; k++) m = fmaxf(m, row[k]);
            float ssum = 0.f;
            #pragma unroll
            for (int k = 0; k < TT; k++) { float e = __expf(row[k] - m); row[k] = e; ssum += e; }
            float inv = 1.0f / ssum;
            #pragma unroll
            for (int k = 0; k < TT; k++) row[k] *= inv;
        }
        __syncthreads();

        for (int p = tid; p < TT*VV; p += 256) {
            int q = p / VV, v = p - (p / VV)*VV;
            int col = h*VV + v;
            const float* arow = sS + q*TT;
            float acc = arow[LL] * sV1[col];
            #pragma unroll
            for (int k = 0; k < LL; k++) acc = fmaf(arow[k], sVc[k*RR + col], acc);
            #pragma unroll
            for (int k = 0; k < LL; k++) acc = fmaf(arow[LL+1+k], sVh[k*RR + col], acc);
            sVal[q*RR + col] = acc;
        }
    }
    __syncthreads();

    if (tid < TT) sPool[tid] = 0.f;

    float acc[TT];
    #pragma unroll
    for (int t = 0; t < TT; t++) acc[t] = 0.f;
    int j = tid;
    bool jact = (j < QQ);

    for (int rc = 0; rc < RR/32; rc++) {
        __syncthreads();
        for (int idx = tid; idx < 32*QQ; idx += 256) {
            int r = idx / QQ, jj = idx - r*QQ;
            sKWT[jj*KWP + r] = keyW[(rc*32 + r)*QQ + jj];
        }
        __syncthreads();
        if (jact) {
            #pragma unroll
            for (int r4 = 0; r4 < 8; r4++) {
                float4 w = *(const float4*)(sKWT + j*KWP + r4*4);
                int rg = rc*32 + r4*4;
                #pragma unroll
                for (int t = 0; t < TT; t++) {
                    float4 sv = *(const float4*)(sVal + t*RR + rg);
                    acc[t] = fmaf(w.x, sv.x, acc[t]);
                    acc[t] = fmaf(w.y, sv.y, acc[t]);
                    acc[t] = fmaf(w.z, sv.z, acc[t]);
                    acc[t] = fmaf(w.w, sv.w, acc[t]);
                }
            }
        }
    }
    {
        float qj = jact ? query[j] : 0.f;
        float kb = jact ? keyb[j]  : 0.f;
        #pragma unroll
        for (int t = 0; t < TT; t++) {
            float v = jact ? qj * tanhf(acc[t] + kb) : 0.f;
            #pragma unroll
            for (int o = 16; o; o >>= 1) v += __shfl_xor_sync(0xffffffffu, v, o);
            if (lane == 0 && warp < 7) atomicAdd(&sPool[t], v);
        }
    }
    __syncthreads();

    if (tid == 0) {
        float m = sPool[0] * INV_SCALE;
        #pragma unroll
        for (int t = 1; t < TT; t++) m = fmaxf(m, sPool[t] * INV_SCALE);
        float ssum = 0.f;
        #pragma unroll
        for (int t = 0; t < TT; t++) { float e = __expf(sPool[t]*INV_SCALE - m); sW[t] = e; ssum += e; }
        float inv = 1.0f / ssum;
        #pragma unroll
        for (int t = 0; t < TT; t++) sW[t] *= inv;
    }
    __syncthreads();

    {
        int r = tid;
        float a2 = 0.f;
        #pragma unroll
        for (int t = 0; t < TT; t++) a2 = fmaf(sW[t], sVal[t*RR + r], a2);
        g_rep[(size_t)bci*RR + r] = a2;
    }
}

// ---------------- mean + ltr ----------------
__global__ void k_fv(const float* __restrict__ ltr_w, const float* __restrict__ ltr_b) {
    __shared__ float red[256];
    int bc = blockIdx.x;
    int r = threadIdx.x;
    float ssum = 0.f;
    for (int i = 0; i < HIS; i++) ssum += g_rep[(size_t)(bc*HIS + i)*RR + r];
    red[r] = (ssum * (1.0f/HIS)) * ltr_w[r];
    __syncthreads();
    for (int off = 128; off; off >>= 1) {
        if (r < off) red[r] += red[r + off];
        __syncthreads();
    }
    if (r == 0) g_score[bc] = red[0] + ltr_b[0];
}

// ---------------- log_softmax ----------------
__global__ void k_out(float* __restrict__ out) {
    int b = threadIdx.x;
    if (b < BB) {
        float s[CDD];
        float m = -1e30f;
        #pragma unroll
        for (int c = 0; c < CDD; c++) { s[c] = g_score[b*CDD + c]; m = fmaxf(m, s[c]); }
        float ssum = 0.f;
        #pragma unroll
        for (int c = 0; c < CDD; c++) ssum += expf(s[c] - m);
        float lse = logf(ssum);
        #pragma unroll
        for (int c = 0; c < CDD; c++) out[b*CDD + c] = s[c] - m - lse;
    }
}

// ---------------- launch ----------------
extern "C" void kernel_launch(void* const* d_in, const int* in_sizes, int n_in,
                              void* d_out, int out_size) {
    const int*   cand  = (const int*)  d_in[0];
    const int*   clk   = (const int*)  d_in[1];
    const float* emb   = (const float*)d_in[2];
    const float* Wq_w  = (const float*)d_in[3];
    const float* Wv_w  = (const float*)d_in[4];
    const float* Wq_i  = (const float*)d_in[5];
    const float* Wv_i  = (const float*)d_in[6];
    const float* keyW  = (const float*)d_in[7];
    const float* keyb  = (const float*)d_in[8];
    const float* query = (const float*)d_in[9];
    const float* ltr_w = (const float*)d_in[10];
    const float* ltr_b = (const float*)d_in[11];
    float* out = (float*)d_out;

    cudaFuncSetAttribute(k_wattn, cudaFuncAttributeMaxDynamicSharedMemorySize,
                         WA_SMEM_FLOATS * sizeof(float));
    cudaFuncSetAttribute(k_fuse, cudaFuncAttributeMaxDynamicSharedMemorySize,
                         K5_SMEM_FLOATS * sizeof(float));

    k_gather<<<NS, 256>>>(cand, clk, emb);
    k_padW<<<HH, 256>>>(Wq_w);
    k_padWv<<<EEP, 256>>>(Wv_w);
    k_padWvi<<<RR, 256>>>(Wv_i);

    k_g128<0><<<dim3(3, 35, HH), 256>>>(nullptr);       // words Q
    k_g128<2><<<dim3(2, 35, 1), 256>>>(nullptr);        // words XV
    k_wattn<<<dim3(NS, HH), 128, WA_SMEM_FLOATS * sizeof(float)>>>();

    k_g128<1><<<dim3(2, 35, HH), 256>>>(Wq_i);          // itrs Q
    k_g128<3><<<dim3(2, 35, 1), 256>>>(nullptr);        // itrs V
    k_ones<<<HH, 256>>>(Wq_i, Wv_i);

    k_diag<<<dim3(NS, HH), 256>>>();
    k_g128<4><<<dim3(8, 1, BB*HH), 256>>>(nullptr);     // Sx1
    k_g128<5><<<dim3(1, 8, BB*HH), 256>>>(nullptr);     // Sx2

    k_fuse<<<NBCI, 256, K5_SMEM_FLOATS * sizeof(float)>>>(keyW, keyb, query);
    k_fv<<<NSC, 256>>>(ltr_w, ltr_b);
    k_out<<<1, 32>>>(out);
}

// round 7
// speedup vs baseline: 5.6517x; 1.3773x over previous
#include <cuda_runtime.h>
#include <math.h>
#include <stdint.h>

#define BB   4
#define CDD  5
#define HIS  50
#define LL   20
#define TT   41
#define EE   300
#define EEP  320
#define HH   16
#define VV   16
#define RR   256
#define QQ   200
#define NSC  (BB*CDD)        // 20
#define NSH  (BB*HIS)        // 200
#define NS   (NSC+NSH)       // 220
#define NTOK (NS*LL)         // 4400
#define NBCI (BB*CDD*HIS)    // 1000

#define INV_SCALE 0.057735026918962584f   // 1/sqrt(300)

// ---------------- device scratch ----------------
__device__ float g_Xp[NTOK*EEP];             // [4400,320] padded embeddings
__device__ float g_Wqp[HH*EEP*EE];           // [16][320][300] padded words Wq
__device__ float g_Wvp[EEP*RR];              // [320][256] words Wv merged heads
__device__ float g_Wvp2[RR*RR];              // [256][256] itrs Wv merged heads
__device__ float g_Qw[(size_t)NS*HH*LL*EE];  // words Q proj [s][h][t][300]
__device__ float g_XV[NTOK*RR];              // words XV [4400][256]
__device__ float g_Rep[NS*LL*RR];            // stage-1 out [220,20,256]
__device__ float g_Q[(size_t)NS*HH*LL*RR];   // itrs Q proj [s][h][t][256]
__device__ float g_V[NS*LL*RR];              // itrs V proj [220,20,256]
__device__ float g_q1[HH*RR];
__device__ float g_v1[RR];
__device__ float g_Scc[NSC*HH*21*21];
__device__ float g_Shh[NSH*HH*21*21];
__device__ float g_Sx1[(size_t)BB*HH*100*1000];
__device__ float g_Sx2[(size_t)BB*HH*1000*100];
__device__ float g_rep[NBCI*RR];
__device__ float g_score[NSC];

// ---------------- K1: gather embeddings (padded) ----------------
__global__ void k_gather(const int* __restrict__ cand, const int* __restrict__ clk,
                         const float* __restrict__ emb) {
    int s = blockIdx.x;
    const int* tok = (s < NSC) ? (cand + s*LL) : (clk + (s-NSC)*LL);
    for (int idx = threadIdx.x; idx < LL*EEP; idx += blockDim.x) {
        int t = idx / EEP, d = idx - t*EEP;
        g_Xp[(s*LL + t)*EEP + d] = (d < EE) ? emb[(size_t)tok[t]*EE + d] : 0.f;
    }
}

// ---------------- pad kernels ----------------
__global__ void k_padW(const float* __restrict__ Wq) {
    int h = blockIdx.x;
    for (int idx = threadIdx.x; idx < EEP*EE; idx += blockDim.x) {
        int k = idx / EE, j = idx - k*EE;
        g_Wqp[(size_t)h*EEP*EE + idx] = (k < EE) ? Wq[(size_t)h*EE*EE + k*EE + j] : 0.f;
    }
}
__global__ void k_padWv(const float* __restrict__ Wv) {
    int idx = blockIdx.x*256 + threadIdx.x;
    int k = idx >> 8, col = idx & 255;
    int h = col >> 4, v = col & 15;
    g_Wvp[idx] = (k < EE) ? Wv[((size_t)h*EE + k)*VV + v] : 0.f;
}
__global__ void k_padWvi(const float* __restrict__ Wv) {
    int idx = blockIdx.x*256 + threadIdx.x;
    int r = idx >> 8, col = idx & 255;
    int h = col >> 4, v = col & 15;
    g_Wvp2[idx] = Wv[((size_t)h*RR + r)*VV + v];
}

// ---------------- tf32 helpers ----------------
__device__ __forceinline__ uint32_t f2tf32(float x) {
    uint32_t u;
    asm("cvt.rna.tf32.f32 %0, %1;" : "=r"(u) : "f"(x));
    return u;
}
__device__ __forceinline__ void mma_tf32(float c[4], const uint32_t a[4], const uint32_t b[2]) {
    asm volatile(
        "mma.sync.aligned.m16n8k8.row.col.f32.tf32.tf32.f32 "
        "{%0,%1,%2,%3}, {%4,%5,%6,%7}, {%8,%9}, {%0,%1,%2,%3};"
        : "+f"(c[0]), "+f"(c[1]), "+f"(c[2]), "+f"(c[3])
        : "r"(a[0]), "r"(a[1]), "r"(a[2]), "r"(a[3]), "r"(b[0]), "r"(b[1]));
}

// ---------------- tf32 tensor-core 128x128x16 GEMM ----------------
// MODE 0: Qw  = Xp  @ Wqp[h]   M=4400 N=300  K=320   grid(3,35,16)
// MODE 1: Q   = Rep @ Wq_i[h]  M=4400 N=256  K=256   grid(2,35,16)
// MODE 4: Sx1 = Qc  @ RepH^T   M=100  N=1000 K=256   grid(8,1,64)
// MODE 5: Sx2 = Qh  @ RepC^T   M=1000 N=100  K=256   grid(1,8,64)
#define BM 128
#define BN 128
#define BK 16
#define TSP 136     // smem pitch: tig stride = 8 banks -> conflict-free frag loads

template<int MODE>
__global__ void __launch_bounds__(256, 2)
k_t128(const float* __restrict__ Bglob) {
    constexpr int K   = (MODE==0) ? EEP : RR;
    constexpr int M   = (MODE==4) ? 100 : (MODE==5 ? 1000 : NTOK);
    constexpr int N   = (MODE==0) ? 300 : (MODE==4 ? 1000 : (MODE==5 ? 100 : RR));
    constexpr bool BT = (MODE>=4);
    constexpr int LDB = (MODE==0) ? 300 : RR;
    constexpr int NCH = K / BK;

    __shared__ float As[2][BK*TSP];
    __shared__ float Bs[2][BK*TSP];

    const int tid = threadIdx.x;
    const int bz = blockIdx.z;
    const int nBase = blockIdx.x * BN;
    const int mBase = blockIdx.y * BM;
    int b = 0, h = 0;
    if (MODE==0 || MODE==1) h = bz;
    if (MODE>=4) { b = bz >> 4; h = bz & 15; }

    // ---- loaders ----
    const int ar  = tid >> 1;
    const int akq = (tid & 1) * 2;
    const float* Arow = nullptr;
    {
        int am = mBase + ar;
        if (am < M) {
            if (MODE==0) Arow = g_Xp + (size_t)am*EEP;
            else if (MODE==1) Arow = g_Rep + (size_t)am*RR;
            else if (MODE==4) { int c = am/20, t = am - 20*c;
                Arow = g_Q + (size_t)(((b*CDD + c)*HH + h)*LL + t)*RR; }
            else { int i = am/20, u = am - 20*i;
                Arow = g_Q + (size_t)(((NSC + b*HIS + i)*HH + h)*LL + u)*RR; }
        }
    }
    const float* Brow = nullptr;
    const float* Bb = nullptr;
    int bkr = 0, bn1 = 0; bool bok1 = false, bok2 = false;
    if (BT) {
        int bn = nBase + ar;
        if (bn < N) {
            if (MODE==4) Brow = g_Rep + ((size_t)(NSC + b*HIS)*LL + bn)*RR;
            else         Brow = g_Rep + ((size_t)(b*CDD)*LL + bn)*RR;
        }
    } else {
        if (MODE==0) Bb = g_Wqp + (size_t)h*EEP*300;
        else Bb = Bglob + (size_t)h*RR*RR;
        bkr = tid >> 4; bn1 = (tid & 15) * 4;
        bok1 = (nBase + bn1) < N;
        bok2 = (nBase + bn1 + 64) < N;
    }

    float4 pa0, pa1, pb0, pb1;
    const float4 fz = make_float4(0.f, 0.f, 0.f, 0.f);

    auto loadChunk = [&](int kc) {
        pa0 = fz; pa1 = fz; pb0 = fz; pb1 = fz;
        if (Arow) {
            pa0 = *(const float4*)(Arow + kc + 4*akq);
            pa1 = *(const float4*)(Arow + kc + 4*akq + 4);
        }
        if (BT) {
            if (Brow) {
                pb0 = *(const float4*)(Brow + kc + 4*akq);
                pb1 = *(const float4*)(Brow + kc + 4*akq + 4);
            }
        } else {
            if (bok1) pb0 = *(const float4*)(Bb + (size_t)(kc + bkr)*LDB + nBase + bn1);
            if (bok2) pb1 = *(const float4*)(Bb + (size_t)(kc + bkr)*LDB + nBase + bn1 + 64);
        }
    };
    auto storeChunk = [&](int buf) {
        float* dA = As[buf]; float* dB = Bs[buf];
        dA[(4*akq+0)*TSP + ar] = __uint_as_float(f2tf32(pa0.x));
        dA[(4*akq+1)*TSP + ar] = __uint_as_float(f2tf32(pa0.y));
        dA[(4*akq+2)*TSP + ar] = __uint_as_float(f2tf32(pa0.z));
        dA[(4*akq+3)*TSP + ar] = __uint_as_float(f2tf32(pa0.w));
        dA[(4*akq+4)*TSP + ar] = __uint_as_float(f2tf32(pa1.x));
        dA[(4*akq+5)*TSP + ar] = __uint_as_float(f2tf32(pa1.y));
        dA[(4*akq+6)*TSP + ar] = __uint_as_float(f2tf32(pa1.z));
        dA[(4*akq+7)*TSP + ar] = __uint_as_float(f2tf32(pa1.w));
        if (BT) {
            dB[(4*akq+0)*TSP + ar] = __uint_as_float(f2tf32(pb0.x));
            dB[(4*akq+1)*TSP + ar] = __uint_as_float(f2tf32(pb0.y));
            dB[(4*akq+2)*TSP + ar] = __uint_as_float(f2tf32(pb0.z));
            dB[(4*akq+3)*TSP + ar] = __uint_as_float(f2tf32(pb0.w));
            dB[(4*akq+4)*TSP + ar] = __uint_as_float(f2tf32(pb1.x));
            dB[(4*akq+5)*TSP + ar] = __uint_as_float(f2tf32(pb1.y));
            dB[(4*akq+6)*TSP + ar] = __uint_as_float(f2tf32(pb1.z));
            dB[(4*akq+7)*TSP + ar] = __uint_as_float(f2tf32(pb1.w));
        } else {
            float4 q0 = make_float4(__uint_as_float(f2tf32(pb0.x)), __uint_as_float(f2tf32(pb0.y)),
                                    __uint_as_float(f2tf32(pb0.z)), __uint_as_float(f2tf32(pb0.w)));
            float4 q1 = make_float4(__uint_as_float(f2tf32(pb1.x)), __uint_as_float(f2tf32(pb1.y)),
                                    __uint_as_float(f2tf32(pb1.z)), __uint_as_float(f2tf32(pb1.w)));
            *(float4*)(dB + bkr*TSP + bn1) = q0;
            *(float4*)(dB + bkr*TSP + bn1 + 64) = q1;
        }
    };

    // ---- warp tiling: 8 warps, each 64x32 (4 m-tiles x 4 n-tiles of m16n8k8) ----
    const int warp = tid >> 5, lane = tid & 31;
    const int wm = (warp >> 2) * 64;
    const int wn = (warp & 3) * 32;
    const int g = lane >> 2, tig = lane & 3;

    float c[4][4][4];
    #pragma unroll
    for (int mt = 0; mt < 4; mt++)
        #pragma unroll
        for (int nt = 0; nt < 4; nt++)
            #pragma unroll
            for (int e = 0; e < 4; e++) c[mt][nt][e] = 0.f;

    loadChunk(0); storeChunk(0); __syncthreads();

    for (int ch = 0; ch < NCH; ch++) {
        int cur = ch & 1;
        if (ch + 1 < NCH) loadChunk((ch + 1) * BK);
        const float* pAs = As[cur];
        const float* pBs = Bs[cur];
        #pragma unroll
        for (int ks = 0; ks < 2; ks++) {
            const int k0 = ks * 8;
            uint32_t af[4][4], bf[4][2];
            #pragma unroll
            for (int mt = 0; mt < 4; mt++) {
                const float* p0 = pAs + (k0 + tig)*TSP + wm + mt*16 + g;
                const float* p1 = pAs + (k0 + tig + 4)*TSP + wm + mt*16 + g;
                af[mt][0] = __float_as_uint(p0[0]);
                af[mt][1] = __float_as_uint(p0[8]);
                af[mt][2] = __float_as_uint(p1[0]);
                af[mt][3] = __float_as_uint(p1[8]);
            }
            #pragma unroll
            for (int nt = 0; nt < 4; nt++) {
                bf[nt][0] = __float_as_uint(pBs[(k0 + tig)*TSP + wn + nt*8 + g]);
                bf[nt][1] = __float_as_uint(pBs[(k0 + tig + 4)*TSP + wn + nt*8 + g]);
            }
            #pragma unroll
            for (int mt = 0; mt < 4; mt++)
                #pragma unroll
                for (int nt = 0; nt < 4; nt++)
                    mma_tf32(c[mt][nt], af[mt], bf[nt]);
        }
        if (ch + 1 < NCH) { storeChunk(cur ^ 1); __syncthreads(); }
    }

    // ---- epilogue ----
    #pragma unroll
    for (int mt = 0; mt < 4; mt++) {
        int row0 = mBase + wm + mt*16 + g;
        int row1 = row0 + 8;
        float *o0 = nullptr, *o1 = nullptr;
        if (row0 < M) {
            if (MODE==0) { int s = row0/20, t = row0 - 20*s; o0 = g_Qw + ((size_t)(s*HH + h)*LL + t)*300; }
            else if (MODE==1) { int s = row0/20, t = row0 - 20*s; o0 = g_Q + ((size_t)(s*HH + h)*LL + t)*RR; }
            else if (MODE==4) o0 = g_Sx1 + (size_t)bz*100000 + (size_t)row0*1000;
            else              o0 = g_Sx2 + (size_t)bz*100000 + (size_t)row0*100;
        }
        if (row1 < M) {
            if (MODE==0) { int s = row1/20, t = row1 - 20*s; o1 = g_Qw + ((size_t)(s*HH + h)*LL + t)*300; }
            else if (MODE==1) { int s = row1/20, t = row1 - 20*s; o1 = g_Q + ((size_t)(s*HH + h)*LL + t)*RR; }
            else if (MODE==4) o1 = g_Sx1 + (size_t)bz*100000 + (size_t)row1*1000;
            else              o1 = g_Sx2 + (size_t)bz*100000 + (size_t)row1*100;
        }
        #pragma unroll
        for (int nt = 0; nt < 4; nt++) {
            int col = nBase + wn + nt*8 + 2*tig;
            if (col < N) {
                if (o0) *(float2*)(o0 + col) = make_float2(c[mt][nt][0], c[mt][nt][1]);
                if (o1) *(float2*)(o1 + col) = make_float2(c[mt][nt][2], c[mt][nt][3]);
            }
        }
    }
}

// ---------------- SIMT 128x128 GEMM kept for small V projections ----------
// MODE 2: XV  = Xp  @ Wvp      M=4400 N=256  K=320   grid(2,35,1)
// MODE 3: V   = Rep @ Wvp2     M=4400 N=256  K=256   grid(2,35,1)
#define SP 132
template<int MODE>
__global__ void __launch_bounds__(256, 2)
k_g128() {
    constexpr int K   = (MODE==2) ? EEP : RR;
    constexpr int M   = NTOK;
    constexpr int N   = RR;
    constexpr int LDB = RR;
    constexpr int NCH = K / BK;

    __shared__ float As[2][BK*SP];
    __shared__ float Bs[2][BK*SP];

    const int tid = threadIdx.x;
    const int nBase = blockIdx.x * BN;
    const int mBase = blockIdx.y * BM;

    const int ar  = tid >> 1;
    const int akq = (tid & 1) * 2;
    const float* Arow = nullptr;
    {
        int am = mBase + ar;
        if (am < M) Arow = ((MODE==2) ? g_Xp + (size_t)am*EEP : g_Rep + (size_t)am*RR);
    }
    const float* Bb = (MODE==2) ? g_Wvp : g_Wvp2;
    int bkr = tid >> 4, bn1 = (tid & 15) * 4;

    float4 pa0, pa1, pb0, pb1;
    const float4 fz = make_float4(0.f, 0.f, 0.f, 0.f);

    auto loadChunk = [&](int kc) {
        pa0 = fz; pa1 = fz;
        if (Arow) {
            pa0 = *(const float4*)(Arow + kc + 4*akq);
            pa1 = *(const float4*)(Arow + kc + 4*akq + 4);
        }
        pb0 = *(const float4*)(Bb + (size_t)(kc + bkr)*LDB + nBase + bn1);
        pb1 = *(const float4*)(Bb + (size_t)(kc + bkr)*LDB + nBase + bn1 + 64);
    };
    auto storeChunk = [&](int buf) {
        float* dA = As[buf]; float* dB = Bs[buf];
        dA[(4*akq+0)*SP + ar] = pa0.x; dA[(4*akq+1)*SP + ar] = pa0.y;
        dA[(4*akq+2)*SP + ar] = pa0.z; dA[(4*akq+3)*SP + ar] = pa0.w;
        dA[(4*akq+4)*SP + ar] = pa1.x; dA[(4*akq+5)*SP + ar] = pa1.y;
        dA[(4*akq+6)*SP + ar] = pa1.z; dA[(4*akq+7)*SP + ar] = pa1.w;
        *(float4*)(dB + bkr*SP + bn1) = pb0;
        *(float4*)(dB + bkr*SP + bn1 + 64) = pb1;
    };

    float acc[8][8];
    #pragma unroll
    for (int r = 0; r < 8; r++)
        #pragma unroll
        for (int j = 0; j < 8; j++) acc[r][j] = 0.f;

    loadChunk(0); storeChunk(0); __syncthreads();

    const int tx = tid & 15, ty = tid >> 4;
    for (int ch = 0; ch < NCH; ch++) {
        int cur = ch & 1;
        if (ch + 1 < NCH) loadChunk((ch + 1) * BK);
        const float* pAs = As[cur];
        const float* pBs = Bs[cur];
        #pragma unroll
        for (int k = 0; k < BK; k++) {
            float4 a0 = *(const float4*)(pAs + k*SP + ty*8);
            float4 a1 = *(const float4*)(pAs + k*SP + ty*8 + 4);
            float4 b0 = *(const float4*)(pBs + k*SP + tx*8);
            float4 b1 = *(const float4*)(pBs + k*SP + tx*8 + 4);
            float av[8] = {a0.x,a0.y,a0.z,a0.w,a1.x,a1.y,a1.z,a1.w};
            float bv[8] = {b0.x,b0.y,b0.z,b0.w,b1.x,b1.y,b1.z,b1.w};
            #pragma unroll
            for (int r = 0; r < 8; r++)
                #pragma unroll
                for (int j = 0; j < 8; j++) acc[r][j] = fmaf(av[r], bv[j], acc[r][j]);
        }
        if (ch + 1 < NCH) { storeChunk(cur ^ 1); __syncthreads(); }
    }

    #pragma unroll
    for (int r = 0; r < 8; r++) {
        int row = mBase + ty*8 + r;
        if (row >= M) continue;
        float* orow = (MODE==2) ? g_XV + (size_t)row*RR : g_V + (size_t)row*RR;
        int col = nBase + tx*8;
        *(float4*)(orow + col) = make_float4(acc[r][0],acc[r][1],acc[r][2],acc[r][3]);
        *(float4*)(orow + col + 4) = make_float4(acc[r][4],acc[r][5],acc[r][6],acc[r][7]);
    }
}

// ---------------- K2: words attention (Q,XV precomputed), per (s,h) ----------
#define WT_XT  0
#define WT_QT  (300*22)
#define WT_S   (2*300*22)
#define WT_XV  (WT_S + 20*22)
#define WA_SMEM_FLOATS (WT_XV + 20*16)

__global__ void __launch_bounds__(128, 4)
k_wattn() {
    extern __shared__ float sm[];
    float* XT = sm + WT_XT;
    float* QT = sm + WT_QT;
    float* S  = sm + WT_S;
    float* XV = sm + WT_XV;

    int s = blockIdx.x, h = blockIdx.y, tid = threadIdx.x;

    for (int d = tid; d < EE; d += 128) {
        const float* xr = g_Xp + (size_t)s*LL*EEP + d;
        const float* qr = g_Qw + ((size_t)(s*HH + h)*LL)*300 + d;
        #pragma unroll
        for (int t = 0; t < LL; t++) {
            XT[d*22 + t] = xr[(size_t)t*EEP];
            QT[d*22 + t] = qr[(size_t)t*300];
        }
    }
    for (int p = tid; p < LL*VV; p += 128) {
        int u = p >> 4, v = p & 15;
        XV[p] = g_XV[(size_t)(s*LL + u)*RR + h*VV + v];
    }
    __syncthreads();

    if (tid < 100) {
        int ti = (tid / 10) * 2, ui = (tid % 10) * 2;
        float a00 = 0.f, a01 = 0.f, a10 = 0.f, a11 = 0.f;
        #pragma unroll 4
        for (int k = 0; k < EE; k++) {
            float2 q = *(const float2*)(QT + k*22 + ti);
            float2 x = *(const float2*)(XT + k*22 + ui);
            a00 = fmaf(q.x, x.x, a00); a01 = fmaf(q.x, x.y, a01);
            a10 = fmaf(q.y, x.x, a10); a11 = fmaf(q.y, x.y, a11);
        }
        S[ ti   *22 + ui  ] = a00 * INV_SCALE;
        S[ ti   *22 + ui+1] = a01 * INV_SCALE;
        S[(ti+1)*22 + ui  ] = a10 * INV_SCALE;
        S[(ti+1)*22 + ui+1] = a11 * INV_SCALE;
    }
    __syncthreads();

    if (tid < LL) {
        float* row = S + tid*22;
        float m = row[0];
        #pragma unroll
        for (int u = 1; u < LL; u++) m = fmaxf(m, row[u]);
        float ssum = 0.f;
        #pragma unroll
        for (int u = 0; u < LL; u++) { float e = __expf(row[u] - m); row[u] = e; ssum += e; }
        float inv = 1.0f / ssum;
        #pragma unroll
        for (int u = 0; u < LL; u++) row[u] *= inv;
    }
    __syncthreads();

    for (int p = tid; p < LL*VV; p += 128) {
        int t = p >> 4, v = p & 15;
        float acc = 0.f;
        #pragma unroll
        for (int u = 0; u < LL; u++) acc = fmaf(S[t*22 + u], XV[u*VV + v], acc);
        g_Rep[(size_t)(s*LL + t)*RR + h*VV + v] = acc;
    }
}

// ---------------- ones-row projections ----------------
__global__ void k_ones(const float* __restrict__ Wq, const float* __restrict__ Wv) {
    int h = blockIdx.x, j = threadIdx.x;
    float acc = 0.f;
    const float* w = Wq + (size_t)h*RR*RR + j;
    for (int r = 0; r < RR; r++) acc += w[r*RR];
    g_q1[h*RR + j] = acc;
    if (j < VV) {
        float a2 = 0.f;
        const float* wv = Wv + (size_t)h*RR*VV + j;
        for (int r = 0; r < RR; r++) a2 += wv[r*VV];
        g_v1[h*VV + j] = a2;
    }
}

// ---------------- diagonal score blocks ----------------
__global__ void __launch_bounds__(256, 4)
k_diag() {
    __shared__ float sQd[21*RR];
    __shared__ float sK[LL*RR];
    int s = blockIdx.x, h = blockIdx.y, tid = threadIdx.x;

    {
        const float4* gq = (const float4*)(g_Q + (size_t)(s*HH + h)*LL*RR);
        const float4* gk = (const float4*)(g_Rep + (size_t)s*LL*RR);
        float4* dQ = (float4*)sQd; float4* dK = (float4*)sK;
        for (int idx = tid; idx < LL*RR/4; idx += 256) { dQ[idx] = gq[idx]; dK[idx] = gk[idx]; }
        if (tid < RR) sQd[LL*RR + tid] = g_q1[h*RR + tid];
    }
    __syncthreads();

    float* out = (s < NSC) ? (g_Scc + ((size_t)s*HH + h)*441)
                           : (g_Shh + ((size_t)(s-NSC)*HH + h)*441);
    int warp = tid >> 5, lane = tid & 31;
    for (int p = warp; p < 21*21; p += 8) {
        int q = p / 21, k = p - q*21;
        const float4* q4 = (const float4*)(sQd + q*RR);
        float4 a = q4[lane], a2 = q4[lane + 32];
        float partial;
        if (k == 20) {
            partial = a.x + a.y + a.z + a.w + a2.x + a2.y + a2.z + a2.w;
        } else {
            const float4* k4 = (const float4*)(sK + k*RR);
            float4 bb = k4[lane], b2 = k4[lane + 32];
            partial  = a.x*bb.x + a.y*bb.y + a.z*bb.z + a.w*bb.w;
            partial += a2.x*b2.x + a2.y*b2.y + a2.z*b2.z + a2.w*b2.w;
        }
        #pragma unroll
        for (int o = 16; o; o >>= 1) partial += __shfl_xor_sync(0xffffffffu, partial, o);
        if (lane == 0) out[p] = partial;
    }
}

// ---------------- K5: fused softmax + AV + pooling ----------------
#define KWP 36
#define SC_VC   0
#define SC_VH   (SC_VC + LL*RR)
#define SC_V1   (SC_VH + LL*RR)
#define SC_VAL  (SC_V1 + RR)
#define SCR     (SC_VAL + TT*RR)
#define SC_POOL (SCR + QQ*KWP)
#define SC_W    (SC_POOL + 48)
#define K5_SMEM_FLOATS (SC_W + 48)

__global__ void __launch_bounds__(256, 2)
k_fuse(const float* __restrict__ keyW, const float* __restrict__ keyb,
       const float* __restrict__ query) {
    extern __shared__ float sm[];
    float* sVc  = sm + SC_VC;
    float* sVh  = sm + SC_VH;
    float* sV1  = sm + SC_V1;
    float* sVal = sm + SC_VAL;
    float* sS   = sm + SCR;
    float* sKWT = sm + SCR;
    float* sPool= sm + SC_POOL;
    float* sW   = sm + SC_W;

    int bci = blockIdx.x;
    int i   = bci % HIS;
    int bc  = bci / HIS;
    int b   = bc / CDD;
    int c   = bc - b*CDD;
    int sc  = bc;
    int sh  = NSC + b*HIS + i;

    int tid = threadIdx.x;
    int warp = tid >> 5, lane = tid & 31;

    {
        const float4* gvc = (const float4*)(g_V + (size_t)sc*LL*RR);
        const float4* gvh = (const float4*)(g_V + (size_t)sh*LL*RR);
        float4* dVc = (float4*)sVc; float4* dVh = (float4*)sVh;
        for (int idx = tid; idx < LL*RR/4; idx += 256) { dVc[idx] = gvc[idx]; dVh[idx] = gvh[idx]; }
        if (tid < RR) sV1[tid] = g_v1[tid];
    }

    for (int h = 0; h < HH; h++) {
        const float* scc = g_Scc + ((size_t)bc*HH + h)*441;
        const float* shh = g_Shh + ((size_t)(b*HIS + i)*HH + h)*441;
        const float* sx1 = g_Sx1 + ((size_t)(b*HH + h))*100*1000;
        const float* sx2 = g_Sx2 + ((size_t)(b*HH + h))*1000*100;

        __syncthreads();
        for (int p = tid; p < TT*TT; p += 256) {
            int q = p / TT, k = p - q*TT;
            float v;
            if (q < LL) {
                if (k < LL)       v = __ldg(&scc[q*21 + k]);
                else if (k == LL) v = __ldg(&scc[q*21 + 20]);
                else              v = __ldg(&sx1[(size_t)(c*20 + q)*1000 + i*20 + (k-LL-1)]);
            } else if (q == LL) {
                if (k < LL)       v = __ldg(&scc[20*21 + k]);
                else if (k == LL) v = __ldg(&scc[20*21 + 20]);
                else              v = __ldg(&shh[20*21 + (k-LL-1)]);
            } else {
                int t = q - LL - 1;
                if (k < LL)       v = __ldg(&sx2[(size_t)(i*20 + t)*100 + c*20 + k]);
                else if (k == LL) v = __ldg(&shh[t*21 + 20]);
                else              v = __ldg(&shh[t*21 + (k-LL-1)]);
            }
            sS[p] = v * INV_SCALE;
        }
        __syncthreads();

        if (tid < TT) {
            float* row = sS + tid*TT;
            float m = row[0];
            #pragma unroll
            for (int k = 1; k < TT; k++) m = fmaxf(m, row[k]);
            float ssum = 0.f;
            #pragma unroll
            for (int k = 0; k < TT; k++) { float e = __expf(row[k] - m); row[k] = e; ssum += e; }
            float inv = 1.0f / ssum;
            #pragma unroll
            for (int k = 0; k < TT; k++) row[k] *= inv;
        }
        __syncthreads();

        for (int p = tid; p < TT*VV; p += 256) {
            int q = p / VV, v = p - (p / VV)*VV;
            int col = h*VV + v;
            const float* arow = sS + q*TT;
            float acc = arow[LL] * sV1[col];
            #pragma unroll
            for (int k = 0; k < LL; k++) acc = fmaf(arow[k], sVc[k*RR + col], acc);
            #pragma unroll
            for (int k = 0; k < LL; k++) acc = fmaf(arow[LL+1+k], sVh[k*RR + col], acc);
            sVal[q*RR + col] = acc;
        }
    }
    __syncthreads();

    if (tid < TT) sPool[tid] = 0.f;

    float acc[TT];
    #pragma unroll
    for (int t = 0; t < TT; t++) acc[t] = 0.f;
    int j = tid;
    bool jact = (j < QQ);

    for (int rc = 0; rc < RR/32; rc++) {
        __syncthreads();
        for (int idx = tid; idx < 32*QQ; idx += 256) {
            int r = idx / QQ, jj = idx - r*QQ;
            sKWT[jj*KWP + r] = keyW[(rc*32 + r)*QQ + jj];
        }
        __syncthreads();
        if (jact) {
            #pragma unroll
            for (int r4 = 0; r4 < 8; r4++) {
                float4 w = *(const float4*)(sKWT + j*KWP + r4*4);
                int rg = rc*32 + r4*4;
                #pragma unroll
                for (int t = 0; t < TT; t++) {
                    float4 sv = *(const float4*)(sVal + t*RR + rg);
                    acc[t] = fmaf(w.x, sv.x, acc[t]);
                    acc[t] = fmaf(w.y, sv.y, acc[t]);
                    acc[t] = fmaf(w.z, sv.z, acc[t]);
                    acc[t] = fmaf(w.w, sv.w, acc[t]);
                }
            }
        }
    }
    {
        float qj = jact ? query[j] : 0.f;
        float kb = jact ? keyb[j]  : 0.f;
        #pragma unroll
        for (int t = 0; t < TT; t++) {
            float v = jact ? qj * tanhf(acc[t] + kb) : 0.f;
            #pragma unroll
            for (int o = 16; o; o >>= 1) v += __shfl_xor_sync(0xffffffffu, v, o);
            if (lane == 0 && warp < 7) atomicAdd(&sPool[t], v);
        }
    }
    __syncthreads();

    if (tid == 0) {
        float m = sPool[0] * INV_SCALE;
        #pragma unroll
        for (int t = 1; t < TT; t++) m = fmaxf(m, sPool[t] * INV_SCALE);
        float ssum = 0.f;
        #pragma unroll
        for (int t = 0; t < TT; t++) { float e = __expf(sPool[t]*INV_SCALE - m); sW[t] = e; ssum += e; }
        float inv = 1.0f / ssum;
        #pragma unroll
        for (int t = 0; t < TT; t++) sW[t] *= inv;
    }
    __syncthreads();

    {
        int r = tid;
        float a2 = 0.f;
        #pragma unroll
        for (int t = 0; t < TT; t++) a2 = fmaf(sW[t], sVal[t*RR + r], a2);
        g_rep[(size_t)bci*RR + r] = a2;
    }
}

// ---------------- mean + ltr ----------------
__global__ void k_fv(const float* __restrict__ ltr_w, const float* __restrict__ ltr_b) {
    __shared__ float red[256];
    int bc = blockIdx.x;
    int r = threadIdx.x;
    float ssum = 0.f;
    for (int i = 0; i < HIS; i++) ssum += g_rep[(size_t)(bc*HIS + i)*RR + r];
    red[r] = (ssum * (1.0f/HIS)) * ltr_w[r];
    __syncthreads();
    for (int off = 128; off; off >>= 1) {
        if (r < off) red[r] += red[r + off];
        __syncthreads();
    }
    if (r == 0) g_score[bc] = red[0] + ltr_b[0];
}

// ---------------- log_softmax ----------------
__global__ void k_out(float* __restrict__ out) {
    int b = threadIdx.x;
    if (b < BB) {
        float s[CDD];
        float m = -1e30f;
        #pragma unroll
        for (int c = 0; c < CDD; c++) { s[c] = g_score[b*CDD + c]; m = fmaxf(m, s[c]); }
        float ssum = 0.f;
        #pragma unroll
        for (int c = 0; c < CDD; c++) ssum += expf(s[c] - m);
        float lse = logf(ssum);
        #pragma unroll
        for (int c = 0; c < CDD; c++) out[b*CDD + c] = s[c] - m - lse;
    }
}

// ---------------- launch ----------------
extern "C" void kernel_launch(void* const* d_in, const int* in_sizes, int n_in,
                              void* d_out, int out_size) {
    const int*   cand  = (const int*)  d_in[0];
    const int*   clk   = (const int*)  d_in[1];
    const float* emb   = (const float*)d_in[2];
    const float* Wq_w  = (const float*)d_in[3];
    const float* Wv_w  = (const float*)d_in[4];
    const float* Wq_i  = (const float*)d_in[5];
    const float* Wv_i  = (const float*)d_in[6];
    const float* keyW  = (const float*)d_in[7];
    const float* keyb  = (const float*)d_in[8];
    const float* query = (const float*)d_in[9];
    const float* ltr_w = (const float*)d_in[10];
    const float* ltr_b = (const float*)d_in[11];
    float* out = (float*)d_out;

    cudaFuncSetAttribute(k_wattn, cudaFuncAttributeMaxDynamicSharedMemorySize,
                         WA_SMEM_FLOATS * sizeof(float));
    cudaFuncSetAttribute(k_fuse, cudaFuncAttributeMaxDynamicSharedMemorySize,
                         K5_SMEM_FLOATS * sizeof(float));

    k_gather<<<NS, 256>>>(cand, clk, emb);
    k_padW<<<HH, 256>>>(Wq_w);
    k_padWv<<<EEP, 256>>>(Wv_w);
    k_padWvi<<<RR, 256>>>(Wv_i);

    k_t128<0><<<dim3(3, 35, HH), 256>>>(nullptr);       // words Q (tf32)
    k_g128<2><<<dim3(2, 35, 1), 256>>>();               // words XV (fp32)
    k_wattn<<<dim3(NS, HH), 128, WA_SMEM_FLOATS * sizeof(float)>>>();

    k_t128<1><<<dim3(2, 35, HH), 256>>>(Wq_i);          // itrs Q (tf32)
    k_g128<3><<<dim3(2, 35, 1), 256>>>();               // itrs V (fp32)
    k_ones<<<HH, 256>>>(Wq_i, Wv_i);

    k_diag<<<dim3(NS, HH), 256>>>();
    k_t128<4><<<dim3(8, 1, BB*HH), 256>>>(nullptr);     // Sx1 (tf32)
    k_t128<5><<<dim3(1, 8, BB*HH), 256>>>(nullptr);     // Sx2 (tf32)

    k_fuse<<<NBCI, 256, K5_SMEM_FLOATS * sizeof(float)>>>(keyW, keyb, query);
    k_fv<<<NSC, 256>>>(ltr_w, ltr_b);
    k_out<<<1, 32>>>(out);
}

// round 8
// speedup vs baseline: 6.5142x; 1.1526x over previous
#include <cuda_runtime.h>
#include <math.h>
#include <stdint.h>

#define BB   4
#define CDD  5
#define HIS  50
#define LL   20
#define TT   41
#define EE   300
#define EEP  320
#define HH   16
#define VV   16
#define RR   256
#define QQ   200
#define NSC  (BB*CDD)        // 20
#define NSH  (BB*HIS)        // 200
#define NS   (NSC+NSH)       // 220
#define NTOK (NS*LL)         // 4400
#define NBCI (BB*CDD*HIS)    // 1000
#define MVAL (NBCI*TT)       // 41000

#define INV_SCALE 0.057735026918962584f   // 1/sqrt(300)

// ---------------- device scratch ----------------
__device__ float g_Xp[NTOK*EEP];
__device__ float g_Wqp[HH*EEP*EE];
__device__ float g_Wvp[EEP*RR];
__device__ float g_Wvp2[RR*RR];
__device__ float g_Qw[(size_t)NS*HH*LL*EE];
__device__ float g_XV[NTOK*RR];
__device__ float g_Rep[NS*LL*RR];
__device__ float g_Q[(size_t)NS*HH*LL*RR];
__device__ float g_V[NS*LL*RR];
__device__ float g_q1[HH*RR];
__device__ float g_v1[RR];
__device__ float g_Scc[NSC*HH*21*21];
__device__ float g_Shh[NSH*HH*21*21];
__device__ float g_Sx1[(size_t)BB*HH*100*1000];
__device__ float g_Sx2[(size_t)BB*HH*1000*100];
__device__ float g_Val[(size_t)MVAL*RR];     // fused-attention values [1000*41, 256]
__device__ float g_Kmat[(size_t)MVAL*QQ];    // Val @ keyW             [1000*41, 200]
__device__ float g_rep[NBCI*RR];
__device__ float g_score[NSC];

// ---------------- K1: gather embeddings (padded) ----------------
__global__ void k_gather(const int* __restrict__ cand, const int* __restrict__ clk,
                         const float* __restrict__ emb) {
    int s = blockIdx.x;
    const int* tok = (s < NSC) ? (cand + s*LL) : (clk + (s-NSC)*LL);
    for (int idx = threadIdx.x; idx < LL*EEP; idx += blockDim.x) {
        int t = idx / EEP, d = idx - t*EEP;
        g_Xp[(s*LL + t)*EEP + d] = (d < EE) ? emb[(size_t)tok[t]*EE + d] : 0.f;
    }
}

// ---------------- pad kernels ----------------
__global__ void k_padW(const float* __restrict__ Wq) {
    int h = blockIdx.x;
    for (int idx = threadIdx.x; idx < EEP*EE; idx += blockDim.x) {
        int k = idx / EE, j = idx - k*EE;
        g_Wqp[(size_t)h*EEP*EE + idx] = (k < EE) ? Wq[(size_t)h*EE*EE + k*EE + j] : 0.f;
    }
}
__global__ void k_padWv(const float* __restrict__ Wv) {
    int idx = blockIdx.x*256 + threadIdx.x;
    int k = idx >> 8, col = idx & 255;
    int h = col >> 4, v = col & 15;
    g_Wvp[idx] = (k < EE) ? Wv[((size_t)h*EE + k)*VV + v] : 0.f;
}
__global__ void k_padWvi(const float* __restrict__ Wv) {
    int idx = blockIdx.x*256 + threadIdx.x;
    int r = idx >> 8, col = idx & 255;
    int h = col >> 4, v = col & 15;
    g_Wvp2[idx] = Wv[((size_t)h*RR + r)*VV + v];
}

// ---------------- tf32 helpers ----------------
__device__ __forceinline__ uint32_t f2tf32(float x) {
    uint32_t u;
    asm("cvt.rna.tf32.f32 %0, %1;" : "=r"(u) : "f"(x));
    return u;
}
__device__ __forceinline__ void mma_tf32(float c[4], const uint32_t a[4], const uint32_t b[2]) {
    asm volatile(
        "mma.sync.aligned.m16n8k8.row.col.f32.tf32.tf32.f32 "
        "{%0,%1,%2,%3}, {%4,%5,%6,%7}, {%8,%9}, {%0,%1,%2,%3};"
        : "+f"(c[0]), "+f"(c[1]), "+f"(c[2]), "+f"(c[3])
        : "r"(a[0]), "r"(a[1]), "r"(a[2]), "r"(a[3]), "r"(b[0]), "r"(b[1]));
}

// ---------------- tf32 tensor-core 128x128x16 GEMM ----------------
// MODE 0: Qw   = Xp  @ Wqp[h]    M=4400  N=300  K=320   grid(3,35,16)
// MODE 1: Q    = Rep @ Wq_i[h]   M=4400  N=256  K=256   grid(2,35,16)
// MODE 2: XV   = Xp  @ Wvp       M=4400  N=256  K=320   grid(2,35,1)
// MODE 3: V    = Rep @ Wvp2      M=4400  N=256  K=256   grid(2,35,1)
// MODE 4: Sx1  = Qc  @ RepH^T    M=100   N=1000 K=256   grid(8,1,64)
// MODE 5: Sx2  = Qh  @ RepC^T    M=1000  N=100  K=256   grid(1,8,64)
// MODE 6: Kmat = Val @ keyW      M=41000 N=200  K=256   grid(2,321,1)
#define BM 128
#define BN 128
#define BK 16
#define TSP 136

template<int MODE>
__global__ void __launch_bounds__(256, 2)
k_t128(const float* __restrict__ Bglob) {
    constexpr int K   = (MODE==0 || MODE==2) ? EEP : RR;
    constexpr int M   = (MODE==4) ? 100 : (MODE==5 ? 1000 : (MODE==6 ? MVAL : NTOK));
    constexpr int N   = (MODE==0) ? 300 : (MODE==4 ? 1000 : (MODE==5 ? 100 : (MODE==6 ? QQ : RR)));
    constexpr bool BT = (MODE==4 || MODE==5);
    constexpr int LDB = (MODE==0) ? 300 : (MODE==6 ? QQ : RR);
    constexpr int NCH = K / BK;

    __shared__ float As[2][BK*TSP];
    __shared__ float Bs[2][BK*TSP];

    const int tid = threadIdx.x;
    const int bz = blockIdx.z;
    const int nBase = blockIdx.x * BN;
    const int mBase = blockIdx.y * BM;
    int b = 0, h = 0;
    if (MODE==0 || MODE==1) h = bz;
    if (BT) { b = bz >> 4; h = bz & 15; }

    // ---- loaders ----
    const int ar  = tid >> 1;
    const int akq = (tid & 1) * 2;
    const float* Arow = nullptr;
    {
        int am = mBase + ar;
        if (am < M) {
            if (MODE==0 || MODE==2) Arow = g_Xp + (size_t)am*EEP;
            else if (MODE==1 || MODE==3) Arow = g_Rep + (size_t)am*RR;
            else if (MODE==6) Arow = g_Val + (size_t)am*RR;
            else if (MODE==4) { int c = am/20, t = am - 20*c;
                Arow = g_Q + (size_t)(((b*CDD + c)*HH + h)*LL + t)*RR; }
            else { int i = am/20, u = am - 20*i;
                Arow = g_Q + (size_t)(((NSC + b*HIS + i)*HH + h)*LL + u)*RR; }
        }
    }
    const float* Brow = nullptr;
    const float* Bb = nullptr;
    int bkr = 0, bn1 = 0; bool bok1 = false, bok2 = false;
    if (BT) {
        int bn = nBase + ar;
        if (bn < N) {
            if (MODE==4) Brow = g_Rep + ((size_t)(NSC + b*HIS)*LL + bn)*RR;
            else         Brow = g_Rep + ((size_t)(b*CDD)*LL + bn)*RR;
        }
    } else {
        if (MODE==0) Bb = g_Wqp + (size_t)h*EEP*300;
        else if (MODE==1) Bb = Bglob + (size_t)h*RR*RR;
        else if (MODE==2) Bb = g_Wvp;
        else if (MODE==3) Bb = g_Wvp2;
        else Bb = Bglob;   // MODE 6: keyW
        bkr = tid >> 4; bn1 = (tid & 15) * 4;
        bok1 = (nBase + bn1) < N;
        bok2 = (nBase + bn1 + 64) < N;
    }

    float4 pa0, pa1, pb0, pb1;
    const float4 fz = make_float4(0.f, 0.f, 0.f, 0.f);

    auto loadChunk = [&](int kc) {
        pa0 = fz; pa1 = fz; pb0 = fz; pb1 = fz;
        if (Arow) {
            pa0 = *(const float4*)(Arow + kc + 4*akq);
            pa1 = *(const float4*)(Arow + kc + 4*akq + 4);
        }
        if (BT) {
            if (Brow) {
                pb0 = *(const float4*)(Brow + kc + 4*akq);
                pb1 = *(const float4*)(Brow + kc + 4*akq + 4);
            }
        } else {
            if (bok1) pb0 = *(const float4*)(Bb + (size_t)(kc + bkr)*LDB + nBase + bn1);
            if (bok2) pb1 = *(const float4*)(Bb + (size_t)(kc + bkr)*LDB + nBase + bn1 + 64);
        }
    };
    auto storeChunk = [&](int buf) {
        float* dA = As[buf]; float* dB = Bs[buf];
        dA[(4*akq+0)*TSP + ar] = __uint_as_float(f2tf32(pa0.x));
        dA[(4*akq+1)*TSP + ar] = __uint_as_float(f2tf32(pa0.y));
        dA[(4*akq+2)*TSP + ar] = __uint_as_float(f2tf32(pa0.z));
        dA[(4*akq+3)*TSP + ar] = __uint_as_float(f2tf32(pa0.w));
        dA[(4*akq+4)*TSP + ar] = __uint_as_float(f2tf32(pa1.x));
        dA[(4*akq+5)*TSP + ar] = __uint_as_float(f2tf32(pa1.y));
        dA[(4*akq+6)*TSP + ar] = __uint_as_float(f2tf32(pa1.z));
        dA[(4*akq+7)*TSP + ar] = __uint_as_float(f2tf32(pa1.w));
        if (BT) {
            dB[(4*akq+0)*TSP + ar] = __uint_as_float(f2tf32(pb0.x));
            dB[(4*akq+1)*TSP + ar] = __uint_as_float(f2tf32(pb0.y));
            dB[(4*akq+2)*TSP + ar] = __uint_as_float(f2tf32(pb0.z));
            dB[(4*akq+3)*TSP + ar] = __uint_as_float(f2tf32(pb0.w));
            dB[(4*akq+4)*TSP + ar] = __uint_as_float(f2tf32(pb1.x));
            dB[(4*akq+5)*TSP + ar] = __uint_as_float(f2tf32(pb1.y));
            dB[(4*akq+6)*TSP + ar] = __uint_as_float(f2tf32(pb1.z));
            dB[(4*akq+7)*TSP + ar] = __uint_as_float(f2tf32(pb1.w));
        } else {
            float4 q0 = make_float4(__uint_as_float(f2tf32(pb0.x)), __uint_as_float(f2tf32(pb0.y)),
                                    __uint_as_float(f2tf32(pb0.z)), __uint_as_float(f2tf32(pb0.w)));
            float4 q1 = make_float4(__uint_as_float(f2tf32(pb1.x)), __uint_as_float(f2tf32(pb1.y)),
                                    __uint_as_float(f2tf32(pb1.z)), __uint_as_float(f2tf32(pb1.w)));
            *(float4*)(dB + bkr*TSP + bn1) = q0;
            *(float4*)(dB + bkr*TSP + bn1 + 64) = q1;
        }
    };

    const int warp = tid >> 5, lane = tid & 31;
    const int wm = (warp >> 2) * 64;
    const int wn = (warp & 3) * 32;
    const int g = lane >> 2, tig = lane & 3;

    float c[4][4][4];
    #pragma unroll
    for (int mt = 0; mt < 4; mt++)
        #pragma unroll
        for (int nt = 0; nt < 4; nt++)
            #pragma unroll
            for (int e = 0; e < 4; e++) c[mt][nt][e] = 0.f;

    loadChunk(0); storeChunk(0); __syncthreads();

    for (int ch = 0; ch < NCH; ch++) {
        int cur = ch & 1;
        if (ch + 1 < NCH) loadChunk((ch + 1) * BK);
        const float* pAs = As[cur];
        const float* pBs = Bs[cur];
        #pragma unroll
        for (int ks = 0; ks < 2; ks++) {
            const int k0 = ks * 8;
            uint32_t af[4][4], bf[4][2];
            #pragma unroll
            for (int mt = 0; mt < 4; mt++) {
                const float* p0 = pAs + (k0 + tig)*TSP + wm + mt*16 + g;
                const float* p1 = pAs + (k0 + tig + 4)*TSP + wm + mt*16 + g;
                af[mt][0] = __float_as_uint(p0[0]);
                af[mt][1] = __float_as_uint(p0[8]);
                af[mt][2] = __float_as_uint(p1[0]);
                af[mt][3] = __float_as_uint(p1[8]);
            }
            #pragma unroll
            for (int nt = 0; nt < 4; nt++) {
                bf[nt][0] = __float_as_uint(pBs[(k0 + tig)*TSP + wn + nt*8 + g]);
                bf[nt][1] = __float_as_uint(pBs[(k0 + tig + 4)*TSP + wn + nt*8 + g]);
            }
            #pragma unroll
            for (int mt = 0; mt < 4; mt++)
                #pragma unroll
                for (int nt = 0; nt < 4; nt++)
                    mma_tf32(c[mt][nt], af[mt], bf[nt]);
        }
        if (ch + 1 < NCH) { storeChunk(cur ^ 1); __syncthreads(); }
    }

    // ---- epilogue ----
    #pragma unroll
    for (int mt = 0; mt < 4; mt++) {
        int row0 = mBase + wm + mt*16 + g;
        int row1 = row0 + 8;
        float *o0 = nullptr, *o1 = nullptr;
        if (row0 < M) {
            if (MODE==0) { int s = row0/20, t = row0 - 20*s; o0 = g_Qw + ((size_t)(s*HH + h)*LL + t)*300; }
            else if (MODE==1) { int s = row0/20, t = row0 - 20*s; o0 = g_Q + ((size_t)(s*HH + h)*LL + t)*RR; }
            else if (MODE==2) o0 = g_XV + (size_t)row0*RR;
            else if (MODE==3) o0 = g_V + (size_t)row0*RR;
            else if (MODE==6) o0 = g_Kmat + (size_t)row0*QQ;
            else if (MODE==4) o0 = g_Sx1 + (size_t)bz*100000 + (size_t)row0*1000;
            else              o0 = g_Sx2 + (size_t)bz*100000 + (size_t)row0*100;
        }
        if (row1 < M) {
            if (MODE==0) { int s = row1/20, t = row1 - 20*s; o1 = g_Qw + ((size_t)(s*HH + h)*LL + t)*300; }
            else if (MODE==1) { int s = row1/20, t = row1 - 20*s; o1 = g_Q + ((size_t)(s*HH + h)*LL + t)*RR; }
            else if (MODE==2) o1 = g_XV + (size_t)row1*RR;
            else if (MODE==3) o1 = g_V + (size_t)row1*RR;
            else if (MODE==6) o1 = g_Kmat + (size_t)row1*QQ;
            else if (MODE==4) o1 = g_Sx1 + (size_t)bz*100000 + (size_t)row1*1000;
            else              o1 = g_Sx2 + (size_t)bz*100000 + (size_t)row1*100;
        }
        #pragma unroll
        for (int nt = 0; nt < 4; nt++) {
            int col = nBase + wn + nt*8 + 2*tig;
            if (col < N) {
                if (o0) *(float2*)(o0 + col) = make_float2(c[mt][nt][0], c[mt][nt][1]);
                if (o1) *(float2*)(o1 + col) = make_float2(c[mt][nt][2], c[mt][nt][3]);
            }
        }
    }
}

// ---------------- K2: words attention (Q,XV precomputed), per (s,h) ----------
#define WT_XT  0
#define WT_QT  (300*22)
#define WT_S   (2*300*22)
#define WT_XV  (WT_S + 20*22)
#define WA_SMEM_FLOATS (WT_XV + 20*16)

__global__ void __launch_bounds__(128, 4)
k_wattn() {
    extern __shared__ float sm[];
    float* XT = sm + WT_XT;
    float* QT = sm + WT_QT;
    float* S  = sm + WT_S;
    float* XV = sm + WT_XV;

    int s = blockIdx.x, h = blockIdx.y, tid = threadIdx.x;

    for (int d = tid; d < EE; d += 128) {
        const float* xr = g_Xp + (size_t)s*LL*EEP + d;
        const float* qr = g_Qw + ((size_t)(s*HH + h)*LL)*300 + d;
        #pragma unroll
        for (int t = 0; t < LL; t++) {
            XT[d*22 + t] = xr[(size_t)t*EEP];
            QT[d*22 + t] = qr[(size_t)t*300];
        }
    }
    for (int p = tid; p < LL*VV; p += 128) {
        int u = p >> 4, v = p & 15;
        XV[p] = g_XV[(size_t)(s*LL + u)*RR + h*VV + v];
    }
    __syncthreads();

    if (tid < 100) {
        int ti = (tid / 10) * 2, ui = (tid % 10) * 2;
        float a00 = 0.f, a01 = 0.f, a10 = 0.f, a11 = 0.f;
        #pragma unroll 4
        for (int k = 0; k < EE; k++) {
            float2 q = *(const float2*)(QT + k*22 + ti);
            float2 x = *(const float2*)(XT + k*22 + ui);
            a00 = fmaf(q.x, x.x, a00); a01 = fmaf(q.x, x.y, a01);
            a10 = fmaf(q.y, x.x, a10); a11 = fmaf(q.y, x.y, a11);
        }
        S[ ti   *22 + ui  ] = a00 * INV_SCALE;
        S[ ti   *22 + ui+1] = a01 * INV_SCALE;
        S[(ti+1)*22 + ui  ] = a10 * INV_SCALE;
        S[(ti+1)*22 + ui+1] = a11 * INV_SCALE;
    }
    __syncthreads();

    if (tid < LL) {
        float* row = S + tid*22;
        float m = row[0];
        #pragma unroll
        for (int u = 1; u < LL; u++) m = fmaxf(m, row[u]);
        float ssum = 0.f;
        #pragma unroll
        for (int u = 0; u < LL; u++) { float e = __expf(row[u] - m); row[u] = e; ssum += e; }
        float inv = 1.0f / ssum;
        #pragma unroll
        for (int u = 0; u < LL; u++) row[u] *= inv;
    }
    __syncthreads();

    for (int p = tid; p < LL*VV; p += 128) {
        int t = p >> 4, v = p & 15;
        float acc = 0.f;
        #pragma unroll
        for (int u = 0; u < LL; u++) acc = fmaf(S[t*22 + u], XV[u*VV + v], acc);
        g_Rep[(size_t)(s*LL + t)*RR + h*VV + v] = acc;
    }
}

// ---------------- ones-row projections ----------------
__global__ void k_ones(const float* __restrict__ Wq, const float* __restrict__ Wv) {
    int h = blockIdx.x, j = threadIdx.x;
    float acc = 0.f;
    const float* w = Wq + (size_t)h*RR*RR + j;
    for (int r = 0; r < RR; r++) acc += w[r*RR];
    g_q1[h*RR + j] = acc;
    if (j < VV) {
        float a2 = 0.f;
        const float* wv = Wv + (size_t)h*RR*VV + j;
        for (int r = 0; r < RR; r++) a2 += wv[r*VV];
        g_v1[h*VV + j] = a2;
    }
}

// ---------------- diagonal score blocks ----------------
__global__ void __launch_bounds__(256, 4)
k_diag() {
    __shared__ float sQd[21*RR];
    __shared__ float sK[LL*RR];
    int s = blockIdx.x, h = blockIdx.y, tid = threadIdx.x;

    {
        const float4* gq = (const float4*)(g_Q + (size_t)(s*HH + h)*LL*RR);
        const float4* gk = (const float4*)(g_Rep + (size_t)s*LL*RR);
        float4* dQ = (float4*)sQd; float4* dK = (float4*)sK;
        for (int idx = tid; idx < LL*RR/4; idx += 256) { dQ[idx] = gq[idx]; dK[idx] = gk[idx]; }
        if (tid < RR) sQd[LL*RR + tid] = g_q1[h*RR + tid];
    }
    __syncthreads();

    float* out = (s < NSC) ? (g_Scc + ((size_t)s*HH + h)*441)
                           : (g_Shh + ((size_t)(s-NSC)*HH + h)*441);
    int warp = tid >> 5, lane = tid & 31;
    for (int p = warp; p < 21*21; p += 8) {
        int q = p / 21, k = p - q*21;
        const float4* q4 = (const float4*)(sQd + q*RR);
        float4 a = q4[lane], a2 = q4[lane + 32];
        float partial;
        if (k == 20) {
            partial = a.x + a.y + a.z + a.w + a2.x + a2.y + a2.z + a2.w;
        } else {
            const float4* k4 = (const float4*)(sK + k*RR);
            float4 bb = k4[lane], b2 = k4[lane + 32];
            partial  = a.x*bb.x + a.y*bb.y + a.z*bb.z + a.w*bb.w;
            partial += a2.x*b2.x + a2.y*b2.y + a2.z*b2.z + a2.w*b2.w;
        }
        #pragma unroll
        for (int o = 16; o; o >>= 1) partial += __shfl_xor_sync(0xffffffffu, partial, o);
        if (lane == 0) out[p] = partial;
    }
}

// ---------------- K5: fused softmax + AV -> g_Val ----------------
#define SC_VC   0
#define SC_VH   (SC_VC + LL*RR)             // 5120
#define SC_V1   (SC_VH + LL*RR)             // 10240
#define SC_VAL  (SC_V1 + RR)                // 10496
#define SC_S    (SC_VAL + TT*RR)            // 20992
#define K5_SMEM_FLOATS (SC_S + TT*TT + 15)  // 22688 floats = 90752 B

__global__ void __launch_bounds__(256, 2)
k_fuse_av() {
    extern __shared__ float sm[];
    float* sVc  = sm + SC_VC;
    float* sVh  = sm + SC_VH;
    float* sV1  = sm + SC_V1;
    float* sVal = sm + SC_VAL;
    float* sS   = sm + SC_S;

    int bci = blockIdx.x;
    int i   = bci % HIS;
    int bc  = bci / HIS;
    int b   = bc / CDD;
    int c   = bc - b*CDD;
    int sc  = bc;
    int sh  = NSC + b*HIS + i;

    int tid = threadIdx.x;

    {
        const float4* gvc = (const float4*)(g_V + (size_t)sc*LL*RR);
        const float4* gvh = (const float4*)(g_V + (size_t)sh*LL*RR);
        float4* dVc = (float4*)sVc; float4* dVh = (float4*)sVh;
        for (int idx = tid; idx < LL*RR/4; idx += 256) { dVc[idx] = gvc[idx]; dVh[idx] = gvh[idx]; }
        if (tid < RR) sV1[tid] = g_v1[tid];
    }

    for (int h = 0; h < HH; h++) {
        const float* scc = g_Scc + ((size_t)bc*HH + h)*441;
        const float* shh = g_Shh + ((size_t)(b*HIS + i)*HH + h)*441;
        const float* sx1 = g_Sx1 + ((size_t)(b*HH + h))*100*1000;
        const float* sx2 = g_Sx2 + ((size_t)(b*HH + h))*1000*100;

        __syncthreads();
        for (int p = tid; p < TT*TT; p += 256) {
            int q = p / TT, k = p - q*TT;
            float v;
            if (q < LL) {
                if (k < LL)       v = __ldg(&scc[q*21 + k]);
                else if (k == LL) v = __ldg(&scc[q*21 + 20]);
                else              v = __ldg(&sx1[(size_t)(c*20 + q)*1000 + i*20 + (k-LL-1)]);
            } else if (q == LL) {
                if (k < LL)       v = __ldg(&scc[20*21 + k]);
                else if (k == LL) v = __ldg(&scc[20*21 + 20]);
                else              v = __ldg(&shh[20*21 + (k-LL-1)]);
            } else {
                int t = q - LL - 1;
                if (k < LL)       v = __ldg(&sx2[(size_t)(i*20 + t)*100 + c*20 + k]);
                else if (k == LL) v = __ldg(&shh[t*21 + 20]);
                else              v = __ldg(&shh[t*21 + (k-LL-1)]);
            }
            sS[p] = v * INV_SCALE;
        }
        __syncthreads();

        if (tid < TT) {
            float* row = sS + tid*TT;
            float m = row[0];
            #pragma unroll
            for (int k = 1; k < TT; k++) m = fmaxf(m, row[k]);
            float ssum = 0.f;
            #pragma unroll
            for (int k = 0; k < TT; k++) { float e = __expf(row[k] - m); row[k] = e; ssum += e; }
            float inv = 1.0f / ssum;
            #pragma unroll
            for (int k = 0; k < TT; k++) row[k] *= inv;
        }
        __syncthreads();

        for (int p = tid; p < TT*VV; p += 256) {
            int q = p / VV, v = p - (p / VV)*VV;
            int col = h*VV + v;
            const float* arow = sS + q*TT;
            float acc = arow[LL] * sV1[col];
            #pragma unroll
            for (int k = 0; k < LL; k++) acc = fmaf(arow[k], sVc[k*RR + col], acc);
            #pragma unroll
            for (int k = 0; k < LL; k++) acc = fmaf(arow[LL+1+k], sVh[k*RR + col], acc);
            sVal[q*RR + col] = acc;
        }
    }
    __syncthreads();

    // dump Val to global (coalesced float4)
    {
        float4* gv = (float4*)(g_Val + (size_t)bci*TT*RR);
        const float4* sv = (const float4*)sVal;
        for (int idx = tid; idx < TT*RR/4; idx += 256) gv[idx] = sv[idx];
    }
}

// ---------------- K6: pooling (tanh + query dot + softmax + weighted sum) ----
__global__ void __launch_bounds__(256, 4)
k_pool(const float* __restrict__ keyb, const float* __restrict__ query) {
    __shared__ float sPool[48];
    __shared__ float sW[48];

    int bci = blockIdx.x, tid = threadIdx.x;
    int warp = tid >> 5, lane = tid & 31;

    if (tid < TT) sPool[tid] = 0.f;
    __syncthreads();

    int j = tid;
    bool jact = (j < QQ);
    float qj = jact ? query[j] : 0.f;
    float kb = jact ? keyb[j]  : 0.f;
    const float* km = g_Kmat + (size_t)bci*TT*QQ;

    #pragma unroll
    for (int t = 0; t < TT; t++) {
        float v = jact ? qj * tanhf(km[t*QQ + j] + kb) : 0.f;
        #pragma unroll
        for (int o = 16; o; o >>= 1) v += __shfl_xor_sync(0xffffffffu, v, o);
        if (lane == 0 && warp < 7) atomicAdd(&sPool[t], v);
    }
    __syncthreads();

    if (tid == 0) {
        float m = sPool[0] * INV_SCALE;
        #pragma unroll
        for (int t = 1; t < TT; t++) m = fmaxf(m, sPool[t] * INV_SCALE);
        float ssum = 0.f;
        #pragma unroll
        for (int t = 0; t < TT; t++) { float e = __expf(sPool[t]*INV_SCALE - m); sW[t] = e; ssum += e; }
        float inv = 1.0f / ssum;
        #pragma unroll
        for (int t = 0; t < TT; t++) sW[t] *= inv;
    }
    __syncthreads();

    {
        int r = tid;  // 256
        const float* vb = g_Val + (size_t)bci*TT*RR + r;
        float a2 = 0.f;
        #pragma unroll
        for (int t = 0; t < TT; t++) a2 = fmaf(sW[t], vb[t*RR], a2);
        g_rep[(size_t)bci*RR + r] = a2;
    }
}

// ---------------- mean + ltr ----------------
__global__ void k_fv(const float* __restrict__ ltr_w, const float* __restrict__ ltr_b) {
    __shared__ float red[256];
    int bc = blockIdx.x;
    int r = threadIdx.x;
    float ssum = 0.f;
    for (int i = 0; i < HIS; i++) ssum += g_rep[(size_t)(bc*HIS + i)*RR + r];
    red[r] = (ssum * (1.0f/HIS)) * ltr_w[r];
    __syncthreads();
    for (int off = 128; off; off >>= 1) {
        if (r < off) red[r] += red[r + off];
        __syncthreads();
    }
    if (r == 0) g_score[bc] = red[0] + ltr_b[0];
}

// ---------------- log_softmax ----------------
__global__ void k_out(float* __restrict__ out) {
    int b = threadIdx.x;
    if (b < BB) {
        float s[CDD];
        float m = -1e30f;
        #pragma unroll
        for (int c = 0; c < CDD; c++) { s[c] = g_score[b*CDD + c]; m = fmaxf(m, s[c]); }
        float ssum = 0.f;
        #pragma unroll
        for (int c = 0; c < CDD; c++) ssum += expf(s[c] - m);
        float lse = logf(ssum);
        #pragma unroll
        for (int c = 0; c < CDD; c++) out[b*CDD + c] = s[c] - m - lse;
    }
}

// ---------------- launch ----------------
extern "C" void kernel_launch(void* const* d_in, const int* in_sizes, int n_in,
                              void* d_out, int out_size) {
    const int*   cand  = (const int*)  d_in[0];
    const int*   clk   = (const int*)  d_in[1];
    const float* emb   = (const float*)d_in[2];
    const float* Wq_w  = (const float*)d_in[3];
    const float* Wv_w  = (const float*)d_in[4];
    const float* Wq_i  = (const float*)d_in[5];
    const float* Wv_i  = (const float*)d_in[6];
    const float* keyW  = (const float*)d_in[7];
    const float* keyb  = (const float*)d_in[8];
    const float* query = (const float*)d_in[9];
    const float* ltr_w = (const float*)d_in[10];
    const float* ltr_b = (const float*)d_in[11];
    float* out = (float*)d_out;

    cudaFuncSetAttribute(k_wattn, cudaFuncAttributeMaxDynamicSharedMemorySize,
                         WA_SMEM_FLOATS * sizeof(float));
    cudaFuncSetAttribute(k_fuse_av, cudaFuncAttributeMaxDynamicSharedMemorySize,
                         K5_SMEM_FLOATS * sizeof(float));

    k_gather<<<NS, 256>>>(cand, clk, emb);
    k_padW<<<HH, 256>>>(Wq_w);
    k_padWv<<<EEP, 256>>>(Wv_w);
    k_padWvi<<<RR, 256>>>(Wv_i);

    k_t128<0><<<dim3(3, 35, HH), 256>>>(nullptr);       // words Q (tf32)
    k_t128<2><<<dim3(2, 35, 1), 256>>>(nullptr);        // words XV (tf32)
    k_wattn<<<dim3(NS, HH), 128, WA_SMEM_FLOATS * sizeof(float)>>>();

    k_t128<1><<<dim3(2, 35, HH), 256>>>(Wq_i);          // itrs Q (tf32)
    k_t128<3><<<dim3(2, 35, 1), 256>>>(nullptr);        // itrs V (tf32)
    k_ones<<<HH, 256>>>(Wq_i, Wv_i);

    k_diag<<<dim3(NS, HH), 256>>>();
    k_t128<4><<<dim3(8, 1, BB*HH), 256>>>(nullptr);     // Sx1 (tf32)
    k_t128<5><<<dim3(1, 8, BB*HH), 256>>>(nullptr);     // Sx2 (tf32)

    k_fuse_av<<<NBCI, 256, K5_SMEM_FLOATS * sizeof(float)>>>();
    k_t128<6><<<dim3(2, 321, 1), 256>>>(keyW);          // Kmat (tf32)
    k_pool<<<NBCI, 256>>>(keyb, query);

    k_fv<<<NSC, 256>>>(ltr_w, ltr_b);
    k_out<<<1, 32>>>(out);
}

// round 10
// speedup vs baseline: 8.1925x; 1.2576x over previous
#include <cuda_runtime.h>
#include <math.h>
#include <stdint.h>

#define BB   4
#define CDD  5
#define HIS  50
#define LL   20
#define TT   41
#define EE   300
#define EEP  320
#define HH   16
#define VV   16
#define RR   256
#define QQ   200
#define NSC  (BB*CDD)        // 20
#define NSH  (BB*HIS)        // 200
#define NS   (NSC+NSH)       // 220
#define NTOK (NS*LL)         // 4400
#define NBCI (BB*CDD*HIS)    // 1000
#define MVAL (NBCI*TT)       // 41000

#define INV_SCALE 0.057735026918962584f   // 1/sqrt(300)

// ---------------- device scratch ----------------
__device__ float g_Xp[NTOK*EEP];
__device__ float g_Wqp[HH*EEP*EE];
__device__ float g_Wvp[EEP*RR];
__device__ float g_Wvp2[RR*RR];
__device__ float g_Qw[(size_t)NS*HH*LL*EEP];   // words Q proj [s][h][t][320] (cols 300..319 zero)
__device__ float g_Sw[(size_t)NS*HH*LL*LL];    // words scores [s][h*20+t][20]
__device__ float g_XV[NTOK*RR];
__device__ float g_Rep[NS*LL*RR];
__device__ float g_Q[(size_t)NS*HH*LL*RR];
__device__ float g_V[NS*LL*RR];
__device__ float g_q1[HH*RR];
__device__ float g_v1[RR];
__device__ float g_ones[RR];
__device__ float g_Scc[NSC*HH*21*21];
__device__ float g_Shh[NSH*HH*21*21];
__device__ float g_Sx1[(size_t)BB*HH*100*1000];
__device__ float g_Sx2[(size_t)BB*HH*1000*100];
__device__ float g_Val[(size_t)MVAL*RR];
__device__ float g_Kmat[(size_t)MVAL*QQ];
__device__ float g_rep[NBCI*RR];
__device__ float g_score[NSC];

// ---------------- K1: gather embeddings (padded) ----------------
__global__ void k_gather(const int* __restrict__ cand, const int* __restrict__ clk,
                         const float* __restrict__ emb) {
    int s = blockIdx.x;
    const int* tok = (s < NSC) ? (cand + s*LL) : (clk + (s-NSC)*LL);
    for (int idx = threadIdx.x; idx < LL*EEP; idx += blockDim.x) {
        int t = idx / EEP, d = idx - t*EEP;
        g_Xp[(s*LL + t)*EEP + d] = (d < EE) ? emb[(size_t)tok[t]*EE + d] : 0.f;
    }
}

// ---------------- pad kernels ----------------
__global__ void k_padW(const float* __restrict__ Wq) {
    int h = blockIdx.x;
    for (int idx = threadIdx.x; idx < EEP*EE; idx += blockDim.x) {
        int k = idx / EE, j = idx - k*EE;
        g_Wqp[(size_t)h*EEP*EE + idx] = (k < EE) ? Wq[(size_t)h*EE*EE + k*EE + j] : 0.f;
    }
}
__global__ void k_padWv(const float* __restrict__ Wv) {
    int idx = blockIdx.x*256 + threadIdx.x;
    int k = idx >> 8, col = idx & 255;
    int h = col >> 4, v = col & 15;
    g_Wvp[idx] = (k < EE) ? Wv[((size_t)h*EE + k)*VV + v] : 0.f;
}
__global__ void k_padWvi(const float* __restrict__ Wv) {
    int idx = blockIdx.x*256 + threadIdx.x;
    int r = idx >> 8, col = idx & 255;
    int h = col >> 4, v = col & 15;
    g_Wvp2[idx] = Wv[((size_t)h*RR + r)*VV + v];
}

// ---------------- tf32 helpers ----------------
__device__ __forceinline__ uint32_t f2tf32(float x) {
    uint32_t u;
    asm("cvt.rna.tf32.f32 %0, %1;" : "=r"(u) : "f"(x));
    return u;
}
__device__ __forceinline__ void mma_tf32(float c[4], const uint32_t a[4], const uint32_t b[2]) {
    asm volatile(
        "mma.sync.aligned.m16n8k8.row.col.f32.tf32.tf32.f32 "
        "{%0,%1,%2,%3}, {%4,%5,%6,%7}, {%8,%9}, {%0,%1,%2,%3};"
        : "+f"(c[0]), "+f"(c[1]), "+f"(c[2]), "+f"(c[3])
        : "r"(a[0]), "r"(a[1]), "r"(a[2]), "r"(a[3]), "r"(b[0]), "r"(b[1]));
}

// ---------------- tf32 tensor-core 128x128 GEMM ----------------
// MODE 0: Qw   = Xp  @ Wqp[h]    M=4400  N=300(store 320, zero pad)  K=320  grid(3,35,16)
// MODE 1: Q    = Rep @ Wq_i[h]   M=4400  N=256  K=256   grid(2,35,16)
// MODE 2: XV   = Xp  @ Wvp       M=4400  N=256  K=320   grid(2,35,1)
// MODE 3: V    = Rep @ Wvp2      M=4400  N=256  K=256   grid(2,35,1)
// MODE 4: Sx1  = Qc  @ RepH^T    M=100   N=1000 K=256   grid(8,1,64)
// MODE 5: Sx2  = Qh  @ RepC^T    M=1000  N=100  K=256   grid(1,8,64)
// MODE 6: Kmat = Val @ keyW      M=41000 N=200  K=256   grid(2,321,1)
// MODE 7: Sw[s]= Qw[s] @ X[s]^T  M=320   N=20   K=320   grid(1,3,220)   bz=s
// MODE 8: diag[s]=Q'[s] @ K'^T   M=336   N=21   K=256   grid(1,3,220)   bz=s  (scalar stores: odd row stride 21/441)
#define BM 128
#define BN 128
#define BK 16
#define TSP 136

template<int MODE>
__global__ void __launch_bounds__(256, 2)
k_t128(const float* __restrict__ Bglob) {
    constexpr int K   = (MODE==0 || MODE==2 || MODE==7) ? EEP : RR;
    constexpr int M   = (MODE==4) ? 100 : (MODE==5 ? 1000 : (MODE==6 ? MVAL :
                        (MODE==7 ? 320 : (MODE==8 ? 336 : NTOK))));
    constexpr int N   = (MODE==0) ? 300 : (MODE==4 ? 1000 : (MODE==5 ? 100 :
                        (MODE==6 ? QQ : (MODE==7 ? 20 : (MODE==8 ? 21 : RR)))));
    constexpr bool BT = (MODE==4 || MODE==5 || MODE==7 || MODE==8);
    constexpr int LDB = (MODE==0) ? 300 : (MODE==6 ? QQ : RR);
    constexpr int NCH = K / BK;

    __shared__ float As[2][BK*TSP];
    __shared__ float Bs[2][BK*TSP];

    const int tid = threadIdx.x;
    const int bz = blockIdx.z;
    const int nBase = blockIdx.x * BN;
    const int mBase = blockIdx.y * BM;
    int b = 0, h = 0;
    if (MODE==0 || MODE==1) h = bz;
    if (MODE==4 || MODE==5) { b = bz >> 4; h = bz & 15; }

    // ---- loaders ----
    const int ar  = tid >> 1;
    const int akq = (tid & 1) * 2;
    const float* Arow = nullptr;
    {
        int am = mBase + ar;
        if (am < M) {
            if (MODE==0 || MODE==2) Arow = g_Xp + (size_t)am*EEP;
            else if (MODE==1 || MODE==3) Arow = g_Rep + (size_t)am*RR;
            else if (MODE==6) Arow = g_Val + (size_t)am*RR;
            else if (MODE==7) Arow = g_Qw + (size_t)(bz*320 + am)*EEP;
            else if (MODE==8) {
                int h8 = am / 21, t8 = am - 21*h8;
                Arow = (t8 < 20) ? g_Q + (((size_t)bz*HH + h8)*LL + t8)*RR
                                 : g_q1 + (size_t)h8*RR;
            }
            else if (MODE==4) { int c = am/20, t = am - 20*c;
                Arow = g_Q + (size_t)(((b*CDD + c)*HH + h)*LL + t)*RR; }
            else { int i = am/20, u = am - 20*i;
                Arow = g_Q + (size_t)(((NSC + b*HIS + i)*HH + h)*LL + u)*RR; }
        }
    }
    const float* Brow = nullptr;
    const float* Bb = nullptr;
    int bkr = 0, bn1 = 0; bool bok1 = false, bok2 = false;
    if (BT) {
        int bn = nBase + ar;
        if (bn < N) {
            if (MODE==4)      Brow = g_Rep + ((size_t)(NSC + b*HIS)*LL + bn)*RR;
            else if (MODE==5) Brow = g_Rep + ((size_t)(b*CDD)*LL + bn)*RR;
            else if (MODE==7) Brow = g_Xp + ((size_t)bz*LL + bn)*EEP;
            else              Brow = (bn < 20) ? g_Rep + ((size_t)bz*LL + bn)*RR : g_ones;
        }
    } else {
        if (MODE==0) Bb = g_Wqp + (size_t)h*EEP*300;
        else if (MODE==1) Bb = Bglob + (size_t)h*RR*RR;
        else if (MODE==2) Bb = g_Wvp;
        else if (MODE==3) Bb = g_Wvp2;
        else Bb = Bglob;   // MODE 6: keyW
        bkr = tid >> 4; bn1 = (tid & 15) * 4;
        bok1 = (nBase + bn1) < N;
        bok2 = (nBase + bn1 + 64) < N;
    }

    float4 pa0, pa1, pb0, pb1;
    const float4 fz = make_float4(0.f, 0.f, 0.f, 0.f);

    auto loadChunk = [&](int kc) {
        pa0 = fz; pa1 = fz; pb0 = fz; pb1 = fz;
        if (Arow) {
            pa0 = *(const float4*)(Arow + kc + 4*akq);
            pa1 = *(const float4*)(Arow + kc + 4*akq + 4);
        }
        if (BT) {
            if (Brow) {
                pb0 = *(const float4*)(Brow + kc + 4*akq);
                pb1 = *(const float4*)(Brow + kc + 4*akq + 4);
            }
        } else {
            if (bok1) pb0 = *(const float4*)(Bb + (size_t)(kc + bkr)*LDB + nBase + bn1);
            if (bok2) pb1 = *(const float4*)(Bb + (size_t)(kc + bkr)*LDB + nBase + bn1 + 64);
        }
    };
    auto storeChunk = [&](int buf) {
        float* dA = As[buf]; float* dB = Bs[buf];
        dA[(4*akq+0)*TSP + ar] = __uint_as_float(f2tf32(pa0.x));
        dA[(4*akq+1)*TSP + ar] = __uint_as_float(f2tf32(pa0.y));
        dA[(4*akq+2)*TSP + ar] = __uint_as_float(f2tf32(pa0.z));
        dA[(4*akq+3)*TSP + ar] = __uint_as_float(f2tf32(pa0.w));
        dA[(4*akq+4)*TSP + ar] = __uint_as_float(f2tf32(pa1.x));
        dA[(4*akq+5)*TSP + ar] = __uint_as_float(f2tf32(pa1.y));
        dA[(4*akq+6)*TSP + ar] = __uint_as_float(f2tf32(pa1.z));
        dA[(4*akq+7)*TSP + ar] = __uint_as_float(f2tf32(pa1.w));
        if (BT) {
            dB[(4*akq+0)*TSP + ar] = __uint_as_float(f2tf32(pb0.x));
            dB[(4*akq+1)*TSP + ar] = __uint_as_float(f2tf32(pb0.y));
            dB[(4*akq+2)*TSP + ar] = __uint_as_float(f2tf32(pb0.z));
            dB[(4*akq+3)*TSP + ar] = __uint_as_float(f2tf32(pb0.w));
            dB[(4*akq+4)*TSP + ar] = __uint_as_float(f2tf32(pb1.x));
            dB[(4*akq+5)*TSP + ar] = __uint_as_float(f2tf32(pb1.y));
            dB[(4*akq+6)*TSP + ar] = __uint_as_float(f2tf32(pb1.z));
            dB[(4*akq+7)*TSP + ar] = __uint_as_float(f2tf32(pb1.w));
        } else {
            float4 q0 = make_float4(__uint_as_float(f2tf32(pb0.x)), __uint_as_float(f2tf32(pb0.y)),
                                    __uint_as_float(f2tf32(pb0.z)), __uint_as_float(f2tf32(pb0.w)));
            float4 q1 = make_float4(__uint_as_float(f2tf32(pb1.x)), __uint_as_float(f2tf32(pb1.y)),
                                    __uint_as_float(f2tf32(pb1.z)), __uint_as_float(f2tf32(pb1.w)));
            *(float4*)(dB + bkr*TSP + bn1) = q0;
            *(float4*)(dB + bkr*TSP + bn1 + 64) = q1;
        }
    };

    const int warp = tid >> 5, lane = tid & 31;
    const int wm = (warp >> 2) * 64;
    const int wn = (warp & 3) * 32;
    const int g = lane >> 2, tig = lane & 3;

    float c[4][4][4];
    #pragma unroll
    for (int mt = 0; mt < 4; mt++)
        #pragma unroll
        for (int nt = 0; nt < 4; nt++)
            #pragma unroll
            for (int e = 0; e < 4; e++) c[mt][nt][e] = 0.f;

    loadChunk(0); storeChunk(0); __syncthreads();

    for (int ch = 0; ch < NCH; ch++) {
        int cur = ch & 1;
        if (ch + 1 < NCH) loadChunk((ch + 1) * BK);
        const float* pAs = As[cur];
        const float* pBs = Bs[cur];
        #pragma unroll
        for (int ks = 0; ks < 2; ks++) {
            const int k0 = ks * 8;
            uint32_t af[4][4], bf[4][2];
            #pragma unroll
            for (int mt = 0; mt < 4; mt++) {
                const float* p0 = pAs + (k0 + tig)*TSP + wm + mt*16 + g;
                const float* p1 = pAs + (k0 + tig + 4)*TSP + wm + mt*16 + g;
                af[mt][0] = __float_as_uint(p0[0]);
                af[mt][1] = __float_as_uint(p0[8]);
                af[mt][2] = __float_as_uint(p1[0]);
                af[mt][3] = __float_as_uint(p1[8]);
            }
            #pragma unroll
            for (int nt = 0; nt < 4; nt++) {
                bf[nt][0] = __float_as_uint(pBs[(k0 + tig)*TSP + wn + nt*8 + g]);
                bf[nt][1] = __float_as_uint(pBs[(k0 + tig + 4)*TSP + wn + nt*8 + g]);
            }
            #pragma unroll
            for (int mt = 0; mt < 4; mt++)
                #pragma unroll
                for (int nt = 0; nt < 4; nt++)
                    mma_tf32(c[mt][nt], af[mt], bf[nt]);
        }
        if (ch + 1 < NCH) { storeChunk(cur ^ 1); __syncthreads(); }
    }

    // ---- epilogue ----
    #pragma unroll
    for (int mt = 0; mt < 4; mt++) {
        #pragma unroll
        for (int half = 0; half < 2; half++) {
            int row = mBase + wm + mt*16 + g + half*8;
            if (row >= M) continue;
            float* o;
            if (MODE==0) { int s = row/20, t = row - 20*s;
                o = g_Qw + ((size_t)(s*HH + h)*LL + t)*EEP; }
            else if (MODE==1) { int s = row/20, t = row - 20*s;
                o = g_Q + ((size_t)(s*HH + h)*LL + t)*RR; }
            else if (MODE==2) o = g_XV + (size_t)row*RR;
            else if (MODE==3) o = g_V + (size_t)row*RR;
            else if (MODE==6) o = g_Kmat + (size_t)row*QQ;
            else if (MODE==7) o = g_Sw + (size_t)bz*(HH*LL*LL) + (size_t)row*20;
            else if (MODE==8) {
                int h8 = row/21, t8 = row - 21*h8;
                float* base = (bz < NSC) ? g_Scc + ((size_t)bz*HH + h8)*441
                                         : g_Shh + ((size_t)(bz-NSC)*HH + h8)*441;
                o = base + t8*21;
            }
            else if (MODE==4) o = g_Sx1 + (size_t)bz*100000 + (size_t)row*1000;
            else              o = g_Sx2 + (size_t)bz*100000 + (size_t)row*100;
            #pragma unroll
            for (int nt = 0; nt < 4; nt++) {
                int col = nBase + wn + nt*8 + 2*tig;
                float c0 = c[mt][nt][half*2], c1 = c[mt][nt][half*2 + 1];
                if (MODE==0) {
                    if (col < EEP) {
                        float v0 = (col     < 300) ? c0 : 0.f;
                        float v1 = (col + 1 < 300) ? c1 : 0.f;
                        *(float2*)(o + col) = make_float2(v0, v1);
                    }
                } else if (MODE==8) {
                    // odd row strides (21/441): float2 would be 4B-aligned -> scalar stores
                    if (col < N)     o[col]     = c0;
                    if (col + 1 < N) o[col + 1] = c1;
                } else {
                    if (col < N) {
                        if (col + 1 < N) *(float2*)(o + col) = make_float2(c0, c1);
                        else o[col] = c0;
                    }
                }
            }
        }
    }
}

// ---------------- K2b: words softmax + A.XV (scores precomputed) ----------
__global__ void __launch_bounds__(320, 4)
k_wattn2() {
    __shared__ float S[20*21];
    __shared__ float XVs[20*16];
    int s = blockIdx.x, h = blockIdx.y, tid = threadIdx.x;

    for (int idx = tid; idx < 400; idx += 320) {
        int t = idx / 20, u = idx - 20*t;
        S[t*21 + u] = g_Sw[(size_t)s*(HH*LL*LL) + (size_t)(h*20 + t)*20 + u] * INV_SCALE;
    }
    {
        int u = tid >> 4, v = tid & 15;
        XVs[tid] = g_XV[((size_t)s*LL + u)*RR + h*VV + v];
    }
    __syncthreads();

    if (tid < LL) {
        float* row = S + tid*21;
        float m = row[0];
        #pragma unroll
        for (int u = 1; u < LL; u++) m = fmaxf(m, row[u]);
        float ssum = 0.f;
        #pragma unroll
        for (int u = 0; u < LL; u++) { float e = __expf(row[u] - m); row[u] = e; ssum += e; }
        float inv = 1.0f / ssum;
        #pragma unroll
        for (int u = 0; u < LL; u++) row[u] *= inv;
    }
    __syncthreads();

    {
        int t = tid >> 4, v = tid & 15;
        float acc = 0.f;
        #pragma unroll
        for (int u = 0; u < LL; u++) acc = fmaf(S[t*21 + u], XVs[u*16 + v], acc);
        g_Rep[((size_t)s*LL + t)*RR + h*VV + v] = acc;
    }
}

// ---------------- ones-row projections (+ g_ones) ----------------
__global__ void k_ones(const float* __restrict__ Wq, const float* __restrict__ Wv) {
    int h = blockIdx.x, j = threadIdx.x;
    if (h == 0) g_ones[j] = 1.0f;
    float acc = 0.f;
    const float* w = Wq + (size_t)h*RR*RR + j;
    for (int r = 0; r < RR; r++) acc += w[r*RR];
    g_q1[h*RR + j] = acc;
    if (j < VV) {
        float a2 = 0.f;
        const float* wv = Wv + (size_t)h*RR*VV + j;
        for (int r = 0; r < RR; r++) a2 += wv[r*VV];
        g_v1[h*VV + j] = a2;
    }
}

// ---------------- K5: fused softmax + AV -> g_Val (direct STG) ----------
#define SC_VC   0
#define SC_VH   (SC_VC + LL*RR)             // 5120
#define SC_V1   (SC_VH + LL*RR)             // 10240
#define SC_S    (SC_V1 + RR)                // 10496
#define K5_SMEM_FLOATS (SC_S + TT*TT + 15)  // 12192 floats = 48768 B

__global__ void __launch_bounds__(256, 4)
k_fuse_av() {
    extern __shared__ float sm[];
    float* sVc  = sm + SC_VC;
    float* sVh  = sm + SC_VH;
    float* sV1  = sm + SC_V1;
    float* sS   = sm + SC_S;

    int bci = blockIdx.x;
    int i   = bci % HIS;
    int bc  = bci / HIS;
    int b   = bc / CDD;
    int c   = bc - b*CDD;
    int sc  = bc;
    int sh  = NSC + b*HIS + i;

    int tid = threadIdx.x;

    {
        const float4* gvc = (const float4*)(g_V + (size_t)sc*LL*RR);
        const float4* gvh = (const float4*)(g_V + (size_t)sh*LL*RR);
        float4* dVc = (float4*)sVc; float4* dVh = (float4*)sVh;
        for (int idx = tid; idx < LL*RR/4; idx += 256) { dVc[idx] = gvc[idx]; dVh[idx] = gvh[idx]; }
        if (tid < RR) sV1[tid] = g_v1[tid];
    }

    float* valOut = g_Val + (size_t)bci*TT*RR;

    for (int h = 0; h < HH; h++) {
        const float* scc = g_Scc + ((size_t)bc*HH + h)*441;
        const float* shh = g_Shh + ((size_t)(b*HIS + i)*HH + h)*441;
        const float* sx1 = g_Sx1 + ((size_t)(b*HH + h))*100*1000;
        const float* sx2 = g_Sx2 + ((size_t)(b*HH + h))*1000*100;

        __syncthreads();
        for (int p = tid; p < TT*TT; p += 256) {
            int q = p / TT, k = p - q*TT;
            float v;
            if (q < LL) {
                if (k < LL)       v = __ldg(&scc[q*21 + k]);
                else if (k == LL) v = __ldg(&scc[q*21 + 20]);
                else              v = __ldg(&sx1[(size_t)(c*20 + q)*1000 + i*20 + (k-LL-1)]);
            } else if (q == LL) {
                if (k < LL)       v = __ldg(&scc[20*21 + k]);
                else if (k == LL) v = __ldg(&scc[20*21 + 20]);
                else              v = __ldg(&shh[20*21 + (k-LL-1)]);
            } else {
                int t = q - LL - 1;
                if (k < LL)       v = __ldg(&sx2[(size_t)(i*20 + t)*100 + c*20 + k]);
                else if (k == LL) v = __ldg(&shh[t*21 + 20]);
                else              v = __ldg(&shh[t*21 + (k-LL-1)]);
            }
            sS[p] = v * INV_SCALE;
        }
        __syncthreads();

        if (tid < TT) {
            float* row = sS + tid*TT;
            float m = row[0];
            #pragma unroll
            for (int k = 1; k < TT; k++) m = fmaxf(m, row[k]);
            float ssum = 0.f;
            #pragma unroll
            for (int k = 0; k < TT; k++) { float e = __expf(row[k] - m); row[k] = e; ssum += e; }
            float inv = 1.0f / ssum;
            #pragma unroll
            for (int k = 0; k < TT; k++) row[k] *= inv;
        }
        __syncthreads();

        for (int p = tid; p < TT*VV; p += 256) {
            int q = p / VV, v = p - (p / VV)*VV;
            int col = h*VV + v;
            const float* arow = sS + q*TT;
            float acc = arow[LL] * sV1[col];
            #pragma unroll
            for (int k = 0; k < LL; k++) acc = fmaf(arow[k], sVc[k*RR + col], acc);
            #pragma unroll
            for (int k = 0; k < LL; k++) acc = fmaf(arow[LL+1+k], sVh[k*RR + col], acc);
            valOut[(size_t)q*RR + col] = acc;
        }
    }
}

// ---------------- K6: pooling ----------------
__global__ void __launch_bounds__(256, 4)
k_pool(const float* __restrict__ keyb, const float* __restrict__ query) {
    __shared__ float sPool[48];
    __shared__ float sW[48];

    int bci = blockIdx.x, tid = threadIdx.x;
    int warp = tid >> 5, lane = tid & 31;

    if (tid < TT) sPool[tid] = 0.f;
    __syncthreads();

    int j = tid;
    bool jact = (j < QQ);
    float qj = jact ? query[j] : 0.f;
    float kb = jact ? keyb[j]  : 0.f;
    const float* km = g_Kmat + (size_t)bci*TT*QQ;

    #pragma unroll
    for (int t = 0; t < TT; t++) {
        float v = jact ? qj * tanhf(km[t*QQ + j] + kb) : 0.f;
        #pragma unroll
        for (int o = 16; o; o >>= 1) v += __shfl_xor_sync(0xffffffffu, v, o);
        if (lane == 0 && warp < 7) atomicAdd(&sPool[t], v);
    }
    __syncthreads();

    if (tid == 0) {
        float m = sPool[0] * INV_SCALE;
        #pragma unroll
        for (int t = 1; t < TT; t++) m = fmaxf(m, sPool[t] * INV_SCALE);
        float ssum = 0.f;
        #pragma unroll
        for (int t = 0; t < TT; t++) { float e = __expf(sPool[t]*INV_SCALE - m); sW[t] = e; ssum += e; }
        float inv = 1.0f / ssum;
        #pragma unroll
        for (int t = 0; t < TT; t++) sW[t] *= inv;
    }
    __syncthreads();

    {
        int r = tid;
        const float* vb = g_Val + (size_t)bci*TT*RR + r;
        float a2 = 0.f;
        #pragma unroll
        for (int t = 0; t < TT; t++) a2 = fmaf(sW[t], vb[t*RR], a2);
        g_rep[(size_t)bci*RR + r] = a2;
    }
}

// ---------------- mean + ltr ----------------
__global__ void k_fv(const float* __restrict__ ltr_w, const float* __restrict__ ltr_b) {
    __shared__ float red[256];
    int bc = blockIdx.x;
    int r = threadIdx.x;
    float ssum = 0.f;
    for (int i = 0; i < HIS; i++) ssum += g_rep[(size_t)(bc*HIS + i)*RR + r];
    red[r] = (ssum * (1.0f/HIS)) * ltr_w[r];
    __syncthreads();
    for (int off = 128; off; off >>= 1) {
        if (r < off) red[r] += red[r + off];
        __syncthreads();
    }
    if (r == 0) g_score[bc] = red[0] + ltr_b[0];
}

// ---------------- log_softmax ----------------
__global__ void k_out(float* __restrict__ out) {
    int b = threadIdx.x;
    if (b < BB) {
        float s[CDD];
        float m = -1e30f;
        #pragma unroll
        for (int c = 0; c < CDD; c++) { s[c] = g_score[b*CDD + c]; m = fmaxf(m, s[c]); }
        float ssum = 0.f;
        #pragma unroll
        for (int c = 0; c < CDD; c++) ssum += expf(s[c] - m);
        float lse = logf(ssum);
        #pragma unroll
        for (int c = 0; c < CDD; c++) out[b*CDD + c] = s[c] - m - lse;
    }
}

// ---------------- launch ----------------
extern "C" void kernel_launch(void* const* d_in, const int* in_sizes, int n_in,
                              void* d_out, int out_size) {
    const int*   cand  = (const int*)  d_in[0];
    const int*   clk   = (const int*)  d_in[1];
    const float* emb   = (const float*)d_in[2];
    const float* Wq_w  = (const float*)d_in[3];
    const float* Wv_w  = (const float*)d_in[4];
    const float* Wq_i  = (const float*)d_in[5];
    const float* Wv_i  = (const float*)d_in[6];
    const float* keyW  = (const float*)d_in[7];
    const float* keyb  = (const float*)d_in[8];
    const float* query = (const float*)d_in[9];
    const float* ltr_w = (const float*)d_in[10];
    const float* ltr_b = (const float*)d_in[11];
    float* out = (float*)d_out;

    cudaFuncSetAttribute(k_fuse_av, cudaFuncAttributeMaxDynamicSharedMemorySize,
                         K5_SMEM_FLOATS * sizeof(float));

    k_gather<<<NS, 256>>>(cand, clk, emb);
    k_padW<<<HH, 256>>>(Wq_w);
    k_padWv<<<EEP, 256>>>(Wv_w);
    k_padWvi<<<RR, 256>>>(Wv_i);

    k_t128<0><<<dim3(3, 35, HH), 256>>>(nullptr);       // words Q (tf32, zero-padded to 320)
    k_t128<2><<<dim3(2, 35, 1), 256>>>(nullptr);        // words XV (tf32)
    k_t128<7><<<dim3(1, 3, NS), 256>>>(nullptr);        // words scores (tf32)
    k_wattn2<<<dim3(NS, HH), 320>>>();                  // softmax + A.XV

    k_t128<1><<<dim3(2, 35, HH), 256>>>(Wq_i);          // itrs Q (tf32)
    k_t128<3><<<dim3(2, 35, 1), 256>>>(nullptr);        // itrs V (tf32)
    k_ones<<<HH, 256>>>(Wq_i, Wv_i);

    k_t128<8><<<dim3(1, 3, NS), 256>>>(nullptr);        // diag scores (tf32, incl ones col)
    k_t128<4><<<dim3(8, 1, BB*HH), 256>>>(nullptr);     // Sx1 (tf32)
    k_t128<5><<<dim3(1, 8, BB*HH), 256>>>(nullptr);     // Sx2 (tf32)

    k_fuse_av<<<NBCI, 256, K5_SMEM_FLOATS * sizeof(float)>>>();
    k_t128<6><<<dim3(2, 321, 1), 256>>>(keyW);          // Kmat (tf32)
    k_pool<<<NBCI, 256>>>(keyb, query);

    k_fv<<<NSC, 256>>>(ltr_w, ltr_b);
    k_out<<<1, 32>>>(out);
}

// round 11
// speedup vs baseline: 8.7992x; 1.0741x over previous
#include <cuda_runtime.h>
#include <math.h>
#include <stdint.h>

#define BB   4
#define CDD  5
#define HIS  50
#define LL   20
#define TT   41
#define EE   300
#define EEP  320
#define HH   16
#define VV   16
#define RR   256
#define QQ   200
#define NSC  (BB*CDD)        // 20
#define NSH  (BB*HIS)        // 200
#define NS   (NSC+NSH)       // 220
#define NTOK (NS*LL)         // 4400
#define NBCI (BB*CDD*HIS)    // 1000
#define MVAL (NBCI*TT)       // 41000
#define NQW  4800            // 16 heads x 300 cols

#define INV_SCALE 0.057735026918962584f   // 1/sqrt(300)

// ---------------- device scratch ----------------
__device__ float g_Xp[NTOK*EEP];
__device__ float g_Wqall[EEP*NQW];             // [320][4800] all-head words Wq (k>=300 rows zero)
__device__ float g_Wvp[EEP*RR];
__device__ float g_Wvp2[RR*RR];
__device__ float g_Qw[(size_t)NS*HH*LL*EEP];   // [s][h][t][320]; cols 300..319 stay zero (static init)
__device__ float g_Sw[(size_t)NS*HH*LL*LL];    // words scores [s][h*20+t][20]
__device__ float g_XV[NTOK*RR];
__device__ float g_Rep[NS*LL*RR];
__device__ float g_Q[(size_t)NS*HH*LL*RR];
__device__ float g_V[NS*LL*RR];
__device__ float g_q1[HH*RR];
__device__ float g_v1[RR];
__device__ float g_ones[RR];
__device__ float g_Scc[NSC*HH*21*21];
__device__ float g_Shh[NSH*HH*21*21];
__device__ float g_Sx1[(size_t)BB*HH*100*1000];
__device__ float g_Sx2[(size_t)BB*HH*1000*100];
__device__ float g_Val[(size_t)MVAL*RR];
__device__ float g_Kmat[(size_t)MVAL*QQ];
__device__ float g_rep[NBCI*RR];
__device__ float g_score[NSC];

// ---------------- K0: merged prep (gather + weight repacks + ones) ----------
// grid: [0,220) gather | [220,236) Wqall | [236,252) Wvp | [252,268) Wvp2 | [268,284) ones
__global__ void k_prep(const int* __restrict__ cand, const int* __restrict__ clk,
                       const float* __restrict__ emb,
                       const float* __restrict__ Wq_w, const float* __restrict__ Wv_w,
                       const float* __restrict__ Wq_i, const float* __restrict__ Wv_i) {
    int blk = blockIdx.x, tid = threadIdx.x;
    if (blk < NS) {
        const int* tok = (blk < NSC) ? (cand + blk*LL) : (clk + (blk-NSC)*LL);
        for (int idx = tid; idx < LL*EEP; idx += 256) {
            int t = idx / EEP, d = idx - t*EEP;
            g_Xp[(blk*LL + t)*EEP + d] = (d < EE) ? emb[(size_t)tok[t]*EE + d] : 0.f;
        }
    } else if (blk < NS + 16) {
        int h = blk - NS;
        for (int idx = tid; idx < EEP*EE; idx += 256) {
            int k = idx / EE, j = idx - k*EE;
            g_Wqall[(size_t)k*NQW + h*EE + j] =
                (k < EE) ? Wq_w[(size_t)h*EE*EE + (size_t)k*EE + j] : 0.f;
        }
    } else if (blk < NS + 32) {
        int part = blk - NS - 16;
        for (int q = 0; q < EEP*RR/(16*256); q++) {
            int idx = part*(EEP*RR/16) + q*256 + tid;
            int k = idx >> 8, col = idx & 255;
            int h = col >> 4, v = col & 15;
            g_Wvp[idx] = (k < EE) ? Wv_w[((size_t)h*EE + k)*VV + v] : 0.f;
        }
    } else if (blk < NS + 48) {
        int part = blk - NS - 32;
        for (int q = 0; q < RR*RR/(16*256); q++) {
            int idx = part*(RR*RR/16) + q*256 + tid;
            int r = idx >> 8, col = idx & 255;
            int h = col >> 4, v = col & 15;
            g_Wvp2[idx] = Wv_i[((size_t)h*RR + r)*VV + v];
        }
    } else {
        int h = blk - NS - 48, j = tid;
        if (h == 0) g_ones[j] = 1.0f;
        float acc = 0.f;
        const float* w = Wq_i + (size_t)h*RR*RR + j;
        for (int r = 0; r < RR; r++) acc += w[r*RR];
        g_q1[h*RR + j] = acc;
        if (j < VV) {
            float a2 = 0.f;
            const float* wv = Wv_i + (size_t)h*RR*VV + j;
            for (int r = 0; r < RR; r++) a2 += wv[r*VV];
            g_v1[h*VV + j] = a2;
        }
    }
}

// ---------------- tf32 helpers ----------------
__device__ __forceinline__ uint32_t f2tf32(float x) {
    uint32_t u;
    asm("cvt.rna.tf32.f32 %0, %1;" : "=r"(u) : "f"(x));
    return u;
}
__device__ __forceinline__ void mma_tf32(float c[4], const uint32_t a[4], const uint32_t b[2]) {
    asm volatile(
        "mma.sync.aligned.m16n8k8.row.col.f32.tf32.tf32.f32 "
        "{%0,%1,%2,%3}, {%4,%5,%6,%7}, {%8,%9}, {%0,%1,%2,%3};"
        : "+f"(c[0]), "+f"(c[1]), "+f"(c[2]), "+f"(c[3])
        : "r"(a[0]), "r"(a[1]), "r"(a[2]), "r"(a[3]), "r"(b[0]), "r"(b[1]));
}

// ---------------- tf32 tensor-core GEMM ----------------
// MODE 0: Qw   = Xp  @ Wqall    M=4400  N=4800 K=320   grid(38,35,1)  (col -> head h=col/300)
// MODE 1: Q    = Rep @ Wq_i[h]  M=4400  N=256  K=256   grid(2,35,16)
// MODE 2: XV   = Xp  @ Wvp      M=4400  N=256  K=320   grid(2,35,1)
// MODE 3: V    = Rep @ Wvp2     M=4400  N=256  K=256   grid(2,35,1)
// MODE 4: Sx1  = Qc  @ RepH^T   M=100   N=1000 K=256   grid(8,1,64)
// MODE 5: Sx2  = Qh  @ RepC^T   M=1000  N=100  K=256   grid(1,8,64)
// MODE 6: Kmat = Val @ keyW     M=41000 N=200  K=256   grid(2,321,1)
// MODE 7: Sw[s]= Qw[s] @ X[s]^T M=320   N=20   K=320   grid(1,3,220)  NARROW BN=32
// MODE 8: diag[s]               M=336   N=21   K=256   grid(1,3,220)  NARROW, scalar stores
#define BM 128
#define BN 128
#define BK 16
#define TSP 136

template<int MODE>
__global__ void __launch_bounds__(256, 2)
k_t128(const float* __restrict__ Bglob) {
    constexpr int K   = (MODE==0 || MODE==2 || MODE==7) ? EEP : RR;
    constexpr int M   = (MODE==4) ? 100 : (MODE==5 ? 1000 : (MODE==6 ? MVAL :
                        (MODE==7 ? 320 : (MODE==8 ? 336 : NTOK))));
    constexpr int N   = (MODE==0) ? NQW : (MODE==4 ? 1000 : (MODE==5 ? 100 :
                        (MODE==6 ? QQ : (MODE==7 ? 20 : (MODE==8 ? 21 : RR)))));
    constexpr bool BT = (MODE==4 || MODE==5 || MODE==7 || MODE==8);
    constexpr bool NARROW = (MODE==7 || MODE==8);
    constexpr int LDB = (MODE==0) ? NQW : (MODE==6 ? QQ : RR);
    constexpr int NCH = K / BK;
    constexpr int NMT = NARROW ? 1 : 4;

    __shared__ float As[2][BK*TSP];
    __shared__ float Bs[2][BK*TSP];

    const int tid = threadIdx.x;
    const int bz = blockIdx.z;
    const int nBase = blockIdx.x * BN;
    const int mBase = blockIdx.y * BM;
    int b = 0, h = 0;
    if (MODE==1) h = bz;
    if (MODE==4 || MODE==5) { b = bz >> 4; h = bz & 15; }

    // ---- loaders ----
    const int ar  = tid >> 1;
    const int akq = (tid & 1) * 2;
    const float* Arow = nullptr;
    {
        int am = mBase + ar;
        if (am < M) {
            if (MODE==0 || MODE==2) Arow = g_Xp + (size_t)am*EEP;
            else if (MODE==1 || MODE==3) Arow = g_Rep + (size_t)am*RR;
            else if (MODE==6) Arow = g_Val + (size_t)am*RR;
            else if (MODE==7) Arow = g_Qw + (size_t)(bz*320 + am)*EEP;
            else if (MODE==8) {
                int h8 = am / 21, t8 = am - 21*h8;
                Arow = (t8 < 20) ? g_Q + (((size_t)bz*HH + h8)*LL + t8)*RR
                                 : g_q1 + (size_t)h8*RR;
            }
            else if (MODE==4) { int c = am/20, t = am - 20*c;
                Arow = g_Q + (size_t)(((b*CDD + c)*HH + h)*LL + t)*RR; }
            else { int i = am/20, u = am - 20*i;
                Arow = g_Q + (size_t)(((NSC + b*HIS + i)*HH + h)*LL + u)*RR; }
        }
    }
    const float* Brow = nullptr;
    const float* Bb = nullptr;
    int bkr = 0, bn1 = 0; bool bok1 = false, bok2 = false;
    if (BT) {
        int bn = nBase + ar;
        if (bn < N) {
            if (MODE==4)      Brow = g_Rep + ((size_t)(NSC + b*HIS)*LL + bn)*RR;
            else if (MODE==5) Brow = g_Rep + ((size_t)(b*CDD)*LL + bn)*RR;
            else if (MODE==7) Brow = g_Xp + ((size_t)bz*LL + bn)*EEP;
            else              Brow = (bn < 20) ? g_Rep + ((size_t)bz*LL + bn)*RR : g_ones;
        }
    } else {
        if (MODE==0) Bb = g_Wqall;
        else if (MODE==1) Bb = Bglob + (size_t)h*RR*RR;
        else if (MODE==2) Bb = g_Wvp;
        else if (MODE==3) Bb = g_Wvp2;
        else Bb = Bglob;   // MODE 6: keyW
        bkr = tid >> 4; bn1 = (tid & 15) * 4;
        bok1 = (nBase + bn1) < N;
        bok2 = (nBase + bn1 + 64) < N;
    }

    float4 pa0, pa1, pb0, pb1;
    const float4 fz = make_float4(0.f, 0.f, 0.f, 0.f);

    auto loadChunk = [&](int kc) {
        pa0 = fz; pa1 = fz; pb0 = fz; pb1 = fz;
        if (Arow) {
            pa0 = *(const float4*)(Arow + kc + 4*akq);
            pa1 = *(const float4*)(Arow + kc + 4*akq + 4);
        }
        if (BT) {
            if (Brow) {
                pb0 = *(const float4*)(Brow + kc + 4*akq);
                pb1 = *(const float4*)(Brow + kc + 4*akq + 4);
            }
        } else {
            if (bok1) pb0 = *(const float4*)(Bb + (size_t)(kc + bkr)*LDB + nBase + bn1);
            if (bok2) pb1 = *(const float4*)(Bb + (size_t)(kc + bkr)*LDB + nBase + bn1 + 64);
        }
    };
    auto storeChunk = [&](int buf) {
        float* dA = As[buf]; float* dB = Bs[buf];
        dA[(4*akq+0)*TSP + ar] = __uint_as_float(f2tf32(pa0.x));
        dA[(4*akq+1)*TSP + ar] = __uint_as_float(f2tf32(pa0.y));
        dA[(4*akq+2)*TSP + ar] = __uint_as_float(f2tf32(pa0.z));
        dA[(4*akq+3)*TSP + ar] = __uint_as_float(f2tf32(pa0.w));
        dA[(4*akq+4)*TSP + ar] = __uint_as_float(f2tf32(pa1.x));
        dA[(4*akq+5)*TSP + ar] = __uint_as_float(f2tf32(pa1.y));
        dA[(4*akq+6)*TSP + ar] = __uint_as_float(f2tf32(pa1.z));
        dA[(4*akq+7)*TSP + ar] = __uint_as_float(f2tf32(pa1.w));
        if (BT) {
            dB[(4*akq+0)*TSP + ar] = __uint_as_float(f2tf32(pb0.x));
            dB[(4*akq+1)*TSP + ar] = __uint_as_float(f2tf32(pb0.y));
            dB[(4*akq+2)*TSP + ar] = __uint_as_float(f2tf32(pb0.z));
            dB[(4*akq+3)*TSP + ar] = __uint_as_float(f2tf32(pb0.w));
            dB[(4*akq+4)*TSP + ar] = __uint_as_float(f2tf32(pb1.x));
            dB[(4*akq+5)*TSP + ar] = __uint_as_float(f2tf32(pb1.y));
            dB[(4*akq+6)*TSP + ar] = __uint_as_float(f2tf32(pb1.z));
            dB[(4*akq+7)*TSP + ar] = __uint_as_float(f2tf32(pb1.w));
        } else {
            float4 q0 = make_float4(__uint_as_float(f2tf32(pb0.x)), __uint_as_float(f2tf32(pb0.y)),
                                    __uint_as_float(f2tf32(pb0.z)), __uint_as_float(f2tf32(pb0.w)));
            float4 q1 = make_float4(__uint_as_float(f2tf32(pb1.x)), __uint_as_float(f2tf32(pb1.y)),
                                    __uint_as_float(f2tf32(pb1.z)), __uint_as_float(f2tf32(pb1.w)));
            *(float4*)(dB + bkr*TSP + bn1) = q0;
            *(float4*)(dB + bkr*TSP + bn1 + 64) = q1;
        }
    };

    const int warp = tid >> 5, lane = tid & 31;
    const int wm = NARROW ? warp*16 : (warp >> 2)*64;
    const int wn = NARROW ? 0 : (warp & 3)*32;
    const int g = lane >> 2, tig = lane & 3;

    float c[NMT][4][4];
    #pragma unroll
    for (int mt = 0; mt < NMT; mt++)
        #pragma unroll
        for (int nt = 0; nt < 4; nt++)
            #pragma unroll
            for (int e = 0; e < 4; e++) c[mt][nt][e] = 0.f;

    loadChunk(0); storeChunk(0); __syncthreads();

    for (int ch = 0; ch < NCH; ch++) {
        int cur = ch & 1;
        if (ch + 1 < NCH) loadChunk((ch + 1) * BK);
        const float* pAs = As[cur];
        const float* pBs = Bs[cur];
        #pragma unroll
        for (int ks = 0; ks < 2; ks++) {
            const int k0 = ks * 8;
            uint32_t af[NMT][4], bf[4][2];
            #pragma unroll
            for (int mt = 0; mt < NMT; mt++) {
                const float* p0 = pAs + (k0 + tig)*TSP + wm + mt*16 + g;
                const float* p1 = pAs + (k0 + tig + 4)*TSP + wm + mt*16 + g;
                af[mt][0] = __float_as_uint(p0[0]);
                af[mt][1] = __float_as_uint(p0[8]);
                af[mt][2] = __float_as_uint(p1[0]);
                af[mt][3] = __float_as_uint(p1[8]);
            }
            #pragma unroll
            for (int nt = 0; nt < 4; nt++) {
                bf[nt][0] = __float_as_uint(pBs[(k0 + tig)*TSP + wn + nt*8 + g]);
                bf[nt][1] = __float_as_uint(pBs[(k0 + tig + 4)*TSP + wn + nt*8 + g]);
            }
            #pragma unroll
            for (int mt = 0; mt < NMT; mt++)
                #pragma unroll
                for (int nt = 0; nt < 4; nt++)
                    mma_tf32(c[mt][nt], af[mt], bf[nt]);
        }
        if (ch + 1 < NCH) { storeChunk(cur ^ 1); __syncthreads(); }
    }

    // ---- epilogue ----
    #pragma unroll
    for (int mt = 0; mt < NMT; mt++) {
        #pragma unroll
        for (int half = 0; half < 2; half++) {
            int row = mBase + wm + mt*16 + g + half*8;
            if (row >= M) continue;
            if (MODE==0) {
                int s = row/20, t = row - 20*s;
                float* obase = g_Qw + ((size_t)(s*HH))*LL*EEP + (size_t)t*EEP;  // + h*LL*EEP + j
                #pragma unroll
                for (int nt = 0; nt < 4; nt++) {
                    int col = nBase + wn + nt*8 + 2*tig;
                    if (col < NQW) {
                        int hh = col / 300;
                        int jj = col - 300*hh;   // even; jj+1 <= 299 same head
                        *(float2*)(obase + (size_t)hh*LL*EEP + jj) =
                            make_float2(c[mt][nt][half*2], c[mt][nt][half*2 + 1]);
                    }
                }
                continue;
            }
            float* o;
            if (MODE==1) { int s = row/20, t = row - 20*s;
                o = g_Q + ((size_t)(s*HH + h)*LL + t)*RR; }
            else if (MODE==2) o = g_XV + (size_t)row*RR;
            else if (MODE==3) o = g_V + (size_t)row*RR;
            else if (MODE==6) o = g_Kmat + (size_t)row*QQ;
            else if (MODE==7) o = g_Sw + (size_t)bz*(HH*LL*LL) + (size_t)row*20;
            else if (MODE==8) {
                int h8 = row/21, t8 = row - 21*h8;
                float* base = (bz < NSC) ? g_Scc + ((size_t)bz*HH + h8)*441
                                         : g_Shh + ((size_t)(bz-NSC)*HH + h8)*441;
                o = base + t8*21;
            }
            else if (MODE==4) o = g_Sx1 + (size_t)bz*100000 + (size_t)row*1000;
            else              o = g_Sx2 + (size_t)bz*100000 + (size_t)row*100;
            #pragma unroll
            for (int nt = 0; nt < 4; nt++) {
                int col = nBase + wn + nt*8 + 2*tig;
                float c0 = c[mt][nt][half*2], c1 = c[mt][nt][half*2 + 1];
                if (MODE==8) {
                    // odd row strides (21/441): scalar stores only
                    if (col < N)     o[col]     = c0;
                    if (col + 1 < N) o[col + 1] = c1;
                } else {
                    if (col < N) {
                        if (col + 1 < N) *(float2*)(o + col) = make_float2(c0, c1);
                        else o[col] = c0;
                    }
                }
            }
        }
    }
}

// ---------------- K2b: words softmax + A.XV (scores precomputed) ----------
__global__ void __launch_bounds__(320, 4)
k_wattn2() {
    __shared__ float S[20*21];
    __shared__ float XVs[20*16];
    int s = blockIdx.x, h = blockIdx.y, tid = threadIdx.x;

    for (int idx = tid; idx < 400; idx += 320) {
        int t = idx / 20, u = idx - 20*t;
        S[t*21 + u] = g_Sw[(size_t)s*(HH*LL*LL) + (size_t)(h*20 + t)*20 + u] * INV_SCALE;
    }
    {
        int u = tid >> 4, v = tid & 15;
        XVs[tid] = g_XV[((size_t)s*LL + u)*RR + h*VV + v];
    }
    __syncthreads();

    if (tid < LL) {
        float* row = S + tid*21;
        float m = row[0];
        #pragma unroll
        for (int u = 1; u < LL; u++) m = fmaxf(m, row[u]);
        float ssum = 0.f;
        #pragma unroll
        for (int u = 0; u < LL; u++) { float e = __expf(row[u] - m); row[u] = e; ssum += e; }
        float inv = 1.0f / ssum;
        #pragma unroll
        for (int u = 0; u < LL; u++) row[u] *= inv;
    }
    __syncthreads();

    {
        int t = tid >> 4, v = tid & 15;
        float acc = 0.f;
        #pragma unroll
        for (int u = 0; u < LL; u++) acc = fmaf(S[t*21 + u], XVs[u*16 + v], acc);
        g_Rep[((size_t)s*LL + t)*RR + h*VV + v] = acc;
    }
}

// ---------------- K5: fused softmax + AV -> g_Val ----------
#define SC_VC   0
#define SC_VH   (SC_VC + LL*RR)
#define SC_V1   (SC_VH + LL*RR)
#define SC_S    (SC_V1 + RR)
#define K5_SMEM_FLOATS (SC_S + TT*TT + 15)  // 12192 floats = 48768 B

__global__ void __launch_bounds__(256, 4)
k_fuse_av() {
    extern __shared__ float sm[];
    float* sVc  = sm + SC_VC;
    float* sVh  = sm + SC_VH;
    float* sV1  = sm + SC_V1;
    float* sS   = sm + SC_S;

    int bci = blockIdx.x;
    int i   = bci % HIS;
    int bc  = bci / HIS;
    int b   = bc / CDD;
    int c   = bc - b*CDD;
    int sc  = bc;
    int sh  = NSC + b*HIS + i;

    int tid = threadIdx.x;
    int wrp = tid >> 5, ln = tid & 31;

    {
        const float4* gvc = (const float4*)(g_V + (size_t)sc*LL*RR);
        const float4* gvh = (const float4*)(g_V + (size_t)sh*LL*RR);
        float4* dVc = (float4*)sVc; float4* dVh = (float4*)sVh;
        for (int idx = tid; idx < LL*RR/4; idx += 256) { dVc[idx] = gvc[idx]; dVh[idx] = gvh[idx]; }
        if (tid < RR) sV1[tid] = g_v1[tid];
    }

    float* valOut = g_Val + (size_t)bci*TT*RR;

    for (int h = 0; h < HH; h++) {
        const float* scc = g_Scc + ((size_t)bc*HH + h)*441;
        const float* shh = g_Shh + ((size_t)(b*HIS + i)*HH + h)*441;
        const float* sx1 = g_Sx1 + ((size_t)(b*HH + h))*100*1000;
        const float* sx2 = g_Sx2 + ((size_t)(b*HH + h))*1000*100;

        __syncthreads();
        for (int p = tid; p < TT*TT; p += 256) {
            int q = p / TT, k = p - q*TT;
            float v;
            if (q < LL) {
                if (k < LL)       v = __ldg(&scc[q*21 + k]);
                else if (k == LL) v = __ldg(&scc[q*21 + 20]);
                else              v = __ldg(&sx1[(size_t)(c*20 + q)*1000 + i*20 + (k-LL-1)]);
            } else if (q == LL) {
                if (k < LL)       v = __ldg(&scc[20*21 + k]);
                else if (k == LL) v = __ldg(&scc[20*21 + 20]);
                else              v = __ldg(&shh[20*21 + (k-LL-1)]);
            } else {
                int t = q - LL - 1;
                if (k < LL)       v = __ldg(&sx2[(size_t)(i*20 + t)*100 + c*20 + k]);
                else if (k == LL) v = __ldg(&shh[t*21 + 20]);
                else              v = __ldg(&shh[t*21 + (k-LL-1)]);
            }
            sS[p] = v * INV_SCALE;
        }
        __syncthreads();

        // warp-parallel softmax: warp per row, lanes over cols
        for (int q = wrp; q < TT; q += 8) {
            float* row = sS + q*TT;
            float v0 = row[ln];                              // ln < 32 <= 41
            float v1 = (ln + 32 < TT) ? row[ln + 32] : -1e30f;
            float m = fmaxf(v0, v1);
            #pragma unroll
            for (int o = 16; o; o >>= 1) m = fmaxf(m, __shfl_xor_sync(0xffffffffu, m, o));
            float e0 = __expf(v0 - m);
            float e1 = (ln + 32 < TT) ? __expf(v1 - m) : 0.f;
            float ss = e0 + e1;
            #pragma unroll
            for (int o = 16; o; o >>= 1) ss += __shfl_xor_sync(0xffffffffu, ss, o);
            float inv = 1.0f / ss;
            row[ln] = e0 * inv;
            if (ln + 32 < TT) row[ln + 32] = e1 * inv;
        }
        __syncthreads();

        for (int p = tid; p < TT*VV; p += 256) {
            int q = p / VV, v = p - (p / VV)*VV;
            int col = h*VV + v;
            const float* arow = sS + q*TT;
            float acc = arow[LL] * sV1[col];
            #pragma unroll
            for (int k = 0; k < LL; k++) acc = fmaf(arow[k], sVc[k*RR + col], acc);
            #pragma unroll
            for (int k = 0; k < LL; k++) acc = fmaf(arow[LL+1+k], sVh[k*RR + col], acc);
            valOut[(size_t)q*RR + col] = acc;
        }
    }
}

// ---------------- K6: pooling ----------------
__global__ void __launch_bounds__(256, 4)
k_pool(const float* __restrict__ keyb, const float* __restrict__ query) {
    __shared__ float sPool[48];
    __shared__ float sW[48];

    int bci = blockIdx.x, tid = threadIdx.x;
    int warp = tid >> 5, lane = tid & 31;

    if (tid < TT) sPool[tid] = 0.f;
    __syncthreads();

    int j = tid;
    bool jact = (j < QQ);
    float qj = jact ? query[j] : 0.f;
    float kb = jact ? keyb[j]  : 0.f;
    const float* km = g_Kmat + (size_t)bci*TT*QQ;

    #pragma unroll
    for (int t = 0; t < TT; t++) {
        float v = jact ? qj * tanhf(km[t*QQ + j] + kb) : 0.f;
        #pragma unroll
        for (int o = 16; o; o >>= 1) v += __shfl_xor_sync(0xffffffffu, v, o);
        if (lane == 0 && warp < 7) atomicAdd(&sPool[t], v);
    }
    __syncthreads();

    if (tid == 0) {
        float m = sPool[0] * INV_SCALE;
        #pragma unroll
        for (int t = 1; t < TT; t++) m = fmaxf(m, sPool[t] * INV_SCALE);
        float ssum = 0.f;
        #pragma unroll
        for (int t = 0; t < TT; t++) { float e = __expf(sPool[t]*INV_SCALE - m); sW[t] = e; ssum += e; }
        float inv = 1.0f / ssum;
        #pragma unroll
        for (int t = 0; t < TT; t++) sW[t] *= inv;
    }
    __syncthreads();

    {
        int r = tid;
        const float* vb = g_Val + (size_t)bci*TT*RR + r;
        float a2 = 0.f;
        #pragma unroll
        for (int t = 0; t < TT; t++) a2 = fmaf(sW[t], vb[t*RR], a2);
        g_rep[(size_t)bci*RR + r] = a2;
    }
}

// ---------------- mean + ltr ----------------
__global__ void k_fv(const float* __restrict__ ltr_w, const float* __restrict__ ltr_b) {
    __shared__ float red[256];
    int bc = blockIdx.x;
    int r = threadIdx.x;
    float ssum = 0.f;
    for (int i = 0; i < HIS; i++) ssum += g_rep[(size_t)(bc*HIS + i)*RR + r];
    red[r] = (ssum * (1.0f/HIS)) * ltr_w[r];
    __syncthreads();
    for (int off = 128; off; off >>= 1) {
        if (r < off) red[r] += red[r + off];
        __syncthreads();
    }
    if (r == 0) g_score[bc] = red[0] + ltr_b[0];
}

// ---------------- log_softmax ----------------
__global__ void k_out(float* __restrict__ out) {
    int b = threadIdx.x;
    if (b < BB) {
        float s[CDD];
        float m = -1e30f;
        #pragma unroll
        for (int c = 0; c < CDD; c++) { s[c] = g_score[b*CDD + c]; m = fmaxf(m, s[c]); }
        float ssum = 0.f;
        #pragma unroll
        for (int c = 0; c < CDD; c++) ssum += expf(s[c] - m);
        float lse = logf(ssum);
        #pragma unroll
        for (int c = 0; c < CDD; c++) out[b*CDD + c] = s[c] - m - lse;
    }
}

// ---------------- launch ----------------
extern "C" void kernel_launch(void* const* d_in, const int* in_sizes, int n_in,
                              void* d_out, int out_size) {
    const int*   cand  = (const int*)  d_in[0];
    const int*   clk   = (const int*)  d_in[1];
    const float* emb   = (const float*)d_in[2];
    const float* Wq_w  = (const float*)d_in[3];
    const float* Wv_w  = (const float*)d_in[4];
    const float* Wq_i  = (const float*)d_in[5];
    const float* Wv_i  = (const float*)d_in[6];
    const float* keyW  = (const float*)d_in[7];
    const float* keyb  = (const float*)d_in[8];
    const float* query = (const float*)d_in[9];
    const float* ltr_w = (const float*)d_in[10];
    const float* ltr_b = (const float*)d_in[11];
    float* out = (float*)d_out;

    cudaFuncSetAttribute(k_fuse_av, cudaFuncAttributeMaxDynamicSharedMemorySize,
                         K5_SMEM_FLOATS * sizeof(float));

    k_prep<<<NS + 64, 256>>>(cand, clk, emb, Wq_w, Wv_w, Wq_i, Wv_i);

    k_t128<0><<<dim3(38, 35, 1), 256>>>(nullptr);       // words Q, all heads (tf32)
    k_t128<2><<<dim3(2, 35, 1), 256>>>(nullptr);        // words XV (tf32)
    k_t128<7><<<dim3(1, 3, NS), 256>>>(nullptr);        // words scores (tf32, narrow)
    k_wattn2<<<dim3(NS, HH), 320>>>();                  // softmax + A.XV

    k_t128<1><<<dim3(2, 35, HH), 256>>>(Wq_i);          // itrs Q (tf32)
    k_t128<3><<<dim3(2, 35, 1), 256>>>(nullptr);        // itrs V (tf32)

    k_t128<8><<<dim3(1, 3, NS), 256>>>(nullptr);        // diag scores (tf32, narrow)
    k_t128<4><<<dim3(8, 1, BB*HH), 256>>>(nullptr);     // Sx1 (tf32)
    k_t128<5><<<dim3(1, 8, BB*HH), 256>>>(nullptr);     // Sx2 (tf32)

    k_fuse_av<<<NBCI, 256, K5_SMEM_FLOATS * sizeof(float)>>>();
    k_t128<6><<<dim3(2, 321, 1), 256>>>(keyW);          // Kmat (tf32)
    k_pool<<<NBCI, 256>>>(keyb, query);

    k_fv<<<NSC, 256>>>(ltr_w, ltr_b);
    k_out<<<1, 32>>>(out);
}

// round 12
// speedup vs baseline: 9.1322x; 1.0378x over previous
#include <cuda_runtime.h>
#include <cuda_fp16.h>
#include <math.h>
#include <stdint.h>

#define BB   4
#define CDD  5
#define HIS  50
#define LL   20
#define TT   41
#define EE   300
#define EEP  320
#define HH   16
#define VV   16
#define RR   256
#define QQ   200
#define NSC  (BB*CDD)        // 20
#define NSH  (BB*HIS)        // 200
#define NS   (NSC+NSH)       // 220
#define NTOK (NS*LL)         // 4400
#define NBCI (BB*CDD*HIS)    // 1000
#define MVAL (NBCI*TT)       // 41000
#define NQW  4800            // 16 heads x 300 cols

#define INV_SCALE 0.057735026918962584f   // 1/sqrt(300)

// ---------------- device scratch ----------------
__device__ float  g_Xp[NTOK*EEP];
__device__ float  g_Wqall[EEP*NQW];
__device__ float  g_Wvp[EEP*RR];
__device__ float  g_Wvp2[RR*RR];
__device__ __half g_Qw[(size_t)NS*HH*LL*EEP];  // fp16; cols 300..319 stay zero (static init)
__device__ float  g_Sw[(size_t)NS*HH*LL*LL];
__device__ float  g_XV[NTOK*RR];
__device__ float  g_Rep[NS*LL*RR];
__device__ __half g_Q[(size_t)NS*HH*LL*RR];    // fp16
__device__ float  g_V[NS*LL*RR];
__device__ __half g_q1h[HH*RR];                // fp16
__device__ float  g_v1[RR];
__device__ float  g_ones[RR];
__device__ float  g_Scc[NSC*HH*21*21];
__device__ float  g_Shh[NSH*HH*21*21];
__device__ float  g_Sx1[(size_t)BB*HH*100*1000];
__device__ float  g_Sx2[(size_t)BB*HH*1000*100];
__device__ __half g_Val[(size_t)MVAL*RR];      // fp16
__device__ __half g_Kmat[(size_t)MVAL*QQ];     // fp16
__device__ float  g_rep[NBCI*RR];
__device__ float  g_score[NSC];

// ---------------- K0: merged prep ----------
__global__ void k_prep(const int* __restrict__ cand, const int* __restrict__ clk,
                       const float* __restrict__ emb,
                       const float* __restrict__ Wq_w, const float* __restrict__ Wv_w,
                       const float* __restrict__ Wq_i, const float* __restrict__ Wv_i) {
    int blk = blockIdx.x, tid = threadIdx.x;
    if (blk < NS) {
        const int* tok = (blk < NSC) ? (cand + blk*LL) : (clk + (blk-NSC)*LL);
        for (int idx = tid; idx < LL*EEP; idx += 256) {
            int t = idx / EEP, d = idx - t*EEP;
            g_Xp[(blk*LL + t)*EEP + d] = (d < EE) ? emb[(size_t)tok[t]*EE + d] : 0.f;
        }
    } else if (blk < NS + 16) {
        int h = blk - NS;
        for (int idx = tid; idx < EEP*EE; idx += 256) {
            int k = idx / EE, j = idx - k*EE;
            g_Wqall[(size_t)k*NQW + h*EE + j] =
                (k < EE) ? Wq_w[(size_t)h*EE*EE + (size_t)k*EE + j] : 0.f;
        }
    } else if (blk < NS + 32) {
        int part = blk - NS - 16;
        for (int q = 0; q < EEP*RR/(16*256); q++) {
            int idx = part*(EEP*RR/16) + q*256 + tid;
            int k = idx >> 8, col = idx & 255;
            int h = col >> 4, v = col & 15;
            g_Wvp[idx] = (k < EE) ? Wv_w[((size_t)h*EE + k)*VV + v] : 0.f;
        }
    } else if (blk < NS + 48) {
        int part = blk - NS - 32;
        for (int q = 0; q < RR*RR/(16*256); q++) {
            int idx = part*(RR*RR/16) + q*256 + tid;
            int r = idx >> 8, col = idx & 255;
            int h = col >> 4, v = col & 15;
            g_Wvp2[idx] = Wv_i[((size_t)h*RR + r)*VV + v];
        }
    } else {
        int h = blk - NS - 48, j = tid;
        if (h == 0) g_ones[j] = 1.0f;
        float acc = 0.f;
        const float* w = Wq_i + (size_t)h*RR*RR + j;
        for (int r = 0; r < RR; r++) acc += w[r*RR];
        g_q1h[h*RR + j] = __float2half(acc);
        if (j < VV) {
            float a2 = 0.f;
            const float* wv = Wv_i + (size_t)h*RR*VV + j;
            for (int r = 0; r < RR; r++) a2 += wv[r*VV];
            g_v1[j] = 0.f;   // placeholder; real value set below (avoid race: each h writes own col)
        }
    }
}
// v1 needs heads concat: separate tiny kernel (16x16 entries)
__global__ void k_v1(const float* __restrict__ Wv_i) {
    int h = threadIdx.x >> 4, v = threadIdx.x & 15;
    float a2 = 0.f;
    const float* wv = Wv_i + (size_t)h*RR*VV + v;
    for (int r = 0; r < RR; r++) a2 += wv[r*VV];
    g_v1[h*VV + v] = a2;
}

// ---------------- tf32 helpers ----------------
__device__ __forceinline__ uint32_t f2tf32(float x) {
    uint32_t u;
    asm("cvt.rna.tf32.f32 %0, %1;" : "=r"(u) : "f"(x));
    return u;
}
__device__ __forceinline__ void mma_tf32(float c[4], const uint32_t a[4], const uint32_t b[2]) {
    asm volatile(
        "mma.sync.aligned.m16n8k8.row.col.f32.tf32.tf32.f32 "
        "{%0,%1,%2,%3}, {%4,%5,%6,%7}, {%8,%9}, {%0,%1,%2,%3};"
        : "+f"(c[0]), "+f"(c[1]), "+f"(c[2]), "+f"(c[3])
        : "r"(a[0]), "r"(a[1]), "r"(a[2]), "r"(a[3]), "r"(b[0]), "r"(b[1]));
}
__device__ __forceinline__ void unpack8h(uint4 raw, float4& lo, float4& hi) {
    const __half2* h2 = (const __half2*)&raw;
    float2 f0 = __half22float2(h2[0]), f1 = __half22float2(h2[1]);
    float2 f2 = __half22float2(h2[2]), f3 = __half22float2(h2[3]);
    lo = make_float4(f0.x, f0.y, f1.x, f1.y);
    hi = make_float4(f2.x, f2.y, f3.x, f3.y);
}

// ---------------- tf32 tensor-core GEMM ----------------
// MODE 0: Qw(h16)  = Xp @ Wqall   M=4400  N=4800 K=320  grid(38,35,1)
// MODE 1: Q (h16)  = Rep @ Wq_i   M=4400  N=256  K=256  grid(2,35,16)
// MODE 2: XV       = Xp @ Wvp     M=4400  N=256  K=320  grid(2,35,1)
// MODE 3: V        = Rep @ Wvp2   M=4400  N=256  K=256  grid(2,35,1)
// MODE 4: Sx1      = Qc @ RepH^T  M=100   N=1000 K=256  grid(8,1,64)   A fp16
// MODE 5: Sx2      = Qh @ RepC^T  M=1000  N=100  K=256  grid(1,8,64)   A fp16
// MODE 6: Kmat(h16)= Val @ keyW   M=41000 N=200  K=256  grid(2,321,1)  A fp16
// MODE 7: Sw[s]    = Qw @ X^T     M=320   N=20   K=320  grid(1,3,220)  NARROW, A fp16
// MODE 8: diag[s]                 M=336   N=21   K=256  grid(1,3,220)  NARROW, A fp16, scalar stores
#define BM 128
#define BN 128
#define BK 16
#define TSP 136

template<int MODE>
__global__ void __launch_bounds__(256, 2)
k_t128(const float* __restrict__ Bglob) {
    constexpr int K   = (MODE==0 || MODE==2 || MODE==7) ? EEP : RR;
    constexpr int M   = (MODE==4) ? 100 : (MODE==5 ? 1000 : (MODE==6 ? MVAL :
                        (MODE==7 ? 320 : (MODE==8 ? 336 : NTOK))));
    constexpr int N   = (MODE==0) ? NQW : (MODE==4 ? 1000 : (MODE==5 ? 100 :
                        (MODE==6 ? QQ : (MODE==7 ? 20 : (MODE==8 ? 21 : RR)))));
    constexpr bool BT = (MODE==4 || MODE==5 || MODE==7 || MODE==8);
    constexpr bool NARROW = (MODE==7 || MODE==8);
    constexpr bool AH = (MODE>=4);          // A operand stored fp16
    constexpr int LDB = (MODE==0) ? NQW : (MODE==6 ? QQ : RR);
    constexpr int NCH = K / BK;
    constexpr int NMT = NARROW ? 1 : 4;

    __shared__ float As[2][BK*TSP];
    __shared__ float Bs[2][BK*TSP];

    const int tid = threadIdx.x;
    const int bz = blockIdx.z;
    const int nBase = blockIdx.x * BN;
    const int mBase = blockIdx.y * BM;
    int b = 0, h = 0;
    if (MODE==1) h = bz;
    if (MODE==4 || MODE==5) { b = bz >> 4; h = bz & 15; }

    // ---- loaders ----
    const int ar  = tid >> 1;
    const int akq = (tid & 1) * 2;
    const float*  ArowF = nullptr;
    const __half* ArowH = nullptr;
    {
        int am = mBase + ar;
        if (am < M) {
            if (MODE==0 || MODE==2) ArowF = g_Xp + (size_t)am*EEP;
            else if (MODE==1 || MODE==3) ArowF = g_Rep + (size_t)am*RR;
            else if (MODE==6) ArowH = g_Val + (size_t)am*RR;
            else if (MODE==7) ArowH = g_Qw + (size_t)(bz*320 + am)*EEP;
            else if (MODE==8) {
                int h8 = am / 21, t8 = am - 21*h8;
                ArowH = (t8 < 20) ? g_Q + (((size_t)bz*HH + h8)*LL + t8)*RR
                                  : g_q1h + (size_t)h8*RR;
            }
            else if (MODE==4) { int c = am/20, t = am - 20*c;
                ArowH = g_Q + (size_t)(((b*CDD + c)*HH + h)*LL + t)*RR; }
            else { int i = am/20, u = am - 20*i;
                ArowH = g_Q + (size_t)(((NSC + b*HIS + i)*HH + h)*LL + u)*RR; }
        }
    }
    const float* Brow = nullptr;
    const float* Bb = nullptr;
    int bkr = 0, bn1 = 0; bool bok1 = false, bok2 = false;
    if (BT) {
        int bn = nBase + ar;
        if (bn < N) {
            if (MODE==4)      Brow = g_Rep + ((size_t)(NSC + b*HIS)*LL + bn)*RR;
            else if (MODE==5) Brow = g_Rep + ((size_t)(b*CDD)*LL + bn)*RR;
            else if (MODE==7) Brow = g_Xp + ((size_t)bz*LL + bn)*EEP;
            else              Brow = (bn < 20) ? g_Rep + ((size_t)bz*LL + bn)*RR : g_ones;
        }
    } else {
        if (MODE==0) Bb = g_Wqall;
        else if (MODE==1) Bb = Bglob + (size_t)h*RR*RR;
        else if (MODE==2) Bb = g_Wvp;
        else if (MODE==3) Bb = g_Wvp2;
        else Bb = Bglob;   // MODE 6: keyW
        bkr = tid >> 4; bn1 = (tid & 15) * 4;
        bok1 = (nBase + bn1) < N;
        bok2 = (nBase + bn1 + 64) < N;
    }

    float4 pa0, pa1, pb0, pb1;
    const float4 fz = make_float4(0.f, 0.f, 0.f, 0.f);

    auto loadChunk = [&](int kc) {
        pa0 = fz; pa1 = fz; pb0 = fz; pb1 = fz;
        if (AH) {
            if (ArowH) { uint4 raw = *(const uint4*)(ArowH + kc + 4*akq); unpack8h(raw, pa0, pa1); }
        } else if (ArowF) {
            pa0 = *(const float4*)(ArowF + kc + 4*akq);
            pa1 = *(const float4*)(ArowF + kc + 4*akq + 4);
        }
        if (BT) {
            if (Brow) {
                pb0 = *(const float4*)(Brow + kc + 4*akq);
                pb1 = *(const float4*)(Brow + kc + 4*akq + 4);
            }
        } else {
            if (bok1) pb0 = *(const float4*)(Bb + (size_t)(kc + bkr)*LDB + nBase + bn1);
            if (bok2) pb1 = *(const float4*)(Bb + (size_t)(kc + bkr)*LDB + nBase + bn1 + 64);
        }
    };
    auto storeChunk = [&](int buf) {
        float* dA = As[buf]; float* dB = Bs[buf];
        dA[(4*akq+0)*TSP + ar] = __uint_as_float(f2tf32(pa0.x));
        dA[(4*akq+1)*TSP + ar] = __uint_as_float(f2tf32(pa0.y));
        dA[(4*akq+2)*TSP + ar] = __uint_as_float(f2tf32(pa0.z));
        dA[(4*akq+3)*TSP + ar] = __uint_as_float(f2tf32(pa0.w));
        dA[(4*akq+4)*TSP + ar] = __uint_as_float(f2tf32(pa1.x));
        dA[(4*akq+5)*TSP + ar] = __uint_as_float(f2tf32(pa1.y));
        dA[(4*akq+6)*TSP + ar] = __uint_as_float(f2tf32(pa1.z));
        dA[(4*akq+7)*TSP + ar] = __uint_as_float(f2tf32(pa1.w));
        if (BT) {
            dB[(4*akq+0)*TSP + ar] = __uint_as_float(f2tf32(pb0.x));
            dB[(4*akq+1)*TSP + ar] = __uint_as_float(f2tf32(pb0.y));
            dB[(4*akq+2)*TSP + ar] = __uint_as_float(f2tf32(pb0.z));
            dB[(4*akq+3)*TSP + ar] = __uint_as_float(f2tf32(pb0.w));
            dB[(4*akq+4)*TSP + ar] = __uint_as_float(f2tf32(pb1.x));
            dB[(4*akq+5)*TSP + ar] = __uint_as_float(f2tf32(pb1.y));
            dB[(4*akq+6)*TSP + ar] = __uint_as_float(f2tf32(pb1.z));
            dB[(4*akq+7)*TSP + ar] = __uint_as_float(f2tf32(pb1.w));
        } else {
            float4 q0 = make_float4(__uint_as_float(f2tf32(pb0.x)), __uint_as_float(f2tf32(pb0.y)),
                                    __uint_as_float(f2tf32(pb0.z)), __uint_as_float(f2tf32(pb0.w)));
            float4 q1 = make_float4(__uint_as_float(f2tf32(pb1.x)), __uint_as_float(f2tf32(pb1.y)),
                                    __uint_as_float(f2tf32(pb1.z)), __uint_as_float(f2tf32(pb1.w)));
            *(float4*)(dB + bkr*TSP + bn1) = q0;
            *(float4*)(dB + bkr*TSP + bn1 + 64) = q1;
        }
    };

    const int warp = tid >> 5, lane = tid & 31;
    const int wm = NARROW ? warp*16 : (warp >> 2)*64;
    const int wn = NARROW ? 0 : (warp & 3)*32;
    const int g = lane >> 2, tig = lane & 3;

    float c[NMT][4][4];
    #pragma unroll
    for (int mt = 0; mt < NMT; mt++)
        #pragma unroll
        for (int nt = 0; nt < 4; nt++)
            #pragma unroll
            for (int e = 0; e < 4; e++) c[mt][nt][e] = 0.f;

    loadChunk(0); storeChunk(0); __syncthreads();

    for (int ch = 0; ch < NCH; ch++) {
        int cur = ch & 1;
        if (ch + 1 < NCH) loadChunk((ch + 1) * BK);
        const float* pAs = As[cur];
        const float* pBs = Bs[cur];
        #pragma unroll
        for (int ks = 0; ks < 2; ks++) {
            const int k0 = ks * 8;
            uint32_t af[NMT][4], bf[4][2];
            #pragma unroll
            for (int mt = 0; mt < NMT; mt++) {
                const float* p0 = pAs + (k0 + tig)*TSP + wm + mt*16 + g;
                const float* p1 = pAs + (k0 + tig + 4)*TSP + wm + mt*16 + g;
                af[mt][0] = __float_as_uint(p0[0]);
                af[mt][1] = __float_as_uint(p0[8]);
                af[mt][2] = __float_as_uint(p1[0]);
                af[mt][3] = __float_as_uint(p1[8]);
            }
            #pragma unroll
            for (int nt = 0; nt < 4; nt++) {
                bf[nt][0] = __float_as_uint(pBs[(k0 + tig)*TSP + wn + nt*8 + g]);
                bf[nt][1] = __float_as_uint(pBs[(k0 + tig + 4)*TSP + wn + nt*8 + g]);
            }
            #pragma unroll
            for (int mt = 0; mt < NMT; mt++)
                #pragma unroll
                for (int nt = 0; nt < 4; nt++)
                    mma_tf32(c[mt][nt], af[mt], bf[nt]);
        }
        if (ch + 1 < NCH) { storeChunk(cur ^ 1); __syncthreads(); }
    }

    // ---- epilogue ----
    #pragma unroll
    for (int mt = 0; mt < NMT; mt++) {
        #pragma unroll
        for (int half = 0; half < 2; half++) {
            int row = mBase + wm + mt*16 + g + half*8;
            if (row >= M) continue;
            if (MODE==0) {
                int s = row/20, t = row - 20*s;
                __half* obase = g_Qw + ((size_t)(s*HH))*LL*EEP + (size_t)t*EEP;
                #pragma unroll
                for (int nt = 0; nt < 4; nt++) {
                    int col = nBase + wn + nt*8 + 2*tig;
                    if (col < NQW) {
                        int hh = col / 300;
                        int jj = col - 300*hh;
                        *(__half2*)(obase + (size_t)hh*LL*EEP + jj) =
                            __floats2half2_rn(c[mt][nt][half*2], c[mt][nt][half*2 + 1]);
                    }
                }
                continue;
            }
            if (MODE==1 || MODE==6) {
                __half* oh;
                if (MODE==1) { int s = row/20, t = row - 20*s;
                    oh = g_Q + ((size_t)(s*HH + h)*LL + t)*RR; }
                else oh = g_Kmat + (size_t)row*QQ;
                #pragma unroll
                for (int nt = 0; nt < 4; nt++) {
                    int col = nBase + wn + nt*8 + 2*tig;
                    if (col < N)
                        *(__half2*)(oh + col) =
                            __floats2half2_rn(c[mt][nt][half*2], c[mt][nt][half*2 + 1]);
                }
                continue;
            }
            float* o;
            if (MODE==2) o = g_XV + (size_t)row*RR;
            else if (MODE==3) o = g_V + (size_t)row*RR;
            else if (MODE==7) o = g_Sw + (size_t)bz*(HH*LL*LL) + (size_t)row*20;
            else if (MODE==8) {
                int h8 = row/21, t8 = row - 21*h8;
                float* base = (bz < NSC) ? g_Scc + ((size_t)bz*HH + h8)*441
                                         : g_Shh + ((size_t)(bz-NSC)*HH + h8)*441;
                o = base + t8*21;
            }
            else if (MODE==4) o = g_Sx1 + (size_t)bz*100000 + (size_t)row*1000;
            else              o = g_Sx2 + (size_t)bz*100000 + (size_t)row*100;
            #pragma unroll
            for (int nt = 0; nt < 4; nt++) {
                int col = nBase + wn + nt*8 + 2*tig;
                float c0 = c[mt][nt][half*2], c1 = c[mt][nt][half*2 + 1];
                if (MODE==8) {
                    if (col < N)     o[col]     = c0;
                    if (col + 1 < N) o[col + 1] = c1;
                } else {
                    if (col < N) {
                        if (col + 1 < N) *(float2*)(o + col) = make_float2(c0, c1);
                        else o[col] = c0;
                    }
                }
            }
        }
    }
}

// ---------------- K2b: words softmax + A.XV ----------
__global__ void __launch_bounds__(320, 4)
k_wattn2() {
    __shared__ float S[20*21];
    __shared__ float XVs[20*16];
    int s = blockIdx.x, h = blockIdx.y, tid = threadIdx.x;

    for (int idx = tid; idx < 400; idx += 320) {
        int t = idx / 20, u = idx - 20*t;
        S[t*21 + u] = g_Sw[(size_t)s*(HH*LL*LL) + (size_t)(h*20 + t)*20 + u] * INV_SCALE;
    }
    {
        int u = tid >> 4, v = tid & 15;
        XVs[tid] = g_XV[((size_t)s*LL + u)*RR + h*VV + v];
    }
    __syncthreads();

    if (tid < LL) {
        float* row = S + tid*21;
        float m = row[0];
        #pragma unroll
        for (int u = 1; u < LL; u++) m = fmaxf(m, row[u]);
        float ssum = 0.f;
        #pragma unroll
        for (int u = 0; u < LL; u++) { float e = __expf(row[u] - m); row[u] = e; ssum += e; }
        float inv = 1.0f / ssum;
        #pragma unroll
        for (int u = 0; u < LL; u++) row[u] *= inv;
    }
    __syncthreads();

    {
        int t = tid >> 4, v = tid & 15;
        float acc = 0.f;
        #pragma unroll
        for (int u = 0; u < LL; u++) acc = fmaf(S[t*21 + u], XVs[u*16 + v], acc);
        g_Rep[((size_t)s*LL + t)*RR + h*VV + v] = acc;
    }
}

// ---------------- K5: fused softmax + AV -> g_Val (fp16 out) ----------
#define SC_VC   0
#define SC_VH   (SC_VC + LL*RR)
#define SC_V1   (SC_VH + LL*RR)
#define SC_S    (SC_V1 + RR)
#define K5_SMEM_FLOATS (SC_S + TT*TT + 15)  // 12192 floats = 48768 B

__global__ void __launch_bounds__(256, 4)
k_fuse_av() {
    extern __shared__ float sm[];
    float* sVc  = sm + SC_VC;
    float* sVh  = sm + SC_VH;
    float* sV1  = sm + SC_V1;
    float* sS   = sm + SC_S;

    int bci = blockIdx.x;
    int i   = bci % HIS;
    int bc  = bci / HIS;
    int b   = bc / CDD;
    int c   = bc - b*CDD;
    int sc  = bc;
    int sh  = NSC + b*HIS + i;

    int tid = threadIdx.x;
    int wrp = tid >> 5, ln = tid & 31;

    {
        const float4* gvc = (const float4*)(g_V + (size_t)sc*LL*RR);
        const float4* gvh = (const float4*)(g_V + (size_t)sh*LL*RR);
        float4* dVc = (float4*)sVc; float4* dVh = (float4*)sVh;
        for (int idx = tid; idx < LL*RR/4; idx += 256) { dVc[idx] = gvc[idx]; dVh[idx] = gvh[idx]; }
        if (tid < RR) sV1[tid] = g_v1[tid];
    }

    __half* valOut = g_Val + (size_t)bci*TT*RR;

    for (int h = 0; h < HH; h++) {
        const float* scc = g_Scc + ((size_t)bc*HH + h)*441;
        const float* shh = g_Shh + ((size_t)(b*HIS + i)*HH + h)*441;
        const float* sx1 = g_Sx1 + ((size_t)(b*HH + h))*100*1000;
        const float* sx2 = g_Sx2 + ((size_t)(b*HH + h))*1000*100;

        __syncthreads();
        for (int p = tid; p < TT*TT; p += 256) {
            int q = p / TT, k = p - q*TT;
            float v;
            if (q < LL) {
                if (k < LL)       v = __ldg(&scc[q*21 + k]);
                else if (k == LL) v = __ldg(&scc[q*21 + 20]);
                else              v = __ldg(&sx1[(size_t)(c*20 + q)*1000 + i*20 + (k-LL-1)]);
            } else if (q == LL) {
                if (k < LL)       v = __ldg(&scc[20*21 + k]);
                else if (k == LL) v = __ldg(&scc[20*21 + 20]);
                else              v = __ldg(&shh[20*21 + (k-LL-1)]);
            } else {
                int t = q - LL - 1;
                if (k < LL)       v = __ldg(&sx2[(size_t)(i*20 + t)*100 + c*20 + k]);
                else if (k == LL) v = __ldg(&shh[t*21 + 20]);
                else              v = __ldg(&shh[t*21 + (k-LL-1)]);
            }
            sS[p] = v * INV_SCALE;
        }
        __syncthreads();

        // warp-parallel softmax
        for (int q = wrp; q < TT; q += 8) {
            float* row = sS + q*TT;
            float v0 = row[ln];
            float v1 = (ln + 32 < TT) ? row[ln + 32] : -1e30f;
            float m = fmaxf(v0, v1);
            #pragma unroll
            for (int o = 16; o; o >>= 1) m = fmaxf(m, __shfl_xor_sync(0xffffffffu, m, o));
            float e0 = __expf(v0 - m);
            float e1 = (ln + 32 < TT) ? __expf(v1 - m) : 0.f;
            float ss = e0 + e1;
            #pragma unroll
            for (int o = 16; o; o >>= 1) ss += __shfl_xor_sync(0xffffffffu, ss, o);
            float inv = 1.0f / ss;
            row[ln] = e0 * inv;
            if (ln + 32 < TT) row[ln + 32] = e1 * inv;
        }
        __syncthreads();

        for (int p = tid; p < TT*VV; p += 256) {
            int q = p / VV, v = p - (p / VV)*VV;
            int col = h*VV + v;
            const float* arow = sS + q*TT;
            float acc = arow[LL] * sV1[col];
            #pragma unroll
            for (int k = 0; k < LL; k++) acc = fmaf(arow[k], sVc[k*RR + col], acc);
            #pragma unroll
            for (int k = 0; k < LL; k++) acc = fmaf(arow[LL+1+k], sVh[k*RR + col], acc);
            valOut[(size_t)q*RR + col] = __float2half(acc);
        }
    }
}

// ---------------- K6: pooling (fp16 in) ----------------
__global__ void __launch_bounds__(256, 4)
k_pool(const float* __restrict__ keyb, const float* __restrict__ query) {
    __shared__ float sPool[48];
    __shared__ float sW[48];

    int bci = blockIdx.x, tid = threadIdx.x;
    int warp = tid >> 5, lane = tid & 31;

    if (tid < TT) sPool[tid] = 0.f;
    __syncthreads();

    int j = tid;
    bool jact = (j < QQ);
    float qj = jact ? query[j] : 0.f;
    float kb = jact ? keyb[j]  : 0.f;
    const __half* km = g_Kmat + (size_t)bci*TT*QQ;

    #pragma unroll
    for (int t = 0; t < TT; t++) {
        float v = jact ? qj * tanhf(__half2float(km[t*QQ + j]) + kb) : 0.f;
        #pragma unroll
        for (int o = 16; o; o >>= 1) v += __shfl_xor_sync(0xffffffffu, v, o);
        if (lane == 0 && warp < 7) atomicAdd(&sPool[t], v);
    }
    __syncthreads();

    if (tid == 0) {
        float m = sPool[0] * INV_SCALE;
        #pragma unroll
        for (int t = 1; t < TT; t++) m = fmaxf(m, sPool[t] * INV_SCALE);
        float ssum = 0.f;
        #pragma unroll
        for (int t = 0; t < TT; t++) { float e = __expf(sPool[t]*INV_SCALE - m); sW[t] = e; ssum += e; }
        float inv = 1.0f / ssum;
        #pragma unroll
        for (int t = 0; t < TT; t++) sW[t] *= inv;
    }
    __syncthreads();

    {
        int r = tid;
        const __half* vb = g_Val + (size_t)bci*TT*RR + r;
        float a2 = 0.f;
        #pragma unroll
        for (int t = 0; t < TT; t++) a2 = fmaf(sW[t], __half2float(vb[t*RR]), a2);
        g_rep[(size_t)bci*RR + r] = a2;
    }
}

// ---------------- mean + ltr ----------------
__global__ void k_fv(const float* __restrict__ ltr_w, const float* __restrict__ ltr_b) {
    __shared__ float red[256];
    int bc = blockIdx.x;
    int r = threadIdx.x;
    float ssum = 0.f;
    for (int i = 0; i < HIS; i++) ssum += g_rep[(size_t)(bc*HIS + i)*RR + r];
    red[r] = (ssum * (1.0f/HIS)) * ltr_w[r];
    __syncthreads();
    for (int off = 128; off; off >>= 1) {
        if (r < off) red[r] += red[r + off];
        __syncthreads();
    }
    if (r == 0) g_score[bc] = red[0] + ltr_b[0];
}

// ---------------- log_softmax ----------------
__global__ void k_out(float* __restrict__ out) {
    int b = threadIdx.x;
    if (b < BB) {
        float s[CDD];
        float m = -1e30f;
        #pragma unroll
        for (int c = 0; c < CDD; c++) { s[c] = g_score[b*CDD + c]; m = fmaxf(m, s[c]); }
        float ssum = 0.f;
        #pragma unroll
        for (int c = 0; c < CDD; c++) ssum += expf(s[c] - m);
        float lse = logf(ssum);
        #pragma unroll
        for (int c = 0; c < CDD; c++) out[b*CDD + c] = s[c] - m - lse;
    }
}

// ---------------- launch ----------------
extern "C" void kernel_launch(void* const* d_in, const int* in_sizes, int n_in,
                              void* d_out, int out_size) {
    const int*   cand  = (const int*)  d_in[0];
    const int*   clk   = (const int*)  d_in[1];
    const float* emb   = (const float*)d_in[2];
    const float* Wq_w  = (const float*)d_in[3];
    const float* Wv_w  = (const float*)d_in[4];
    const float* Wq_i  = (const float*)d_in[5];
    const float* Wv_i  = (const float*)d_in[6];
    const float* keyW  = (const float*)d_in[7];
    const float* keyb  = (const float*)d_in[8];
    const float* query = (const float*)d_in[9];
    const float* ltr_w = (const float*)d_in[10];
    const float* ltr_b = (const float*)d_in[11];
    float* out = (float*)d_out;

    cudaFuncSetAttribute(k_fuse_av, cudaFuncAttributeMaxDynamicSharedMemorySize,
                         K5_SMEM_FLOATS * sizeof(float));

    k_prep<<<NS + 64, 256>>>(cand, clk, emb, Wq_w, Wv_w, Wq_i, Wv_i);
    k_v1<<<1, 256>>>(Wv_i);

    k_t128<0><<<dim3(38, 35, 1), 256>>>(nullptr);       // words Q -> fp16
    k_t128<2><<<dim3(2, 35, 1), 256>>>(nullptr);        // words XV
    k_t128<7><<<dim3(1, 3, NS), 256>>>(nullptr);        // words scores (fp16 A)
    k_wattn2<<<dim3(NS, HH), 320>>>();

    k_t128<1><<<dim3(2, 35, HH), 256>>>(Wq_i);          // itrs Q -> fp16
    k_t128<3><<<dim3(2, 35, 1), 256>>>(nullptr);        // itrs V

    k_t128<8><<<dim3(1, 3, NS), 256>>>(nullptr);        // diag scores (fp16 A)
    k_t128<4><<<dim3(8, 1, BB*HH), 256>>>(nullptr);     // Sx1 (fp16 A)
    k_t128<5><<<dim3(1, 8, BB*HH), 256>>>(nullptr);     // Sx2 (fp16 A)

    k_fuse_av<<<NBCI, 256, K5_SMEM_FLOATS * sizeof(float)>>>();
    k_t128<6><<<dim3(2, 321, 1), 256>>>(keyW);          // Kmat -> fp16 (fp16 A)
    k_pool<<<NBCI, 256>>>(keyb, query);

    k_fv<<<NSC, 256>>>(ltr_w, ltr_b);
    k_out<<<1, 32>>>(out);
}

// round 13
// speedup vs baseline: 9.5875x; 1.0499x over previous
#include <cuda_runtime.h>
#include <cuda_fp16.h>
#include <math.h>
#include <stdint.h>

#define BB   4
#define CDD  5
#define HIS  50
#define LL   20
#define TT   41
#define EE   300
#define EEP  320
#define HH   16
#define VV   16
#define RR   256
#define QQ   200
#define NSC  (BB*CDD)        // 20
#define NSH  (BB*HIS)        // 200
#define NS   (NSC+NSH)       // 220
#define NTOK (NS*LL)         // 4400
#define NBCI (BB*CDD*HIS)    // 1000
#define MVAL (NBCI*TT)       // 41000
#define NQW  4800

#define INV_SCALE 0.057735026918962584f   // 1/sqrt(300)

// ---------------- device scratch ----------------
__device__ float  g_Xp[NTOK*EEP];
__device__ float  g_Wqall[EEP*NQW];
__device__ float  g_Wvp[EEP*RR];
__device__ float  g_Wvp2[RR*RR];
__device__ __half g_Qw[(size_t)NS*HH*LL*EEP];  // fp16; cols 300..319 stay zero (static init)
__device__ float  g_Sw[(size_t)NS*HH*LL*LL];
__device__ float  g_XV[NTOK*RR];
__device__ float  g_Rep[NS*LL*RR];
__device__ __half g_Q[(size_t)NS*HH*LL*RR];
__device__ float  g_V[NS*LL*RR];
__device__ __half g_q1h[HH*RR];
__device__ float  g_v1[RR];
__device__ float  g_ones[RR];
__device__ float  g_Scc[NSC*HH*21*21];
__device__ float  g_Shh[NSH*HH*21*21];
__device__ float  g_Sx1[(size_t)BB*HH*100*1000];
__device__ float  g_Sx2[(size_t)BB*HH*1000*100];
__device__ __half g_Val[(size_t)MVAL*RR];
__device__ __half g_Kmat[(size_t)MVAL*QQ];
__device__ float  g_rep[NBCI*RR];
__device__ float  g_score[NSC];

// ---------------- K0: merged prep (gather + repacks + ones + q1 + v1) ----------
__global__ void k_prep(const int* __restrict__ cand, const int* __restrict__ clk,
                       const float* __restrict__ emb,
                       const float* __restrict__ Wq_w, const float* __restrict__ Wv_w,
                       const float* __restrict__ Wq_i, const float* __restrict__ Wv_i) {
    int blk = blockIdx.x, tid = threadIdx.x;
    if (blk < NS) {
        const int* tok = (blk < NSC) ? (cand + blk*LL) : (clk + (blk-NSC)*LL);
        for (int idx = tid; idx < LL*EEP; idx += 256) {
            int t = idx / EEP, d = idx - t*EEP;
            g_Xp[(blk*LL + t)*EEP + d] = (d < EE) ? emb[(size_t)tok[t]*EE + d] : 0.f;
        }
    } else if (blk < NS + 16) {
        int h = blk - NS;
        for (int idx = tid; idx < EEP*EE; idx += 256) {
            int k = idx / EE, j = idx - k*EE;
            g_Wqall[(size_t)k*NQW + h*EE + j] =
                (k < EE) ? Wq_w[(size_t)h*EE*EE + (size_t)k*EE + j] : 0.f;
        }
    } else if (blk < NS + 32) {
        int part = blk - NS - 16;
        for (int q = 0; q < EEP*RR/(16*256); q++) {
            int idx = part*(EEP*RR/16) + q*256 + tid;
            int k = idx >> 8, col = idx & 255;
            int h = col >> 4, v = col & 15;
            g_Wvp[idx] = (k < EE) ? Wv_w[((size_t)h*EE + k)*VV + v] : 0.f;
        }
    } else if (blk < NS + 48) {
        int part = blk - NS - 32;
        for (int q = 0; q < RR*RR/(16*256); q++) {
            int idx = part*(RR*RR/16) + q*256 + tid;
            int r = idx >> 8, col = idx & 255;
            int h = col >> 4, v = col & 15;
            g_Wvp2[idx] = Wv_i[((size_t)h*RR + r)*VV + v];
        }
    } else if (blk < NS + 64) {
        int h = blk - NS - 48, j = tid;
        if (h == 0) g_ones[j] = 1.0f;
        float acc = 0.f;
        const float* w = Wq_i + (size_t)h*RR*RR + j;
        for (int r = 0; r < RR; r++) acc += w[r*RR];
        g_q1h[h*RR + j] = __float2half(acc);
    } else {
        int h = tid >> 4, v = tid & 15;
        float a2 = 0.f;
        const float* wv = Wv_i + (size_t)h*RR*VV + v;
        for (int r = 0; r < RR; r++) a2 += wv[r*VV];
        g_v1[h*VV + v] = a2;
    }
}

// ---------------- tf32 helpers ----------------
__device__ __forceinline__ uint32_t f2tf32(float x) {
    uint32_t u;
    asm("cvt.rna.tf32.f32 %0, %1;" : "=r"(u) : "f"(x));
    return u;
}
__device__ __forceinline__ void mma_tf32(float c[4], const uint32_t a[4], const uint32_t b[2]) {
    asm volatile(
        "mma.sync.aligned.m16n8k8.row.col.f32.tf32.tf32.f32 "
        "{%0,%1,%2,%3}, {%4,%5,%6,%7}, {%8,%9}, {%0,%1,%2,%3};"
        : "+f"(c[0]), "+f"(c[1]), "+f"(c[2]), "+f"(c[3])
        : "r"(a[0]), "r"(a[1]), "r"(a[2]), "r"(a[3]), "r"(b[0]), "r"(b[1]));
}
__device__ __forceinline__ void unpack8h(uint4 raw, float4& lo, float4& hi) {
    const __half2* h2 = (const __half2*)&raw;
    float2 f0 = __half22float2(h2[0]), f1 = __half22float2(h2[1]);
    float2 f2 = __half22float2(h2[2]), f3 = __half22float2(h2[3]);
    lo = make_float4(f0.x, f0.y, f1.x, f1.y);
    hi = make_float4(f2.x, f2.y, f3.x, f3.y);
}

// ---------------- GEMM body (dynamic smem, block coords passed in) --------
// MODE 0: Qw(h16)  = Xp @ Wqall   M=4400  N=4800 K=320  (38,35)
// MODE 1: Q (h16)  = Rep @ Wq_i   M=4400  N=256  K=256  (2,35,z=h16)
// MODE 2: XV       = Xp @ Wvp     M=4400  N=256  K=320  (2,35)
// MODE 3: V        = Rep @ Wvp2   M=4400  N=256  K=256  (2,35)
// MODE 4: Sx1      = Qc @ RepH^T  M=100   N=1000 K=256  (8,1,z=64)  A fp16
// MODE 5: Sx2      = Qh @ RepC^T  M=1000  N=100  K=256  (1,8,z=64)  A fp16
// MODE 6: Kmat(h16)= Val @ keyW   M=41000 N=200  K=256  (2,321)     A fp16
// MODE 7: Sw[s]    = Qw @ X^T     M=320   N=20   K=320  (1,3,z=220) NARROW, A fp16
// MODE 8: diag[s]                 M=336   N=21   K=256  (1,3,z=220) NARROW, A fp16, scalar st
#define BM 128
#define BN 128
#define BK 16
#define TSP 136
#define GEMM_SMEM (4*BK*TSP*4)   // 34816 B

template<int MODE>
__device__ __forceinline__ void gemm_body(const float* __restrict__ Bglob,
                                          int bxi, int byi, int bzi, float* sm) {
    constexpr int K   = (MODE==0 || MODE==2 || MODE==7) ? EEP : RR;
    constexpr int M   = (MODE==4) ? 100 : (MODE==5 ? 1000 : (MODE==6 ? MVAL :
                        (MODE==7 ? 320 : (MODE==8 ? 336 : NTOK))));
    constexpr int N   = (MODE==0) ? NQW : (MODE==4 ? 1000 : (MODE==5 ? 100 :
                        (MODE==6 ? QQ : (MODE==7 ? 20 : (MODE==8 ? 21 : RR)))));
    constexpr bool BT = (MODE==4 || MODE==5 || MODE==7 || MODE==8);
    constexpr bool NARROW = (MODE==7 || MODE==8);
    constexpr bool AH = (MODE>=4);
    constexpr int LDB = (MODE==0) ? NQW : (MODE==6 ? QQ : RR);
    constexpr int NCH = K / BK;
    constexpr int NMT = NARROW ? 1 : 4;

    float* AsB = sm;                    // [2][BK*TSP]
    float* BsB = sm + 2*BK*TSP;         // [2][BK*TSP]

    const int tid = threadIdx.x;
    const int bz = bzi;
    const int nBase = bxi * BN;
    const int mBase = byi * BM;
    int b = 0, h = 0;
    if (MODE==1) h = bz;
    if (MODE==4 || MODE==5) { b = bz >> 4; h = bz & 15; }

    const int ar  = tid >> 1;
    const int akq = (tid & 1) * 2;
    const float*  ArowF = nullptr;
    const __half* ArowH = nullptr;
    {
        int am = mBase + ar;
        if (am < M) {
            if (MODE==0 || MODE==2) ArowF = g_Xp + (size_t)am*EEP;
            else if (MODE==1 || MODE==3) ArowF = g_Rep + (size_t)am*RR;
            else if (MODE==6) ArowH = g_Val + (size_t)am*RR;
            else if (MODE==7) ArowH = g_Qw + (size_t)(bz*320 + am)*EEP;
            else if (MODE==8) {
                int h8 = am / 21, t8 = am - 21*h8;
                ArowH = (t8 < 20) ? g_Q + (((size_t)bz*HH + h8)*LL + t8)*RR
                                  : g_q1h + (size_t)h8*RR;
            }
            else if (MODE==4) { int c = am/20, t = am - 20*c;
                ArowH = g_Q + (size_t)(((b*CDD + c)*HH + h)*LL + t)*RR; }
            else { int i = am/20, u = am - 20*i;
                ArowH = g_Q + (size_t)(((NSC + b*HIS + i)*HH + h)*LL + u)*RR; }
        }
    }
    const float* Brow = nullptr;
    const float* Bb = nullptr;
    int bkr = 0, bn1 = 0; bool bok1 = false, bok2 = false;
    if (BT) {
        int bn = nBase + ar;
        if (bn < N) {
            if (MODE==4)      Brow = g_Rep + ((size_t)(NSC + b*HIS)*LL + bn)*RR;
            else if (MODE==5) Brow = g_Rep + ((size_t)(b*CDD)*LL + bn)*RR;
            else if (MODE==7) Brow = g_Xp + ((size_t)bz*LL + bn)*EEP;
            else              Brow = (bn < 20) ? g_Rep + ((size_t)bz*LL + bn)*RR : g_ones;
        }
    } else {
        if (MODE==0) Bb = g_Wqall;
        else if (MODE==1) Bb = Bglob + (size_t)h*RR*RR;
        else if (MODE==2) Bb = g_Wvp;
        else if (MODE==3) Bb = g_Wvp2;
        else Bb = Bglob;   // MODE 6
        bkr = tid >> 4; bn1 = (tid & 15) * 4;
        bok1 = (nBase + bn1) < N;
        bok2 = (nBase + bn1 + 64) < N;
    }

    float4 pa0, pa1, pb0, pb1;
    const float4 fz = make_float4(0.f, 0.f, 0.f, 0.f);

    auto loadChunk = [&](int kc) {
        pa0 = fz; pa1 = fz; pb0 = fz; pb1 = fz;
        if (AH) {
            if (ArowH) { uint4 raw = *(const uint4*)(ArowH + kc + 4*akq); unpack8h(raw, pa0, pa1); }
        } else if (ArowF) {
            pa0 = *(const float4*)(ArowF + kc + 4*akq);
            pa1 = *(const float4*)(ArowF + kc + 4*akq + 4);
        }
        if (BT) {
            if (Brow) {
                pb0 = *(const float4*)(Brow + kc + 4*akq);
                pb1 = *(const float4*)(Brow + kc + 4*akq + 4);
            }
        } else {
            if (bok1) pb0 = *(const float4*)(Bb + (size_t)(kc + bkr)*LDB + nBase + bn1);
            if (bok2) pb1 = *(const float4*)(Bb + (size_t)(kc + bkr)*LDB + nBase + bn1 + 64);
        }
    };
    auto storeChunk = [&](int buf) {
        float* dA = AsB + buf*BK*TSP; float* dB = BsB + buf*BK*TSP;
        dA[(4*akq+0)*TSP + ar] = __uint_as_float(f2tf32(pa0.x));
        dA[(4*akq+1)*TSP + ar] = __uint_as_float(f2tf32(pa0.y));
        dA[(4*akq+2)*TSP + ar] = __uint_as_float(f2tf32(pa0.z));
        dA[(4*akq+3)*TSP + ar] = __uint_as_float(f2tf32(pa0.w));
        dA[(4*akq+4)*TSP + ar] = __uint_as_float(f2tf32(pa1.x));
        dA[(4*akq+5)*TSP + ar] = __uint_as_float(f2tf32(pa1.y));
        dA[(4*akq+6)*TSP + ar] = __uint_as_float(f2tf32(pa1.z));
        dA[(4*akq+7)*TSP + ar] = __uint_as_float(f2tf32(pa1.w));
        if (BT) {
            dB[(4*akq+0)*TSP + ar] = __uint_as_float(f2tf32(pb0.x));
            dB[(4*akq+1)*TSP + ar] = __uint_as_float(f2tf32(pb0.y));
            dB[(4*akq+2)*TSP + ar] = __uint_as_float(f2tf32(pb0.z));
            dB[(4*akq+3)*TSP + ar] = __uint_as_float(f2tf32(pb0.w));
            dB[(4*akq+4)*TSP + ar] = __uint_as_float(f2tf32(pb1.x));
            dB[(4*akq+5)*TSP + ar] = __uint_as_float(f2tf32(pb1.y));
            dB[(4*akq+6)*TSP + ar] = __uint_as_float(f2tf32(pb1.z));
            dB[(4*akq+7)*TSP + ar] = __uint_as_float(f2tf32(pb1.w));
        } else {
            float4 q0 = make_float4(__uint_as_float(f2tf32(pb0.x)), __uint_as_float(f2tf32(pb0.y)),
                                    __uint_as_float(f2tf32(pb0.z)), __uint_as_float(f2tf32(pb0.w)));
            float4 q1 = make_float4(__uint_as_float(f2tf32(pb1.x)), __uint_as_float(f2tf32(pb1.y)),
                                    __uint_as_float(f2tf32(pb1.z)), __uint_as_float(f2tf32(pb1.w)));
            *(float4*)(dB + bkr*TSP + bn1) = q0;
            *(float4*)(dB + bkr*TSP + bn1 + 64) = q1;
        }
    };

    const int warp = tid >> 5, lane = tid & 31;
    const int wm = NARROW ? warp*16 : (warp >> 2)*64;
    const int wn = NARROW ? 0 : (warp & 3)*32;
    const int g = lane >> 2, tig = lane & 3;

    float c[NMT][4][4];
    #pragma unroll
    for (int mt = 0; mt < NMT; mt++)
        #pragma unroll
        for (int nt = 0; nt < 4; nt++)
            #pragma unroll
            for (int e = 0; e < 4; e++) c[mt][nt][e] = 0.f;

    loadChunk(0); storeChunk(0); __syncthreads();

    for (int ch = 0; ch < NCH; ch++) {
        int cur = ch & 1;
        if (ch + 1 < NCH) loadChunk((ch + 1) * BK);
        const float* pAs = AsB + cur*BK*TSP;
        const float* pBs = BsB + cur*BK*TSP;
        #pragma unroll
        for (int ks = 0; ks < 2; ks++) {
            const int k0 = ks * 8;
            uint32_t af[NMT][4], bf[4][2];
            #pragma unroll
            for (int mt = 0; mt < NMT; mt++) {
                const float* p0 = pAs + (k0 + tig)*TSP + wm + mt*16 + g;
                const float* p1 = pAs + (k0 + tig + 4)*TSP + wm + mt*16 + g;
                af[mt][0] = __float_as_uint(p0[0]);
                af[mt][1] = __float_as_uint(p0[8]);
                af[mt][2] = __float_as_uint(p1[0]);
                af[mt][3] = __float_as_uint(p1[8]);
            }
            #pragma unroll
            for (int nt = 0; nt < 4; nt++) {
                bf[nt][0] = __float_as_uint(pBs[(k0 + tig)*TSP + wn + nt*8 + g]);
                bf[nt][1] = __float_as_uint(pBs[(k0 + tig + 4)*TSP + wn + nt*8 + g]);
            }
            #pragma unroll
            for (int mt = 0; mt < NMT; mt++)
                #pragma unroll
                for (int nt = 0; nt < 4; nt++)
                    mma_tf32(c[mt][nt], af[mt], bf[nt]);
        }
        if (ch + 1 < NCH) { storeChunk(cur ^ 1); __syncthreads(); }
    }

    // ---- epilogue ----
    #pragma unroll
    for (int mt = 0; mt < NMT; mt++) {
        #pragma unroll
        for (int half = 0; half < 2; half++) {
            int row = mBase + wm + mt*16 + g + half*8;
            if (row >= M) continue;
            if (MODE==0) {
                int s = row/20, t = row - 20*s;
                __half* obase = g_Qw + ((size_t)(s*HH))*LL*EEP + (size_t)t*EEP;
                #pragma unroll
                for (int nt = 0; nt < 4; nt++) {
                    int col = nBase + wn + nt*8 + 2*tig;
                    if (col < NQW) {
                        int hh = col / 300;
                        int jj = col - 300*hh;
                        *(__half2*)(obase + (size_t)hh*LL*EEP + jj) =
                            __floats2half2_rn(c[mt][nt][half*2], c[mt][nt][half*2 + 1]);
                    }
                }
                continue;
            }
            if (MODE==1 || MODE==6) {
                __half* oh;
                if (MODE==1) { int s = row/20, t = row - 20*s;
                    oh = g_Q + ((size_t)(s*HH + h)*LL + t)*RR; }
                else oh = g_Kmat + (size_t)row*QQ;
                #pragma unroll
                for (int nt = 0; nt < 4; nt++) {
                    int col = nBase + wn + nt*8 + 2*tig;
                    if (col < N)
                        *(__half2*)(oh + col) =
                            __floats2half2_rn(c[mt][nt][half*2], c[mt][nt][half*2 + 1]);
                }
                continue;
            }
            float* o;
            if (MODE==2) o = g_XV + (size_t)row*RR;
            else if (MODE==3) o = g_V + (size_t)row*RR;
            else if (MODE==7) o = g_Sw + (size_t)bz*(HH*LL*LL) + (size_t)row*20;
            else if (MODE==8) {
                int h8 = row/21, t8 = row - 21*h8;
                float* base = (bz < NSC) ? g_Scc + ((size_t)bz*HH + h8)*441
                                         : g_Shh + ((size_t)(bz-NSC)*HH + h8)*441;
                o = base + t8*21;
            }
            else if (MODE==4) o = g_Sx1 + (size_t)bz*100000 + (size_t)row*1000;
            else              o = g_Sx2 + (size_t)bz*100000 + (size_t)row*100;
            #pragma unroll
            for (int nt = 0; nt < 4; nt++) {
                int col = nBase + wn + nt*8 + 2*tig;
                float c0 = c[mt][nt][half*2], c1 = c[mt][nt][half*2 + 1];
                if (MODE==8) {
                    if (col < N)     o[col]     = c0;
                    if (col + 1 < N) o[col + 1] = c1;
                } else {
                    if (col < N) {
                        if (col + 1 < N) *(float2*)(o + col) = make_float2(c0, c1);
                        else o[col] = c0;
                    }
                }
            }
        }
    }
}

// ---- combo kernels (block-id dispatch) ----
__global__ void __launch_bounds__(256, 2)
k_gA() {   // mode0 (38x35=1330) + mode2 (2x35=70)
    extern __shared__ float sm[];
    int bid = blockIdx.x;
    if (bid < 1330) gemm_body<0>(nullptr, bid % 38, bid / 38, 0, sm);
    else { int r = bid - 1330; gemm_body<2>(nullptr, r % 2, r / 2, 0, sm); }
}
__global__ void __launch_bounds__(256, 2)
k_gB(const float* __restrict__ Wq_i) {   // mode1 (2x35x16=1120) + mode3 (70)
    extern __shared__ float sm[];
    int bid = blockIdx.x;
    if (bid < 1120) gemm_body<1>(Wq_i, bid % 2, (bid / 2) % 35, bid / 70, sm);
    else { int r = bid - 1120; gemm_body<3>(nullptr, r % 2, r / 2, 0, sm); }
}
__global__ void __launch_bounds__(256, 2)
k_gC() {   // mode8 (3x220=660) + mode4 (8x64=512) + mode5 (8x64=512)
    extern __shared__ float sm[];
    int bid = blockIdx.x;
    if (bid < 660) gemm_body<8>(nullptr, 0, bid % 3, bid / 3, sm);
    else if (bid < 660 + 512) { int r = bid - 660; gemm_body<4>(nullptr, r % 8, 0, r / 8, sm); }
    else { int r = bid - 1172; gemm_body<5>(nullptr, 0, r % 8, r / 8, sm); }
}
template<int MODE>
__global__ void __launch_bounds__(256, 2)
k_t128(const float* __restrict__ Bglob) {
    extern __shared__ float sm[];
    gemm_body<MODE>(Bglob, blockIdx.x, blockIdx.y, blockIdx.z, sm);
}

// ---------------- K2b: words softmax + A.XV ----------
__global__ void __launch_bounds__(320, 4)
k_wattn2() {
    __shared__ float S[20*21];
    __shared__ float XVs[20*16];
    int s = blockIdx.x, h = blockIdx.y, tid = threadIdx.x;

    for (int idx = tid; idx < 400; idx += 320) {
        int t = idx / 20, u = idx - 20*t;
        S[t*21 + u] = g_Sw[(size_t)s*(HH*LL*LL) + (size_t)(h*20 + t)*20 + u] * INV_SCALE;
    }
    {
        int u = tid >> 4, v = tid & 15;
        XVs[tid] = g_XV[((size_t)s*LL + u)*RR + h*VV + v];
    }
    __syncthreads();

    if (tid < LL) {
        float* row = S + tid*21;
        float m = row[0];
        #pragma unroll
        for (int u = 1; u < LL; u++) m = fmaxf(m, row[u]);
        float ssum = 0.f;
        #pragma unroll
        for (int u = 0; u < LL; u++) { float e = __expf(row[u] - m); row[u] = e; ssum += e; }
        float inv = 1.0f / ssum;
        #pragma unroll
        for (int u = 0; u < LL; u++) row[u] *= inv;
    }
    __syncthreads();

    {
        int t = tid >> 4, v = tid & 15;
        float acc = 0.f;
        #pragma unroll
        for (int u = 0; u < LL; u++) acc = fmaf(S[t*21 + u], XVs[u*16 + v], acc);
        g_Rep[((size_t)s*LL + t)*RR + h*VV + v] = acc;
    }
}

// ---------------- K5: fused softmax + AV -> g_Val (fp16 out) ----------
#define SC_VC   0
#define SC_VH   (SC_VC + LL*RR)
#define SC_V1   (SC_VH + LL*RR)
#define SC_S    (SC_V1 + RR)
#define K5_SMEM_FLOATS (SC_S + TT*TT + 15)

__global__ void __launch_bounds__(256, 4)
k_fuse_av() {
    extern __shared__ float sm[];
    float* sVc  = sm + SC_VC;
    float* sVh  = sm + SC_VH;
    float* sV1  = sm + SC_V1;
    float* sS   = sm + SC_S;

    int bci = blockIdx.x;
    int i   = bci % HIS;
    int bc  = bci / HIS;
    int b   = bc / CDD;
    int c   = bc - b*CDD;
    int sc  = bc;
    int sh  = NSC + b*HIS + i;

    int tid = threadIdx.x;
    int wrp = tid >> 5, ln = tid & 31;

    {
        const float4* gvc = (const float4*)(g_V + (size_t)sc*LL*RR);
        const float4* gvh = (const float4*)(g_V + (size_t)sh*LL*RR);
        float4* dVc = (float4*)sVc; float4* dVh = (float4*)sVh;
        for (int idx = tid; idx < LL*RR/4; idx += 256) { dVc[idx] = gvc[idx]; dVh[idx] = gvh[idx]; }
        if (tid < RR) sV1[tid] = g_v1[tid];
    }

    __half* valOut = g_Val + (size_t)bci*TT*RR;

    for (int h = 0; h < HH; h++) {
        const float* scc = g_Scc + ((size_t)bc*HH + h)*441;
        const float* shh = g_Shh + ((size_t)(b*HIS + i)*HH + h)*441;
        const float* sx1 = g_Sx1 + ((size_t)(b*HH + h))*100*1000;
        const float* sx2 = g_Sx2 + ((size_t)(b*HH + h))*1000*100;

        __syncthreads();
        for (int p = tid; p < TT*TT; p += 256) {
            int q = p / TT, k = p - q*TT;
            float v;
            if (q < LL) {
                if (k < LL)       v = __ldg(&scc[q*21 + k]);
                else if (k == LL) v = __ldg(&scc[q*21 + 20]);
                else              v = __ldg(&sx1[(size_t)(c*20 + q)*1000 + i*20 + (k-LL-1)]);
            } else if (q == LL) {
                if (k < LL)       v = __ldg(&scc[20*21 + k]);
                else if (k == LL) v = __ldg(&scc[20*21 + 20]);
                else              v = __ldg(&shh[20*21 + (k-LL-1)]);
            } else {
                int t = q - LL - 1;
                if (k < LL)       v = __ldg(&sx2[(size_t)(i*20 + t)*100 + c*20 + k]);
                else if (k == LL) v = __ldg(&shh[t*21 + 20]);
                else              v = __ldg(&shh[t*21 + (k-LL-1)]);
            }
            sS[p] = v * INV_SCALE;
        }
        __syncthreads();

        for (int q = wrp; q < TT; q += 8) {
            float* row = sS + q*TT;
            float v0 = row[ln];
            float v1 = (ln + 32 < TT) ? row[ln + 32] : -1e30f;
            float m = fmaxf(v0, v1);
            #pragma unroll
            for (int o = 16; o; o >>= 1) m = fmaxf(m, __shfl_xor_sync(0xffffffffu, m, o));
            float e0 = __expf(v0 - m);
            float e1 = (ln + 32 < TT) ? __expf(v1 - m) : 0.f;
            float ss = e0 + e1;
            #pragma unroll
            for (int o = 16; o; o >>= 1) ss += __shfl_xor_sync(0xffffffffu, ss, o);
            float inv = 1.0f / ss;
            row[ln] = e0 * inv;
            if (ln + 32 < TT) row[ln + 32] = e1 * inv;
        }
        __syncthreads();

        for (int p = tid; p < TT*VV; p += 256) {
            int q = p / VV, v = p - (p / VV)*VV;
            int col = h*VV + v;
            const float* arow = sS + q*TT;
            float acc = arow[LL] * sV1[col];
            #pragma unroll
            for (int k = 0; k < LL; k++) acc = fmaf(arow[k], sVc[k*RR + col], acc);
            #pragma unroll
            for (int k = 0; k < LL; k++) acc = fmaf(arow[LL+1+k], sVh[k*RR + col], acc);
            valOut[(size_t)q*RR + col] = __float2half(acc);
        }
    }
}

// ---------------- K6: pooling ----------------
__global__ void __launch_bounds__(256, 4)
k_pool(const float* __restrict__ keyb, const float* __restrict__ query) {
    __shared__ float sPool[48];
    __shared__ float sW[48];

    int bci = blockIdx.x, tid = threadIdx.x;
    int warp = tid >> 5, lane = tid & 31;

    if (tid < TT) sPool[tid] = 0.f;
    __syncthreads();

    int j = tid;
    bool jact = (j < QQ);
    float qj = jact ? query[j] : 0.f;
    float kb = jact ? keyb[j]  : 0.f;
    const __half* km = g_Kmat + (size_t)bci*TT*QQ;

    #pragma unroll
    for (int t = 0; t < TT; t++) {
        float v = jact ? qj * tanhf(__half2float(km[t*QQ + j]) + kb) : 0.f;
        #pragma unroll
        for (int o = 16; o; o >>= 1) v += __shfl_xor_sync(0xffffffffu, v, o);
        if (lane == 0 && warp < 7) atomicAdd(&sPool[t], v);
    }
    __syncthreads();

    if (tid == 0) {
        float m = sPool[0] * INV_SCALE;
        #pragma unroll
        for (int t = 1; t < TT; t++) m = fmaxf(m, sPool[t] * INV_SCALE);
        float ssum = 0.f;
        #pragma unroll
        for (int t = 0; t < TT; t++) { float e = __expf(sPool[t]*INV_SCALE - m); sW[t] = e; ssum += e; }
        float inv = 1.0f / ssum;
        #pragma unroll
        for (int t = 0; t < TT; t++) sW[t] *= inv;
    }
    __syncthreads();

    {
        int r = tid;
        const __half* vb = g_Val + (size_t)bci*TT*RR + r;
        float a2 = 0.f;
        #pragma unroll
        for (int t = 0; t < TT; t++) a2 = fmaf(sW[t], __half2float(vb[t*RR]), a2);
        g_rep[(size_t)bci*RR + r] = a2;
    }
}

// ---------------- mean + ltr ----------------
__global__ void k_fv(const float* __restrict__ ltr_w, const float* __restrict__ ltr_b) {
    __shared__ float red[256];
    int bc = blockIdx.x;
    int r = threadIdx.x;
    float ssum = 0.f;
    for (int i = 0; i < HIS; i++) ssum += g_rep[(size_t)(bc*HIS + i)*RR + r];
    red[r] = (ssum * (1.0f/HIS)) * ltr_w[r];
    __syncthreads();
    for (int off = 128; off; off >>= 1) {
        if (r < off) red[r] += red[r + off];
        __syncthreads();
    }
    if (r == 0) g_score[bc] = red[0] + ltr_b[0];
}

// ---------------- log_softmax ----------------
__global__ void k_out(float* __restrict__ out) {
    int b = threadIdx.x;
    if (b < BB) {
        float s[CDD];
        float m = -1e30f;
        #pragma unroll
        for (int c = 0; c < CDD; c++) { s[c] = g_score[b*CDD + c]; m = fmaxf(m, s[c]); }
        float ssum = 0.f;
        #pragma unroll
        for (int c = 0; c < CDD; c++) ssum += expf(s[c] - m);
        float lse = logf(ssum);
        #pragma unroll
        for (int c = 0; c < CDD; c++) out[b*CDD + c] = s[c] - m - lse;
    }
}

// ---------------- launch ----------------
extern "C" void kernel_launch(void* const* d_in, const int* in_sizes, int n_in,
                              void* d_out, int out_size) {
    const int*   cand  = (const int*)  d_in[0];
    const int*   clk   = (const int*)  d_in[1];
    const float* emb   = (const float*)d_in[2];
    const float* Wq_w  = (const float*)d_in[3];
    const float* Wv_w  = (const float*)d_in[4];
    const float* Wq_i  = (const float*)d_in[5];
    const float* Wv_i  = (const float*)d_in[6];
    const float* keyW  = (const float*)d_in[7];
    const float* keyb  = (const float*)d_in[8];
    const float* query = (const float*)d_in[9];
    const float* ltr_w = (const float*)d_in[10];
    const float* ltr_b = (const float*)d_in[11];
    float* out = (float*)d_out;

    cudaFuncSetAttribute(k_fuse_av, cudaFuncAttributeMaxDynamicSharedMemorySize,
                         K5_SMEM_FLOATS * sizeof(float));

    k_prep<<<NS + 65, 256>>>(cand, clk, emb, Wq_w, Wv_w, Wq_i, Wv_i);

    k_gA<<<1400, 256, GEMM_SMEM>>>();                       // words Q + words XV
    k_t128<7><<<dim3(1, 3, NS), 256, GEMM_SMEM>>>(nullptr); // words scores
    k_wattn2<<<dim3(NS, HH), 320>>>();

    k_gB<<<1190, 256, GEMM_SMEM>>>(Wq_i);                   // itrs Q + itrs V
    k_gC<<<1684, 256, GEMM_SMEM>>>();                       // diag + Sx1 + Sx2

    k_fuse_av<<<NBCI, 256, K5_SMEM_FLOATS * sizeof(float)>>>();
    k_t128<6><<<dim3(2, 321, 1), 256, GEMM_SMEM>>>(keyW);   // Kmat
    k_pool<<<NBCI, 256>>>(keyb, query);

    k_fv<<<NSC, 256>>>(ltr_w, ltr_b);
    k_out<<<1, 32>>>(out);
}

// round 14
// speedup vs baseline: 9.9807x; 1.0410x over previous
#include <cuda_runtime.h>
#include <cuda_fp16.h>
#include <math.h>
#include <stdint.h>

#define BB   4
#define CDD  5
#define HIS  50
#define LL   20
#define TT   41
#define EE   300
#define EEP  320
#define HH   16
#define VV   16
#define RR   256
#define QQ   200
#define NSC  (BB*CDD)        // 20
#define NSH  (BB*HIS)        // 200
#define NS   (NSC+NSH)       // 220
#define NTOK (NS*LL)         // 4400
#define NBCI (BB*CDD*HIS)    // 1000
#define MVAL (NBCI*TT)       // 41000
#define NQW  4800

#define INV_SCALE 0.057735026918962584f   // 1/sqrt(300)

// ---------------- device scratch ----------------
__device__ float  g_Xp[NTOK*EEP];
__device__ float  g_Wqall[EEP*NQW];
__device__ float  g_Wvp[EEP*RR];
__device__ float  g_Wvp2[RR*RR];
__device__ __half g_Qw[(size_t)NS*HH*LL*EEP];  // fp16; cols 300..319 stay zero (static init)
__device__ float  g_Sw[(size_t)NS*HH*LL*LL];
__device__ float  g_XV[NTOK*RR];
__device__ float  g_Rep[NS*LL*RR];
__device__ __half g_Q[(size_t)NS*HH*LL*RR];
__device__ float  g_V[NS*LL*RR];
__device__ __half g_q1h[HH*RR];
__device__ float  g_v1[RR];
__device__ float  g_ones[RR];
__device__ float  g_Scc[NSC*HH*21*21];
__device__ float  g_Shh[NSH*HH*21*21];
__device__ float  g_Sx1[(size_t)BB*HH*100*1000];
__device__ float  g_Sx2[(size_t)BB*HH*1000*100];
__device__ __half g_Val[(size_t)MVAL*RR];
__device__ __half g_Kmat[(size_t)MVAL*QQ];
__device__ float  g_rep[NBCI*RR];
__device__ float  g_score[NSC];

// ---------------- K0: merged prep ----------
__global__ void k_prep(const int* __restrict__ cand, const int* __restrict__ clk,
                       const float* __restrict__ emb,
                       const float* __restrict__ Wq_w, const float* __restrict__ Wv_w,
                       const float* __restrict__ Wq_i, const float* __restrict__ Wv_i) {
    int blk = blockIdx.x, tid = threadIdx.x;
    if (blk < NS) {
        const int* tok = (blk < NSC) ? (cand + blk*LL) : (clk + (blk-NSC)*LL);
        for (int idx = tid; idx < LL*EEP; idx += 256) {
            int t = idx / EEP, d = idx - t*EEP;
            g_Xp[(blk*LL + t)*EEP + d] = (d < EE) ? emb[(size_t)tok[t]*EE + d] : 0.f;
        }
    } else if (blk < NS + 16) {
        int h = blk - NS;
        for (int idx = tid; idx < EEP*EE; idx += 256) {
            int k = idx / EE, j = idx - k*EE;
            g_Wqall[(size_t)k*NQW + h*EE + j] =
                (k < EE) ? Wq_w[(size_t)h*EE*EE + (size_t)k*EE + j] : 0.f;
        }
    } else if (blk < NS + 32) {
        int part = blk - NS - 16;
        for (int q = 0; q < EEP*RR/(16*256); q++) {
            int idx = part*(EEP*RR/16) + q*256 + tid;
            int k = idx >> 8, col = idx & 255;
            int h = col >> 4, v = col & 15;
            g_Wvp[idx] = (k < EE) ? Wv_w[((size_t)h*EE + k)*VV + v] : 0.f;
        }
    } else if (blk < NS + 48) {
        int part = blk - NS - 32;
        for (int q = 0; q < RR*RR/(16*256); q++) {
            int idx = part*(RR*RR/16) + q*256 + tid;
            int r = idx >> 8, col = idx & 255;
            int h = col >> 4, v = col & 15;
            g_Wvp2[idx] = Wv_i[((size_t)h*RR + r)*VV + v];
        }
    } else if (blk < NS + 64) {
        int h = blk - NS - 48, j = tid;
        if (h == 0) g_ones[j] = 1.0f;
        float acc = 0.f;
        const float* w = Wq_i + (size_t)h*RR*RR + j;
        for (int r = 0; r < RR; r++) acc += w[r*RR];
        g_q1h[h*RR + j] = __float2half(acc);
    } else {
        int h = tid >> 4, v = tid & 15;
        float a2 = 0.f;
        const float* wv = Wv_i + (size_t)h*RR*VV + v;
        for (int r = 0; r < RR; r++) a2 += wv[r*VV];
        g_v1[h*VV + v] = a2;
    }
}

// ---------------- fp16 mma helpers ----------------
__device__ __forceinline__ void mma_f16(float c[4], const uint32_t a[4], const uint32_t b[2]) {
    asm volatile(
        "mma.sync.aligned.m16n8k16.row.col.f32.f16.f16.f32 "
        "{%0,%1,%2,%3}, {%4,%5,%6,%7}, {%8,%9}, {%0,%1,%2,%3};"
        : "+f"(c[0]), "+f"(c[1]), "+f"(c[2]), "+f"(c[3])
        : "r"(a[0]), "r"(a[1]), "r"(a[2]), "r"(a[3]), "r"(b[0]), "r"(b[1]));
}
__device__ __forceinline__ uint4 pack8h(float4 lo, float4 hi) {
    __half2 h0 = __floats2half2_rn(lo.x, lo.y);
    __half2 h1 = __floats2half2_rn(lo.z, lo.w);
    __half2 h2 = __floats2half2_rn(hi.x, hi.y);
    __half2 h3 = __floats2half2_rn(hi.z, hi.w);
    uint4 r;
    r.x = *(uint32_t*)&h0; r.y = *(uint32_t*)&h1;
    r.z = *(uint32_t*)&h2; r.w = *(uint32_t*)&h3;
    return r;
}

// ---------------- fp16 tensor-core GEMM (m16n8k16) ----------------
// MODE 0: Qw(h16)  = Xp @ Wqall   M=4400  N=4800 K=320  (38,35)
// MODE 1: Q (h16)  = Rep @ Wq_i   M=4400  N=256  K=256  (2,35,z=h16)
// MODE 2: XV       = Xp @ Wvp     M=4400  N=256  K=320  (2,35)
// MODE 3: V        = Rep @ Wvp2   M=4400  N=256  K=256  (2,35)
// MODE 4: Sx1      = Qc @ RepH^T  M=100   N=1000 K=256  (8,1,z=64)  A fp16
// MODE 5: Sx2      = Qh @ RepC^T  M=1000  N=100  K=256  (1,8,z=64)  A fp16
// MODE 6: Kmat(h16)= Val @ keyW   M=41000 N=200  K=256  (2,321)     A fp16
// MODE 7: Sw[s]    = Qw @ X^T     M=320   N=20   K=320  (1,3,z=220) NARROW, A fp16
// MODE 8: diag[s]                 M=336   N=21   K=256  (1,3,z=220) NARROW, A fp16, scalar st
#define BM 128
#define BN 128
#define BK 16
#define ASP 24                               // halves pitch (48B rows: 16B-aligned, conflict-free frags)
#define GEMM_SMEM ((2*BM*ASP + 2*BN*ASP)*2)  // 24576 B

template<int MODE>
__device__ __forceinline__ void gemm_body(const float* __restrict__ Bglob,
                                          int bxi, int byi, int bzi, __half* smh) {
    constexpr int K   = (MODE==0 || MODE==2 || MODE==7) ? EEP : RR;
    constexpr int M   = (MODE==4) ? 100 : (MODE==5 ? 1000 : (MODE==6 ? MVAL :
                        (MODE==7 ? 320 : (MODE==8 ? 336 : NTOK))));
    constexpr int N   = (MODE==0) ? NQW : (MODE==4 ? 1000 : (MODE==5 ? 100 :
                        (MODE==6 ? QQ : (MODE==7 ? 20 : (MODE==8 ? 21 : RR)))));
    constexpr bool BT = (MODE==4 || MODE==5 || MODE==7 || MODE==8);
    constexpr bool NARROW = (MODE==7 || MODE==8);
    constexpr bool AH = (MODE>=4);
    constexpr int LDB = (MODE==0) ? NQW : (MODE==6 ? QQ : RR);
    constexpr int NCH = K / BK;
    constexpr int NMT = NARROW ? 1 : 4;

    __half* AsB = smh;                 // [2][BM*ASP]
    __half* BsB = smh + 2*BM*ASP;      // [2][BN*ASP]

    const int tid = threadIdx.x;
    const int bz = bzi;
    const int nBase = bxi * BN;
    const int mBase = byi * BM;
    int b = 0, h = 0;
    if (MODE==1) h = bz;
    if (MODE==4 || MODE==5) { b = bz >> 4; h = bz & 15; }

    const int ar  = tid >> 1;          // row within tile (0..127)
    const int akq = (tid & 1) * 2;     // k-offset: halves 4*akq in {0, 8}
    const float*  ArowF = nullptr;
    const __half* ArowH = nullptr;
    {
        int am = mBase + ar;
        if (am < M) {
            if (MODE==0 || MODE==2) ArowF = g_Xp + (size_t)am*EEP;
            else if (MODE==1 || MODE==3) ArowF = g_Rep + (size_t)am*RR;
            else if (MODE==6) ArowH = g_Val + (size_t)am*RR;
            else if (MODE==7) ArowH = g_Qw + (size_t)(bz*320 + am)*EEP;
            else if (MODE==8) {
                int h8 = am / 21, t8 = am - 21*h8;
                ArowH = (t8 < 20) ? g_Q + (((size_t)bz*HH + h8)*LL + t8)*RR
                                  : g_q1h + (size_t)h8*RR;
            }
            else if (MODE==4) { int c = am/20, t = am - 20*c;
                ArowH = g_Q + (size_t)(((b*CDD + c)*HH + h)*LL + t)*RR; }
            else { int i = am/20, u = am - 20*i;
                ArowH = g_Q + (size_t)(((NSC + b*HIS + i)*HH + h)*LL + u)*RR; }
        }
    }
    const float* Brow = nullptr;
    const float* Bb = nullptr;
    int bkr = 0, bn1 = 0; bool bok1 = false, bok2 = false;
    if (BT) {
        int bn = nBase + ar;
        if (bn < N) {
            if (MODE==4)      Brow = g_Rep + ((size_t)(NSC + b*HIS)*LL + bn)*RR;
            else if (MODE==5) Brow = g_Rep + ((size_t)(b*CDD)*LL + bn)*RR;
            else if (MODE==7) Brow = g_Xp + ((size_t)bz*LL + bn)*EEP;
            else              Brow = (bn < 20) ? g_Rep + ((size_t)bz*LL + bn)*RR : g_ones;
        }
    } else {
        if (MODE==0) Bb = g_Wqall;
        else if (MODE==1) Bb = Bglob + (size_t)h*RR*RR;
        else if (MODE==2) Bb = g_Wvp;
        else if (MODE==3) Bb = g_Wvp2;
        else Bb = Bglob;   // MODE 6
        bkr = tid >> 4; bn1 = (tid & 15) * 4;
        bok1 = (nBase + bn1) < N;
        bok2 = (nBase + bn1 + 64) < N;
    }

    uint4 aRaw; float4 pb0, pb1;
    const float4 fz = make_float4(0.f, 0.f, 0.f, 0.f);
    const uint4 uz = make_uint4(0u, 0u, 0u, 0u);
    uint4 bRaw;   // BT path

    auto loadChunk = [&](int kc) {
        aRaw = uz; pb0 = fz; pb1 = fz; bRaw = uz;
        if (AH) {
            if (ArowH) aRaw = *(const uint4*)(ArowH + kc + 4*akq);
        } else if (ArowF) {
            float4 a0 = *(const float4*)(ArowF + kc + 4*akq);
            float4 a1 = *(const float4*)(ArowF + kc + 4*akq + 4);
            aRaw = pack8h(a0, a1);
        }
        if (BT) {
            if (Brow) {
                float4 b0 = *(const float4*)(Brow + kc + 4*akq);
                float4 b1 = *(const float4*)(Brow + kc + 4*akq + 4);
                bRaw = pack8h(b0, b1);
            }
        } else {
            if (bok1) pb0 = *(const float4*)(Bb + (size_t)(kc + bkr)*LDB + nBase + bn1);
            if (bok2) pb1 = *(const float4*)(Bb + (size_t)(kc + bkr)*LDB + nBase + bn1 + 64);
        }
    };
    auto storeChunk = [&](int buf) {
        __half* dA = AsB + buf*BM*ASP;
        __half* dB = BsB + buf*BN*ASP;
        *(uint4*)(dA + ar*ASP + 4*akq) = aRaw;     // 48B rows -> 16B-aligned
        if (BT) {
            *(uint4*)(dB + ar*ASP + 4*akq) = bRaw;
        } else {
            dB[(bn1+0)*ASP + bkr] = __float2half(pb0.x);
            dB[(bn1+1)*ASP + bkr] = __float2half(pb0.y);
            dB[(bn1+2)*ASP + bkr] = __float2half(pb0.z);
            dB[(bn1+3)*ASP + bkr] = __float2half(pb0.w);
            dB[(bn1+64)*ASP + bkr] = __float2half(pb1.x);
            dB[(bn1+65)*ASP + bkr] = __float2half(pb1.y);
            dB[(bn1+66)*ASP + bkr] = __float2half(pb1.z);
            dB[(bn1+67)*ASP + bkr] = __float2half(pb1.w);
        }
    };

    const int warp = tid >> 5, lane = tid & 31;
    const int wm = NARROW ? warp*16 : (warp >> 2)*64;
    const int wn = NARROW ? 0 : (warp & 3)*32;
    const int g = lane >> 2, tig = lane & 3;

    float c[NMT][4][4];
    #pragma unroll
    for (int mt = 0; mt < NMT; mt++)
        #pragma unroll
        for (int nt = 0; nt < 4; nt++)
            #pragma unroll
            for (int e = 0; e < 4; e++) c[mt][nt][e] = 0.f;

    loadChunk(0); storeChunk(0); __syncthreads();

    for (int ch = 0; ch < NCH; ch++) {
        int cur = ch & 1;
        if (ch + 1 < NCH) loadChunk((ch + 1) * BK);
        const __half* pA = AsB + cur*BM*ASP;
        const __half* pB = BsB + cur*BN*ASP;
        uint32_t af[NMT][4], bf[4][2];
        #pragma unroll
        for (int mt = 0; mt < NMT; mt++) {
            const __half* r0 = pA + (wm + mt*16 + g)*ASP + 2*tig;
            const __half* r1 = pA + (wm + mt*16 + g + 8)*ASP + 2*tig;
            af[mt][0] = *(const uint32_t*)r0;
            af[mt][1] = *(const uint32_t*)r1;
            af[mt][2] = *(const uint32_t*)(r0 + 8);
            af[mt][3] = *(const uint32_t*)(r1 + 8);
        }
        #pragma unroll
        for (int nt = 0; nt < 4; nt++) {
            const __half* rb = pB + (wn + nt*8 + g)*ASP + 2*tig;
            bf[nt][0] = *(const uint32_t*)rb;
            bf[nt][1] = *(const uint32_t*)(rb + 8);
        }
        #pragma unroll
        for (int mt = 0; mt < NMT; mt++)
            #pragma unroll
            for (int nt = 0; nt < 4; nt++)
                mma_f16(c[mt][nt], af[mt], bf[nt]);
        if (ch + 1 < NCH) { storeChunk(cur ^ 1); __syncthreads(); }
    }

    // ---- epilogue (identical C layout to tf32 m16n8k8) ----
    #pragma unroll
    for (int mt = 0; mt < NMT; mt++) {
        #pragma unroll
        for (int half = 0; half < 2; half++) {
            int row = mBase + wm + mt*16 + g + half*8;
            if (row >= M) continue;
            if (MODE==0) {
                int s = row/20, t = row - 20*s;
                __half* obase = g_Qw + ((size_t)(s*HH))*LL*EEP + (size_t)t*EEP;
                #pragma unroll
                for (int nt = 0; nt < 4; nt++) {
                    int col = nBase + wn + nt*8 + 2*tig;
                    if (col < NQW) {
                        int hh = col / 300;
                        int jj = col - 300*hh;
                        *(__half2*)(obase + (size_t)hh*LL*EEP + jj) =
                            __floats2half2_rn(c[mt][nt][half*2], c[mt][nt][half*2 + 1]);
                    }
                }
                continue;
            }
            if (MODE==1 || MODE==6) {
                __half* oh;
                if (MODE==1) { int s = row/20, t = row - 20*s;
                    oh = g_Q + ((size_t)(s*HH + h)*LL + t)*RR; }
                else oh = g_Kmat + (size_t)row*QQ;
                #pragma unroll
                for (int nt = 0; nt < 4; nt++) {
                    int col = nBase + wn + nt*8 + 2*tig;
                    if (col < N)
                        *(__half2*)(oh + col) =
                            __floats2half2_rn(c[mt][nt][half*2], c[mt][nt][half*2 + 1]);
                }
                continue;
            }
            float* o;
            if (MODE==2) o = g_XV + (size_t)row*RR;
            else if (MODE==3) o = g_V + (size_t)row*RR;
            else if (MODE==7) o = g_Sw + (size_t)bz*(HH*LL*LL) + (size_t)row*20;
            else if (MODE==8) {
                int h8 = row/21, t8 = row - 21*h8;
                float* base = (bz < NSC) ? g_Scc + ((size_t)bz*HH + h8)*441
                                         : g_Shh + ((size_t)(bz-NSC)*HH + h8)*441;
                o = base + t8*21;
            }
            else if (MODE==4) o = g_Sx1 + (size_t)bz*100000 + (size_t)row*1000;
            else              o = g_Sx2 + (size_t)bz*100000 + (size_t)row*100;
            #pragma unroll
            for (int nt = 0; nt < 4; nt++) {
                int col = nBase + wn + nt*8 + 2*tig;
                float c0 = c[mt][nt][half*2], c1 = c[mt][nt][half*2 + 1];
                if (MODE==8) {
                    if (col < N)     o[col]     = c0;
                    if (col + 1 < N) o[col + 1] = c1;
                } else {
                    if (col < N) {
                        if (col + 1 < N) *(float2*)(o + col) = make_float2(c0, c1);
                        else o[col] = c0;
                    }
                }
            }
        }
    }
}

// ---- combo kernels (block-id dispatch) ----
__global__ void __launch_bounds__(256, 2)
k_gA() {   // mode0 (38x35=1330) + mode2 (2x35=70)
    extern __shared__ __align__(16) char smraw[];
    __half* sm = (__half*)smraw;
    int bid = blockIdx.x;
    if (bid < 1330) gemm_body<0>(nullptr, bid % 38, bid / 38, 0, sm);
    else { int r = bid - 1330; gemm_body<2>(nullptr, r % 2, r / 2, 0, sm); }
}
__global__ void __launch_bounds__(256, 2)
k_gB(const float* __restrict__ Wq_i) {   // mode1 (1120) + mode3 (70)
    extern __shared__ __align__(16) char smraw[];
    __half* sm = (__half*)smraw;
    int bid = blockIdx.x;
    if (bid < 1120) gemm_body<1>(Wq_i, bid % 2, (bid / 2) % 35, bid / 70, sm);
    else { int r = bid - 1120; gemm_body<3>(nullptr, r % 2, r / 2, 0, sm); }
}
__global__ void __launch_bounds__(256, 2)
k_gC() {   // mode8 (660) + mode4 (512) + mode5 (512)
    extern __shared__ __align__(16) char smraw[];
    __half* sm = (__half*)smraw;
    int bid = blockIdx.x;
    if (bid < 660) gemm_body<8>(nullptr, 0, bid % 3, bid / 3, sm);
    else if (bid < 660 + 512) { int r = bid - 660; gemm_body<4>(nullptr, r % 8, 0, r / 8, sm); }
    else { int r = bid - 1172; gemm_body<5>(nullptr, 0, r % 8, r / 8, sm); }
}
template<int MODE>
__global__ void __launch_bounds__(256, 2)
k_t128(const float* __restrict__ Bglob) {
    extern __shared__ __align__(16) char smraw[];
    __half* sm = (__half*)smraw;
    gemm_body<MODE>(Bglob, blockIdx.x, blockIdx.y, blockIdx.z, sm);
}

// ---------------- K2b: words softmax + A.XV ----------
__global__ void __launch_bounds__(320, 4)
k_wattn2() {
    __shared__ float S[20*21];
    __shared__ float XVs[20*16];
    int s = blockIdx.x, h = blockIdx.y, tid = threadIdx.x;

    for (int idx = tid; idx < 400; idx += 320) {
        int t = idx / 20, u = idx - 20*t;
        S[t*21 + u] = g_Sw[(size_t)s*(HH*LL*LL) + (size_t)(h*20 + t)*20 + u] * INV_SCALE;
    }
    {
        int u = tid >> 4, v = tid & 15;
        XVs[tid] = g_XV[((size_t)s*LL + u)*RR + h*VV + v];
    }
    __syncthreads();

    if (tid < LL) {
        float* row = S + tid*21;
        float m = row[0];
        #pragma unroll
        for (int u = 1; u < LL; u++) m = fmaxf(m, row[u]);
        float ssum = 0.f;
        #pragma unroll
        for (int u = 0; u < LL; u++) { float e = __expf(row[u] - m); row[u] = e; ssum += e; }
        float inv = 1.0f / ssum;
        #pragma unroll
        for (int u = 0; u < LL; u++) row[u] *= inv;
    }
    __syncthreads();

    {
        int t = tid >> 4, v = tid & 15;
        float acc = 0.f;
        #pragma unroll
        for (int u = 0; u < LL; u++) acc = fmaf(S[t*21 + u], XVs[u*16 + v], acc);
        g_Rep[((size_t)s*LL + t)*RR + h*VV + v] = acc;
    }
}

// ---------------- K5: fused softmax + AV -> g_Val (fp16 out) ----------
#define SC_VC   0
#define SC_VH   (SC_VC + LL*RR)
#define SC_V1   (SC_VH + LL*RR)
#define SC_S    (SC_V1 + RR)
#define K5_SMEM_FLOATS (SC_S + TT*TT + 15)

__global__ void __launch_bounds__(256, 4)
k_fuse_av() {
    extern __shared__ float sm[];
    float* sVc  = sm + SC_VC;
    float* sVh  = sm + SC_VH;
    float* sV1  = sm + SC_V1;
    float* sS   = sm + SC_S;

    int bci = blockIdx.x;
    int i   = bci % HIS;
    int bc  = bci / HIS;
    int b   = bc / CDD;
    int c   = bc - b*CDD;
    int sc  = bc;
    int sh  = NSC + b*HIS + i;

    int tid = threadIdx.x;
    int wrp = tid >> 5, ln = tid & 31;

    {
        const float4* gvc = (const float4*)(g_V + (size_t)sc*LL*RR);
        const float4* gvh = (const float4*)(g_V + (size_t)sh*LL*RR);
        float4* dVc = (float4*)sVc; float4* dVh = (float4*)sVh;
        for (int idx = tid; idx < LL*RR/4; idx += 256) { dVc[idx] = gvc[idx]; dVh[idx] = gvh[idx]; }
        if (tid < RR) sV1[tid] = g_v1[tid];
    }

    __half* valOut = g_Val + (size_t)bci*TT*RR;

    for (int h = 0; h < HH; h++) {
        const float* scc = g_Scc + ((size_t)bc*HH + h)*441;
        const float* shh = g_Shh + ((size_t)(b*HIS + i)*HH + h)*441;
        const float* sx1 = g_Sx1 + ((size_t)(b*HH + h))*100*1000;
        const float* sx2 = g_Sx2 + ((size_t)(b*HH + h))*1000*100;

        __syncthreads();
        for (int p = tid; p < TT*TT; p += 256) {
            int q = p / TT, k = p - q*TT;
            float v;
            if (q < LL) {
                if (k < LL)       v = __ldg(&scc[q*21 + k]);
                else if (k == LL) v = __ldg(&scc[q*21 + 20]);
                else              v = __ldg(&sx1[(size_t)(c*20 + q)*1000 + i*20 + (k-LL-1)]);
            } else if (q == LL) {
                if (k < LL)       v = __ldg(&scc[20*21 + k]);
                else if (k == LL) v = __ldg(&scc[20*21 + 20]);
                else              v = __ldg(&shh[20*21 + (k-LL-1)]);
            } else {
                int t = q - LL - 1;
                if (k < LL)       v = __ldg(&sx2[(size_t)(i*20 + t)*100 + c*20 + k]);
                else if (k == LL) v = __ldg(&shh[t*21 + 20]);
                else              v = __ldg(&shh[t*21 + (k-LL-1)]);
            }
            sS[p] = v * INV_SCALE;
        }
        __syncthreads();

        for (int q = wrp; q < TT; q += 8) {
            float* row = sS + q*TT;
            float v0 = row[ln];
            float v1 = (ln + 32 < TT) ? row[ln + 32] : -1e30f;
            float m = fmaxf(v0, v1);
            #pragma unroll
            for (int o = 16; o; o >>= 1) m = fmaxf(m, __shfl_xor_sync(0xffffffffu, m, o));
            float e0 = __expf(v0 - m);
            float e1 = (ln + 32 < TT) ? __expf(v1 - m) : 0.f;
            float ss = e0 + e1;
            #pragma unroll
            for (int o = 16; o; o >>= 1) ss += __shfl_xor_sync(0xffffffffu, ss, o);
            float inv = 1.0f / ss;
            row[ln] = e0 * inv;
            if (ln + 32 < TT) row[ln + 32] = e1 * inv;
        }
        __syncthreads();

        for (int p = tid; p < TT*VV; p += 256) {
            int q = p / VV, v = p - (p / VV)*VV;
            int col = h*VV + v;
            const float* arow = sS + q*TT;
            float acc = arow[LL] * sV1[col];
            #pragma unroll
            for (int k = 0; k < LL; k++) acc = fmaf(arow[k], sVc[k*RR + col], acc);
            #pragma unroll
            for (int k = 0; k < LL; k++) acc = fmaf(arow[LL+1+k], sVh[k*RR + col], acc);
            valOut[(size_t)q*RR + col] = __float2half(acc);
        }
    }
}

// ---------------- K6: pooling ----------------
__global__ void __launch_bounds__(256, 4)
k_pool(const float* __restrict__ keyb, const float* __restrict__ query) {
    __shared__ float sPool[48];
    __shared__ float sW[48];

    int bci = blockIdx.x, tid = threadIdx.x;
    int warp = tid >> 5, lane = tid & 31;

    if (tid < TT) sPool[tid] = 0.f;
    __syncthreads();

    int j = tid;
    bool jact = (j < QQ);
    float qj = jact ? query[j] : 0.f;
    float kb = jact ? keyb[j]  : 0.f;
    const __half* km = g_Kmat + (size_t)bci*TT*QQ;

    #pragma unroll
    for (int t = 0; t < TT; t++) {
        float v = jact ? qj * tanhf(__half2float(km[t*QQ + j]) + kb) : 0.f;
        #pragma unroll
        for (int o = 16; o; o >>= 1) v += __shfl_xor_sync(0xffffffffu, v, o);
        if (lane == 0 && warp < 7) atomicAdd(&sPool[t], v);
    }
    __syncthreads();

    if (tid == 0) {
        float m = sPool[0] * INV_SCALE;
        #pragma unroll
        for (int t = 1; t < TT; t++) m = fmaxf(m, sPool[t] * INV_SCALE);
        float ssum = 0.f;
        #pragma unroll
        for (int t = 0; t < TT; t++) { float e = __expf(sPool[t]*INV_SCALE - m); sW[t] = e; ssum += e; }
        float inv = 1.0f / ssum;
        #pragma unroll
        for (int t = 0; t < TT; t++) sW[t] *= inv;
    }
    __syncthreads();

    {
        int r = tid;
        const __half* vb = g_Val + (size_t)bci*TT*RR + r;
        float a2 = 0.f;
        #pragma unroll
        for (int t = 0; t < TT; t++) a2 = fmaf(sW[t], __half2float(vb[t*RR]), a2);
        g_rep[(size_t)bci*RR + r] = a2;
    }
}

// ---------------- mean + ltr ----------------
__global__ void k_fv(const float* __restrict__ ltr_w, const float* __restrict__ ltr_b) {
    __shared__ float red[256];
    int bc = blockIdx.x;
    int r = threadIdx.x;
    float ssum = 0.f;
    for (int i = 0; i < HIS; i++) ssum += g_rep[(size_t)(bc*HIS + i)*RR + r];
    red[r] = (ssum * (1.0f/HIS)) * ltr_w[r];
    __syncthreads();
    for (int off = 128; off; off >>= 1) {
        if (r < off) red[r] += red[r + off];
        __syncthreads();
    }
    if (r == 0) g_score[bc] = red[0] + ltr_b[0];
}

// ---------------- log_softmax ----------------
__global__ void k_out(float* __restrict__ out) {
    int b = threadIdx.x;
    if (b < BB) {
        float s[CDD];
        float m = -1e30f;
        #pragma unroll
        for (int c = 0; c < CDD; c++) { s[c] = g_score[b*CDD + c]; m = fmaxf(m, s[c]); }
        float ssum = 0.f;
        #pragma unroll
        for (int c = 0; c < CDD; c++) ssum += expf(s[c] - m);
        float lse = logf(ssum);
        #pragma unroll
        for (int c = 0; c < CDD; c++) out[b*CDD + c] = s[c] - m - lse;
    }
}

// ---------------- launch ----------------
extern "C" void kernel_launch(void* const* d_in, const int* in_sizes, int n_in,
                              void* d_out, int out_size) {
    const int*   cand  = (const int*)  d_in[0];
    const int*   clk   = (const int*)  d_in[1];
    const float* emb   = (const float*)d_in[2];
    const float* Wq_w  = (const float*)d_in[3];
    const float* Wv_w  = (const float*)d_in[4];
    const float* Wq_i  = (const float*)d_in[5];
    const float* Wv_i  = (const float*)d_in[6];
    const float* keyW  = (const float*)d_in[7];
    const float* keyb  = (const float*)d_in[8];
    const float* query = (const float*)d_in[9];
    const float* ltr_w = (const float*)d_in[10];
    const float* ltr_b = (const float*)d_in[11];
    float* out = (float*)d_out;

    cudaFuncSetAttribute(k_fuse_av, cudaFuncAttributeMaxDynamicSharedMemorySize,
                         K5_SMEM_FLOATS * sizeof(float));

    k_prep<<<NS + 65, 256>>>(cand, clk, emb, Wq_w, Wv_w, Wq_i, Wv_i);

    k_gA<<<1400, 256, GEMM_SMEM>>>();                       // words Q + words XV
    k_t128<7><<<dim3(1, 3, NS), 256, GEMM_SMEM>>>(nullptr); // words scores
    k_wattn2<<<dim3(NS, HH), 320>>>();

    k_gB<<<1190, 256, GEMM_SMEM>>>(Wq_i);                   // itrs Q + itrs V
    k_gC<<<1684, 256, GEMM_SMEM>>>();                       // diag + Sx1 + Sx2

    k_fuse_av<<<NBCI, 256, K5_SMEM_FLOATS * sizeof(float)>>>();
    k_t128<6><<<dim3(2, 321, 1), 256, GEMM_SMEM>>>(keyW);   // Kmat
    k_pool<<<NBCI, 256>>>(keyb, query);

    k_fv<<<NSC, 256>>>(ltr_w, ltr_b);
    k_out<<<1, 32>>>(out);
}

// round 15
// speedup vs baseline: 10.3735x; 1.0394x over previous
#include <cuda_runtime.h>
#include <cuda_fp16.h>
#include <math.h>
#include <stdint.h>

#define BB   4
#define CDD  5
#define HIS  50
#define LL   20
#define TT   41
#define EE   300
#define EEP  320
#define HH   16
#define VV   16
#define RR   256
#define QQ   200
#define NSC  (BB*CDD)        // 20
#define NSH  (BB*HIS)        // 200
#define NS   (NSC+NSH)       // 220
#define NTOK (NS*LL)         // 4400
#define NBCI (BB*CDD*HIS)    // 1000
#define MVAL (NBCI*TT)       // 41000
#define NQW  4800

#define INV_SCALE 0.057735026918962584f   // 1/sqrt(300)

// ---------------- device scratch ----------------
__device__ float  g_Xp[NTOK*EEP];
__device__ float  g_Wqall[EEP*NQW];
__device__ float  g_Wvp[EEP*RR];
__device__ float  g_Wvp2[RR*RR];
__device__ __half g_Qw[(size_t)NS*HH*LL*EEP];  // fp16; cols 300..319 stay zero (static init)
__device__ float  g_Sw[(size_t)NS*HH*LL*LL];
__device__ float  g_XV[NTOK*RR];
__device__ float  g_Rep[NS*LL*RR];
__device__ __half g_Q[(size_t)NS*HH*LL*RR];
__device__ float  g_V[NS*LL*RR];
__device__ __half g_q1h[HH*RR];
__device__ float  g_v1[RR];
__device__ float  g_ones[RR];
__device__ float  g_Scc[NSC*HH*21*21];
__device__ float  g_Shh[NSH*HH*21*21];
__device__ float  g_Sx1[(size_t)BB*HH*100*1000];
__device__ float  g_Sx2[(size_t)BB*HH*1000*100];
__device__ __half g_Val[(size_t)MVAL*RR];
__device__ __half g_Kmat[(size_t)MVAL*QQ];
__device__ float  g_rep[NBCI*RR];
__device__ float  g_score[NSC];

// ---------------- K0: merged prep ----------
__global__ void k_prep(const int* __restrict__ cand, const int* __restrict__ clk,
                       const float* __restrict__ emb,
                       const float* __restrict__ Wq_w, const float* __restrict__ Wv_w,
                       const float* __restrict__ Wq_i, const float* __restrict__ Wv_i) {
    int blk = blockIdx.x, tid = threadIdx.x;
    if (blk < NS) {
        const int* tok = (blk < NSC) ? (cand + blk*LL) : (clk + (blk-NSC)*LL);
        for (int idx = tid; idx < LL*EEP; idx += 256) {
            int t = idx / EEP, d = idx - t*EEP;
            g_Xp[(blk*LL + t)*EEP + d] = (d < EE) ? emb[(size_t)tok[t]*EE + d] : 0.f;
        }
    } else if (blk < NS + 16) {
        int h = blk - NS;
        for (int idx = tid; idx < EEP*EE; idx += 256) {
            int k = idx / EE, j = idx - k*EE;
            g_Wqall[(size_t)k*NQW + h*EE + j] =
                (k < EE) ? Wq_w[(size_t)h*EE*EE + (size_t)k*EE + j] : 0.f;
        }
    } else if (blk < NS + 32) {
        int part = blk - NS - 16;
        for (int q = 0; q < EEP*RR/(16*256); q++) {
            int idx = part*(EEP*RR/16) + q*256 + tid;
            int k = idx >> 8, col = idx & 255;
            int h = col >> 4, v = col & 15;
            g_Wvp[idx] = (k < EE) ? Wv_w[((size_t)h*EE + k)*VV + v] : 0.f;
        }
    } else if (blk < NS + 48) {
        int part = blk - NS - 32;
        for (int q = 0; q < RR*RR/(16*256); q++) {
            int idx = part*(RR*RR/16) + q*256 + tid;
            int r = idx >> 8, col = idx & 255;
            int h = col >> 4, v = col & 15;
            g_Wvp2[idx] = Wv_i[((size_t)h*RR + r)*VV + v];
        }
    } else if (blk < NS + 64) {
        int h = blk - NS - 48, j = tid;
        if (h == 0) g_ones[j] = 1.0f;
        float acc = 0.f;
        const float* w = Wq_i + (size_t)h*RR*RR + j;
        for (int r = 0; r < RR; r++) acc += w[r*RR];
        g_q1h[h*RR + j] = __float2half(acc);
    } else {
        int h = tid >> 4, v = tid & 15;
        float a2 = 0.f;
        const float* wv = Wv_i + (size_t)h*RR*VV + v;
        for (int r = 0; r < RR; r++) a2 += wv[r*VV];
        g_v1[h*VV + v] = a2;
    }
}

// ---------------- fp16 mma helpers ----------------
__device__ __forceinline__ void mma_f16(float c[4], const uint32_t a[4], const uint32_t b[2]) {
    asm volatile(
        "mma.sync.aligned.m16n8k16.row.col.f32.f16.f16.f32 "
        "{%0,%1,%2,%3}, {%4,%5,%6,%7}, {%8,%9}, {%0,%1,%2,%3};"
        : "+f"(c[0]), "+f"(c[1]), "+f"(c[2]), "+f"(c[3])
        : "r"(a[0]), "r"(a[1]), "r"(a[2]), "r"(a[3]), "r"(b[0]), "r"(b[1]));
}
__device__ __forceinline__ uint4 pack8h(float4 lo, float4 hi) {
    __half2 h0 = __floats2half2_rn(lo.x, lo.y);
    __half2 h1 = __floats2half2_rn(lo.z, lo.w);
    __half2 h2 = __floats2half2_rn(hi.x, hi.y);
    __half2 h3 = __floats2half2_rn(hi.z, hi.w);
    uint4 r;
    r.x = *(uint32_t*)&h0; r.y = *(uint32_t*)&h1;
    r.z = *(uint32_t*)&h2; r.w = *(uint32_t*)&h3;
    return r;
}

// ---------------- fp16 tensor-core GEMM (m16n8k16, 2-ahead pipelined) ----------
// MODE 0: Qw(h16)  = Xp @ Wqall   M=4400  N=4800 K=320  (38,35)
// MODE 1: Q (h16)  = Rep @ Wq_i   M=4400  N=256  K=256  (2,35,z=h16)
// MODE 2: XV       = Xp @ Wvp     M=4400  N=256  K=320  (2,35)
// MODE 3: V        = Rep @ Wvp2   M=4400  N=256  K=256  (2,35)
// MODE 4: Sx1      = Qc @ RepH^T  M=100   N=1000 K=256  (8,1,z=64)  A fp16
// MODE 5: Sx2      = Qh @ RepC^T  M=1000  N=100  K=256  (1,8,z=64)  A fp16
// MODE 6: Kmat(h16)= Val @ keyW   M=41000 N=200  K=256  (2,321)     A fp16
// MODE 7: Sw[s]    = Qw @ X^T     M=320   N=20   K=320  (1,3,z=220) NARROW, A fp16
// MODE 8: diag[s]                 M=336   N=21   K=256  (1,3,z=220) NARROW, A fp16, scalar st
#define BM 128
#define BN 128
#define BK 16
#define ASP 24                               // halves pitch (48B rows)
#define GEMM_SMEM ((2*BM*ASP + 2*BN*ASP)*2)  // 24576 B

template<int MODE>
__device__ __forceinline__ void gemm_body(const float* __restrict__ Bglob,
                                          int bxi, int byi, int bzi, __half* smh) {
    constexpr int K   = (MODE==0 || MODE==2 || MODE==7) ? EEP : RR;
    constexpr int M   = (MODE==4) ? 100 : (MODE==5 ? 1000 : (MODE==6 ? MVAL :
                        (MODE==7 ? 320 : (MODE==8 ? 336 : NTOK))));
    constexpr int N   = (MODE==0) ? NQW : (MODE==4 ? 1000 : (MODE==5 ? 100 :
                        (MODE==6 ? QQ : (MODE==7 ? 20 : (MODE==8 ? 21 : RR)))));
    constexpr bool BT = (MODE==4 || MODE==5 || MODE==7 || MODE==8);
    constexpr bool NARROW = (MODE==7 || MODE==8);
    constexpr bool AH = (MODE>=4);
    constexpr int LDB = (MODE==0) ? NQW : (MODE==6 ? QQ : RR);
    constexpr int NCH = K / BK;
    constexpr int NMT = NARROW ? 1 : 4;

    __half* AsB = smh;                 // [2][BM*ASP]
    __half* BsB = smh + 2*BM*ASP;      // [2][BN*ASP]

    const int tid = threadIdx.x;
    const int bz = bzi;
    const int nBase = bxi * BN;
    const int mBase = byi * BM;
    int b = 0, h = 0;
    if (MODE==1) h = bz;
    if (MODE==4 || MODE==5) { b = bz >> 4; h = bz & 15; }

    const int ar  = tid >> 1;
    const int akq = (tid & 1) * 2;
    const float*  ArowF = nullptr;
    const __half* ArowH = nullptr;
    {
        int am = mBase + ar;
        if (am < M) {
            if (MODE==0 || MODE==2) ArowF = g_Xp + (size_t)am*EEP;
            else if (MODE==1 || MODE==3) ArowF = g_Rep + (size_t)am*RR;
            else if (MODE==6) ArowH = g_Val + (size_t)am*RR;
            else if (MODE==7) ArowH = g_Qw + (size_t)(bz*320 + am)*EEP;
            else if (MODE==8) {
                int h8 = am / 21, t8 = am - 21*h8;
                ArowH = (t8 < 20) ? g_Q + (((size_t)bz*HH + h8)*LL + t8)*RR
                                  : g_q1h + (size_t)h8*RR;
            }
            else if (MODE==4) { int c = am/20, t = am - 20*c;
                ArowH = g_Q + (size_t)(((b*CDD + c)*HH + h)*LL + t)*RR; }
            else { int i = am/20, u = am - 20*i;
                ArowH = g_Q + (size_t)(((NSC + b*HIS + i)*HH + h)*LL + u)*RR; }
        }
    }
    const float* Brow = nullptr;
    const float* Bb = nullptr;
    int bkr = 0, bn1 = 0; bool bok1 = false, bok2 = false;
    if (BT) {
        int bn = nBase + ar;
        if (bn < N) {
            if (MODE==4)      Brow = g_Rep + ((size_t)(NSC + b*HIS)*LL + bn)*RR;
            else if (MODE==5) Brow = g_Rep + ((size_t)(b*CDD)*LL + bn)*RR;
            else if (MODE==7) Brow = g_Xp + ((size_t)bz*LL + bn)*EEP;
            else              Brow = (bn < 20) ? g_Rep + ((size_t)bz*LL + bn)*RR : g_ones;
        }
    } else {
        if (MODE==0) Bb = g_Wqall;
        else if (MODE==1) Bb = Bglob + (size_t)h*RR*RR;
        else if (MODE==2) Bb = g_Wvp;
        else if (MODE==3) Bb = g_Wvp2;
        else Bb = Bglob;   // MODE 6
        bkr = tid >> 4; bn1 = (tid & 15) * 4;
        bok1 = (nBase + bn1) < N;
        bok2 = (nBase + bn1 + 64) < N;
    }

    // two register staging sets (slot 0 / slot 1), names kept distinct for reg allocation
    uint4 aR0, aR1, bR0, bR1;
    float4 p00, p01, p10, p11;
    const float4 fz = make_float4(0.f, 0.f, 0.f, 0.f);
    const uint4 uz = make_uint4(0u, 0u, 0u, 0u);

    auto load0 = [&](int kc) {
        aR0 = uz; p00 = fz; p01 = fz; bR0 = uz;
        if (AH) { if (ArowH) aR0 = *(const uint4*)(ArowH + kc + 4*akq); }
        else if (ArowF) {
            float4 a0 = *(const float4*)(ArowF + kc + 4*akq);
            float4 a1 = *(const float4*)(ArowF + kc + 4*akq + 4);
            aR0 = pack8h(a0, a1);
        }
        if (BT) {
            if (Brow) {
                float4 b0 = *(const float4*)(Brow + kc + 4*akq);
                float4 b1 = *(const float4*)(Brow + kc + 4*akq + 4);
                bR0 = pack8h(b0, b1);
            }
        } else {
            if (bok1) p00 = *(const float4*)(Bb + (size_t)(kc + bkr)*LDB + nBase + bn1);
            if (bok2) p01 = *(const float4*)(Bb + (size_t)(kc + bkr)*LDB + nBase + bn1 + 64);
        }
    };
    auto load1 = [&](int kc) {
        aR1 = uz; p10 = fz; p11 = fz; bR1 = uz;
        if (AH) { if (ArowH) aR1 = *(const uint4*)(ArowH + kc + 4*akq); }
        else if (ArowF) {
            float4 a0 = *(const float4*)(ArowF + kc + 4*akq);
            float4 a1 = *(const float4*)(ArowF + kc + 4*akq + 4);
            aR1 = pack8h(a0, a1);
        }
        if (BT) {
            if (Brow) {
                float4 b0 = *(const float4*)(Brow + kc + 4*akq);
                float4 b1 = *(const float4*)(Brow + kc + 4*akq + 4);
                bR1 = pack8h(b0, b1);
            }
        } else {
            if (bok1) p10 = *(const float4*)(Bb + (size_t)(kc + bkr)*LDB + nBase + bn1);
            if (bok2) p11 = *(const float4*)(Bb + (size_t)(kc + bkr)*LDB + nBase + bn1 + 64);
        }
    };
    auto storeSlot = [&](int buf, uint4 aRv, uint4 bRv, float4 pb0, float4 pb1) {
        __half* dA = AsB + buf*BM*ASP;
        __half* dB = BsB + buf*BN*ASP;
        *(uint4*)(dA + ar*ASP + 4*akq) = aRv;
        if (BT) {
            *(uint4*)(dB + ar*ASP + 4*akq) = bRv;
        } else {
            dB[(bn1+0)*ASP + bkr] = __float2half(pb0.x);
            dB[(bn1+1)*ASP + bkr] = __float2half(pb0.y);
            dB[(bn1+2)*ASP + bkr] = __float2half(pb0.z);
            dB[(bn1+3)*ASP + bkr] = __float2half(pb0.w);
            dB[(bn1+64)*ASP + bkr] = __float2half(pb1.x);
            dB[(bn1+65)*ASP + bkr] = __float2half(pb1.y);
            dB[(bn1+66)*ASP + bkr] = __float2half(pb1.z);
            dB[(bn1+67)*ASP + bkr] = __float2half(pb1.w);
        }
    };

    const int warp = tid >> 5, lane = tid & 31;
    const int wm = NARROW ? warp*16 : (warp >> 2)*64;
    const int wn = NARROW ? 0 : (warp & 3)*32;
    const int g = lane >> 2, tig = lane & 3;

    float c[NMT][4][4];
    #pragma unroll
    for (int mt = 0; mt < NMT; mt++)
        #pragma unroll
        for (int nt = 0; nt < 4; nt++)
            #pragma unroll
            for (int e = 0; e < 4; e++) c[mt][nt][e] = 0.f;

    auto compute = [&](int buf) {
        const __half* pA = AsB + buf*BM*ASP;
        const __half* pB = BsB + buf*BN*ASP;
        uint32_t af[NMT][4], bf[4][2];
        #pragma unroll
        for (int mt = 0; mt < NMT; mt++) {
            const __half* r0 = pA + (wm + mt*16 + g)*ASP + 2*tig;
            const __half* r1 = pA + (wm + mt*16 + g + 8)*ASP + 2*tig;
            af[mt][0] = *(const uint32_t*)r0;
            af[mt][1] = *(const uint32_t*)r1;
            af[mt][2] = *(const uint32_t*)(r0 + 8);
            af[mt][3] = *(const uint32_t*)(r1 + 8);
        }
        #pragma unroll
        for (int nt = 0; nt < 4; nt++) {
            const __half* rb = pB + (wn + nt*8 + g)*ASP + 2*tig;
            bf[nt][0] = *(const uint32_t*)rb;
            bf[nt][1] = *(const uint32_t*)(rb + 8);
        }
        #pragma unroll
        for (int mt = 0; mt < NMT; mt++)
            #pragma unroll
            for (int nt = 0; nt < 4; nt++)
                mma_f16(c[mt][nt], af[mt], bf[nt]);
    };

    // prologue: chunks 0 (slot0) and 1 (slot1) in flight; store chunk 0
    load0(0);
    load1(BK);
    storeSlot(0, aR0, bR0, p00, p01);
    __syncthreads();

    // main loop, 2 chunks per iteration (NCH is even for all modes)
    for (int ch = 0; ch < NCH; ch += 2) {
        if (ch + 2 < NCH) load0((ch + 2) * BK);       // slot0 free (chunk ch already in smem)
        compute(0);
        if (ch + 1 < NCH) { storeSlot(1, aR1, bR1, p10, p11); __syncthreads(); }
        if (ch + 1 < NCH) {
            if (ch + 3 < NCH) load1((ch + 3) * BK);   // slot1 free
            compute(1);
            if (ch + 2 < NCH) { storeSlot(0, aR0, bR0, p00, p01); __syncthreads(); }
        }
    }

    // ---- epilogue (identical C layout) ----
    #pragma unroll
    for (int mt = 0; mt < NMT; mt++) {
        #pragma unroll
        for (int half = 0; half < 2; half++) {
            int row = mBase + wm + mt*16 + g + half*8;
            if (row >= M) continue;
            if (MODE==0) {
                int s = row/20, t = row - 20*s;
                __half* obase = g_Qw + ((size_t)(s*HH))*LL*EEP + (size_t)t*EEP;
                #pragma unroll
                for (int nt = 0; nt < 4; nt++) {
                    int col = nBase + wn + nt*8 + 2*tig;
                    if (col < NQW) {
                        int hh = col / 300;
                        int jj = col - 300*hh;
                        *(__half2*)(obase + (size_t)hh*LL*EEP + jj) =
                            __floats2half2_rn(c[mt][nt][half*2], c[mt][nt][half*2 + 1]);
                    }
                }
                continue;
            }
            if (MODE==1 || MODE==6) {
                __half* oh;
                if (MODE==1) { int s = row/20, t = row - 20*s;
                    oh = g_Q + ((size_t)(s*HH + h)*LL + t)*RR; }
                else oh = g_Kmat + (size_t)row*QQ;
                #pragma unroll
                for (int nt = 0; nt < 4; nt++) {
                    int col = nBase + wn + nt*8 + 2*tig;
                    if (col < N)
                        *(__half2*)(oh + col) =
                            __floats2half2_rn(c[mt][nt][half*2], c[mt][nt][half*2 + 1]);
                }
                continue;
            }
            float* o;
            if (MODE==2) o = g_XV + (size_t)row*RR;
            else if (MODE==3) o = g_V + (size_t)row*RR;
            else if (MODE==7) o = g_Sw + (size_t)bz*(HH*LL*LL) + (size_t)row*20;
            else if (MODE==8) {
                int h8 = row/21, t8 = row - 21*h8;
                float* base = (bz < NSC) ? g_Scc + ((size_t)bz*HH + h8)*441
                                         : g_Shh + ((size_t)(bz-NSC)*HH + h8)*441;
                o = base + t8*21;
            }
            else if (MODE==4) o = g_Sx1 + (size_t)bz*100000 + (size_t)row*1000;
            else              o = g_Sx2 + (size_t)bz*100000 + (size_t)row*100;
            #pragma unroll
            for (int nt = 0; nt < 4; nt++) {
                int col = nBase + wn + nt*8 + 2*tig;
                float c0 = c[mt][nt][half*2], c1 = c[mt][nt][half*2 + 1];
                if (MODE==8) {
                    if (col < N)     o[col]     = c0;
                    if (col + 1 < N) o[col + 1] = c1;
                } else {
                    if (col < N) {
                        if (col + 1 < N) *(float2*)(o + col) = make_float2(c0, c1);
                        else o[col] = c0;
                    }
                }
            }
        }
    }
}

// ---- combo kernels (block-id dispatch) ----
__global__ void __launch_bounds__(256, 2)
k_gA() {   // mode0 (38x35=1330) + mode2 (2x35=70)
    extern __shared__ __align__(16) char smraw[];
    __half* sm = (__half*)smraw;
    int bid = blockIdx.x;
    if (bid < 1330) gemm_body<0>(nullptr, bid % 38, bid / 38, 0, sm);
    else { int r = bid - 1330; gemm_body<2>(nullptr, r % 2, r / 2, 0, sm); }
}
__global__ void __launch_bounds__(256, 2)
k_gB(const float* __restrict__ Wq_i) {   // mode1 (1120) + mode3 (70)
    extern __shared__ __align__(16) char smraw[];
    __half* sm = (__half*)smraw;
    int bid = blockIdx.x;
    if (bid < 1120) gemm_body<1>(Wq_i, bid % 2, (bid / 2) % 35, bid / 70, sm);
    else { int r = bid - 1120; gemm_body<3>(nullptr, r % 2, r / 2, 0, sm); }
}
__global__ void __launch_bounds__(256, 2)
k_gC() {   // mode8 (660) + mode4 (512) + mode5 (512)
    extern __shared__ __align__(16) char smraw[];
    __half* sm = (__half*)smraw;
    int bid = blockIdx.x;
    if (bid < 660) gemm_body<8>(nullptr, 0, bid % 3, bid / 3, sm);
    else if (bid < 660 + 512) { int r = bid - 660; gemm_body<4>(nullptr, r % 8, 0, r / 8, sm); }
    else { int r = bid - 1172; gemm_body<5>(nullptr, 0, r % 8, r / 8, sm); }
}
template<int MODE>
__global__ void __launch_bounds__(256, 2)
k_t128(const float* __restrict__ Bglob) {
    extern __shared__ __align__(16) char smraw[];
    __half* sm = (__half*)smraw;
    gemm_body<MODE>(Bglob, blockIdx.x, blockIdx.y, blockIdx.z, sm);
}

// ---------------- K2b: words softmax + A.XV ----------
__global__ void __launch_bounds__(320, 4)
k_wattn2() {
    __shared__ float S[20*21];
    __shared__ float XVs[20*16];
    int s = blockIdx.x, h = blockIdx.y, tid = threadIdx.x;

    for (int idx = tid; idx < 400; idx += 320) {
        int t = idx / 20, u = idx - 20*t;
        S[t*21 + u] = g_Sw[(size_t)s*(HH*LL*LL) + (size_t)(h*20 + t)*20 + u] * INV_SCALE;
    }
    {
        int u = tid >> 4, v = tid & 15;
        XVs[tid] = g_XV[((size_t)s*LL + u)*RR + h*VV + v];
    }
    __syncthreads();

    if (tid < LL) {
        float* row = S + tid*21;
        float m = row[0];
        #pragma unroll
        for (int u = 1; u < LL; u++) m = fmaxf(m, row[u]);
        float ssum = 0.f;
        #pragma unroll
        for (int u = 0; u < LL; u++) { float e = __expf(row[u] - m); row[u] = e; ssum += e; }
        float inv = 1.0f / ssum;
        #pragma unroll
        for (int u = 0; u < LL; u++) row[u] *= inv;
    }
    __syncthreads();

    {
        int t = tid >> 4, v = tid & 15;
        float acc = 0.f;
        #pragma unroll
        for (int u = 0; u < LL; u++) acc = fmaf(S[t*21 + u], XVs[u*16 + v], acc);
        g_Rep[((size_t)s*LL + t)*RR + h*VV + v] = acc;
    }
}

// ---------------- K5: fused softmax + AV -> g_Val (fp16 out) ----------
#define SC_VC   0
#define SC_VH   (SC_VC + LL*RR)
#define SC_V1   (SC_VH + LL*RR)
#define SC_S    (SC_V1 + RR)
#define K5_SMEM_FLOATS (SC_S + TT*TT + 15)

__global__ void __launch_bounds__(256, 4)
k_fuse_av() {
    extern __shared__ float sm[];
    float* sVc  = sm + SC_VC;
    float* sVh  = sm + SC_VH;
    float* sV1  = sm + SC_V1;
    float* sS   = sm + SC_S;

    int bci = blockIdx.x;
    int i   = bci % HIS;
    int bc  = bci / HIS;
    int b   = bc / CDD;
    int c   = bc - b*CDD;
    int sc  = bc;
    int sh  = NSC + b*HIS + i;

    int tid = threadIdx.x;
    int wrp = tid >> 5, ln = tid & 31;

    {
        const float4* gvc = (const float4*)(g_V + (size_t)sc*LL*RR);
        const float4* gvh = (const float4*)(g_V + (size_t)sh*LL*RR);
        float4* dVc = (float4*)sVc; float4* dVh = (float4*)sVh;
        for (int idx = tid; idx < LL*RR/4; idx += 256) { dVc[idx] = gvc[idx]; dVh[idx] = gvh[idx]; }
        if (tid < RR) sV1[tid] = g_v1[tid];
    }

    // precompute gather descriptors for this thread's score elements
    int psrc[7], poff[7];
    #pragma unroll
    for (int r = 0; r < 7; r++) {
        int p = tid + 256*r;
        psrc[r] = -1; poff[r] = 0;
        if (p < TT*TT) {
            int q = p / TT, k = p - q*TT;
            if (q < LL) {
                if (k < LL)       { psrc[r] = 0; poff[r] = q*21 + k; }
                else if (k == LL) { psrc[r] = 0; poff[r] = q*21 + 20; }
                else              { psrc[r] = 2; poff[r] = (c*20 + q)*1000 + i*20 + (k - LL - 1); }
            } else if (q == LL) {
                if (k < LL)       { psrc[r] = 0; poff[r] = 20*21 + k; }
                else if (k == LL) { psrc[r] = 0; poff[r] = 20*21 + 20; }
                else              { psrc[r] = 1; poff[r] = 20*21 + (k - LL - 1); }
            } else {
                int t = q - LL - 1;
                if (k < LL)       { psrc[r] = 3; poff[r] = (i*20 + t)*100 + c*20 + k; }
                else if (k == LL) { psrc[r] = 1; poff[r] = t*21 + 20; }
                else              { psrc[r] = 1; poff[r] = t*21 + (k - LL - 1); }
            }
        }
    }

    __half* valOut = g_Val + (size_t)bci*TT*RR;

    for (int h = 0; h < HH; h++) {
        const float* scc = g_Scc + ((size_t)bc*HH + h)*441;
        const float* shh = g_Shh + ((size_t)(b*HIS + i)*HH + h)*441;
        const float* sx1 = g_Sx1 + ((size_t)(b*HH + h))*100*1000;
        const float* sx2 = g_Sx2 + ((size_t)(b*HH + h))*1000*100;

        __syncthreads();
        #pragma unroll
        for (int r = 0; r < 7; r++) {
            if (psrc[r] >= 0) {
                const float* bp = (psrc[r] == 0) ? scc :
                                  (psrc[r] == 1) ? shh :
                                  (psrc[r] == 2) ? sx1 : sx2;
                sS[tid + 256*r] = __ldg(bp + poff[r]) * INV_SCALE;
            }
        }
        __syncthreads();

        for (int q = wrp; q < TT; q += 8) {
            float* row = sS + q*TT;
            float v0 = row[ln];
            float v1 = (ln + 32 < TT) ? row[ln + 32] : -1e30f;
            float m = fmaxf(v0, v1);
            #pragma unroll
            for (int o = 16; o; o >>= 1) m = fmaxf(m, __shfl_xor_sync(0xffffffffu, m, o));
            float e0 = __expf(v0 - m);
            float e1 = (ln + 32 < TT) ? __expf(v1 - m) : 0.f;
            float ss = e0 + e1;
            #pragma unroll
            for (int o = 16; o; o >>= 1) ss += __shfl_xor_sync(0xffffffffu, ss, o);
            float inv = 1.0f / ss;
            row[ln] = e0 * inv;
            if (ln + 32 < TT) row[ln + 32] = e1 * inv;
        }
        __syncthreads();

        for (int p = tid; p < TT*VV; p += 256) {
            int q = p / VV, v = p - (p / VV)*VV;
            int col = h*VV + v;
            const float* arow = sS + q*TT;
            float acc = arow[LL] * sV1[col];
            #pragma unroll
            for (int k = 0; k < LL; k++) acc = fmaf(arow[k], sVc[k*RR + col], acc);
            #pragma unroll
            for (int k = 0; k < LL; k++) acc = fmaf(arow[LL+1+k], sVh[k*RR + col], acc);
            valOut[(size_t)q*RR + col] = __float2half(acc);
        }
    }
}

// ---------------- K6: pooling ----------------
__global__ void __launch_bounds__(256, 4)
k_pool(const float* __restrict__ keyb, const float* __restrict__ query) {
    __shared__ float sPool[48];
    __shared__ float sW[48];

    int bci = blockIdx.x, tid = threadIdx.x;
    int warp = tid >> 5, lane = tid & 31;

    if (tid < TT) sPool[tid] = 0.f;
    __syncthreads();

    int j = tid;
    bool jact = (j < QQ);
    float qj = jact ? query[j] : 0.f;
    float kb = jact ? keyb[j]  : 0.f;
    const __half* km = g_Kmat + (size_t)bci*TT*QQ;

    #pragma unroll
    for (int t = 0; t < TT; t++) {
        float v = jact ? qj * tanhf(__half2float(km[t*QQ + j]) + kb) : 0.f;
        #pragma unroll
        for (int o = 16; o; o >>= 1) v += __shfl_xor_sync(0xffffffffu, v, o);
        if (lane == 0 && warp < 7) atomicAdd(&sPool[t], v);
    }
    __syncthreads();

    if (tid == 0) {
        float m = sPool[0] * INV_SCALE;
        #pragma unroll
        for (int t = 1; t < TT; t++) m = fmaxf(m, sPool[t] * INV_SCALE);
        float ssum = 0.f;
        #pragma unroll
        for (int t = 0; t < TT; t++) { float e = __expf(sPool[t]*INV_SCALE - m); sW[t] = e; ssum += e; }
        float inv = 1.0f / ssum;
        #pragma unroll
        for (int t = 0; t < TT; t++) sW[t] *= inv;
    }
    __syncthreads();

    {
        int r = tid;
        const __half* vb = g_Val + (size_t)bci*TT*RR + r;
        float a2 = 0.f;
        #pragma unroll
        for (int t = 0; t < TT; t++) a2 = fmaf(sW[t], __half2float(vb[t*RR]), a2);
        g_rep[(size_t)bci*RR + r] = a2;
    }
}

// ---------------- mean + ltr ----------------
__global__ void k_fv(const float* __restrict__ ltr_w, const float* __restrict__ ltr_b) {
    __shared__ float red[256];
    int bc = blockIdx.x;
    int r = threadIdx.x;
    float ssum = 0.f;
    for (int i = 0; i < HIS; i++) ssum += g_rep[(size_t)(bc*HIS + i)*RR + r];
    red[r] = (ssum * (1.0f/HIS)) * ltr_w[r];
    __syncthreads();
    for (int off = 128; off; off >>= 1) {
        if (r < off) red[r] += red[r + off];
        __syncthreads();
    }
    if (r == 0) g_score[bc] = red[0] + ltr_b[0];
}

// ---------------- log_softmax ----------------
__global__ void k_out(float* __restrict__ out) {
    int b = threadIdx.x;
    if (b < BB) {
        float s[CDD];
        float m = -1e30f;
        #pragma unroll
        for (int c = 0; c < CDD; c++) { s[c] = g_score[b*CDD + c]; m = fmaxf(m, s[c]); }
        float ssum = 0.f;
        #pragma unroll
        for (int c = 0; c < CDD; c++) ssum += expf(s[c] - m);
        float lse = logf(ssum);
        #pragma unroll
        for (int c = 0; c < CDD; c++) out[b*CDD + c] = s[c] - m - lse;
    }
}

// ---------------- launch ----------------
extern "C" void kernel_launch(void* const* d_in, const int* in_sizes, int n_in,
                              void* d_out, int out_size) {
    const int*   cand  = (const int*)  d_in[0];
    const int*   clk   = (const int*)  d_in[1];
    const float* emb   = (const float*)d_in[2];
    const float* Wq_w  = (const float*)d_in[3];
    const float* Wv_w  = (const float*)d_in[4];
    const float* Wq_i  = (const float*)d_in[5];
    const float* Wv_i  = (const float*)d_in[6];
    const float* keyW  = (const float*)d_in[7];
    const float* keyb  = (const float*)d_in[8];
    const float* query = (const float*)d_in[9];
    const float* ltr_w = (const float*)d_in[10];
    const float* ltr_b = (const float*)d_in[11];
    float* out = (float*)d_out;

    cudaFuncSetAttribute(k_fuse_av, cudaFuncAttributeMaxDynamicSharedMemorySize,
                         K5_SMEM_FLOATS * sizeof(float));

    k_prep<<<NS + 65, 256>>>(cand, clk, emb, Wq_w, Wv_w, Wq_i, Wv_i);

    k_gA<<<1400, 256, GEMM_SMEM>>>();                       // words Q + words XV
    k_t128<7><<<dim3(1, 3, NS), 256, GEMM_SMEM>>>(nullptr); // words scores
    k_wattn2<<<dim3(NS, HH), 320>>>();

    k_gB<<<1190, 256, GEMM_SMEM>>>(Wq_i);                   // itrs Q + itrs V
    k_gC<<<1684, 256, GEMM_SMEM>>>();                       // diag + Sx1 + Sx2

    k_fuse_av<<<NBCI, 256, K5_SMEM_FLOATS * sizeof(float)>>>();
    k_t128<6><<<dim3(2, 321, 1), 256, GEMM_SMEM>>>(keyW);   // Kmat
    k_pool<<<NBCI, 256>>>(keyb, query);

    k_fv<<<NSC, 256>>>(ltr_w, ltr_b);
    k_out<<<1, 32>>>(out);
}

// round 16
// speedup vs baseline: 10.6204x; 1.0238x over previous
#include <cuda_runtime.h>
#include <cuda_fp16.h>
#include <math.h>
#include <stdint.h>

#define BB   4
#define CDD  5
#define HIS  50
#define LL   20
#define TT   41
#define EE   300
#define EEP  320
#define HH   16
#define VV   16
#define RR   256
#define QQ   200
#define NSC  (BB*CDD)        // 20
#define NSH  (BB*HIS)        // 200
#define NS   (NSC+NSH)       // 220
#define NTOK (NS*LL)         // 4400
#define NBCI (BB*CDD*HIS)    // 1000
#define MVAL (NBCI*TT)       // 41000
#define NQW  4800

#define INV_SCALE 0.057735026918962584f   // 1/sqrt(300)

// ---------------- device scratch ----------------
__device__ float  g_Xp[NTOK*EEP];
__device__ float  g_Wqall[EEP*NQW];
__device__ float  g_Wvp[EEP*RR];
__device__ float  g_Wvp2[RR*RR];
__device__ __half g_Qw[(size_t)NS*HH*LL*EEP];  // fp16; cols 300..319 stay zero (static init)
__device__ float  g_Sw[(size_t)NS*HH*LL*LL];
__device__ float  g_XV[NTOK*RR];
__device__ float  g_Rep[NS*LL*RR];
__device__ __half g_Q[(size_t)NS*HH*LL*RR];
__device__ float  g_V[NS*LL*RR];
__device__ __half g_q1h[HH*RR];
__device__ float  g_v1[RR];
__device__ float  g_ones[RR];
__device__ float  g_Scc[NSC*HH*21*21];
__device__ float  g_Shh[NSH*HH*21*21];
__device__ float  g_Sx1[(size_t)BB*HH*100*1000];
__device__ float  g_Sx2[(size_t)BB*HH*1000*100];
__device__ __half g_Val[(size_t)MVAL*RR];
__device__ __half g_Kmat[(size_t)MVAL*QQ];
__device__ float  g_rep[NBCI*RR];
__device__ float  g_score[NSC];

// ---------------- K0: merged prep ----------
__global__ void k_prep(const int* __restrict__ cand, const int* __restrict__ clk,
                       const float* __restrict__ emb,
                       const float* __restrict__ Wq_w, const float* __restrict__ Wv_w,
                       const float* __restrict__ Wq_i, const float* __restrict__ Wv_i) {
    int blk = blockIdx.x, tid = threadIdx.x;
    if (blk < NS) {
        const int* tok = (blk < NSC) ? (cand + blk*LL) : (clk + (blk-NSC)*LL);
        for (int idx = tid; idx < LL*EEP; idx += 256) {
            int t = idx / EEP, d = idx - t*EEP;
            g_Xp[(blk*LL + t)*EEP + d] = (d < EE) ? emb[(size_t)tok[t]*EE + d] : 0.f;
        }
    } else if (blk < NS + 16) {
        int h = blk - NS;
        for (int idx = tid; idx < EEP*EE; idx += 256) {
            int k = idx / EE, j = idx - k*EE;
            g_Wqall[(size_t)k*NQW + h*EE + j] =
                (k < EE) ? Wq_w[(size_t)h*EE*EE + (size_t)k*EE + j] : 0.f;
        }
    } else if (blk < NS + 32) {
        int part = blk - NS - 16;
        for (int q = 0; q < EEP*RR/(16*256); q++) {
            int idx = part*(EEP*RR/16) + q*256 + tid;
            int k = idx >> 8, col = idx & 255;
            int h = col >> 4, v = col & 15;
            g_Wvp[idx] = (k < EE) ? Wv_w[((size_t)h*EE + k)*VV + v] : 0.f;
        }
    } else if (blk < NS + 48) {
        int part = blk - NS - 32;
        for (int q = 0; q < RR*RR/(16*256); q++) {
            int idx = part*(RR*RR/16) + q*256 + tid;
            int r = idx >> 8, col = idx & 255;
            int h = col >> 4, v = col & 15;
            g_Wvp2[idx] = Wv_i[((size_t)h*RR + r)*VV + v];
        }
    } else if (blk < NS + 64) {
        int h = blk - NS - 48, j = tid;
        if (h == 0) g_ones[j] = 1.0f;
        float acc = 0.f;
        const float* w = Wq_i + (size_t)h*RR*RR + j;
        for (int r = 0; r < RR; r++) acc += w[r*RR];
        g_q1h[h*RR + j] = __float2half(acc);
    } else {
        int h = tid >> 4, v = tid & 15;
        float a2 = 0.f;
        const float* wv = Wv_i + (size_t)h*RR*VV + v;
        for (int r = 0; r < RR; r++) a2 += wv[r*VV];
        g_v1[h*VV + v] = a2;
    }
}

// ---------------- fp16 mma helpers ----------------
__device__ __forceinline__ void mma_f16(float c[4], const uint32_t a[4], const uint32_t b[2]) {
    asm volatile(
        "mma.sync.aligned.m16n8k16.row.col.f32.f16.f16.f32 "
        "{%0,%1,%2,%3}, {%4,%5,%6,%7}, {%8,%9}, {%0,%1,%2,%3};"
        : "+f"(c[0]), "+f"(c[1]), "+f"(c[2]), "+f"(c[3])
        : "r"(a[0]), "r"(a[1]), "r"(a[2]), "r"(a[3]), "r"(b[0]), "r"(b[1]));
}
__device__ __forceinline__ uint4 pack8h(float4 lo, float4 hi) {
    __half2 h0 = __floats2half2_rn(lo.x, lo.y);
    __half2 h1 = __floats2half2_rn(lo.z, lo.w);
    __half2 h2 = __floats2half2_rn(hi.x, hi.y);
    __half2 h3 = __floats2half2_rn(hi.z, hi.w);
    uint4 r;
    r.x = *(uint32_t*)&h0; r.y = *(uint32_t*)&h1;
    r.z = *(uint32_t*)&h2; r.w = *(uint32_t*)&h3;
    return r;
}
__device__ __forceinline__ float fast_tanh(float x) {
    x = fminf(fmaxf(x, -15.f), 15.f);
    float e = __expf(2.f * x);
    return (e - 1.f) / (e + 1.f);
}

// ---------------- fp16 tensor-core GEMM (m16n8k16, 2-ahead pipelined) ----------
// MODE 0: Qw(h16)  = Xp @ Wqall   M=4400  N=4800 K=320  (38,35)
// MODE 1: Q (h16)  = Rep @ Wq_i   M=4400  N=256  K=256  (2,35,z=h16)
// MODE 2: XV       = Xp @ Wvp     M=4400  N=256  K=320  (2,35)
// MODE 3: V        = Rep @ Wvp2   M=4400  N=256  K=256  (2,35)
// MODE 4: Sx1      = Qc @ RepH^T  M=100   N=1000 K=256  (8,1,z=64)  A fp16
// MODE 5: Sx2      = Qh @ RepC^T  M=1000  N=100  K=256  (1,8,z=64)  A fp16
// MODE 6: Kmat(h16)= Val @ keyW   M=41000 N=200  K=256  (2,321)     A fp16
// MODE 7: Sw[s]    = Qw @ X^T     M=320   N=20   K=320  (1,3,z=220) NARROW, A fp16
// MODE 8: diag[s]                 M=336   N=21   K=256  (1,3,z=220) NARROW, A fp16, scalar st
#define BM 128
#define BN 128
#define BK 16
#define ASP 24
#define GEMM_SMEM ((2*BM*ASP + 2*BN*ASP)*2)  // 24576 B

template<int MODE>
__device__ __forceinline__ void gemm_body(const float* __restrict__ Bglob,
                                          int bxi, int byi, int bzi, __half* smh) {
    constexpr int K   = (MODE==0 || MODE==2 || MODE==7) ? EEP : RR;
    constexpr int M   = (MODE==4) ? 100 : (MODE==5 ? 1000 : (MODE==6 ? MVAL :
                        (MODE==7 ? 320 : (MODE==8 ? 336 : NTOK))));
    constexpr int N   = (MODE==0) ? NQW : (MODE==4 ? 1000 : (MODE==5 ? 100 :
                        (MODE==6 ? QQ : (MODE==7 ? 20 : (MODE==8 ? 21 : RR)))));
    constexpr bool BT = (MODE==4 || MODE==5 || MODE==7 || MODE==8);
    constexpr bool NARROW = (MODE==7 || MODE==8);
    constexpr bool AH = (MODE>=4);
    constexpr int LDB = (MODE==0) ? NQW : (MODE==6 ? QQ : RR);
    constexpr int NCH = K / BK;
    constexpr int NMT = NARROW ? 1 : 4;

    __half* AsB = smh;
    __half* BsB = smh + 2*BM*ASP;

    const int tid = threadIdx.x;
    const int bz = bzi;
    const int nBase = bxi * BN;
    const int mBase = byi * BM;
    int b = 0, h = 0;
    if (MODE==1) h = bz;
    if (MODE==4 || MODE==5) { b = bz >> 4; h = bz & 15; }

    const int ar  = tid >> 1;
    const int akq = (tid & 1) * 2;
    const float*  ArowF = nullptr;
    const __half* ArowH = nullptr;
    {
        int am = mBase + ar;
        if (am < M) {
            if (MODE==0 || MODE==2) ArowF = g_Xp + (size_t)am*EEP;
            else if (MODE==1 || MODE==3) ArowF = g_Rep + (size_t)am*RR;
            else if (MODE==6) ArowH = g_Val + (size_t)am*RR;
            else if (MODE==7) ArowH = g_Qw + (size_t)(bz*320 + am)*EEP;
            else if (MODE==8) {
                int h8 = am / 21, t8 = am - 21*h8;
                ArowH = (t8 < 20) ? g_Q + (((size_t)bz*HH + h8)*LL + t8)*RR
                                  : g_q1h + (size_t)h8*RR;
            }
            else if (MODE==4) { int c = am/20, t = am - 20*c;
                ArowH = g_Q + (size_t)(((b*CDD + c)*HH + h)*LL + t)*RR; }
            else { int i = am/20, u = am - 20*i;
                ArowH = g_Q + (size_t)(((NSC + b*HIS + i)*HH + h)*LL + u)*RR; }
        }
    }
    const float* Brow = nullptr;
    const float* Bb = nullptr;
    int bkr = 0, bn1 = 0; bool bok1 = false, bok2 = false;
    if (BT) {
        int bn = nBase + ar;
        if (bn < N) {
            if (MODE==4)      Brow = g_Rep + ((size_t)(NSC + b*HIS)*LL + bn)*RR;
            else if (MODE==5) Brow = g_Rep + ((size_t)(b*CDD)*LL + bn)*RR;
            else if (MODE==7) Brow = g_Xp + ((size_t)bz*LL + bn)*EEP;
            else              Brow = (bn < 20) ? g_Rep + ((size_t)bz*LL + bn)*RR : g_ones;
        }
    } else {
        if (MODE==0) Bb = g_Wqall;
        else if (MODE==1) Bb = Bglob + (size_t)h*RR*RR;
        else if (MODE==2) Bb = g_Wvp;
        else if (MODE==3) Bb = g_Wvp2;
        else Bb = Bglob;   // MODE 6
        bkr = tid >> 4; bn1 = (tid & 15) * 4;
        bok1 = (nBase + bn1) < N;
        bok2 = (nBase + bn1 + 64) < N;
    }

    uint4 aR0, aR1, bR0, bR1;
    float4 p00, p01, p10, p11;
    const float4 fz = make_float4(0.f, 0.f, 0.f, 0.f);
    const uint4 uz = make_uint4(0u, 0u, 0u, 0u);

    auto load0 = [&](int kc) {
        aR0 = uz; p00 = fz; p01 = fz; bR0 = uz;
        if (AH) { if (ArowH) aR0 = *(const uint4*)(ArowH + kc + 4*akq); }
        else if (ArowF) {
            float4 a0 = *(const float4*)(ArowF + kc + 4*akq);
            float4 a1 = *(const float4*)(ArowF + kc + 4*akq + 4);
            aR0 = pack8h(a0, a1);
        }
        if (BT) {
            if (Brow) {
                float4 b0 = *(const float4*)(Brow + kc + 4*akq);
                float4 b1 = *(const float4*)(Brow + kc + 4*akq + 4);
                bR0 = pack8h(b0, b1);
            }
        } else {
            if (bok1) p00 = *(const float4*)(Bb + (size_t)(kc + bkr)*LDB + nBase + bn1);
            if (bok2) p01 = *(const float4*)(Bb + (size_t)(kc + bkr)*LDB + nBase + bn1 + 64);
        }
    };
    auto load1 = [&](int kc) {
        aR1 = uz; p10 = fz; p11 = fz; bR1 = uz;
        if (AH) { if (ArowH) aR1 = *(const uint4*)(ArowH + kc + 4*akq); }
        else if (ArowF) {
            float4 a0 = *(const float4*)(ArowF + kc + 4*akq);
            float4 a1 = *(const float4*)(ArowF + kc + 4*akq + 4);
            aR1 = pack8h(a0, a1);
        }
        if (BT) {
            if (Brow) {
                float4 b0 = *(const float4*)(Brow + kc + 4*akq);
                float4 b1 = *(const float4*)(Brow + kc + 4*akq + 4);
                bR1 = pack8h(b0, b1);
            }
        } else {
            if (bok1) p10 = *(const float4*)(Bb + (size_t)(kc + bkr)*LDB + nBase + bn1);
            if (bok2) p11 = *(const float4*)(Bb + (size_t)(kc + bkr)*LDB + nBase + bn1 + 64);
        }
    };
    auto storeSlot = [&](int buf, uint4 aRv, uint4 bRv, float4 pb0, float4 pb1) {
        __half* dA = AsB + buf*BM*ASP;
        __half* dB = BsB + buf*BN*ASP;
        *(uint4*)(dA + ar*ASP + 4*akq) = aRv;
        if (BT) {
            *(uint4*)(dB + ar*ASP + 4*akq) = bRv;
        } else {
            dB[(bn1+0)*ASP + bkr] = __float2half(pb0.x);
            dB[(bn1+1)*ASP + bkr] = __float2half(pb0.y);
            dB[(bn1+2)*ASP + bkr] = __float2half(pb0.z);
            dB[(bn1+3)*ASP + bkr] = __float2half(pb0.w);
            dB[(bn1+64)*ASP + bkr] = __float2half(pb1.x);
            dB[(bn1+65)*ASP + bkr] = __float2half(pb1.y);
            dB[(bn1+66)*ASP + bkr] = __float2half(pb1.z);
            dB[(bn1+67)*ASP + bkr] = __float2half(pb1.w);
        }
    };

    const int warp = tid >> 5, lane = tid & 31;
    const int wm = NARROW ? warp*16 : (warp >> 2)*64;
    const int wn = NARROW ? 0 : (warp & 3)*32;
    const int g = lane >> 2, tig = lane & 3;

    float c[NMT][4][4];
    #pragma unroll
    for (int mt = 0; mt < NMT; mt++)
        #pragma unroll
        for (int nt = 0; nt < 4; nt++)
            #pragma unroll
            for (int e = 0; e < 4; e++) c[mt][nt][e] = 0.f;

    auto compute = [&](int buf) {
        const __half* pA = AsB + buf*BM*ASP;
        const __half* pB = BsB + buf*BN*ASP;
        uint32_t af[NMT][4], bf[4][2];
        #pragma unroll
        for (int mt = 0; mt < NMT; mt++) {
            const __half* r0 = pA + (wm + mt*16 + g)*ASP + 2*tig;
            const __half* r1 = pA + (wm + mt*16 + g + 8)*ASP + 2*tig;
            af[mt][0] = *(const uint32_t*)r0;
            af[mt][1] = *(const uint32_t*)r1;
            af[mt][2] = *(const uint32_t*)(r0 + 8);
            af[mt][3] = *(const uint32_t*)(r1 + 8);
        }
        #pragma unroll
        for (int nt = 0; nt < 4; nt++) {
            const __half* rb = pB + (wn + nt*8 + g)*ASP + 2*tig;
            bf[nt][0] = *(const uint32_t*)rb;
            bf[nt][1] = *(const uint32_t*)(rb + 8);
        }
        #pragma unroll
        for (int mt = 0; mt < NMT; mt++)
            #pragma unroll
            for (int nt = 0; nt < 4; nt++)
                mma_f16(c[mt][nt], af[mt], bf[nt]);
    };

    load0(0);
    load1(BK);
    storeSlot(0, aR0, bR0, p00, p01);
    __syncthreads();

    for (int ch = 0; ch < NCH; ch += 2) {
        if (ch + 2 < NCH) load0((ch + 2) * BK);
        compute(0);
        if (ch + 1 < NCH) { storeSlot(1, aR1, bR1, p10, p11); __syncthreads(); }
        if (ch + 1 < NCH) {
            if (ch + 3 < NCH) load1((ch + 3) * BK);
            compute(1);
            if (ch + 2 < NCH) { storeSlot(0, aR0, bR0, p00, p01); __syncthreads(); }
        }
    }

    // ---- epilogue ----
    #pragma unroll
    for (int mt = 0; mt < NMT; mt++) {
        #pragma unroll
        for (int half = 0; half < 2; half++) {
            int row = mBase + wm + mt*16 + g + half*8;
            if (row >= M) continue;
            if (MODE==0) {
                int s = row/20, t = row - 20*s;
                __half* obase = g_Qw + ((size_t)(s*HH))*LL*EEP + (size_t)t*EEP;
                #pragma unroll
                for (int nt = 0; nt < 4; nt++) {
                    int col = nBase + wn + nt*8 + 2*tig;
                    if (col < NQW) {
                        int hh = col / 300;
                        int jj = col - 300*hh;
                        *(__half2*)(obase + (size_t)hh*LL*EEP + jj) =
                            __floats2half2_rn(c[mt][nt][half*2], c[mt][nt][half*2 + 1]);
                    }
                }
                continue;
            }
            if (MODE==1 || MODE==6) {
                __half* oh;
                if (MODE==1) { int s = row/20, t = row - 20*s;
                    oh = g_Q + ((size_t)(s*HH + h)*LL + t)*RR; }
                else oh = g_Kmat + (size_t)row*QQ;
                #pragma unroll
                for (int nt = 0; nt < 4; nt++) {
                    int col = nBase + wn + nt*8 + 2*tig;
                    if (col < N)
                        *(__half2*)(oh + col) =
                            __floats2half2_rn(c[mt][nt][half*2], c[mt][nt][half*2 + 1]);
                }
                continue;
            }
            float* o;
            if (MODE==2) o = g_XV + (size_t)row*RR;
            else if (MODE==3) o = g_V + (size_t)row*RR;
            else if (MODE==7) o = g_Sw + (size_t)bz*(HH*LL*LL) + (size_t)row*20;
            else if (MODE==8) {
                int h8 = row/21, t8 = row - 21*h8;
                float* base = (bz < NSC) ? g_Scc + ((size_t)bz*HH + h8)*441
                                         : g_Shh + ((size_t)(bz-NSC)*HH + h8)*441;
                o = base + t8*21;
            }
            else if (MODE==4) o = g_Sx1 + (size_t)bz*100000 + (size_t)row*1000;
            else              o = g_Sx2 + (size_t)bz*100000 + (size_t)row*100;
            #pragma unroll
            for (int nt = 0; nt < 4; nt++) {
                int col = nBase + wn + nt*8 + 2*tig;
                float c0 = c[mt][nt][half*2], c1 = c[mt][nt][half*2 + 1];
                if (MODE==8) {
                    if (col < N)     o[col]     = c0;
                    if (col + 1 < N) o[col + 1] = c1;
                } else {
                    if (col < N) {
                        if (col + 1 < N) *(float2*)(o + col) = make_float2(c0, c1);
                        else o[col] = c0;
                    }
                }
            }
        }
    }
}

// ---- combo kernels ----
__global__ void __launch_bounds__(256, 2)
k_gA() {
    extern __shared__ __align__(16) char smraw[];
    __half* sm = (__half*)smraw;
    int bid = blockIdx.x;
    if (bid < 1330) gemm_body<0>(nullptr, bid % 38, bid / 38, 0, sm);
    else { int r = bid - 1330; gemm_body<2>(nullptr, r % 2, r / 2, 0, sm); }
}
__global__ void __launch_bounds__(256, 2)
k_gB(const float* __restrict__ Wq_i) {
    extern __shared__ __align__(16) char smraw[];
    __half* sm = (__half*)smraw;
    int bid = blockIdx.x;
    if (bid < 1120) gemm_body<1>(Wq_i, bid % 2, (bid / 2) % 35, bid / 70, sm);
    else { int r = bid - 1120; gemm_body<3>(nullptr, r % 2, r / 2, 0, sm); }
}
__global__ void __launch_bounds__(256, 2)
k_gC() {
    extern __shared__ __align__(16) char smraw[];
    __half* sm = (__half*)smraw;
    int bid = blockIdx.x;
    if (bid < 660) gemm_body<8>(nullptr, 0, bid % 3, bid / 3, sm);
    else if (bid < 660 + 512) { int r = bid - 660; gemm_body<4>(nullptr, r % 8, 0, r / 8, sm); }
    else { int r = bid - 1172; gemm_body<5>(nullptr, 0, r % 8, r / 8, sm); }
}
template<int MODE>
__global__ void __launch_bounds__(256, 2)
k_t128(const float* __restrict__ Bglob) {
    extern __shared__ __align__(16) char smraw[];
    __half* sm = (__half*)smraw;
    gemm_body<MODE>(Bglob, blockIdx.x, blockIdx.y, blockIdx.z, sm);
}

// ---------------- K2b: words softmax + A.XV ----------
__global__ void __launch_bounds__(320, 4)
k_wattn2() {
    __shared__ float S[20*21];
    __shared__ float XVs[20*16];
    int s = blockIdx.x, h = blockIdx.y, tid = threadIdx.x;

    for (int idx = tid; idx < 400; idx += 320) {
        int t = idx / 20, u = idx - 20*t;
        S[t*21 + u] = g_Sw[(size_t)s*(HH*LL*LL) + (size_t)(h*20 + t)*20 + u] * INV_SCALE;
    }
    {
        int u = tid >> 4, v = tid & 15;
        XVs[tid] = g_XV[((size_t)s*LL + u)*RR + h*VV + v];
    }
    __syncthreads();

    if (tid < LL) {
        float* row = S + tid*21;
        float m = row[0];
        #pragma unroll
        for (int u = 1; u < LL; u++) m = fmaxf(m, row[u]);
        float ssum = 0.f;
        #pragma unroll
        for (int u = 0; u < LL; u++) { float e = __expf(row[u] - m); row[u] = e; ssum += e; }
        float inv = 1.0f / ssum;
        #pragma unroll
        for (int u = 0; u < LL; u++) row[u] *= inv;
    }
    __syncthreads();

    {
        int t = tid >> 4, v = tid & 15;
        float acc = 0.f;
        #pragma unroll
        for (int u = 0; u < LL; u++) acc = fmaf(S[t*21 + u], XVs[u*16 + v], acc);
        g_Rep[((size_t)s*LL + t)*RR + h*VV + v] = acc;
    }
}

// ---------------- K5: fused softmax + AV -> g_Val (fp16 out, float4 AV) ----------
#define SC_VC   0
#define SC_VH   (SC_VC + LL*RR)
#define SC_V1   (SC_VH + LL*RR)
#define SC_S    (SC_V1 + RR)
#define K5_SMEM_FLOATS (SC_S + TT*TT + 15)

__global__ void __launch_bounds__(256, 4)
k_fuse_av() {
    extern __shared__ float sm[];
    float* sVc  = sm + SC_VC;
    float* sVh  = sm + SC_VH;
    float* sV1  = sm + SC_V1;
    float* sS   = sm + SC_S;

    int bci = blockIdx.x;
    int i   = bci % HIS;
    int bc  = bci / HIS;
    int b   = bc / CDD;
    int c   = bc - b*CDD;
    int sc  = bc;
    int sh  = NSC + b*HIS + i;

    int tid = threadIdx.x;
    int wrp = tid >> 5, ln = tid & 31;

    {
        const float4* gvc = (const float4*)(g_V + (size_t)sc*LL*RR);
        const float4* gvh = (const float4*)(g_V + (size_t)sh*LL*RR);
        float4* dVc = (float4*)sVc; float4* dVh = (float4*)sVh;
        for (int idx = tid; idx < LL*RR/4; idx += 256) { dVc[idx] = gvc[idx]; dVh[idx] = gvh[idx]; }
        if (tid < RR) sV1[tid] = g_v1[tid];
    }

    // precompute gather descriptors
    int psrc[7], poff[7];
    #pragma unroll
    for (int r = 0; r < 7; r++) {
        int p = tid + 256*r;
        psrc[r] = -1; poff[r] = 0;
        if (p < TT*TT) {
            int q = p / TT, k = p - q*TT;
            if (q < LL) {
                if (k < LL)       { psrc[r] = 0; poff[r] = q*21 + k; }
                else if (k == LL) { psrc[r] = 0; poff[r] = q*21 + 20; }
                else              { psrc[r] = 2; poff[r] = (c*20 + q)*1000 + i*20 + (k - LL - 1); }
            } else if (q == LL) {
                if (k < LL)       { psrc[r] = 0; poff[r] = 20*21 + k; }
                else if (k == LL) { psrc[r] = 0; poff[r] = 20*21 + 20; }
                else              { psrc[r] = 1; poff[r] = 20*21 + (k - LL - 1); }
            } else {
                int t = q - LL - 1;
                if (k < LL)       { psrc[r] = 3; poff[r] = (i*20 + t)*100 + c*20 + k; }
                else if (k == LL) { psrc[r] = 1; poff[r] = t*21 + 20; }
                else              { psrc[r] = 1; poff[r] = t*21 + (k - LL - 1); }
            }
        }
    }

    __half* valOut = g_Val + (size_t)bci*TT*RR;
    // AV thread mapping: tid < 164 handles (q = tid>>2, col-group = tid&3)
    const int avq = tid >> 2, avg = tid & 3;
    const bool avact = (tid < TT*4);

    for (int h = 0; h < HH; h++) {
        const float* scc = g_Scc + ((size_t)bc*HH + h)*441;
        const float* shh = g_Shh + ((size_t)(b*HIS + i)*HH + h)*441;
        const float* sx1 = g_Sx1 + ((size_t)(b*HH + h))*100*1000;
        const float* sx2 = g_Sx2 + ((size_t)(b*HH + h))*1000*100;

        __syncthreads();
        #pragma unroll
        for (int r = 0; r < 7; r++) {
            if (psrc[r] >= 0) {
                const float* bp = (psrc[r] == 0) ? scc :
                                  (psrc[r] == 1) ? shh :
                                  (psrc[r] == 2) ? sx1 : sx2;
                sS[tid + 256*r] = __ldg(bp + poff[r]) * INV_SCALE;
            }
        }
        __syncthreads();

        for (int q = wrp; q < TT; q += 8) {
            float* row = sS + q*TT;
            float v0 = row[ln];
            float v1 = (ln + 32 < TT) ? row[ln + 32] : -1e30f;
            float m = fmaxf(v0, v1);
            #pragma unroll
            for (int o = 16; o; o >>= 1) m = fmaxf(m, __shfl_xor_sync(0xffffffffu, m, o));
            float e0 = __expf(v0 - m);
            float e1 = (ln + 32 < TT) ? __expf(v1 - m) : 0.f;
            float ss = e0 + e1;
            #pragma unroll
            for (int o = 16; o; o >>= 1) ss += __shfl_xor_sync(0xffffffffu, ss, o);
            float inv = 1.0f / ss;
            row[ln] = e0 * inv;
            if (ln + 32 < TT) row[ln + 32] = e1 * inv;
        }
        __syncthreads();

        if (avact) {
            int col = h*VV + avg*4;
            const float* arow = sS + avq*TT;
            float a20 = arow[LL];
            float4 v1v = *(const float4*)(sV1 + col);
            float ax = a20*v1v.x, ay = a20*v1v.y, az = a20*v1v.z, aw = a20*v1v.w;
            #pragma unroll
            for (int k = 0; k < LL; k++) {
                float ak = arow[k];
                float4 vc = *(const float4*)(sVc + k*RR + col);
                ax = fmaf(ak, vc.x, ax); ay = fmaf(ak, vc.y, ay);
                az = fmaf(ak, vc.z, az); aw = fmaf(ak, vc.w, aw);
            }
            #pragma unroll
            for (int k = 0; k < LL; k++) {
                float ak = arow[LL+1+k];
                float4 vh = *(const float4*)(sVh + k*RR + col);
                ax = fmaf(ak, vh.x, ax); ay = fmaf(ak, vh.y, ay);
                az = fmaf(ak, vh.z, az); aw = fmaf(ak, vh.w, aw);
            }
            __half2 h01 = __floats2half2_rn(ax, ay);
            __half2 h23 = __floats2half2_rn(az, aw);
            uint2 packed;
            packed.x = *(uint32_t*)&h01; packed.y = *(uint32_t*)&h23;
            *(uint2*)(valOut + (size_t)avq*RR + col) = packed;
        }
    }
}

// ---------------- K6: pooling (fast tanh) ----------------
__global__ void __launch_bounds__(256, 4)
k_pool(const float* __restrict__ keyb, const float* __restrict__ query) {
    __shared__ float sPool[48];
    __shared__ float sW[48];

    int bci = blockIdx.x, tid = threadIdx.x;
    int warp = tid >> 5, lane = tid & 31;

    if (tid < TT) sPool[tid] = 0.f;
    __syncthreads();

    int j = tid;
    bool jact = (j < QQ);
    float qj = jact ? query[j] : 0.f;
    float kb = jact ? keyb[j]  : 0.f;
    const __half* km = g_Kmat + (size_t)bci*TT*QQ;

    #pragma unroll
    for (int t = 0; t < TT; t++) {
        float v = jact ? qj * fast_tanh(__half2float(km[t*QQ + j]) + kb) : 0.f;
        #pragma unroll
        for (int o = 16; o; o >>= 1) v += __shfl_xor_sync(0xffffffffu, v, o);
        if (lane == 0 && warp < 7) atomicAdd(&sPool[t], v);
    }
    __syncthreads();

    if (tid == 0) {
        float m = sPool[0] * INV_SCALE;
        #pragma unroll
        for (int t = 1; t < TT; t++) m = fmaxf(m, sPool[t] * INV_SCALE);
        float ssum = 0.f;
        #pragma unroll
        for (int t = 0; t < TT; t++) { float e = __expf(sPool[t]*INV_SCALE - m); sW[t] = e; ssum += e; }
        float inv = 1.0f / ssum;
        #pragma unroll
        for (int t = 0; t < TT; t++) sW[t] *= inv;
    }
    __syncthreads();

    {
        int r = tid;
        const __half* vb = g_Val + (size_t)bci*TT*RR + r;
        float a2 = 0.f;
        #pragma unroll
        for (int t = 0; t < TT; t++) a2 = fmaf(sW[t], __half2float(vb[t*RR]), a2);
        g_rep[(size_t)bci*RR + r] = a2;
    }
}

// ---------------- mean + ltr ----------------
__global__ void k_fv(const float* __restrict__ ltr_w, const float* __restrict__ ltr_b) {
    __shared__ float red[256];
    int bc = blockIdx.x;
    int r = threadIdx.x;
    float ssum = 0.f;
    for (int i = 0; i < HIS; i++) ssum += g_rep[(size_t)(bc*HIS + i)*RR + r];
    red[r] = (ssum * (1.0f/HIS)) * ltr_w[r];
    __syncthreads();
    for (int off = 128; off; off >>= 1) {
        if (r < off) red[r] += red[r + off];
        __syncthreads();
    }
    if (r == 0) g_score[bc] = red[0] + ltr_b[0];
}

// ---------------- log_softmax ----------------
__global__ void k_out(float* __restrict__ out) {
    int b = threadIdx.x;
    if (b < BB) {
        float s[CDD];
        float m = -1e30f;
        #pragma unroll
        for (int c = 0; c < CDD; c++) { s[c] = g_score[b*CDD + c]; m = fmaxf(m, s[c]); }
        float ssum = 0.f;
        #pragma unroll
        for (int c = 0; c < CDD; c++) ssum += expf(s[c] - m);
        float lse = logf(ssum);
        #pragma unroll
        for (int c = 0; c < CDD; c++) out[b*CDD + c] = s[c] - m - lse;
    }
}

// ---------------- launch ----------------
extern "C" void kernel_launch(void* const* d_in, const int* in_sizes, int n_in,
                              void* d_out, int out_size) {
    const int*   cand  = (const int*)  d_in[0];
    const int*   clk   = (const int*)  d_in[1];
    const float* emb   = (const float*)d_in[2];
    const float* Wq_w  = (const float*)d_in[3];
    const float* Wv_w  = (const float*)d_in[4];
    const float* Wq_i  = (const float*)d_in[5];
    const float* Wv_i  = (const float*)d_in[6];
    const float* keyW  = (const float*)d_in[7];
    const float* keyb  = (const float*)d_in[8];
    const float* query = (const float*)d_in[9];
    const float* ltr_w = (const float*)d_in[10];
    const float* ltr_b = (const float*)d_in[11];
    float* out = (float*)d_out;

    cudaFuncSetAttribute(k_fuse_av, cudaFuncAttributeMaxDynamicSharedMemorySize,
                         K5_SMEM_FLOATS * sizeof(float));

    k_prep<<<NS + 65, 256>>>(cand, clk, emb, Wq_w, Wv_w, Wq_i, Wv_i);

    k_gA<<<1400, 256, GEMM_SMEM>>>();                       // words Q + words XV
    k_t128<7><<<dim3(1, 3, NS), 256, GEMM_SMEM>>>(nullptr); // words scores
    k_wattn2<<<dim3(NS, HH), 320>>>();

    k_gB<<<1190, 256, GEMM_SMEM>>>(Wq_i);                   // itrs Q + itrs V
    k_gC<<<1684, 256, GEMM_SMEM>>>();                       // diag + Sx1 + Sx2

    k_fuse_av<<<NBCI, 256, K5_SMEM_FLOATS * sizeof(float)>>>();
    k_t128<6><<<dim3(2, 321, 1), 256, GEMM_SMEM>>>(keyW);   // Kmat
    k_pool<<<NBCI, 256>>>(keyb, query);

    k_fv<<<NSC, 256>>>(ltr_w, ltr_b);
    k_out<<<1, 32>>>(out);
}

// round 17
// speedup vs baseline: 11.0016x; 1.0359x over previous
#include <cuda_runtime.h>
#include <cuda_fp16.h>
#include <math.h>
#include <stdint.h>

#define BB   4
#define CDD  5
#define HIS  50
#define LL   20
#define TT   41
#define EE   300
#define EEP  320
#define HH   16
#define VV   16
#define RR   256
#define QQ   200
#define NSC  (BB*CDD)        // 20
#define NSH  (BB*HIS)        // 200
#define NS   (NSC+NSH)       // 220
#define NTOK (NS*LL)         // 4400
#define NBCI (BB*CDD*HIS)    // 1000
#define MVAL (NBCI*TT)       // 41000
#define NQW  4800

#define INV_SCALE 0.057735026918962584f   // 1/sqrt(300)

// ---------------- device scratch ----------------
__device__ float  g_Xp[NTOK*EEP];
__device__ float  g_Wqall[EEP*NQW];
__device__ float  g_Wvp[EEP*RR];
__device__ float  g_Wvp2[RR*RR];
__device__ __half g_Qw[(size_t)NS*HH*LL*EEP];  // fp16; cols 300..319 stay zero (static init)
__device__ float  g_Sw[(size_t)NS*HH*LL*LL];
__device__ float  g_XV[NTOK*RR];
__device__ float  g_Rep[NS*LL*RR];
__device__ __half g_Q[(size_t)NS*HH*LL*RR];
__device__ float  g_V[NS*LL*RR];
__device__ __half g_q1h[HH*RR];
__device__ float  g_v1[RR];
__device__ float  g_ones[RR];
__device__ float  g_Scc[NSC*HH*21*21];
__device__ float  g_Shh[NSH*HH*21*21];
__device__ float  g_Sx1[(size_t)BB*HH*100*1000];
__device__ float  g_Sx2[(size_t)BB*HH*1000*100];
__device__ __half g_Val[(size_t)MVAL*RR];
__device__ float  g_poolsum[MVAL];             // fused pool partial sums
__device__ float  g_kb[QQ];
__device__ float  g_qu[QQ];
__device__ float  g_rep[NBCI*RR];
__device__ float  g_score[NSC];

// ---------------- K0: merged prep ----------
__global__ void k_prep(const int* __restrict__ cand, const int* __restrict__ clk,
                       const float* __restrict__ emb,
                       const float* __restrict__ Wq_w, const float* __restrict__ Wv_w,
                       const float* __restrict__ Wq_i, const float* __restrict__ Wv_i,
                       const float* __restrict__ keyb, const float* __restrict__ query) {
    int blk = blockIdx.x, tid = threadIdx.x;
    if (blk < NS) {
        const int* tok = (blk < NSC) ? (cand + blk*LL) : (clk + (blk-NSC)*LL);
        for (int idx = tid; idx < LL*EEP; idx += 256) {
            int t = idx / EEP, d = idx - t*EEP;
            g_Xp[(blk*LL + t)*EEP + d] = (d < EE) ? emb[(size_t)tok[t]*EE + d] : 0.f;
        }
    } else if (blk < NS + 16) {
        int h = blk - NS;
        for (int idx = tid; idx < EEP*EE; idx += 256) {
            int k = idx / EE, j = idx - k*EE;
            g_Wqall[(size_t)k*NQW + h*EE + j] =
                (k < EE) ? Wq_w[(size_t)h*EE*EE + (size_t)k*EE + j] : 0.f;
        }
    } else if (blk < NS + 32) {
        int part = blk - NS - 16;
        for (int q = 0; q < EEP*RR/(16*256); q++) {
            int idx = part*(EEP*RR/16) + q*256 + tid;
            int k = idx >> 8, col = idx & 255;
            int h = col >> 4, v = col & 15;
            g_Wvp[idx] = (k < EE) ? Wv_w[((size_t)h*EE + k)*VV + v] : 0.f;
        }
    } else if (blk < NS + 48) {
        int part = blk - NS - 32;
        for (int q = 0; q < RR*RR/(16*256); q++) {
            int idx = part*(RR*RR/16) + q*256 + tid;
            int r = idx >> 8, col = idx & 255;
            int h = col >> 4, v = col & 15;
            g_Wvp2[idx] = Wv_i[((size_t)h*RR + r)*VV + v];
        }
    } else if (blk < NS + 64) {
        int h = blk - NS - 48, j = tid;
        if (h == 0) g_ones[j] = 1.0f;
        float acc = 0.f;
        const float* w = Wq_i + (size_t)h*RR*RR + j;
        for (int r = 0; r < RR; r++) acc += w[r*RR];
        g_q1h[h*RR + j] = __float2half(acc);
    } else if (blk < NS + 65) {
        int h = tid >> 4, v = tid & 15;
        float a2 = 0.f;
        const float* wv = Wv_i + (size_t)h*RR*VV + v;
        for (int r = 0; r < RR; r++) a2 += wv[r*VV];
        g_v1[h*VV + v] = a2;
    } else {
        if (tid < QQ) { g_kb[tid] = keyb[tid]; g_qu[tid] = query[tid]; }
    }
}

// ---------------- fp16 mma helpers ----------------
__device__ __forceinline__ void mma_f16(float c[4], const uint32_t a[4], const uint32_t b[2]) {
    asm volatile(
        "mma.sync.aligned.m16n8k16.row.col.f32.f16.f16.f32 "
        "{%0,%1,%2,%3}, {%4,%5,%6,%7}, {%8,%9}, {%0,%1,%2,%3};"
        : "+f"(c[0]), "+f"(c[1]), "+f"(c[2]), "+f"(c[3])
        : "r"(a[0]), "r"(a[1]), "r"(a[2]), "r"(a[3]), "r"(b[0]), "r"(b[1]));
}
__device__ __forceinline__ uint4 pack8h(float4 lo, float4 hi) {
    __half2 h0 = __floats2half2_rn(lo.x, lo.y);
    __half2 h1 = __floats2half2_rn(lo.z, lo.w);
    __half2 h2 = __floats2half2_rn(hi.x, hi.y);
    __half2 h3 = __floats2half2_rn(hi.z, hi.w);
    uint4 r;
    r.x = *(uint32_t*)&h0; r.y = *(uint32_t*)&h1;
    r.z = *(uint32_t*)&h2; r.w = *(uint32_t*)&h3;
    return r;
}
__device__ __forceinline__ float fast_tanh(float x) {
    x = fminf(fmaxf(x, -15.f), 15.f);
    float e = __expf(2.f * x);
    return (e - 1.f) / (e + 1.f);
}

// ---------------- fp16 tensor-core GEMM (m16n8k16, 2-ahead pipelined) ----------
// MODE 0: Qw(h16)  = Xp @ Wqall   M=4400  N=4800 K=320  (38,35)
// MODE 1: Q (h16)  = Rep @ Wq_i   M=4400  N=256  K=256  (2,35,z=h16)
// MODE 2: XV       = Xp @ Wvp     M=4400  N=256  K=320  (2,35)
// MODE 3: V        = Rep @ Wvp2   M=4400  N=256  K=256  (2,35)
// MODE 4: Sx1      = Qc @ RepH^T  M=100   N=1000 K=256  (8,1,z=64)  A fp16
// MODE 5: Sx2      = Qh @ RepC^T  M=1000  N=100  K=256  (1,8,z=64)  A fp16
// MODE 6: poolsum += q.tanh(Val@keyW + b)  M=41000 N=200 K=256 (2,321)  A fp16, fused epilogue
// MODE 7: Sw[s]    = Qw @ X^T     M=320   N=20   K=320  (1,3,z=220) NARROW, A fp16
// MODE 8: diag[s]                 M=336   N=21   K=256  (1,3,z=220) NARROW, A fp16, scalar st
#define BM 128
#define BN 128
#define BK 16
#define ASP 24
#define GEMM_SMEM ((2*BM*ASP + 2*BN*ASP)*2)  // 24576 B

template<int MODE>
__device__ __forceinline__ void gemm_body(const float* __restrict__ Bglob,
                                          int bxi, int byi, int bzi, __half* smh) {
    constexpr int K   = (MODE==0 || MODE==2 || MODE==7) ? EEP : RR;
    constexpr int M   = (MODE==4) ? 100 : (MODE==5 ? 1000 : (MODE==6 ? MVAL :
                        (MODE==7 ? 320 : (MODE==8 ? 336 : NTOK))));
    constexpr int N   = (MODE==0) ? NQW : (MODE==4 ? 1000 : (MODE==5 ? 100 :
                        (MODE==6 ? QQ : (MODE==7 ? 20 : (MODE==8 ? 21 : RR)))));
    constexpr bool BT = (MODE==4 || MODE==5 || MODE==7 || MODE==8);
    constexpr bool NARROW = (MODE==7 || MODE==8);
    constexpr bool AH = (MODE>=4);
    constexpr int LDB = (MODE==0) ? NQW : (MODE==6 ? QQ : RR);
    constexpr int NCH = K / BK;
    constexpr int NMT = NARROW ? 1 : 4;

    __half* AsB = smh;
    __half* BsB = smh + 2*BM*ASP;

    const int tid = threadIdx.x;
    const int bz = bzi;
    const int nBase = bxi * BN;
    const int mBase = byi * BM;
    int b = 0, h = 0;
    if (MODE==1) h = bz;
    if (MODE==4 || MODE==5) { b = bz >> 4; h = bz & 15; }

    const int ar  = tid >> 1;
    const int akq = (tid & 1) * 2;
    const float*  ArowF = nullptr;
    const __half* ArowH = nullptr;
    {
        int am = mBase + ar;
        if (am < M) {
            if (MODE==0 || MODE==2) ArowF = g_Xp + (size_t)am*EEP;
            else if (MODE==1 || MODE==3) ArowF = g_Rep + (size_t)am*RR;
            else if (MODE==6) ArowH = g_Val + (size_t)am*RR;
            else if (MODE==7) ArowH = g_Qw + (size_t)(bz*320 + am)*EEP;
            else if (MODE==8) {
                int h8 = am / 21, t8 = am - 21*h8;
                ArowH = (t8 < 20) ? g_Q + (((size_t)bz*HH + h8)*LL + t8)*RR
                                  : g_q1h + (size_t)h8*RR;
            }
            else if (MODE==4) { int c = am/20, t = am - 20*c;
                ArowH = g_Q + (size_t)(((b*CDD + c)*HH + h)*LL + t)*RR; }
            else { int i = am/20, u = am - 20*i;
                ArowH = g_Q + (size_t)(((NSC + b*HIS + i)*HH + h)*LL + u)*RR; }
        }
    }
    const float* Brow = nullptr;
    const float* Bb = nullptr;
    int bkr = 0, bn1 = 0; bool bok1 = false, bok2 = false;
    if (BT) {
        int bn = nBase + ar;
        if (bn < N) {
            if (MODE==4)      Brow = g_Rep + ((size_t)(NSC + b*HIS)*LL + bn)*RR;
            else if (MODE==5) Brow = g_Rep + ((size_t)(b*CDD)*LL + bn)*RR;
            else if (MODE==7) Brow = g_Xp + ((size_t)bz*LL + bn)*EEP;
            else              Brow = (bn < 20) ? g_Rep + ((size_t)bz*LL + bn)*RR : g_ones;
        }
    } else {
        if (MODE==0) Bb = g_Wqall;
        else if (MODE==1) Bb = Bglob + (size_t)h*RR*RR;
        else if (MODE==2) Bb = g_Wvp;
        else if (MODE==3) Bb = g_Wvp2;
        else Bb = Bglob;   // MODE 6: keyW
        bkr = tid >> 4; bn1 = (tid & 15) * 4;
        bok1 = (nBase + bn1) < N;
        bok2 = (nBase + bn1 + 64) < N;
    }

    uint4 aR0, aR1, bR0, bR1;
    float4 p00, p01, p10, p11;
    const float4 fz = make_float4(0.f, 0.f, 0.f, 0.f);
    const uint4 uz = make_uint4(0u, 0u, 0u, 0u);

    auto load0 = [&](int kc) {
        aR0 = uz; p00 = fz; p01 = fz; bR0 = uz;
        if (AH) { if (ArowH) aR0 = *(const uint4*)(ArowH + kc + 4*akq); }
        else if (ArowF) {
            float4 a0 = *(const float4*)(ArowF + kc + 4*akq);
            float4 a1 = *(const float4*)(ArowF + kc + 4*akq + 4);
            aR0 = pack8h(a0, a1);
        }
        if (BT) {
            if (Brow) {
                float4 b0 = *(const float4*)(Brow + kc + 4*akq);
                float4 b1 = *(const float4*)(Brow + kc + 4*akq + 4);
                bR0 = pack8h(b0, b1);
            }
        } else {
            if (bok1) p00 = *(const float4*)(Bb + (size_t)(kc + bkr)*LDB + nBase + bn1);
            if (bok2) p01 = *(const float4*)(Bb + (size_t)(kc + bkr)*LDB + nBase + bn1 + 64);
        }
    };
    auto load1 = [&](int kc) {
        aR1 = uz; p10 = fz; p11 = fz; bR1 = uz;
        if (AH) { if (ArowH) aR1 = *(const uint4*)(ArowH + kc + 4*akq); }
        else if (ArowF) {
            float4 a0 = *(const float4*)(ArowF + kc + 4*akq);
            float4 a1 = *(const float4*)(ArowF + kc + 4*akq + 4);
            aR1 = pack8h(a0, a1);
        }
        if (BT) {
            if (Brow) {
                float4 b0 = *(const float4*)(Brow + kc + 4*akq);
                float4 b1 = *(const float4*)(Brow + kc + 4*akq + 4);
                bR1 = pack8h(b0, b1);
            }
        } else {
            if (bok1) p10 = *(const float4*)(Bb + (size_t)(kc + bkr)*LDB + nBase + bn1);
            if (bok2) p11 = *(const float4*)(Bb + (size_t)(kc + bkr)*LDB + nBase + bn1 + 64);
        }
    };
    auto storeSlot = [&](int buf, uint4 aRv, uint4 bRv, float4 pb0, float4 pb1) {
        __half* dA = AsB + buf*BM*ASP;
        __half* dB = BsB + buf*BN*ASP;
        *(uint4*)(dA + ar*ASP + 4*akq) = aRv;
        if (BT) {
            *(uint4*)(dB + ar*ASP + 4*akq) = bRv;
        } else {
            dB[(bn1+0)*ASP + bkr] = __float2half(pb0.x);
            dB[(bn1+1)*ASP + bkr] = __float2half(pb0.y);
            dB[(bn1+2)*ASP + bkr] = __float2half(pb0.z);
            dB[(bn1+3)*ASP + bkr] = __float2half(pb0.w);
            dB[(bn1+64)*ASP + bkr] = __float2half(pb1.x);
            dB[(bn1+65)*ASP + bkr] = __float2half(pb1.y);
            dB[(bn1+66)*ASP + bkr] = __float2half(pb1.z);
            dB[(bn1+67)*ASP + bkr] = __float2half(pb1.w);
        }
    };

    const int warp = tid >> 5, lane = tid & 31;
    const int wm = NARROW ? warp*16 : (warp >> 2)*64;
    const int wn = NARROW ? 0 : (warp & 3)*32;
    const int g = lane >> 2, tig = lane & 3;

    float c[NMT][4][4];
    #pragma unroll
    for (int mt = 0; mt < NMT; mt++)
        #pragma unroll
        for (int nt = 0; nt < 4; nt++)
            #pragma unroll
            for (int e = 0; e < 4; e++) c[mt][nt][e] = 0.f;

    auto compute = [&](int buf) {
        const __half* pA = AsB + buf*BM*ASP;
        const __half* pB = BsB + buf*BN*ASP;
        uint32_t af[NMT][4], bf[4][2];
        #pragma unroll
        for (int mt = 0; mt < NMT; mt++) {
            const __half* r0 = pA + (wm + mt*16 + g)*ASP + 2*tig;
            const __half* r1 = pA + (wm + mt*16 + g + 8)*ASP + 2*tig;
            af[mt][0] = *(const uint32_t*)r0;
            af[mt][1] = *(const uint32_t*)r1;
            af[mt][2] = *(const uint32_t*)(r0 + 8);
            af[mt][3] = *(const uint32_t*)(r1 + 8);
        }
        #pragma unroll
        for (int nt = 0; nt < 4; nt++) {
            const __half* rb = pB + (wn + nt*8 + g)*ASP + 2*tig;
            bf[nt][0] = *(const uint32_t*)rb;
            bf[nt][1] = *(const uint32_t*)(rb + 8);
        }
        #pragma unroll
        for (int mt = 0; mt < NMT; mt++)
            #pragma unroll
            for (int nt = 0; nt < 4; nt++)
                mma_f16(c[mt][nt], af[mt], bf[nt]);
    };

    load0(0);
    load1(BK);
    storeSlot(0, aR0, bR0, p00, p01);
    __syncthreads();

    for (int ch = 0; ch < NCH; ch += 2) {
        if (ch + 2 < NCH) load0((ch + 2) * BK);
        compute(0);
        if (ch + 1 < NCH) { storeSlot(1, aR1, bR1, p10, p11); __syncthreads(); }
        if (ch + 1 < NCH) {
            if (ch + 3 < NCH) load1((ch + 3) * BK);
            compute(1);
            if (ch + 2 < NCH) { storeSlot(0, aR0, bR0, p00, p01); __syncthreads(); }
        }
    }

    // ---- epilogue ----
    #pragma unroll
    for (int mt = 0; mt < NMT; mt++) {
        #pragma unroll
        for (int half = 0; half < 2; half++) {
            int row = mBase + wm + mt*16 + g + half*8;
            if (row >= M) continue;
            if (MODE==0) {
                int s = row/20, t = row - 20*s;
                __half* obase = g_Qw + ((size_t)(s*HH))*LL*EEP + (size_t)t*EEP;
                #pragma unroll
                for (int nt = 0; nt < 4; nt++) {
                    int col = nBase + wn + nt*8 + 2*tig;
                    if (col < NQW) {
                        int hh = col / 300;
                        int jj = col - 300*hh;
                        *(__half2*)(obase + (size_t)hh*LL*EEP + jj) =
                            __floats2half2_rn(c[mt][nt][half*2], c[mt][nt][half*2 + 1]);
                    }
                }
                continue;
            }
            if (MODE==1) {
                int s = row/20, t = row - 20*s;
                __half* oh = g_Q + ((size_t)(s*HH + h)*LL + t)*RR;
                #pragma unroll
                for (int nt = 0; nt < 4; nt++) {
                    int col = nBase + wn + nt*8 + 2*tig;
                    if (col < N)
                        *(__half2*)(oh + col) =
                            __floats2half2_rn(c[mt][nt][half*2], c[mt][nt][half*2 + 1]);
                }
                continue;
            }
            if (MODE==6) {
                // fused additive-attention pooling: partial = sum_j q_j * tanh(Kmat + b_j)
                float partial = 0.f;
                #pragma unroll
                for (int nt = 0; nt < 4; nt++) {
                    int col = nBase + wn + nt*8 + 2*tig;
                    if (col < QQ) {
                        partial += g_qu[col] * fast_tanh(c[mt][nt][half*2] + g_kb[col]);
                        if (col + 1 < QQ)
                            partial += g_qu[col+1] * fast_tanh(c[mt][nt][half*2+1] + g_kb[col+1]);
                    }
                }
                atomicAdd(&g_poolsum[row], partial);
                continue;
            }
            float* o;
            if (MODE==2) o = g_XV + (size_t)row*RR;
            else if (MODE==3) o = g_V + (size_t)row*RR;
            else if (MODE==7) o = g_Sw + (size_t)bz*(HH*LL*LL) + (size_t)row*20;
            else if (MODE==8) {
                int h8 = row/21, t8 = row - 21*h8;
                float* base = (bz < NSC) ? g_Scc + ((size_t)bz*HH + h8)*441
                                         : g_Shh + ((size_t)(bz-NSC)*HH + h8)*441;
                o = base + t8*21;
            }
            else if (MODE==4) o = g_Sx1 + (size_t)bz*100000 + (size_t)row*1000;
            else              o = g_Sx2 + (size_t)bz*100000 + (size_t)row*100;
            #pragma unroll
            for (int nt = 0; nt < 4; nt++) {
                int col = nBase + wn + nt*8 + 2*tig;
                float c0 = c[mt][nt][half*2], c1 = c[mt][nt][half*2 + 1];
                if (MODE==8) {
                    if (col < N)     o[col]     = c0;
                    if (col + 1 < N) o[col + 1] = c1;
                } else {
                    if (col < N) {
                        if (col + 1 < N) *(float2*)(o + col) = make_float2(c0, c1);
                        else o[col] = c0;
                    }
                }
            }
        }
    }
}

// ---- combo kernels ----
__global__ void __launch_bounds__(256, 2)
k_gA() {
    extern __shared__ __align__(16) char smraw[];
    __half* sm = (__half*)smraw;
    int bid = blockIdx.x;
    if (bid < 1330) gemm_body<0>(nullptr, bid % 38, bid / 38, 0, sm);
    else { int r = bid - 1330; gemm_body<2>(nullptr, r % 2, r / 2, 0, sm); }
}
__global__ void __launch_bounds__(256, 2)
k_gB(const float* __restrict__ Wq_i) {
    extern __shared__ __align__(16) char smraw[];
    __half* sm = (__half*)smraw;
    int bid = blockIdx.x;
    if (bid < 1120) gemm_body<1>(Wq_i, bid % 2, (bid / 2) % 35, bid / 70, sm);
    else { int r = bid - 1120; gemm_body<3>(nullptr, r % 2, r / 2, 0, sm); }
}
__global__ void __launch_bounds__(256, 2)
k_gC() {
    extern __shared__ __align__(16) char smraw[];
    __half* sm = (__half*)smraw;
    int bid = blockIdx.x;
    if (bid < 660) gemm_body<8>(nullptr, 0, bid % 3, bid / 3, sm);
    else if (bid < 660 + 512) { int r = bid - 660; gemm_body<4>(nullptr, r % 8, 0, r / 8, sm); }
    else { int r = bid - 1172; gemm_body<5>(nullptr, 0, r % 8, r / 8, sm); }
}
template<int MODE>
__global__ void __launch_bounds__(256, 2)
k_t128(const float* __restrict__ Bglob) {
    extern __shared__ __align__(16) char smraw[];
    __half* sm = (__half*)smraw;
    gemm_body<MODE>(Bglob, blockIdx.x, blockIdx.y, blockIdx.z, sm);
}

// ---------------- K2b: words softmax + A.XV ----------
__global__ void __launch_bounds__(320, 4)
k_wattn2() {
    __shared__ float S[20*21];
    __shared__ float XVs[20*16];
    int s = blockIdx.x, h = blockIdx.y, tid = threadIdx.x;

    for (int idx = tid; idx < 400; idx += 320) {
        int t = idx / 20, u = idx - 20*t;
        S[t*21 + u] = g_Sw[(size_t)s*(HH*LL*LL) + (size_t)(h*20 + t)*20 + u] * INV_SCALE;
    }
    {
        int u = tid >> 4, v = tid & 15;
        XVs[tid] = g_XV[((size_t)s*LL + u)*RR + h*VV + v];
    }
    __syncthreads();

    if (tid < LL) {
        float* row = S + tid*21;
        float m = row[0];
        #pragma unroll
        for (int u = 1; u < LL; u++) m = fmaxf(m, row[u]);
        float ssum = 0.f;
        #pragma unroll
        for (int u = 0; u < LL; u++) { float e = __expf(row[u] - m); row[u] = e; ssum += e; }
        float inv = 1.0f / ssum;
        #pragma unroll
        for (int u = 0; u < LL; u++) row[u] *= inv;
    }
    __syncthreads();

    {
        int t = tid >> 4, v = tid & 15;
        float acc = 0.f;
        #pragma unroll
        for (int u = 0; u < LL; u++) acc = fmaf(S[t*21 + u], XVs[u*16 + v], acc);
        g_Rep[((size_t)s*LL + t)*RR + h*VV + v] = acc;
    }
}

// ---------------- K5: fused softmax + AV -> g_Val (fp16 out, float4 AV) ----------
#define SC_VC   0
#define SC_VH   (SC_VC + LL*RR)
#define SC_V1   (SC_VH + LL*RR)
#define SC_S    (SC_V1 + RR)
#define K5_SMEM_FLOATS (SC_S + TT*TT + 15)

__global__ void __launch_bounds__(256, 4)
k_fuse_av() {
    extern __shared__ float sm[];
    float* sVc  = sm + SC_VC;
    float* sVh  = sm + SC_VH;
    float* sV1  = sm + SC_V1;
    float* sS   = sm + SC_S;

    int bci = blockIdx.x;
    int i   = bci % HIS;
    int bc  = bci / HIS;
    int b   = bc / CDD;
    int c   = bc - b*CDD;
    int sc  = bc;
    int sh  = NSC + b*HIS + i;

    int tid = threadIdx.x;
    int wrp = tid >> 5, ln = tid & 31;

    if (tid < TT) g_poolsum[bci*TT + tid] = 0.f;   // zero pool rows for MODE 6 atomics

    {
        const float4* gvc = (const float4*)(g_V + (size_t)sc*LL*RR);
        const float4* gvh = (const float4*)(g_V + (size_t)sh*LL*RR);
        float4* dVc = (float4*)sVc; float4* dVh = (float4*)sVh;
        for (int idx = tid; idx < LL*RR/4; idx += 256) { dVc[idx] = gvc[idx]; dVh[idx] = gvh[idx]; }
        if (tid < RR) sV1[tid] = g_v1[tid];
    }

    // precompute gather descriptors
    int psrc[7], poff[7];
    #pragma unroll
    for (int r = 0; r < 7; r++) {
        int p = tid + 256*r;
        psrc[r] = -1; poff[r] = 0;
        if (p < TT*TT) {
            int q = p / TT, k = p - q*TT;
            if (q < LL) {
                if (k < LL)       { psrc[r] = 0; poff[r] = q*21 + k; }
                else if (k == LL) { psrc[r] = 0; poff[r] = q*21 + 20; }
                else              { psrc[r] = 2; poff[r] = (c*20 + q)*1000 + i*20 + (k - LL - 1); }
            } else if (q == LL) {
                if (k < LL)       { psrc[r] = 0; poff[r] = 20*21 + k; }
                else if (k == LL) { psrc[r] = 0; poff[r] = 20*21 + 20; }
                else              { psrc[r] = 1; poff[r] = 20*21 + (k - LL - 1); }
            } else {
                int t = q - LL - 1;
                if (k < LL)       { psrc[r] = 3; poff[r] = (i*20 + t)*100 + c*20 + k; }
                else if (k == LL) { psrc[r] = 1; poff[r] = t*21 + 20; }
                else              { psrc[r] = 1; poff[r] = t*21 + (k - LL - 1); }
            }
        }
    }

    __half* valOut = g_Val + (size_t)bci*TT*RR;
    const int avq = tid >> 2, avg = tid & 3;
    const bool avact = (tid < TT*4);

    for (int h = 0; h < HH; h++) {
        const float* scc = g_Scc + ((size_t)bc*HH + h)*441;
        const float* shh = g_Shh + ((size_t)(b*HIS + i)*HH + h)*441;
        const float* sx1 = g_Sx1 + ((size_t)(b*HH + h))*100*1000;
        const float* sx2 = g_Sx2 + ((size_t)(b*HH + h))*1000*100;

        __syncthreads();
        #pragma unroll
        for (int r = 0; r < 7; r++) {
            if (psrc[r] >= 0) {
                const float* bp = (psrc[r] == 0) ? scc :
                                  (psrc[r] == 1) ? shh :
                                  (psrc[r] == 2) ? sx1 : sx2;
                sS[tid + 256*r] = __ldg(bp + poff[r]) * INV_SCALE;
            }
        }
        __syncthreads();

        for (int q = wrp; q < TT; q += 8) {
            float* row = sS + q*TT;
            float v0 = row[ln];
            float v1 = (ln + 32 < TT) ? row[ln + 32] : -1e30f;
            float m = fmaxf(v0, v1);
            #pragma unroll
            for (int o = 16; o; o >>= 1) m = fmaxf(m, __shfl_xor_sync(0xffffffffu, m, o));
            float e0 = __expf(v0 - m);
            float e1 = (ln + 32 < TT) ? __expf(v1 - m) : 0.f;
            float ss = e0 + e1;
            #pragma unroll
            for (int o = 16; o; o >>= 1) ss += __shfl_xor_sync(0xffffffffu, ss, o);
            float inv = 1.0f / ss;
            row[ln] = e0 * inv;
            if (ln + 32 < TT) row[ln + 32] = e1 * inv;
        }
        __syncthreads();

        if (avact) {
            int col = h*VV + avg*4;
            const float* arow = sS + avq*TT;
            float a20 = arow[LL];
            float4 v1v = *(const float4*)(sV1 + col);
            float ax = a20*v1v.x, ay = a20*v1v.y, az = a20*v1v.z, aw = a20*v1v.w;
            #pragma unroll
            for (int k = 0; k < LL; k++) {
                float ak = arow[k];
                float4 vc = *(const float4*)(sVc + k*RR + col);
                ax = fmaf(ak, vc.x, ax); ay = fmaf(ak, vc.y, ay);
                az = fmaf(ak, vc.z, az); aw = fmaf(ak, vc.w, aw);
            }
            #pragma unroll
            for (int k = 0; k < LL; k++) {
                float ak = arow[LL+1+k];
                float4 vh = *(const float4*)(sVh + k*RR + col);
                ax = fmaf(ak, vh.x, ax); ay = fmaf(ak, vh.y, ay);
                az = fmaf(ak, vh.z, az); aw = fmaf(ak, vh.w, aw);
            }
            __half2 h01 = __floats2half2_rn(ax, ay);
            __half2 h23 = __floats2half2_rn(az, aw);
            uint2 packed;
            packed.x = *(uint32_t*)&h01; packed.y = *(uint32_t*)&h23;
            *(uint2*)(valOut + (size_t)avq*RR + col) = packed;
        }
    }
}

// ---------------- K6: pooling (poolsum precomputed by MODE 6) ----------------
__global__ void __launch_bounds__(256, 4)
k_pool() {
    __shared__ float sW[48];

    int bci = blockIdx.x, tid = threadIdx.x;

    if (tid == 0) {
        const float* ps = g_poolsum + bci*TT;
        float m = ps[0] * INV_SCALE;
        #pragma unroll
        for (int t = 1; t < TT; t++) m = fmaxf(m, ps[t] * INV_SCALE);
        float ssum = 0.f;
        #pragma unroll
        for (int t = 0; t < TT; t++) { float e = __expf(ps[t]*INV_SCALE - m); sW[t] = e; ssum += e; }
        float inv = 1.0f / ssum;
        #pragma unroll
        for (int t = 0; t < TT; t++) sW[t] *= inv;
    }
    __syncthreads();

    {
        int r = tid;
        const __half* vb = g_Val + (size_t)bci*TT*RR + r;
        float a2 = 0.f;
        #pragma unroll
        for (int t = 0; t < TT; t++) a2 = fmaf(sW[t], __half2float(vb[t*RR]), a2);
        g_rep[(size_t)bci*RR + r] = a2;
    }
}

// ---------------- mean + ltr ----------------
__global__ void k_fv(const float* __restrict__ ltr_w, const float* __restrict__ ltr_b) {
    __shared__ float red[256];
    int bc = blockIdx.x;
    int r = threadIdx.x;
    float ssum = 0.f;
    for (int i = 0; i < HIS; i++) ssum += g_rep[(size_t)(bc*HIS + i)*RR + r];
    red[r] = (ssum * (1.0f/HIS)) * ltr_w[r];
    __syncthreads();
    for (int off = 128; off; off >>= 1) {
        if (r < off) red[r] += red[r + off];
        __syncthreads();
    }
    if (r == 0) g_score[bc] = red[0] + ltr_b[0];
}

// ---------------- log_softmax ----------------
__global__ void k_out(float* __restrict__ out) {
    int b = threadIdx.x;
    if (b < BB) {
        float s[CDD];
        float m = -1e30f;
        #pragma unroll
        for (int c = 0; c < CDD; c++) { s[c] = g_score[b*CDD + c]; m = fmaxf(m, s[c]); }
        float ssum = 0.f;
        #pragma unroll
        for (int c = 0; c < CDD; c++) ssum += expf(s[c] - m);
        float lse = logf(ssum);
        #pragma unroll
        for (int c = 0; c < CDD; c++) out[b*CDD + c] = s[c] - m - lse;
    }
}

// ---------------- launch ----------------
extern "C" void kernel_launch(void* const* d_in, const int* in_sizes, int n_in,
                              void* d_out, int out_size) {
    const int*   cand  = (const int*)  d_in[0];
    const int*   clk   = (const int*)  d_in[1];
    const float* emb   = (const float*)d_in[2];
    const float* Wq_w  = (const float*)d_in[3];
    const float* Wv_w  = (const float*)d_in[4];
    const float* Wq_i  = (const float*)d_in[5];
    const float* Wv_i  = (const float*)d_in[6];
    const float* keyW  = (const float*)d_in[7];
    const float* keyb  = (const float*)d_in[8];
    const float* query = (const float*)d_in[9];
    const float* ltr_w = (const float*)d_in[10];
    const float* ltr_b = (const float*)d_in[11];
    float* out = (float*)d_out;

    cudaFuncSetAttribute(k_fuse_av, cudaFuncAttributeMaxDynamicSharedMemorySize,
                         K5_SMEM_FLOATS * sizeof(float));

    k_prep<<<NS + 66, 256>>>(cand, clk, emb, Wq_w, Wv_w, Wq_i, Wv_i, keyb, query);

    k_gA<<<1400, 256, GEMM_SMEM>>>();                       // words Q + words XV
    k_t128<7><<<dim3(1, 3, NS), 256, GEMM_SMEM>>>(nullptr); // words scores
    k_wattn2<<<dim3(NS, HH), 320>>>();

    k_gB<<<1190, 256, GEMM_SMEM>>>(Wq_i);                   // itrs Q + itrs V
    k_gC<<<1684, 256, GEMM_SMEM>>>();                       // diag + Sx1 + Sx2

    k_fuse_av<<<NBCI, 256, K5_SMEM_FLOATS * sizeof(float)>>>();
    k_t128<6><<<dim3(2, 321, 1), 256, GEMM_SMEM>>>(keyW);   // Kmat GEMM + fused tanh-pool
    k_pool<<<NBCI, 256>>>();

    k_fv<<<NSC, 256>>>(ltr_w, ltr_b);
    k_out<<<1, 32>>>(out);
}